// round 8
// baseline (speedup 1.0000x reference)
#include <cuda_runtime.h>
#include <cuda_bf16.h>
#include <math.h>

#define B_    2
#define N_    8192
#define R_    (B_*N_)          // 16384 rows
#define DS    128
#define DP    16
#define DT    384
#define NTOK  1024
#define QWIN  64
#define KWIN  128
#define PADW  32
#define NW    (N_/QWIN)        // 128 windows
#define HEADS 4
#define DH    32
#define DEPTH 3
#define KFEAT 389
#define KFP   416              // padded to multiple of 32

// packed bf16 weight offsets (hi/lo arrays, layout [N][Kp] row-major)
#define OFF_EMB   0            // 128 x 416
#define OFF_QKV   53248        // 3 layers x [Wq|Wk|Wv] 384 x 128
#define OFF_WO    200704       // 3 x 128 x 128
#define OFF_FF1   249856       // 3 x 512 x 128
#define OFF_FF2   446464       // 3 x 128 x 512
#define OFF_WOUT  643072       // 384 x 128
#define PACK_TOT  692224

// ---------------- scratch (device globals: allocation-free) ----------------
__device__ float g_feats[(size_t)R_*KFP];
__device__ float g_x    [(size_t)R_*DS];
__device__ float g_qkv  [(size_t)R_*3*DS];
__device__ float g_p    [(size_t)R_*2*DP];
__device__ float g_bias [(size_t)B_*NW*HEADS*QWIN*KWIN];
__device__ float g_tok  [(size_t)R_*DT];
__device__ __nv_bfloat16 g_hh[(size_t)R_*DS],  g_hl[(size_t)R_*DS];   // LN(x) split
__device__ __nv_bfloat16 g_bh[PACK_TOT];
__device__ __nv_bfloat16 g_bl[PACK_TOT];

// ---------------- feats = concat(pos, charge, mask, element, chars), pad 0 --
__global__ void build_feats_kernel(const float* __restrict__ pos,
                                   const float* __restrict__ charge,
                                   const float* __restrict__ mask,
                                   const float* __restrict__ elem,
                                   const float* __restrict__ chars)
{
    int row = blockIdx.x;
    float* fr = g_feats + (size_t)row*KFP;
    for (int f = threadIdx.x; f < KFP; f += blockDim.x) {
        float v;
        if      (f < 3)    v = pos[row*3 + f];
        else if (f == 3)   v = charge[row];
        else if (f == 4)   v = mask[row];
        else if (f < 133)  v = elem[(size_t)row*128 + (f-5)];
        else if (f < KFEAT)v = chars[(size_t)row*256 + (f-133)];
        else               v = 0.f;
        fr[f] = v;
    }
}

// ---------------- one fused weight-pack kernel (transpose + hi/lo split) ----
__global__ void pack_all_kernel(const float* __restrict__ Ws, const float* __restrict__ Wq,
                                const float* __restrict__ Wk, const float* __restrict__ Wv,
                                const float* __restrict__ Wo, const float* __restrict__ W1,
                                const float* __restrict__ W2, const float* __restrict__ Wout)
{
    long idx = (long)blockIdx.x*256 + threadIdx.x;
    if (idx >= PACK_TOT) return;
    const float* src; int K, N, Kp; long rem;
    if (idx < OFF_QKV)      { src = Ws;  K = KFEAT; N = 128; Kp = KFP; rem = idx; }
    else if (idx < OFF_WO)  { long r = idx - OFF_QKV; int l = (int)(r/49152); r %= 49152;
                              int ws = (int)(r/16384); rem = r % 16384;
                              src = (ws==0 ? Wq : ws==1 ? Wk : Wv) + (size_t)l*16384;
                              K = 128; N = 128; Kp = 128; }
    else if (idx < OFF_FF1) { long r = idx - OFF_WO; int l = (int)(r/16384); rem = r % 16384;
                              src = Wo + (size_t)l*16384; K = 128; N = 128; Kp = 128; }
    else if (idx < OFF_FF2) { long r = idx - OFF_FF1; int l = (int)(r/65536); rem = r % 65536;
                              src = W1 + (size_t)l*65536; K = 128; N = 512; Kp = 128; }
    else if (idx < OFF_WOUT){ long r = idx - OFF_FF2; int l = (int)(r/65536); rem = r % 65536;
                              src = W2 + (size_t)l*65536; K = 512; N = 128; Kp = 512; }
    else                    { rem = idx - OFF_WOUT; src = Wout; K = 128; N = 384; Kp = 128; }
    int n = (int)(rem / Kp), k = (int)(rem % Kp);
    float v = (k < K) ? src[(size_t)k*N + n] : 0.f;
    __nv_bfloat16 h = __float2bfloat16(v);
    g_bh[idx] = h;
    g_bl[idx] = __float2bfloat16(v - __bfloat162float(h));
}

// ---------------- mma helpers ------------------------------------------------
__device__ __forceinline__ void ldsm4(unsigned &r0, unsigned &r1, unsigned &r2, unsigned &r3,
                                      const __nv_bfloat16* p)
{
    unsigned a = (unsigned)__cvta_generic_to_shared(p);
    asm volatile("ldmatrix.sync.aligned.m8n8.x4.shared.b16 {%0,%1,%2,%3},[%4];"
                 : "=r"(r0), "=r"(r1), "=r"(r2), "=r"(r3) : "r"(a));
}
__device__ __forceinline__ void mma16816(float* d, const unsigned* a, unsigned b0, unsigned b1)
{
    asm volatile("mma.sync.aligned.m16n8k16.row.col.f32.bf16.bf16.f32 "
                 "{%0,%1,%2,%3},{%4,%5,%6,%7},{%8,%9},{%0,%1,%2,%3};"
                 : "+f"(d[0]), "+f"(d[1]), "+f"(d[2]), "+f"(d[3])
                 : "r"(a[0]), "r"(a[1]), "r"(a[2]), "r"(a[3]), "r"(b0), "r"(b1));
}

// shared 32-k-step mma over one A chunk + one B tile (both bf16-split, LD=40)
__device__ __forceinline__ void mma_chunk(float acc[2][8][4],
    const __nv_bfloat16* sXh, const __nv_bfloat16* sXl,
    const __nv_bfloat16* sBh, const __nv_bfloat16* sBl,
    int lane, int warpM, int warpN)
{
    constexpr int LD = 40;
    #pragma unroll
    for (int ks = 0; ks < 2; ks++) {
        int rowin = lane & 7, tile = lane >> 3;
        unsigned ah[2][4], al[2][4];
        #pragma unroll
        for (int mi = 0; mi < 2; mi++) {
            int r = warpM + mi*16 + (tile & 1)*8 + rowin;
            int c = ks*16 + (tile >> 1)*8;
            ldsm4(ah[mi][0], ah[mi][1], ah[mi][2], ah[mi][3], &sXh[r*LD + c]);
            ldsm4(al[mi][0], al[mi][1], al[mi][2], al[mi][3], &sXl[r*LD + c]);
        }
        #pragma unroll
        for (int np = 0; np < 4; np++) {
            int nrow = warpN + np*16 + (tile >> 1)*8 + rowin;
            int c = ks*16 + (tile & 1)*8;
            unsigned bh0, bh1, bh2, bh3, bl0, bl1, bl2, bl3;
            ldsm4(bh0, bh1, bh2, bh3, &sBh[nrow*LD + c]);
            ldsm4(bl0, bl1, bl2, bl3, &sBl[nrow*LD + c]);
            #pragma unroll
            for (int mi = 0; mi < 2; mi++) {
                mma16816(acc[mi][np*2],   ah[mi], bh0, bh1);
                mma16816(acc[mi][np*2],   al[mi], bh0, bh1);
                mma16816(acc[mi][np*2],   ah[mi], bl0, bl1);
                mma16816(acc[mi][np*2+1], ah[mi], bh2, bh3);
                mma16816(acc[mi][np*2+1], al[mi], bh2, bh3);
                mma16816(acc[mi][np*2+1], ah[mi], bl2, bl3);
            }
        }
    }
}

// 32x32 warp-tile variant (M=64 kernels): acc[2][4][4]
__device__ __forceinline__ void mma_chunk64(float acc[2][4][4],
    const __nv_bfloat16* sXh, const __nv_bfloat16* sXl,
    const __nv_bfloat16* sBh, const __nv_bfloat16* sBl,
    int lane, int warpM, int warpN)
{
    constexpr int LD = 40;
    #pragma unroll
    for (int ks = 0; ks < 2; ks++) {
        int rowin = lane & 7, tile = lane >> 3;
        unsigned ah[2][4], al[2][4];
        #pragma unroll
        for (int mi = 0; mi < 2; mi++) {
            int r = warpM + mi*16 + (tile & 1)*8 + rowin;
            int c = ks*16 + (tile >> 1)*8;
            ldsm4(ah[mi][0], ah[mi][1], ah[mi][2], ah[mi][3], &sXh[r*LD + c]);
            ldsm4(al[mi][0], al[mi][1], al[mi][2], al[mi][3], &sXl[r*LD + c]);
        }
        #pragma unroll
        for (int np = 0; np < 2; np++) {
            int nrow = warpN + np*16 + (tile >> 1)*8 + rowin;
            int c = ks*16 + (tile & 1)*8;
            unsigned bh0, bh1, bh2, bh3, bl0, bl1, bl2, bl3;
            ldsm4(bh0, bh1, bh2, bh3, &sBh[nrow*LD + c]);
            ldsm4(bl0, bl1, bl2, bl3, &sBl[nrow*LD + c]);
            #pragma unroll
            for (int mi = 0; mi < 2; mi++) {
                mma16816(acc[mi][np*2],   ah[mi], bh0, bh1);
                mma16816(acc[mi][np*2],   al[mi], bh0, bh1);
                mma16816(acc[mi][np*2],   ah[mi], bl0, bl1);
                mma16816(acc[mi][np*2+1], ah[mi], bh2, bh3);
                mma16816(acc[mi][np*2+1], al[mi], bh2, bh3);
                mma16816(acc[mi][np*2+1], ah[mi], bl2, bl3);
            }
        }
    }
}

// ---------------- tensor-core GEMM with fused epilogues (BM=128) -------------
// ABF16: A pre-split bf16; else A fp32 split on the fly.
// EPI: 0 = plain fp32 C, 1 = fp32 C + LayerNorm -> Hh/Hl (N=128, grid.x=1),
//      2 = relu -> bf16 split Hh/Hl only, 3 = relu -> fp32 C.
template<bool ABF16, int EPI, bool ACC>
__global__ void __launch_bounds__(256)
mma_gemm(const float* __restrict__ A,
         const __nv_bfloat16* __restrict__ Agh, const __nv_bfloat16* __restrict__ Agl,
         const __nv_bfloat16* __restrict__ Bh,  const __nv_bfloat16* __restrict__ Bl,
         const float* __restrict__ Cin, float* __restrict__ C,
         __nv_bfloat16* __restrict__ Hh, __nv_bfloat16* __restrict__ Hl,
         int M, int N, int K)
{
    constexpr int LD = 40;
    __shared__ __nv_bfloat16 sAh[128*LD], sAl[128*LD], sBh[128*LD], sBl[128*LD];
    __shared__ float2 ssum[128][2];
    int tid = threadIdx.x, lane = tid & 31, warp = tid >> 5;
    int m0 = blockIdx.y*128, n0 = blockIdx.x*128;
    int warpM = (warp >> 1)*32, warpN = (warp & 1)*64;

    float acc[2][8][4] = {};
    float4 pa[4]; uint4 pah[2], pal[2], pbh[2], pbl[2];

    if (ABF16) {
        #pragma unroll
        for (int i = 0; i < 2; i++) {
            int idx = tid + i*256, row = idx >> 2, q = idx & 3;
            pah[i] = *(const uint4*)&Agh[(size_t)(m0+row)*K + q*8];
            pal[i] = *(const uint4*)&Agl[(size_t)(m0+row)*K + q*8];
        }
    } else {
        #pragma unroll
        for (int i = 0; i < 4; i++) {
            int idx = tid + i*256, row = idx >> 3, c4 = idx & 7;
            pa[i] = *(const float4*)&A[(size_t)(m0+row)*K + c4*4];
        }
    }
    #pragma unroll
    for (int i = 0; i < 2; i++) {
        int idx = tid + i*256, row = idx >> 2, q = idx & 3;
        pbh[i] = *(const uint4*)&Bh[(size_t)(n0+row)*K + q*8];
        pbl[i] = *(const uint4*)&Bl[(size_t)(n0+row)*K + q*8];
    }

    int nt = K / 32;
    for (int t = 0; t < nt; t++) {
        __syncthreads();
        if (ABF16) {
            #pragma unroll
            for (int i = 0; i < 2; i++) {
                int idx = tid + i*256, row = idx >> 2, q = idx & 3;
                *(uint4*)&sAh[row*LD + q*8] = pah[i];
                *(uint4*)&sAl[row*LD + q*8] = pal[i];
            }
        } else {
            #pragma unroll
            for (int i = 0; i < 4; i++) {
                int idx = tid + i*256, row = idx >> 3, c = (idx & 7)*4;
                float4 v = pa[i];
                __nv_bfloat16 h0 = __float2bfloat16(v.x), h1 = __float2bfloat16(v.y);
                __nv_bfloat16 h2 = __float2bfloat16(v.z), h3 = __float2bfloat16(v.w);
                __nv_bfloat162 hh0; hh0.x = h0; hh0.y = h1;
                __nv_bfloat162 hh1; hh1.x = h2; hh1.y = h3;
                *(__nv_bfloat162*)&sAh[row*LD + c]     = hh0;
                *(__nv_bfloat162*)&sAh[row*LD + c + 2] = hh1;
                __nv_bfloat162 ll0, ll1;
                ll0.x = __float2bfloat16(v.x - __bfloat162float(h0));
                ll0.y = __float2bfloat16(v.y - __bfloat162float(h1));
                ll1.x = __float2bfloat16(v.z - __bfloat162float(h2));
                ll1.y = __float2bfloat16(v.w - __bfloat162float(h3));
                *(__nv_bfloat162*)&sAl[row*LD + c]     = ll0;
                *(__nv_bfloat162*)&sAl[row*LD + c + 2] = ll1;
            }
        }
        #pragma unroll
        for (int i = 0; i < 2; i++) {
            int idx = tid + i*256, row = idx >> 2, q = idx & 3;
            *(uint4*)&sBh[row*LD + q*8] = pbh[i];
            *(uint4*)&sBl[row*LD + q*8] = pbl[i];
        }
        __syncthreads();
        if (t + 1 < nt) {
            int kc = (t+1)*32;
            if (ABF16) {
                #pragma unroll
                for (int i = 0; i < 2; i++) {
                    int idx = tid + i*256, row = idx >> 2, q = idx & 3;
                    pah[i] = *(const uint4*)&Agh[(size_t)(m0+row)*K + kc + q*8];
                    pal[i] = *(const uint4*)&Agl[(size_t)(m0+row)*K + kc + q*8];
                }
            } else {
                #pragma unroll
                for (int i = 0; i < 4; i++) {
                    int idx = tid + i*256, row = idx >> 3, c4 = idx & 7;
                    pa[i] = *(const float4*)&A[(size_t)(m0+row)*K + kc + c4*4];
                }
            }
            #pragma unroll
            for (int i = 0; i < 2; i++) {
                int idx = tid + i*256, row = idx >> 2, q = idx & 3;
                pbh[i] = *(const uint4*)&Bh[(size_t)(n0+row)*K + kc + q*8];
                pbl[i] = *(const uint4*)&Bl[(size_t)(n0+row)*K + kc + q*8];
            }
        }
        mma_chunk(acc, sAh, sAl, sBh, sBl, lane, warpM, warpN);
    }

    if (ACC) {
        #pragma unroll
        for (int mi = 0; mi < 2; mi++) {
            #pragma unroll
            for (int nj = 0; nj < 8; nj++) {
                int r0  = m0 + warpM + mi*16 + (lane >> 2);
                int col = n0 + warpN + nj*8 + (lane & 3)*2;
                float2 c0 = *(const float2*)&Cin[(size_t)r0*N + col];
                float2 c1 = *(const float2*)&Cin[(size_t)(r0+8)*N + col];
                acc[mi][nj][0] += c0.x; acc[mi][nj][1] += c0.y;
                acc[mi][nj][2] += c1.x; acc[mi][nj][3] += c1.y;
            }
        }
    }

    float mean[4], rsig[4];
    if (EPI == 1) {
        float s[4] = {}, s2[4] = {};
        #pragma unroll
        for (int mi = 0; mi < 2; mi++)
            #pragma unroll
            for (int nj = 0; nj < 8; nj++) {
                float v0 = acc[mi][nj][0], v1 = acc[mi][nj][1];
                float v2 = acc[mi][nj][2], v3 = acc[mi][nj][3];
                s[mi*2]    += v0 + v1;      s2[mi*2]   += v0*v0 + v1*v1;
                s[mi*2+1]  += v2 + v3;      s2[mi*2+1] += v2*v2 + v3*v3;
            }
        #pragma unroll
        for (int off = 1; off <= 2; off <<= 1)
            #pragma unroll
            for (int r = 0; r < 4; r++) {
                s[r]  += __shfl_xor_sync(~0u, s[r],  off);
                s2[r] += __shfl_xor_sync(~0u, s2[r], off);
            }
        if ((lane & 3) == 0) {
            #pragma unroll
            for (int slot = 0; slot < 4; slot++) {
                int row = warpM + (slot >> 1)*16 + (lane >> 2) + 8*(slot & 1);
                ssum[row][warp & 1] = make_float2(s[slot], s2[slot]);
            }
        }
        __syncthreads();
        #pragma unroll
        for (int slot = 0; slot < 4; slot++) {
            int row = warpM + (slot >> 1)*16 + (lane >> 2) + 8*(slot & 1);
            float2 a = ssum[row][0], b = ssum[row][1];
            float m  = (a.x + b.x) * (1.f/128.f);
            float vv = (a.y + b.y) * (1.f/128.f) - m*m;
            mean[slot] = m;
            rsig[slot] = rsqrtf(vv + 1e-5f);
        }
    }

    #pragma unroll
    for (int mi = 0; mi < 2; mi++) {
        #pragma unroll
        for (int nj = 0; nj < 8; nj++) {
            int r0  = m0 + warpM + mi*16 + (lane >> 2);
            int col = n0 + warpN + nj*8 + (lane & 3)*2;
            float v0 = acc[mi][nj][0], v1 = acc[mi][nj][1];
            float v2 = acc[mi][nj][2], v3 = acc[mi][nj][3];
            if (EPI == 2 || EPI == 3) {
                v0 = fmaxf(v0, 0.f); v1 = fmaxf(v1, 0.f);
                v2 = fmaxf(v2, 0.f); v3 = fmaxf(v3, 0.f);
            }
            if (EPI == 0 || EPI == 1 || EPI == 3) {
                float2 o0; o0.x = v0; o0.y = v1;
                float2 o1; o1.x = v2; o1.y = v3;
                *(float2*)&C[(size_t)r0*N + col]     = o0;
                *(float2*)&C[(size_t)(r0+8)*N + col] = o1;
            }
            if (EPI == 1) {
                v0 = (v0 - mean[mi*2])*rsig[mi*2];
                v1 = (v1 - mean[mi*2])*rsig[mi*2];
                v2 = (v2 - mean[mi*2+1])*rsig[mi*2+1];
                v3 = (v3 - mean[mi*2+1])*rsig[mi*2+1];
            }
            if (EPI == 1 || EPI == 2) {
                __nv_bfloat162 hh0, hh1, ll0, ll1;
                hh0.x = __float2bfloat16(v0); hh0.y = __float2bfloat16(v1);
                hh1.x = __float2bfloat16(v2); hh1.y = __float2bfloat16(v3);
                ll0.x = __float2bfloat16(v0 - __bfloat162float(hh0.x));
                ll0.y = __float2bfloat16(v1 - __bfloat162float(hh0.y));
                ll1.x = __float2bfloat16(v2 - __bfloat162float(hh1.x));
                ll1.y = __float2bfloat16(v3 - __bfloat162float(hh1.y));
                *(__nv_bfloat162*)&Hh[(size_t)r0*N + col]     = hh0;
                *(__nv_bfloat162*)&Hh[(size_t)(r0+8)*N + col] = hh1;
                *(__nv_bfloat162*)&Hl[(size_t)r0*N + col]     = ll0;
                *(__nv_bfloat162*)&Hl[(size_t)(r0+8)*N + col] = ll1;
            }
        }
    }
}

// ---------------- wide GEMM: BM=256, 512 threads, dynamic smem ---------------
template<bool ABF16, int EPI>
__global__ void __launch_bounds__(512)
mma_gemm_wide(const float* __restrict__ A,
              const __nv_bfloat16* __restrict__ Agh, const __nv_bfloat16* __restrict__ Agl,
              const __nv_bfloat16* __restrict__ Bh,  const __nv_bfloat16* __restrict__ Bl,
              float* __restrict__ C,
              __nv_bfloat16* __restrict__ Hh, __nv_bfloat16* __restrict__ Hl,
              int M, int N, int K)
{
    constexpr int LD = 40;
    extern __shared__ __nv_bfloat16 dyns[];
    __nv_bfloat16* sAh = dyns;
    __nv_bfloat16* sAl = sAh + 256*LD;
    __nv_bfloat16* sBh = sAl + 256*LD;
    __nv_bfloat16* sBl = sBh + 128*LD;
    int tid = threadIdx.x, lane = tid & 31, warp = tid >> 5;
    int m0 = blockIdx.y*256, n0 = blockIdx.x*128;
    int warpM = (warp >> 1)*32, warpN = (warp & 1)*64;

    float acc[2][8][4] = {};
    float4 pa[4]; uint4 pah[2], pal[2], pbh, pbl;

    if (ABF16) {
        #pragma unroll
        for (int i = 0; i < 2; i++) {
            int idx = tid + i*512, row = idx >> 2, q = idx & 3;
            pah[i] = *(const uint4*)&Agh[(size_t)(m0+row)*K + q*8];
            pal[i] = *(const uint4*)&Agl[(size_t)(m0+row)*K + q*8];
        }
    } else {
        #pragma unroll
        for (int i = 0; i < 4; i++) {
            int idx = tid + i*512, row = idx >> 3, c4 = idx & 7;
            pa[i] = *(const float4*)&A[(size_t)(m0+row)*K + c4*4];
        }
    }
    {
        int row = tid >> 2, q = tid & 3;
        pbh = *(const uint4*)&Bh[(size_t)(n0+row)*K + q*8];
        pbl = *(const uint4*)&Bl[(size_t)(n0+row)*K + q*8];
    }

    int nt = K / 32;
    for (int t = 0; t < nt; t++) {
        __syncthreads();
        if (ABF16) {
            #pragma unroll
            for (int i = 0; i < 2; i++) {
                int idx = tid + i*512, row = idx >> 2, q = idx & 3;
                *(uint4*)&sAh[row*LD + q*8] = pah[i];
                *(uint4*)&sAl[row*LD + q*8] = pal[i];
            }
        } else {
            #pragma unroll
            for (int i = 0; i < 4; i++) {
                int idx = tid + i*512, row = idx >> 3, c = (idx & 7)*4;
                float4 v = pa[i];
                __nv_bfloat16 h0 = __float2bfloat16(v.x), h1 = __float2bfloat16(v.y);
                __nv_bfloat16 h2 = __float2bfloat16(v.z), h3 = __float2bfloat16(v.w);
                __nv_bfloat162 hh0; hh0.x = h0; hh0.y = h1;
                __nv_bfloat162 hh1; hh1.x = h2; hh1.y = h3;
                *(__nv_bfloat162*)&sAh[row*LD + c]     = hh0;
                *(__nv_bfloat162*)&sAh[row*LD + c + 2] = hh1;
                __nv_bfloat162 ll0, ll1;
                ll0.x = __float2bfloat16(v.x - __bfloat162float(h0));
                ll0.y = __float2bfloat16(v.y - __bfloat162float(h1));
                ll1.x = __float2bfloat16(v.z - __bfloat162float(h2));
                ll1.y = __float2bfloat16(v.w - __bfloat162float(h3));
                *(__nv_bfloat162*)&sAl[row*LD + c]     = ll0;
                *(__nv_bfloat162*)&sAl[row*LD + c + 2] = ll1;
            }
        }
        {
            int row = tid >> 2, q = tid & 3;
            *(uint4*)&sBh[row*LD + q*8] = pbh;
            *(uint4*)&sBl[row*LD + q*8] = pbl;
        }
        __syncthreads();
        if (t + 1 < nt) {
            int kc = (t+1)*32;
            if (ABF16) {
                #pragma unroll
                for (int i = 0; i < 2; i++) {
                    int idx = tid + i*512, row = idx >> 2, q = idx & 3;
                    pah[i] = *(const uint4*)&Agh[(size_t)(m0+row)*K + kc + q*8];
                    pal[i] = *(const uint4*)&Agl[(size_t)(m0+row)*K + kc + q*8];
                }
            } else {
                #pragma unroll
                for (int i = 0; i < 4; i++) {
                    int idx = tid + i*512, row = idx >> 3, c4 = idx & 7;
                    pa[i] = *(const float4*)&A[(size_t)(m0+row)*K + kc + c4*4];
                }
            }
            {
                int row = tid >> 2, q = tid & 3;
                pbh = *(const uint4*)&Bh[(size_t)(n0+row)*K + kc + q*8];
                pbl = *(const uint4*)&Bl[(size_t)(n0+row)*K + kc + q*8];
            }
        }
        mma_chunk(acc, sAh, sAl, sBh, sBl, lane, warpM, warpN);
    }

    #pragma unroll
    for (int mi = 0; mi < 2; mi++) {
        #pragma unroll
        for (int nj = 0; nj < 8; nj++) {
            int r0  = m0 + warpM + mi*16 + (lane >> 2);
            int col = n0 + warpN + nj*8 + (lane & 3)*2;
            float v0 = acc[mi][nj][0], v1 = acc[mi][nj][1];
            float v2 = acc[mi][nj][2], v3 = acc[mi][nj][3];
            if (EPI == 2 || EPI == 3) {
                v0 = fmaxf(v0, 0.f); v1 = fmaxf(v1, 0.f);
                v2 = fmaxf(v2, 0.f); v3 = fmaxf(v3, 0.f);
            }
            if (EPI == 0 || EPI == 3) {
                float2 o0; o0.x = v0; o0.y = v1;
                float2 o1; o1.x = v2; o1.y = v3;
                *(float2*)&C[(size_t)r0*N + col]     = o0;
                *(float2*)&C[(size_t)(r0+8)*N + col] = o1;
            }
            if (EPI == 2) {
                __nv_bfloat162 hh0, hh1, ll0, ll1;
                hh0.x = __float2bfloat16(v0); hh0.y = __float2bfloat16(v1);
                hh1.x = __float2bfloat16(v2); hh1.y = __float2bfloat16(v3);
                ll0.x = __float2bfloat16(v0 - __bfloat162float(hh0.x));
                ll0.y = __float2bfloat16(v1 - __bfloat162float(hh0.y));
                ll1.x = __float2bfloat16(v2 - __bfloat162float(hh1.x));
                ll1.y = __float2bfloat16(v3 - __bfloat162float(hh1.y));
                *(__nv_bfloat162*)&Hh[(size_t)r0*N + col]     = hh0;
                *(__nv_bfloat162*)&Hh[(size_t)(r0+8)*N + col] = hh1;
                *(__nv_bfloat162*)&Hl[(size_t)r0*N + col]     = ll0;
                *(__nv_bfloat162*)&Hl[(size_t)(r0+8)*N + col] = ll1;
            }
        }
    }
}

// ---------------- fused attention + WO + residual + LN -----------------------
// One CTA per (b, w): all 4 heads; o kept in smem; then x += o@Wo, LN -> hh/hl.
__global__ void __launch_bounds__(256)
attn_wo(const float* __restrict__ qkv,
        const __nv_bfloat16* __restrict__ Bh, const __nv_bfloat16* __restrict__ Bl,
        const float* __restrict__ Cin, float* __restrict__ C,
        __nv_bfloat16* __restrict__ Hh, __nv_bfloat16* __restrict__ Hl)
{
    constexpr int LD = 40;
    constexpr int CH64 = 64*LD;           // one 64x32 A chunk
    extern __shared__ char dynraw[];
    float4* ks4 = (float4*)dynraw;                         // [4][128][8]
    float4* vs4 = ks4 + 4*128*8;                           // [4][128][8]
    __nv_bfloat16* sOh = (__nv_bfloat16*)(vs4 + 4*128*8);  // 4 chunks
    __nv_bfloat16* sOl = sOh + 4*CH64;
    __nv_bfloat16* sBh = sOl + 4*CH64;                     // 1 B chunk (128xLD)
    __nv_bfloat16* sBl = sBh + 128*LD;
    __shared__ float  ps[8][2][KWIN];
    __shared__ float2 ssum[64][4];

    int bw = blockIdx.x;
    int w  = bw & (NW-1);
    int b  = bw >> 7;
    int tid = threadIdx.x, lane = tid & 31, warp = tid >> 5;
    int rowbase = b*N_ + w*QWIN;          // == bw*64

    // ---- load K/V for all 4 heads (swizzled) ----
    for (int s = tid; s < 4*KWIN*8; s += 256) {
        int h = s >> 10, rem = s & 1023, kk = rem >> 3, i = rem & 7;
        int j = w*QWIN + kk - PADW;
        float4 kv = make_float4(0,0,0,0), vv = make_float4(0,0,0,0);
        if (j >= 0 && j < N_) {
            const float* base = &qkv[(size_t)(b*N_ + j)*384 + h*32 + i*4];
            kv = *(const float4*)(base + 128);
            vv = *(const float4*)(base + 256);
        }
        int sw = i ^ (kk & 7);
        ks4[h*1024 + kk*8 + sw] = kv;
        vs4[h*1024 + kk*8 + sw] = vv;
    }

    // ---- prefetch Wo chunk 0 (independent of attention) ----
    int brow = tid >> 2, bq = tid & 3;    // brow in [0,64)
    uint4 pbh[2], pbl[2];
    pbh[0] = *(const uint4*)&Bh[(size_t)brow*128 + bq*8];
    pbh[1] = *(const uint4*)&Bh[(size_t)(brow+64)*128 + bq*8];
    pbl[0] = *(const uint4*)&Bl[(size_t)brow*128 + bq*8];
    pbl[1] = *(const uint4*)&Bl[(size_t)(brow+64)*128 + bq*8];

    __syncthreads();

    // ---- attention phase: warp -> head (warp&3), rows (warp>>2)*32..+32 ----
    const float scale = 0.17677669529663687f;
    int h = warp & 3, half = warp >> 2;
    const float4* ksh = ks4 + h*1024;
    const float4* vsh = vs4 + h*1024;
    const float* browp = g_bias + ((size_t)bw*HEADS + h)*QWIN*KWIN;
    int lhi = lane >> 2, llo = lane & 3;

    #pragma unroll 1
    for (int pass = 0; pass < 16; pass++) {
        int rA = half*32 + pass*2, rB = rA + 1;
        float4 qa[8], qb[8];
        #pragma unroll
        for (int i = 0; i < 8; i++) {
            qa[i] = *(const float4*)&qkv[(size_t)(rowbase+rA)*384 + h*32 + i*4];
            qb[i] = *(const float4*)&qkv[(size_t)(rowbase+rB)*384 + h*32 + i*4];
        }
        float4 aA[4], aB[4];
        #pragma unroll
        for (int g = 0; g < 4; g++) { aA[g] = make_float4(0,0,0,0); aB[g] = make_float4(0,0,0,0); }
        #pragma unroll
        for (int i = 0; i < 8; i++) {
            #pragma unroll
            for (int g = 0; g < 4; g++) {
                int kk = g*32 + lane;
                float4 kv = ksh[kk*8 + (i ^ (kk & 7))];
                aA[g].x += qa[i].x*kv.x; aA[g].y += qa[i].y*kv.y;
                aA[g].z += qa[i].z*kv.z; aA[g].w += qa[i].w*kv.w;
                aB[g].x += qb[i].x*kv.x; aB[g].y += qb[i].y*kv.y;
                aB[g].z += qb[i].z*kv.z; aB[g].w += qb[i].w*kv.w;
            }
        }
        float lA[4], lB[4];
        float mA = -1e30f, mB = -1e30f;
        #pragma unroll
        for (int g = 0; g < 4; g++) {
            int kk = g*32 + lane;
            int j = w*QWIN + kk - PADW;
            float msk = (j >= 0 && j < N_) ? 0.f : -1e9f;
            lA[g] = ((aA[g].x+aA[g].y)+(aA[g].z+aA[g].w))*scale + browp[(rA<<7)+kk] + msk;
            lB[g] = ((aB[g].x+aB[g].y)+(aB[g].z+aB[g].w))*scale + browp[(rB<<7)+kk] + msk;
            mA = fmaxf(mA, lA[g]); mB = fmaxf(mB, lB[g]);
        }
        #pragma unroll
        for (int off = 16; off > 0; off >>= 1) {
            mA = fmaxf(mA, __shfl_xor_sync(~0u, mA, off));
            mB = fmaxf(mB, __shfl_xor_sync(~0u, mB, off));
        }
        float sA = 0.f, sB = 0.f, eA[4], eB[4];
        #pragma unroll
        for (int g = 0; g < 4; g++) {
            eA[g] = __expf(lA[g]-mA); sA += eA[g];
            eB[g] = __expf(lB[g]-mB); sB += eB[g];
        }
        #pragma unroll
        for (int off = 16; off > 0; off >>= 1) {
            sA += __shfl_xor_sync(~0u, sA, off);
            sB += __shfl_xor_sync(~0u, sB, off);
        }
        float rsA = 1.f/sA, rsB = 1.f/sB;
        #pragma unroll
        for (int g = 0; g < 4; g++) {
            ps[warp][0][g*32+lane] = eA[g]*rsA;
            ps[warp][1][g*32+lane] = eB[g]*rsB;
        }
        __syncwarp();
        float oA = 0.f, oB = 0.f;
        #pragma unroll 4
        for (int k4 = 0; k4 < 32; k4++) {
            float4 pA = *(const float4*)&ps[warp][0][k4*4];
            float4 pB = *(const float4*)&ps[warp][1][k4*4];
            #pragma unroll
            for (int t = 0; t < 4; t++) {
                int kk = k4*4 + t;
                float v = ((const float*)&vsh[kk*8])[(((lhi ^ (kk&7))<<2) | llo)];
                oA += (&pA.x)[t]*v;
                oB += (&pB.x)[t]*v;
            }
        }
        // write o bf16-split into smem (chunk index = head)
        {
            __nv_bfloat16 hA = __float2bfloat16(oA);
            __nv_bfloat16 hB = __float2bfloat16(oB);
            sOh[h*CH64 + rA*LD + lane] = hA;
            sOh[h*CH64 + rB*LD + lane] = hB;
            sOl[h*CH64 + rA*LD + lane] = __float2bfloat16(oA - __bfloat162float(hA));
            sOl[h*CH64 + rB*LD + lane] = __float2bfloat16(oB - __bfloat162float(hB));
        }
        __syncwarp();
    }

    __syncthreads();

    // ---- WO GEMM: x[64x128] += o[64x128] @ Wo[128x128], then LN ----
    int warpM = (warp >> 2)*32, warpN = (warp & 3)*32;
    float acc[2][4][4] = {};

    #pragma unroll
    for (int t = 0; t < 4; t++) {
        if (t > 0) __syncthreads();
        *(uint4*)&sBh[brow*LD + bq*8]      = pbh[0];
        *(uint4*)&sBh[(brow+64)*LD + bq*8] = pbh[1];
        *(uint4*)&sBl[brow*LD + bq*8]      = pbl[0];
        *(uint4*)&sBl[(brow+64)*LD + bq*8] = pbl[1];
        __syncthreads();
        if (t + 1 < 4) {
            int kc = (t+1)*32;
            pbh[0] = *(const uint4*)&Bh[(size_t)brow*128 + kc + bq*8];
            pbh[1] = *(const uint4*)&Bh[(size_t)(brow+64)*128 + kc + bq*8];
            pbl[0] = *(const uint4*)&Bl[(size_t)brow*128 + kc + bq*8];
            pbl[1] = *(const uint4*)&Bl[(size_t)(brow+64)*128 + kc + bq*8];
        }
        mma_chunk64(acc, sOh + t*CH64, sOl + t*CH64, sBh, sBl, lane, warpM, warpN);
    }

    // residual
    #pragma unroll
    for (int mi = 0; mi < 2; mi++) {
        #pragma unroll
        for (int nj = 0; nj < 4; nj++) {
            int r0  = rowbase + warpM + mi*16 + (lane >> 2);
            int col = warpN + nj*8 + (lane & 3)*2;
            float2 c0 = *(const float2*)&Cin[(size_t)r0*128 + col];
            float2 c1 = *(const float2*)&Cin[(size_t)(r0+8)*128 + col];
            acc[mi][nj][0] += c0.x; acc[mi][nj][1] += c0.y;
            acc[mi][nj][2] += c1.x; acc[mi][nj][3] += c1.y;
        }
    }

    // LN stats: 4 N-partials per row
    float s[4] = {}, s2[4] = {};
    #pragma unroll
    for (int mi = 0; mi < 2; mi++)
        #pragma unroll
        for (int nj = 0; nj < 4; nj++) {
            float v0 = acc[mi][nj][0], v1 = acc[mi][nj][1];
            float v2 = acc[mi][nj][2], v3 = acc[mi][nj][3];
            s[mi*2]    += v0 + v1;      s2[mi*2]   += v0*v0 + v1*v1;
            s[mi*2+1]  += v2 + v3;      s2[mi*2+1] += v2*v2 + v3*v3;
        }
    #pragma unroll
    for (int off = 1; off <= 2; off <<= 1)
        #pragma unroll
        for (int r = 0; r < 4; r++) {
            s[r]  += __shfl_xor_sync(~0u, s[r],  off);
            s2[r] += __shfl_xor_sync(~0u, s2[r], off);
        }
    __syncthreads();
    if ((lane & 3) == 0) {
        #pragma unroll
        for (int slot = 0; slot < 4; slot++) {
            int row = warpM + (slot >> 1)*16 + (lane >> 2) + 8*(slot & 1);
            ssum[row][warp & 3] = make_float2(s[slot], s2[slot]);
        }
    }
    __syncthreads();
    float mean[4], rsig[4];
    #pragma unroll
    for (int slot = 0; slot < 4; slot++) {
        int row = warpM + (slot >> 1)*16 + (lane >> 2) + 8*(slot & 1);
        float2 a0 = ssum[row][0], a1 = ssum[row][1], a2 = ssum[row][2], a3 = ssum[row][3];
        float m  = (a0.x + a1.x + a2.x + a3.x) * (1.f/128.f);
        float vv = (a0.y + a1.y + a2.y + a3.y) * (1.f/128.f) - m*m;
        mean[slot] = m;
        rsig[slot] = rsqrtf(vv + 1e-5f);
    }

    #pragma unroll
    for (int mi = 0; mi < 2; mi++) {
        #pragma unroll
        for (int nj = 0; nj < 4; nj++) {
            int r0  = rowbase + warpM + mi*16 + (lane >> 2);
            int col = warpN + nj*8 + (lane & 3)*2;
            float v0 = acc[mi][nj][0], v1 = acc[mi][nj][1];
            float v2 = acc[mi][nj][2], v3 = acc[mi][nj][3];
            float2 o0; o0.x = v0; o0.y = v1;
            float2 o1; o1.x = v2; o1.y = v3;
            *(float2*)&C[(size_t)r0*128 + col]     = o0;
            *(float2*)&C[(size_t)(r0+8)*128 + col] = o1;
            v0 = (v0 - mean[mi*2])*rsig[mi*2];
            v1 = (v1 - mean[mi*2])*rsig[mi*2];
            v2 = (v2 - mean[mi*2+1])*rsig[mi*2+1];
            v3 = (v3 - mean[mi*2+1])*rsig[mi*2+1];
            __nv_bfloat162 hh0, hh1, ll0, ll1;
            hh0.x = __float2bfloat16(v0); hh0.y = __float2bfloat16(v1);
            hh1.x = __float2bfloat16(v2); hh1.y = __float2bfloat16(v3);
            ll0.x = __float2bfloat16(v0 - __bfloat162float(hh0.x));
            ll0.y = __float2bfloat16(v1 - __bfloat162float(hh0.y));
            ll1.x = __float2bfloat16(v2 - __bfloat162float(hh1.x));
            ll1.y = __float2bfloat16(v3 - __bfloat162float(hh1.y));
            *(__nv_bfloat162*)&Hh[(size_t)r0*128 + col]     = hh0;
            *(__nv_bfloat162*)&Hh[(size_t)(r0+8)*128 + col] = hh1;
            *(__nv_bfloat162*)&Hl[(size_t)r0*128 + col]     = ll0;
            *(__nv_bfloat162*)&Hl[(size_t)(r0+8)*128 + col] = ll1;
        }
    }
}

// ---------------- fused FF: x += relu(h@W1)@W2, then optional LN -> hh/hl ----
template<bool LAST>
__global__ void __launch_bounds__(256)
ff_fused(const __nv_bfloat16* __restrict__ Agh, const __nv_bfloat16* __restrict__ Agl,
         const __nv_bfloat16* __restrict__ B1h, const __nv_bfloat16* __restrict__ B1l,
         const __nv_bfloat16* __restrict__ B2h, const __nv_bfloat16* __restrict__ B2l,
         const float* __restrict__ Cin, float* __restrict__ C,
         __nv_bfloat16* __restrict__ Hh, __nv_bfloat16* __restrict__ Hl)
{
    constexpr int LD = 40;
    constexpr int CH = 128*LD;
    extern __shared__ __nv_bfloat16 dyns[];
    __nv_bfloat16* sAh = dyns;
    __nv_bfloat16* sAl = sAh + 4*CH;
    __nv_bfloat16* sFh = sAl + 4*CH;
    __nv_bfloat16* sFl = sFh + 4*CH;
    __nv_bfloat16* sBh = sFl + 4*CH;
    __nv_bfloat16* sBl = sBh + CH;
    __shared__ float2 ssum[128][2];

    int tid = threadIdx.x, lane = tid & 31, warp = tid >> 5;
    int m0 = blockIdx.x*128;
    int warpM = (warp >> 1)*32, warpN = (warp & 1)*64;
    int brow = tid >> 2, bq = tid & 3;

    #pragma unroll
    for (int i = 0; i < 8; i++) {
        int idx = tid + i*256;
        int row = idx >> 4, q = idx & 15;
        int off = (q >> 2)*CH + row*LD + (q & 3)*8;
        *(uint4*)&sAh[off] = *(const uint4*)&Agh[(size_t)(m0+row)*128 + q*8];
        *(uint4*)&sAl[off] = *(const uint4*)&Agl[(size_t)(m0+row)*128 + q*8];
    }

    auto bptr = [&](int i, int row, const __nv_bfloat16* b1, const __nv_bfloat16* b2)
        -> const __nv_bfloat16* {
        int c = i >> 3, t = i & 3;
        if (((i >> 2) & 1) == 0)
            return &b1[(size_t)(c*128 + row)*128 + t*32 + bq*8];
        else
            return &b2[(size_t)row*512 + c*128 + t*32 + bq*8];
    };

    uint4 pbh[2], pbl[2];
    pbh[0] = *(const uint4*)bptr(0, brow,    B1h, B2h);
    pbh[1] = *(const uint4*)bptr(0, brow+64, B1h, B2h);
    pbl[0] = *(const uint4*)bptr(0, brow,    B1l, B2l);
    pbl[1] = *(const uint4*)bptr(0, brow+64, B1l, B2l);
    float acc2[2][8][4] = {};

    #pragma unroll 1
    for (int c = 0; c < 4; c++) {
        float acc1[2][8][4] = {};
        #pragma unroll
        for (int t = 0; t < 4; t++) {
            __syncthreads();
            *(uint4*)&sBh[brow*LD + bq*8]      = pbh[0];
            *(uint4*)&sBh[(brow+64)*LD + bq*8] = pbh[1];
            *(uint4*)&sBl[brow*LD + bq*8]      = pbl[0];
            *(uint4*)&sBl[(brow+64)*LD + bq*8] = pbl[1];
            __syncthreads();
            int ni = c*8 + t + 1;
            pbh[0] = *(const uint4*)bptr(ni, brow,    B1h, B2h);
            pbh[1] = *(const uint4*)bptr(ni, brow+64, B1h, B2h);
            pbl[0] = *(const uint4*)bptr(ni, brow,    B1l, B2l);
            pbl[1] = *(const uint4*)bptr(ni, brow+64, B1l, B2l);
            mma_chunk(acc1, sAh + t*CH, sAl + t*CH, sBh, sBl, lane, warpM, warpN);
        }
        #pragma unroll
        for (int mi = 0; mi < 2; mi++) {
            #pragma unroll
            for (int nj = 0; nj < 8; nj++) {
                int r   = warpM + mi*16 + (lane >> 2);
                int col = warpN + nj*8 + (lane & 3)*2;
                int off = (col >> 5)*CH + (col & 31);
                float v0 = fmaxf(acc1[mi][nj][0], 0.f), v1 = fmaxf(acc1[mi][nj][1], 0.f);
                float v2 = fmaxf(acc1[mi][nj][2], 0.f), v3 = fmaxf(acc1[mi][nj][3], 0.f);
                __nv_bfloat162 h0, h1, l0, l1;
                h0.x = __float2bfloat16(v0); h0.y = __float2bfloat16(v1);
                h1.x = __float2bfloat16(v2); h1.y = __float2bfloat16(v3);
                l0.x = __float2bfloat16(v0 - __bfloat162float(h0.x));
                l0.y = __float2bfloat16(v1 - __bfloat162float(h0.y));
                l1.x = __float2bfloat16(v2 - __bfloat162float(h1.x));
                l1.y = __float2bfloat16(v3 - __bfloat162float(h1.y));
                *(__nv_bfloat162*)&sFh[off + r*LD]     = h0;
                *(__nv_bfloat162*)&sFh[off + (r+8)*LD] = h1;
                *(__nv_bfloat162*)&sFl[off + r*LD]     = l0;
                *(__nv_bfloat162*)&sFl[off + (r+8)*LD] = l1;
            }
        }
        #pragma unroll
        for (int t = 0; t < 4; t++) {
            __syncthreads();
            *(uint4*)&sBh[brow*LD + bq*8]      = pbh[0];
            *(uint4*)&sBh[(brow+64)*LD + bq*8] = pbh[1];
            *(uint4*)&sBl[brow*LD + bq*8]      = pbl[0];
            *(uint4*)&sBl[(brow+64)*LD + bq*8] = pbl[1];
            __syncthreads();
            int ni = c*8 + t + 5;
            if (ni < 32) {
                pbh[0] = *(const uint4*)bptr(ni, brow,    B1h, B2h);
                pbh[1] = *(const uint4*)bptr(ni, brow+64, B1h, B2h);
                pbl[0] = *(const uint4*)bptr(ni, brow,    B1l, B2l);
                pbl[1] = *(const uint4*)bptr(ni, brow+64, B1l, B2l);
            }
            mma_chunk(acc2, sFh + t*CH, sFl + t*CH, sBh, sBl, lane, warpM, warpN);
        }
    }

    #pragma unroll
    for (int mi = 0; mi < 2; mi++) {
        #pragma unroll
        for (int nj = 0; nj < 8; nj++) {
            int r0  = m0 + warpM + mi*16 + (lane >> 2);
            int col = warpN + nj*8 + (lane & 3)*2;
            float2 c0 = *(const float2*)&Cin[(size_t)r0*128 + col];
            float2 c1 = *(const float2*)&Cin[(size_t)(r0+8)*128 + col];
            acc2[mi][nj][0] += c0.x; acc2[mi][nj][1] += c0.y;
            acc2[mi][nj][2] += c1.x; acc2[mi][nj][3] += c1.y;
        }
    }

    float mean[4], rsig[4];
    if (!LAST) {
        float s[4] = {}, s2[4] = {};
        #pragma unroll
        for (int mi = 0; mi < 2; mi++)
            #pragma unroll
            for (int nj = 0; nj < 8; nj++) {
                float v0 = acc2[mi][nj][0], v1 = acc2[mi][nj][1];
                float v2 = acc2[mi][nj][2], v3 = acc2[mi][nj][3];
                s[mi*2]    += v0 + v1;      s2[mi*2]   += v0*v0 + v1*v1;
                s[mi*2+1]  += v2 + v3;      s2[mi*2+1] += v2*v2 + v3*v3;
            }
        #pragma unroll
        for (int off = 1; off <= 2; off <<= 1)
            #pragma unroll
            for (int r = 0; r < 4; r++) {
                s[r]  += __shfl_xor_sync(~0u, s[r],  off);
                s2[r] += __shfl_xor_sync(~0u, s2[r], off);
            }
        __syncthreads();
        if ((lane & 3) == 0) {
            #pragma unroll
            for (int slot = 0; slot < 4; slot++) {
                int row = warpM + (slot >> 1)*16 + (lane >> 2) + 8*(slot & 1);
                ssum[row][warp & 1] = make_float2(s[slot], s2[slot]);
            }
        }
        __syncthreads();
        #pragma unroll
        for (int slot = 0; slot < 4; slot++) {
            int row = warpM + (slot >> 1)*16 + (lane >> 2) + 8*(slot & 1);
            float2 a = ssum[row][0], b = ssum[row][1];
            float m  = (a.x + b.x) * (1.f/128.f);
            float vv = (a.y + b.y) * (1.f/128.f) - m*m;
            mean[slot] = m;
            rsig[slot] = rsqrtf(vv + 1e-5f);
        }
    }

    #pragma unroll
    for (int mi = 0; mi < 2; mi++) {
        #pragma unroll
        for (int nj = 0; nj < 8; nj++) {
            int r0  = m0 + warpM + mi*16 + (lane >> 2);
            int col = warpN + nj*8 + (lane & 3)*2;
            float v0 = acc2[mi][nj][0], v1 = acc2[mi][nj][1];
            float v2 = acc2[mi][nj][2], v3 = acc2[mi][nj][3];
            float2 o0; o0.x = v0; o0.y = v1;
            float2 o1; o1.x = v2; o1.y = v3;
            *(float2*)&C[(size_t)r0*128 + col]     = o0;
            *(float2*)&C[(size_t)(r0+8)*128 + col] = o1;
            if (!LAST) {
                v0 = (v0 - mean[mi*2])*rsig[mi*2];
                v1 = (v1 - mean[mi*2])*rsig[mi*2];
                v2 = (v2 - mean[mi*2+1])*rsig[mi*2+1];
                v3 = (v3 - mean[mi*2+1])*rsig[mi*2+1];
                __nv_bfloat162 hh0, hh1, ll0, ll1;
                hh0.x = __float2bfloat16(v0); hh0.y = __float2bfloat16(v1);
                hh1.x = __float2bfloat16(v2); hh1.y = __float2bfloat16(v3);
                ll0.x = __float2bfloat16(v0 - __bfloat162float(hh0.x));
                ll0.y = __float2bfloat16(v1 - __bfloat162float(hh0.y));
                ll1.x = __float2bfloat16(v2 - __bfloat162float(hh1.x));
                ll1.y = __float2bfloat16(v3 - __bfloat162float(hh1.y));
                *(__nv_bfloat162*)&Hh[(size_t)r0*128 + col]     = hh0;
                *(__nv_bfloat162*)&Hh[(size_t)(r0+8)*128 + col] = hh1;
                *(__nv_bfloat162*)&Hl[(size_t)r0*128 + col]     = ll0;
                *(__nv_bfloat162*)&Hl[(size_t)(r0+8)*128 + col] = ll1;
            }
        }
    }
}

// ---------------- small SIMT GEMM (only for N=32 outer projection) ----------
template<int BN, bool RELU_A, bool RELU_C, bool ACC>
__global__ void __launch_bounds__(256)
sgemm_kernel(const float* __restrict__ A, const float* __restrict__ Bm,
             const float* __restrict__ Cin, float* __restrict__ C,
             int M, int N, int K)
{
    constexpr int BM = 128, BK = 16;
    constexpr int TN = BN/16;
    constexpr int BSLOT = (BK*BN)/(4*256);
    __shared__ float As[BK][BM];
    __shared__ float Bs[BK][BN];
    int tid = threadIdx.x;
    int m0 = blockIdx.y*BM, n0 = blockIdx.x*BN;
    int ty = tid >> 4, tx = tid & 15;

    float4 areg[2], breg[BSLOT];
    #pragma unroll
    for (int i = 0; i < 2; i++) {
        int s = tid + i*256, m = s >> 2, kv = s & 3;
        float4 v = *(const float4*)&A[(size_t)(m0+m)*K + kv*4];
        if (RELU_A) { v.x=fmaxf(v.x,0.f); v.y=fmaxf(v.y,0.f); v.z=fmaxf(v.z,0.f); v.w=fmaxf(v.w,0.f); }
        areg[i] = v;
    }
    #pragma unroll
    for (int i = 0; i < BSLOT; i++) {
        int s = tid + i*256, r = s/(BN/4), nv = s%(BN/4);
        int gn = n0 + nv*4;
        breg[i] = (gn < N) ? *(const float4*)&Bm[(size_t)r*N + gn] : make_float4(0,0,0,0);
    }
    float acc[8][TN];
    #pragma unroll
    for (int i = 0; i < 8; i++)
        #pragma unroll
        for (int j = 0; j < TN; j++) acc[i][j] = 0.f;

    int ntiles = K / BK;
    for (int t = 0; t < ntiles; t++) {
        __syncthreads();
        #pragma unroll
        for (int i = 0; i < 2; i++) {
            int s = tid + i*256, m = s >> 2, kv = s & 3;
            As[kv*4+0][m] = areg[i].x; As[kv*4+1][m] = areg[i].y;
            As[kv*4+2][m] = areg[i].z; As[kv*4+3][m] = areg[i].w;
        }
        #pragma unroll
        for (int i = 0; i < BSLOT; i++) {
            int s = tid + i*256, r = s/(BN/4), nv = s%(BN/4);
            *(float4*)&Bs[r][nv*4] = breg[i];
        }
        __syncthreads();
        if (t+1 < ntiles) {
            int kt = (t+1)*BK;
            #pragma unroll
            for (int i = 0; i < 2; i++) {
                int s = tid + i*256, m = s >> 2, kv = s & 3;
                float4 v = *(const float4*)&A[(size_t)(m0+m)*K + kt + kv*4];
                if (RELU_A) { v.x=fmaxf(v.x,0.f); v.y=fmaxf(v.y,0.f); v.z=fmaxf(v.z,0.f); v.w=fmaxf(v.w,0.f); }
                areg[i] = v;
            }
            #pragma unroll
            for (int i = 0; i < BSLOT; i++) {
                int s = tid + i*256, r = s/(BN/4), nv = s%(BN/4);
                int gn = n0 + nv*4;
                breg[i] = (gn < N) ? *(const float4*)&Bm[(size_t)(kt+r)*N + gn] : make_float4(0,0,0,0);
            }
        }
        #pragma unroll
        for (int k = 0; k < BK; k++) {
            float a[8], bb[TN];
            *(float4*)&a[0] = *(const float4*)&As[k][ty*8];
            *(float4*)&a[4] = *(const float4*)&As[k][ty*8+4];
            #pragma unroll
            for (int j = 0; j < TN/4; j++)
                *(float4*)&bb[j*4] = *(const float4*)&Bs[k][tx*TN + j*4];
            #pragma unroll
            for (int i = 0; i < 8; i++)
                #pragma unroll
                for (int j = 0; j < TN; j++) acc[i][j] += a[i]*bb[j];
        }
    }
    #pragma unroll
    for (int i = 0; i < 8; i++) {
        int gm = m0 + ty*8 + i;
        #pragma unroll
        for (int j = 0; j < TN; j++) {
            int gn = n0 + tx*TN + j;
            if (gn < N) {
                float v = acc[i][j];
                if (ACC) v += Cin[(size_t)gm*N + gn];
                if (RELU_C) v = fmaxf(v, 0.f);
                C[(size_t)gm*N + gn] = v;
            }
        }
    }
}

// ---------------- fused pair-feature -> LN -> FF -> head bias ---------------
__global__ void __launch_bounds__(256)
bias_kernel(const float* __restrict__ pos, const int* __restrict__ uid,
            const float* __restrict__ Wp, const float* __restrict__ W1,
            const float* __restrict__ W2, const float* __restrict__ Wb)
{
    __shared__ float sposi[32][3], sposj[KWIN][3];
    __shared__ int   suidi[32],    suidj[KWIN];
    __shared__ float4 spi4[32][4], spj4[KWIN][4];
    __shared__ float sWp[80], sWb[64];
    __shared__ float4 sW1T[64][4];
    __shared__ float4 sW2b[64];
    __shared__ unsigned char svalid[KWIN];

    int bb = blockIdx.x;
    int half = bb & 1;
    int bw = bb >> 1;
    int b = bw / NW, w = bw % NW;
    int q0 = half*32;
    int tid = threadIdx.x;

    for (int i = tid; i < 80; i += 256) sWp[i] = Wp[i];
    for (int i = tid; i < 64; i += 256) sWb[i] = Wb[i];
    for (int i = tid; i < 1024; i += 256) {
        int j = i >> 4, c = i & 15;
        ((float*)sW1T)[j*16 + c] = W1[c*64 + j];
    }
    if (tid < 64) {
        float4 r = make_float4(0,0,0,0);
        #pragma unroll
        for (int c = 0; c < 16; c++) {
            float w2v = W2[tid*16 + c];
            r.x += w2v*Wb[c*4+0]; r.y += w2v*Wb[c*4+1];
            r.z += w2v*Wb[c*4+2]; r.w += w2v*Wb[c*4+3];
        }
        sW2b[tid] = r;
    }
    for (int q = tid; q < 32; q += 256) {
        int gi = b*N_ + w*QWIN + q0 + q;
        sposi[q][0] = pos[gi*3]; sposi[q][1] = pos[gi*3+1]; sposi[q][2] = pos[gi*3+2];
        suidi[q] = uid[gi];
        const float4* pp = (const float4*)&g_p[(size_t)gi*32];
        spi4[q][0] = pp[0]; spi4[q][1] = pp[1]; spi4[q][2] = pp[2]; spi4[q][3] = pp[3];
    }
    for (int k = tid; k < KWIN; k += 256) {
        int j = w*QWIN + k - PADW;
        bool valid = (j >= 0 && j < N_);
        svalid[k] = valid;
        if (valid) {
            int gj = b*N_ + j;
            sposj[k][0] = pos[gj*3]; sposj[k][1] = pos[gj*3+1]; sposj[k][2] = pos[gj*3+2];
            suidj[k] = uid[gj];
            const float4* pp = (const float4*)&g_p[(size_t)gj*32 + 16];
            spj4[k][0] = pp[0]; spj4[k][1] = pp[1]; spj4[k][2] = pp[2]; spj4[k][3] = pp[3];
        } else {
            sposj[k][0] = sposj[k][1] = sposj[k][2] = 0.f; suidj[k] = -1;
            float4 z = make_float4(0,0,0,0);
            spj4[k][0] = z; spj4[k][1] = z; spj4[k][2] = z; spj4[k][3] = z;
        }
    }
    __syncthreads();

    float* brow = g_bias + (size_t)bw*HEADS*QWIN*KWIN;

    auto prep = [&](int q, int k, float4* u, float& bh0, float& bh1, float& bh2, float& bh3) {
        float dx = sposi[q][0]-sposj[k][0];
        float dy = sposi[q][1]-sposj[k][1];
        float dz = sposi[q][2]-sposj[k][2];
        float inv = 1.f / (1.f + dx*dx + dy*dy + dz*dz);
        float bij = (suidi[q] == suidj[k]) ? 1.f : 0.f;
        float4 pr[4];
        #pragma unroll
        for (int c4 = 0; c4 < 4; c4++) {
            float4 r;
            #pragma unroll
            for (int e = 0; e < 4; e++) {
                int c = c4*4 + e;
                float base = dx*sWp[c] + dy*sWp[16+c] + dz*sWp[32+c] + inv*sWp[48+c] + sWp[64+c];
                (&r.x)[e] = base*bij + (&spi4[q][c4].x)[e] + (&spj4[k][c4].x)[e];
            }
            pr[c4] = r;
        }
        float s = 0.f, s2 = 0.f;
        #pragma unroll
        for (int c4 = 0; c4 < 4; c4++) {
            s  += pr[c4].x + pr[c4].y + pr[c4].z + pr[c4].w;
            s2 += pr[c4].x*pr[c4].x + pr[c4].y*pr[c4].y + pr[c4].z*pr[c4].z + pr[c4].w*pr[c4].w;
        }
        float mean = s * (1.f/DP);
        float var  = s2 * (1.f/DP) - mean*mean;
        float rinv = rsqrtf(var + 1e-5f);
        bh0 = bh1 = bh2 = bh3 = 0.f;
        #pragma unroll
        for (int c4 = 0; c4 < 4; c4++) {
            #pragma unroll
            for (int e = 0; e < 4; e++) {
                int c = c4*4 + e;
                float pv = (&pr[c4].x)[e];
                bh0 += pv*sWb[c*4+0]; bh1 += pv*sWb[c*4+1];
                bh2 += pv*sWb[c*4+2]; bh3 += pv*sWb[c*4+3];
                (&u[c4].x)[e] = (pv - mean)*rinv;
            }
        }
    };

    for (int t = tid; t < 32*64; t += 256) {
        int q = t >> 6, k0 = t & 63, k1 = k0 + 64;
        int gq = q0 + q;
        float4 u0[4], u1[4];
        float a0,a1,a2,a3, c0,c1,c2,c3;
        prep(q, k0, u0, a0, a1, a2, a3);
        prep(q, k1, u1, c0, c1, c2, c3);
        #pragma unroll 2
        for (int j = 0; j < 64; j++) {
            float4 w0 = sW1T[j][0], w1 = sW1T[j][1], w2 = sW1T[j][2], w3 = sW1T[j][3];
            float t0 = u0[0].x*w0.x + u0[0].y*w0.y + u0[0].z*w0.z + u0[0].w*w0.w
                     + u0[1].x*w1.x + u0[1].y*w1.y + u0[1].z*w1.z + u0[1].w*w1.w
                     + u0[2].x*w2.x + u0[2].y*w2.y + u0[2].z*w2.z + u0[2].w*w2.w
                     + u0[3].x*w3.x + u0[3].y*w3.y + u0[3].z*w3.z + u0[3].w*w3.w;
            float t1 = u1[0].x*w0.x + u1[0].y*w0.y + u1[0].z*w0.z + u1[0].w*w0.w
                     + u1[1].x*w1.x + u1[1].y*w1.y + u1[1].z*w1.z + u1[1].w*w1.w
                     + u1[2].x*w2.x + u1[2].y*w2.y + u1[2].z*w2.z + u1[2].w*w2.w
                     + u1[3].x*w3.x + u1[3].y*w3.y + u1[3].z*w3.z + u1[3].w*w3.w;
            t0 = fmaxf(t0, 0.f); t1 = fmaxf(t1, 0.f);
            float4 wb2 = sW2b[j];
            a0 += t0*wb2.x; a1 += t0*wb2.y; a2 += t0*wb2.z; a3 += t0*wb2.w;
            c0 += t1*wb2.x; c1 += t1*wb2.y; c2 += t1*wb2.z; c3 += t1*wb2.w;
        }
        bool v0 = svalid[k0], v1 = svalid[k1];
        brow[((0*QWIN + gq) << 7) + k0] = v0 ? a0 : 0.f;
        brow[((1*QWIN + gq) << 7) + k0] = v0 ? a1 : 0.f;
        brow[((2*QWIN + gq) << 7) + k0] = v0 ? a2 : 0.f;
        brow[((3*QWIN + gq) << 7) + k0] = v0 ? a3 : 0.f;
        brow[((0*QWIN + gq) << 7) + k1] = v1 ? c0 : 0.f;
        brow[((1*QWIN + gq) << 7) + k1] = v1 ? c1 : 0.f;
        brow[((2*QWIN + gq) << 7) + k1] = v1 ? c2 : 0.f;
        brow[((3*QWIN + gq) << 7) + k1] = v1 ? c3 : 0.f;
    }
}

// ---------------- deterministic segment mean (indices sorted) ---------------
__global__ void segmean_kernel(const int* __restrict__ a2t, float* __restrict__ out)
{
    int bt = blockIdx.x;
    int b = bt / NTOK, t = bt % NTOK;
    const int* idx = a2t + b*N_;
    __shared__ int slo, shi;
    if (threadIdx.x == 0) {
        int lo = 0, hi = N_;
        while (lo < hi) { int mid = (lo+hi) >> 1; if (idx[mid] < t) lo = mid+1; else hi = mid; }
        slo = lo;
        int lo2 = lo, hi2 = N_;
        while (lo2 < hi2) { int mid = (lo2+hi2) >> 1; if (idx[mid] < t+1) lo2 = mid+1; else hi2 = mid; }
        shi = lo2;
    }
    __syncthreads();
    int lo = slo, hi = shi;
    float rcnt = 1.f / fmaxf((float)(hi - lo), 1.f);
    for (int d = threadIdx.x; d < DT; d += blockDim.x) {
        float ssum = 0.f;
        for (int i = lo; i < hi; i++) ssum += g_tok[((size_t)(b*N_ + i))*DT + d];
        out[(size_t)bt*DT + d] = ssum * rcnt;
    }
}

// ---------------- launch ----------------------------------------------------
extern "C" void kernel_launch(void* const* d_in, const int* in_sizes, int n_in,
                              void* d_out, int out_size)
{
    const float* ref_pos    = (const float*)d_in[0];
    const float* ref_charge = (const float*)d_in[1];
    const float* ref_mask   = (const float*)d_in[2];
    const float* ref_elem   = (const float*)d_in[3];
    const float* ref_chars  = (const float*)d_in[4];
    const float* W_single   = (const float*)d_in[5];
    const float* W_pair     = (const float*)d_in[6];
    const float* W_outer    = (const float*)d_in[7];
    const float* Wp_ff1     = (const float*)d_in[8];
    const float* Wp_ff2     = (const float*)d_in[9];
    const float* Wq         = (const float*)d_in[10];
    const float* Wk         = (const float*)d_in[11];
    const float* Wv         = (const float*)d_in[12];
    const float* Wo         = (const float*)d_in[13];
    const float* Wb         = (const float*)d_in[14];
    const float* Wff1       = (const float*)d_in[15];
    const float* Wff2       = (const float*)d_in[16];
    const float* W_out      = (const float*)d_in[17];
    const int*   uid        = (const int*)d_in[18];
    const int*   a2t        = (const int*)d_in[19];
    float* out = (float*)d_out;

    float *feats, *x, *qkv, *p, *tok;
    __nv_bfloat16 *bh, *bl, *hh, *hl;
    cudaGetSymbolAddress((void**)&feats, g_feats);
    cudaGetSymbolAddress((void**)&x,     g_x);
    cudaGetSymbolAddress((void**)&qkv,   g_qkv);
    cudaGetSymbolAddress((void**)&p,     g_p);
    cudaGetSymbolAddress((void**)&tok,   g_tok);
    cudaGetSymbolAddress((void**)&bh,    g_bh);
    cudaGetSymbolAddress((void**)&bl,    g_bl);
    cudaGetSymbolAddress((void**)&hh,    g_hh);
    cudaGetSymbolAddress((void**)&hl,    g_hl);

    const int WIDE_SMEM = (2*256*40 + 2*128*40) * 2;                 // 61440 bytes
    const int FF_SMEM   = (4*128*40*4 + 2*128*40) * 2;               // 184320 bytes
    const int AW_SMEM   = 2*4*128*8*16 + (2*4*64*40 + 2*128*40)*2;   // 192512 bytes
    cudaFuncSetAttribute(mma_gemm_wide<true,0>,  cudaFuncAttributeMaxDynamicSharedMemorySize, WIDE_SMEM);
    cudaFuncSetAttribute(mma_gemm_wide<false,3>, cudaFuncAttributeMaxDynamicSharedMemorySize, WIDE_SMEM);
    cudaFuncSetAttribute(ff_fused<false>, cudaFuncAttributeMaxDynamicSharedMemorySize, FF_SMEM);
    cudaFuncSetAttribute(ff_fused<true>,  cudaFuncAttributeMaxDynamicSharedMemorySize, FF_SMEM);
    cudaFuncSetAttribute(attn_wo, cudaFuncAttributeMaxDynamicSharedMemorySize, AW_SMEM);

    // 0) pack all weights (one launch)
    pack_all_kernel<<<(PACK_TOT+255)/256, 256>>>(W_single, Wq, Wk, Wv, Wo, Wff1, Wff2, W_out);

    // 1) feats + embed: x = feats @ W_single, fused LN -> h split
    build_feats_kernel<<<R_, 128>>>(ref_pos, ref_charge, ref_mask, ref_elem, ref_chars);
    mma_gemm<false,1,false><<<dim3(1, R_/128), 256>>>(feats, nullptr, nullptr,
        bh+OFF_EMB, bl+OFF_EMB, nullptr, x, hh, hl, R_, DS, KFP);

    // 2) p = relu(s) @ W_outer  (N=32, SIMT)
    sgemm_kernel<64,true,false,false><<<dim3(1, R_/128), 256>>>(x, W_outer, nullptr, p, R_, 2*DP, DS);

    // 3) pair bias
    bias_kernel<<<B_*NW*2, 256>>>(ref_pos, uid, W_pair, Wp_ff1, Wp_ff2, Wb);

    // 4) transformer layers: QKV (wide) -> fused attn+WO+LN -> fused FF
    for (int l = 0; l < DEPTH; l++) {
        mma_gemm_wide<true,0><<<dim3(3, R_/256), 512, WIDE_SMEM>>>(nullptr, hh, hl,
            bh+OFF_QKV+(size_t)l*49152, bl+OFF_QKV+(size_t)l*49152,
            qkv, nullptr, nullptr, R_, 3*DS, DS);
        attn_wo<<<B_*NW, 256, AW_SMEM>>>(qkv,
            bh+OFF_WO+(size_t)l*16384, bl+OFF_WO+(size_t)l*16384,
            x, x, hh, hl);
        if (l < DEPTH-1) {
            ff_fused<false><<<R_/128, 256, FF_SMEM>>>(hh, hl,
                bh+OFF_FF1+(size_t)l*65536, bl+OFF_FF1+(size_t)l*65536,
                bh+OFF_FF2+(size_t)l*65536, bl+OFF_FF2+(size_t)l*65536,
                x, x, hh, hl);
        } else {
            ff_fused<true><<<R_/128, 256, FF_SMEM>>>(hh, hl,
                bh+OFF_FF1+(size_t)l*65536, bl+OFF_FF1+(size_t)l*65536,
                bh+OFF_FF2+(size_t)l*65536, bl+OFF_FF2+(size_t)l*65536,
                x, x, nullptr, nullptr);
        }
    }

    // 5) tok = relu(x @ W_out); segment mean -> out
    mma_gemm_wide<false,3><<<dim3(3, R_/256), 512, WIDE_SMEM>>>(x, nullptr, nullptr,
        bh+OFF_WOUT, bl+OFF_WOUT, tok, nullptr, nullptr, R_, DT, DS);
    segmean_kernel<<<B_*NTOK, 384>>>(a2t, out);
}

// round 9
// speedup vs baseline: 1.1491x; 1.1491x over previous
#include <cuda_runtime.h>
#include <cuda_bf16.h>
#include <math.h>

#define B_    2
#define N_    8192
#define R_    (B_*N_)          // 16384 rows
#define DS    128
#define DP    16
#define DT    384
#define NTOK  1024
#define QWIN  64
#define KWIN  128
#define PADW  32
#define NW    (N_/QWIN)        // 128 windows
#define HEADS 4
#define DH    32
#define DEPTH 3
#define KFEAT 389
#define KFP   416              // padded to multiple of 32

// packed bf16 weight offsets (hi/lo arrays, layout [N][Kp] row-major)
#define OFF_EMB   0            // 128 x 416
#define OFF_QKV   53248        // 3 layers x [Wq|Wk|Wv] 384 x 128
#define OFF_WO    200704       // 3 x 128 x 128
#define OFF_FF1   249856       // 3 x 512 x 128
#define OFF_FF2   446464       // 3 x 128 x 512
#define OFF_WOUT  643072       // 384 x 128
#define PACK_TOT  692224

// ---------------- scratch (device globals: allocation-free) ----------------
__device__ float g_feats[(size_t)R_*KFP];
__device__ float g_x    [(size_t)R_*DS];
__device__ float g_qkv  [(size_t)R_*3*DS];
__device__ float g_o    [(size_t)R_*DS];
__device__ float g_p    [(size_t)R_*2*DP];
__device__ float g_bias [(size_t)B_*NW*HEADS*QWIN*KWIN];
__device__ float g_tok  [(size_t)R_*DT];
__device__ __nv_bfloat16 g_hh[(size_t)R_*DS],  g_hl[(size_t)R_*DS];   // LN(x) split
__device__ __nv_bfloat16 g_bh[PACK_TOT];
__device__ __nv_bfloat16 g_bl[PACK_TOT];

// ---------------- feats = concat(pos, charge, mask, element, chars), pad 0 --
__global__ void build_feats_kernel(const float* __restrict__ pos,
                                   const float* __restrict__ charge,
                                   const float* __restrict__ mask,
                                   const float* __restrict__ elem,
                                   const float* __restrict__ chars)
{
    int row = blockIdx.x;
    float* fr = g_feats + (size_t)row*KFP;
    for (int f = threadIdx.x; f < KFP; f += blockDim.x) {
        float v;
        if      (f < 3)    v = pos[row*3 + f];
        else if (f == 3)   v = charge[row];
        else if (f == 4)   v = mask[row];
        else if (f < 133)  v = elem[(size_t)row*128 + (f-5)];
        else if (f < KFEAT)v = chars[(size_t)row*256 + (f-133)];
        else               v = 0.f;
        fr[f] = v;
    }
}

// ---------------- one fused weight-pack kernel (transpose + hi/lo split) ----
__global__ void pack_all_kernel(const float* __restrict__ Ws, const float* __restrict__ Wq,
                                const float* __restrict__ Wk, const float* __restrict__ Wv,
                                const float* __restrict__ Wo, const float* __restrict__ W1,
                                const float* __restrict__ W2, const float* __restrict__ Wout)
{
    long idx = (long)blockIdx.x*256 + threadIdx.x;
    if (idx >= PACK_TOT) return;
    const float* src; int K, N, Kp; long rem;
    if (idx < OFF_QKV)      { src = Ws;  K = KFEAT; N = 128; Kp = KFP; rem = idx; }
    else if (idx < OFF_WO)  { long r = idx - OFF_QKV; int l = (int)(r/49152); r %= 49152;
                              int ws = (int)(r/16384); rem = r % 16384;
                              src = (ws==0 ? Wq : ws==1 ? Wk : Wv) + (size_t)l*16384;
                              K = 128; N = 128; Kp = 128; }
    else if (idx < OFF_FF1) { long r = idx - OFF_WO; int l = (int)(r/16384); rem = r % 16384;
                              src = Wo + (size_t)l*16384; K = 128; N = 128; Kp = 128; }
    else if (idx < OFF_FF2) { long r = idx - OFF_FF1; int l = (int)(r/65536); rem = r % 65536;
                              src = W1 + (size_t)l*65536; K = 128; N = 512; Kp = 128; }
    else if (idx < OFF_WOUT){ long r = idx - OFF_FF2; int l = (int)(r/65536); rem = r % 65536;
                              src = W2 + (size_t)l*65536; K = 512; N = 128; Kp = 512; }
    else                    { rem = idx - OFF_WOUT; src = Wout; K = 128; N = 384; Kp = 128; }
    int n = (int)(rem / Kp), k = (int)(rem % Kp);
    float v = (k < K) ? src[(size_t)k*N + n] : 0.f;
    __nv_bfloat16 h = __float2bfloat16(v);
    g_bh[idx] = h;
    g_bl[idx] = __float2bfloat16(v - __bfloat162float(h));
}

// ---------------- mma helpers ------------------------------------------------
__device__ __forceinline__ void ldsm4(unsigned &r0, unsigned &r1, unsigned &r2, unsigned &r3,
                                      const __nv_bfloat16* p)
{
    unsigned a = (unsigned)__cvta_generic_to_shared(p);
    asm volatile("ldmatrix.sync.aligned.m8n8.x4.shared.b16 {%0,%1,%2,%3},[%4];"
                 : "=r"(r0), "=r"(r1), "=r"(r2), "=r"(r3) : "r"(a));
}
__device__ __forceinline__ void mma16816(float* d, const unsigned* a, unsigned b0, unsigned b1)
{
    asm volatile("mma.sync.aligned.m16n8k16.row.col.f32.bf16.bf16.f32 "
                 "{%0,%1,%2,%3},{%4,%5,%6,%7},{%8,%9},{%0,%1,%2,%3};"
                 : "+f"(d[0]), "+f"(d[1]), "+f"(d[2]), "+f"(d[3])
                 : "r"(a[0]), "r"(a[1]), "r"(a[2]), "r"(a[3]), "r"(b0), "r"(b1));
}

// shared 32-k-step mma over one A chunk + one B tile (both bf16-split, LD=40)
__device__ __forceinline__ void mma_chunk(float acc[2][8][4],
    const __nv_bfloat16* sXh, const __nv_bfloat16* sXl,
    const __nv_bfloat16* sBh, const __nv_bfloat16* sBl,
    int lane, int warpM, int warpN)
{
    constexpr int LD = 40;
    #pragma unroll
    for (int ks = 0; ks < 2; ks++) {
        int rowin = lane & 7, tile = lane >> 3;
        unsigned ah[2][4], al[2][4];
        #pragma unroll
        for (int mi = 0; mi < 2; mi++) {
            int r = warpM + mi*16 + (tile & 1)*8 + rowin;
            int c = ks*16 + (tile >> 1)*8;
            ldsm4(ah[mi][0], ah[mi][1], ah[mi][2], ah[mi][3], &sXh[r*LD + c]);
            ldsm4(al[mi][0], al[mi][1], al[mi][2], al[mi][3], &sXl[r*LD + c]);
        }
        #pragma unroll
        for (int np = 0; np < 4; np++) {
            int nrow = warpN + np*16 + (tile >> 1)*8 + rowin;
            int c = ks*16 + (tile & 1)*8;
            unsigned bh0, bh1, bh2, bh3, bl0, bl1, bl2, bl3;
            ldsm4(bh0, bh1, bh2, bh3, &sBh[nrow*LD + c]);
            ldsm4(bl0, bl1, bl2, bl3, &sBl[nrow*LD + c]);
            #pragma unroll
            for (int mi = 0; mi < 2; mi++) {
                mma16816(acc[mi][np*2],   ah[mi], bh0, bh1);
                mma16816(acc[mi][np*2],   al[mi], bh0, bh1);
                mma16816(acc[mi][np*2],   ah[mi], bl0, bl1);
                mma16816(acc[mi][np*2+1], ah[mi], bh2, bh3);
                mma16816(acc[mi][np*2+1], al[mi], bh2, bh3);
                mma16816(acc[mi][np*2+1], ah[mi], bl2, bl3);
            }
        }
    }
}

// ---------------- tensor-core GEMM with fused epilogues (BM=128) -------------
// ABF16: A pre-split bf16; else A fp32 split on the fly.
// EPI: 0 = plain fp32 C, 1 = fp32 C + LayerNorm -> Hh/Hl (N=128, grid.x=1),
//      2 = relu -> bf16 split Hh/Hl only, 3 = relu -> fp32 C.
template<bool ABF16, int EPI, bool ACC>
__global__ void __launch_bounds__(256)
mma_gemm(const float* __restrict__ A,
         const __nv_bfloat16* __restrict__ Agh, const __nv_bfloat16* __restrict__ Agl,
         const __nv_bfloat16* __restrict__ Bh,  const __nv_bfloat16* __restrict__ Bl,
         const float* __restrict__ Cin, float* __restrict__ C,
         __nv_bfloat16* __restrict__ Hh, __nv_bfloat16* __restrict__ Hl,
         int M, int N, int K)
{
    constexpr int LD = 40;
    __shared__ __nv_bfloat16 sAh[128*LD], sAl[128*LD], sBh[128*LD], sBl[128*LD];
    __shared__ float2 ssum[128][2];
    int tid = threadIdx.x, lane = tid & 31, warp = tid >> 5;
    int m0 = blockIdx.y*128, n0 = blockIdx.x*128;
    int warpM = (warp >> 1)*32, warpN = (warp & 1)*64;

    float acc[2][8][4] = {};
    float4 pa[4]; uint4 pah[2], pal[2], pbh[2], pbl[2];

    if (ABF16) {
        #pragma unroll
        for (int i = 0; i < 2; i++) {
            int idx = tid + i*256, row = idx >> 2, q = idx & 3;
            pah[i] = *(const uint4*)&Agh[(size_t)(m0+row)*K + q*8];
            pal[i] = *(const uint4*)&Agl[(size_t)(m0+row)*K + q*8];
        }
    } else {
        #pragma unroll
        for (int i = 0; i < 4; i++) {
            int idx = tid + i*256, row = idx >> 3, c4 = idx & 7;
            pa[i] = *(const float4*)&A[(size_t)(m0+row)*K + c4*4];
        }
    }
    #pragma unroll
    for (int i = 0; i < 2; i++) {
        int idx = tid + i*256, row = idx >> 2, q = idx & 3;
        pbh[i] = *(const uint4*)&Bh[(size_t)(n0+row)*K + q*8];
        pbl[i] = *(const uint4*)&Bl[(size_t)(n0+row)*K + q*8];
    }

    int nt = K / 32;
    for (int t = 0; t < nt; t++) {
        __syncthreads();
        if (ABF16) {
            #pragma unroll
            for (int i = 0; i < 2; i++) {
                int idx = tid + i*256, row = idx >> 2, q = idx & 3;
                *(uint4*)&sAh[row*LD + q*8] = pah[i];
                *(uint4*)&sAl[row*LD + q*8] = pal[i];
            }
        } else {
            #pragma unroll
            for (int i = 0; i < 4; i++) {
                int idx = tid + i*256, row = idx >> 3, c = (idx & 7)*4;
                float4 v = pa[i];
                __nv_bfloat16 h0 = __float2bfloat16(v.x), h1 = __float2bfloat16(v.y);
                __nv_bfloat16 h2 = __float2bfloat16(v.z), h3 = __float2bfloat16(v.w);
                __nv_bfloat162 hh0; hh0.x = h0; hh0.y = h1;
                __nv_bfloat162 hh1; hh1.x = h2; hh1.y = h3;
                *(__nv_bfloat162*)&sAh[row*LD + c]     = hh0;
                *(__nv_bfloat162*)&sAh[row*LD + c + 2] = hh1;
                __nv_bfloat162 ll0, ll1;
                ll0.x = __float2bfloat16(v.x - __bfloat162float(h0));
                ll0.y = __float2bfloat16(v.y - __bfloat162float(h1));
                ll1.x = __float2bfloat16(v.z - __bfloat162float(h2));
                ll1.y = __float2bfloat16(v.w - __bfloat162float(h3));
                *(__nv_bfloat162*)&sAl[row*LD + c]     = ll0;
                *(__nv_bfloat162*)&sAl[row*LD + c + 2] = ll1;
            }
        }
        #pragma unroll
        for (int i = 0; i < 2; i++) {
            int idx = tid + i*256, row = idx >> 2, q = idx & 3;
            *(uint4*)&sBh[row*LD + q*8] = pbh[i];
            *(uint4*)&sBl[row*LD + q*8] = pbl[i];
        }
        __syncthreads();
        if (t + 1 < nt) {
            int kc = (t+1)*32;
            if (ABF16) {
                #pragma unroll
                for (int i = 0; i < 2; i++) {
                    int idx = tid + i*256, row = idx >> 2, q = idx & 3;
                    pah[i] = *(const uint4*)&Agh[(size_t)(m0+row)*K + kc + q*8];
                    pal[i] = *(const uint4*)&Agl[(size_t)(m0+row)*K + kc + q*8];
                }
            } else {
                #pragma unroll
                for (int i = 0; i < 4; i++) {
                    int idx = tid + i*256, row = idx >> 3, c4 = idx & 7;
                    pa[i] = *(const float4*)&A[(size_t)(m0+row)*K + kc + c4*4];
                }
            }
            #pragma unroll
            for (int i = 0; i < 2; i++) {
                int idx = tid + i*256, row = idx >> 2, q = idx & 3;
                pbh[i] = *(const uint4*)&Bh[(size_t)(n0+row)*K + kc + q*8];
                pbl[i] = *(const uint4*)&Bl[(size_t)(n0+row)*K + kc + q*8];
            }
        }
        mma_chunk(acc, sAh, sAl, sBh, sBl, lane, warpM, warpN);
    }

    if (ACC) {
        #pragma unroll
        for (int mi = 0; mi < 2; mi++) {
            #pragma unroll
            for (int nj = 0; nj < 8; nj++) {
                int r0  = m0 + warpM + mi*16 + (lane >> 2);
                int col = n0 + warpN + nj*8 + (lane & 3)*2;
                float2 c0 = *(const float2*)&Cin[(size_t)r0*N + col];
                float2 c1 = *(const float2*)&Cin[(size_t)(r0+8)*N + col];
                acc[mi][nj][0] += c0.x; acc[mi][nj][1] += c0.y;
                acc[mi][nj][2] += c1.x; acc[mi][nj][3] += c1.y;
            }
        }
    }

    float mean[4], rsig[4];
    if (EPI == 1) {
        float s[4] = {}, s2[4] = {};
        #pragma unroll
        for (int mi = 0; mi < 2; mi++)
            #pragma unroll
            for (int nj = 0; nj < 8; nj++) {
                float v0 = acc[mi][nj][0], v1 = acc[mi][nj][1];
                float v2 = acc[mi][nj][2], v3 = acc[mi][nj][3];
                s[mi*2]    += v0 + v1;      s2[mi*2]   += v0*v0 + v1*v1;
                s[mi*2+1]  += v2 + v3;      s2[mi*2+1] += v2*v2 + v3*v3;
            }
        #pragma unroll
        for (int off = 1; off <= 2; off <<= 1)
            #pragma unroll
            for (int r = 0; r < 4; r++) {
                s[r]  += __shfl_xor_sync(~0u, s[r],  off);
                s2[r] += __shfl_xor_sync(~0u, s2[r], off);
            }
        if ((lane & 3) == 0) {
            #pragma unroll
            for (int slot = 0; slot < 4; slot++) {
                int row = warpM + (slot >> 1)*16 + (lane >> 2) + 8*(slot & 1);
                ssum[row][warp & 1] = make_float2(s[slot], s2[slot]);
            }
        }
        __syncthreads();
        #pragma unroll
        for (int slot = 0; slot < 4; slot++) {
            int row = warpM + (slot >> 1)*16 + (lane >> 2) + 8*(slot & 1);
            float2 a = ssum[row][0], b = ssum[row][1];
            float m  = (a.x + b.x) * (1.f/128.f);
            float vv = (a.y + b.y) * (1.f/128.f) - m*m;
            mean[slot] = m;
            rsig[slot] = rsqrtf(vv + 1e-5f);
        }
    }

    #pragma unroll
    for (int mi = 0; mi < 2; mi++) {
        #pragma unroll
        for (int nj = 0; nj < 8; nj++) {
            int r0  = m0 + warpM + mi*16 + (lane >> 2);
            int col = n0 + warpN + nj*8 + (lane & 3)*2;
            float v0 = acc[mi][nj][0], v1 = acc[mi][nj][1];
            float v2 = acc[mi][nj][2], v3 = acc[mi][nj][3];
            if (EPI == 2 || EPI == 3) {
                v0 = fmaxf(v0, 0.f); v1 = fmaxf(v1, 0.f);
                v2 = fmaxf(v2, 0.f); v3 = fmaxf(v3, 0.f);
            }
            if (EPI == 0 || EPI == 1 || EPI == 3) {
                float2 o0; o0.x = v0; o0.y = v1;
                float2 o1; o1.x = v2; o1.y = v3;
                *(float2*)&C[(size_t)r0*N + col]     = o0;
                *(float2*)&C[(size_t)(r0+8)*N + col] = o1;
            }
            if (EPI == 1) {
                v0 = (v0 - mean[mi*2])*rsig[mi*2];
                v1 = (v1 - mean[mi*2])*rsig[mi*2];
                v2 = (v2 - mean[mi*2+1])*rsig[mi*2+1];
                v3 = (v3 - mean[mi*2+1])*rsig[mi*2+1];
            }
            if (EPI == 1 || EPI == 2) {
                __nv_bfloat162 hh0, hh1, ll0, ll1;
                hh0.x = __float2bfloat16(v0); hh0.y = __float2bfloat16(v1);
                hh1.x = __float2bfloat16(v2); hh1.y = __float2bfloat16(v3);
                ll0.x = __float2bfloat16(v0 - __bfloat162float(hh0.x));
                ll0.y = __float2bfloat16(v1 - __bfloat162float(hh0.y));
                ll1.x = __float2bfloat16(v2 - __bfloat162float(hh1.x));
                ll1.y = __float2bfloat16(v3 - __bfloat162float(hh1.y));
                *(__nv_bfloat162*)&Hh[(size_t)r0*N + col]     = hh0;
                *(__nv_bfloat162*)&Hh[(size_t)(r0+8)*N + col] = hh1;
                *(__nv_bfloat162*)&Hl[(size_t)r0*N + col]     = ll0;
                *(__nv_bfloat162*)&Hl[(size_t)(r0+8)*N + col] = ll1;
            }
        }
    }
}

// ---------------- wide GEMM: BM=256, 512 threads, dynamic smem ---------------
template<bool ABF16, int EPI>
__global__ void __launch_bounds__(512)
mma_gemm_wide(const float* __restrict__ A,
              const __nv_bfloat16* __restrict__ Agh, const __nv_bfloat16* __restrict__ Agl,
              const __nv_bfloat16* __restrict__ Bh,  const __nv_bfloat16* __restrict__ Bl,
              float* __restrict__ C,
              __nv_bfloat16* __restrict__ Hh, __nv_bfloat16* __restrict__ Hl,
              int M, int N, int K)
{
    constexpr int LD = 40;
    extern __shared__ __nv_bfloat16 dyns[];
    __nv_bfloat16* sAh = dyns;
    __nv_bfloat16* sAl = sAh + 256*LD;
    __nv_bfloat16* sBh = sAl + 256*LD;
    __nv_bfloat16* sBl = sBh + 128*LD;
    int tid = threadIdx.x, lane = tid & 31, warp = tid >> 5;
    int m0 = blockIdx.y*256, n0 = blockIdx.x*128;
    int warpM = (warp >> 1)*32, warpN = (warp & 1)*64;

    float acc[2][8][4] = {};
    float4 pa[4]; uint4 pah[2], pal[2], pbh, pbl;

    if (ABF16) {
        #pragma unroll
        for (int i = 0; i < 2; i++) {
            int idx = tid + i*512, row = idx >> 2, q = idx & 3;
            pah[i] = *(const uint4*)&Agh[(size_t)(m0+row)*K + q*8];
            pal[i] = *(const uint4*)&Agl[(size_t)(m0+row)*K + q*8];
        }
    } else {
        #pragma unroll
        for (int i = 0; i < 4; i++) {
            int idx = tid + i*512, row = idx >> 3, c4 = idx & 7;
            pa[i] = *(const float4*)&A[(size_t)(m0+row)*K + c4*4];
        }
    }
    {
        int row = tid >> 2, q = tid & 3;
        pbh = *(const uint4*)&Bh[(size_t)(n0+row)*K + q*8];
        pbl = *(const uint4*)&Bl[(size_t)(n0+row)*K + q*8];
    }

    int nt = K / 32;
    for (int t = 0; t < nt; t++) {
        __syncthreads();
        if (ABF16) {
            #pragma unroll
            for (int i = 0; i < 2; i++) {
                int idx = tid + i*512, row = idx >> 2, q = idx & 3;
                *(uint4*)&sAh[row*LD + q*8] = pah[i];
                *(uint4*)&sAl[row*LD + q*8] = pal[i];
            }
        } else {
            #pragma unroll
            for (int i = 0; i < 4; i++) {
                int idx = tid + i*512, row = idx >> 3, c = (idx & 7)*4;
                float4 v = pa[i];
                __nv_bfloat16 h0 = __float2bfloat16(v.x), h1 = __float2bfloat16(v.y);
                __nv_bfloat16 h2 = __float2bfloat16(v.z), h3 = __float2bfloat16(v.w);
                __nv_bfloat162 hh0; hh0.x = h0; hh0.y = h1;
                __nv_bfloat162 hh1; hh1.x = h2; hh1.y = h3;
                *(__nv_bfloat162*)&sAh[row*LD + c]     = hh0;
                *(__nv_bfloat162*)&sAh[row*LD + c + 2] = hh1;
                __nv_bfloat162 ll0, ll1;
                ll0.x = __float2bfloat16(v.x - __bfloat162float(h0));
                ll0.y = __float2bfloat16(v.y - __bfloat162float(h1));
                ll1.x = __float2bfloat16(v.z - __bfloat162float(h2));
                ll1.y = __float2bfloat16(v.w - __bfloat162float(h3));
                *(__nv_bfloat162*)&sAl[row*LD + c]     = ll0;
                *(__nv_bfloat162*)&sAl[row*LD + c + 2] = ll1;
            }
        }
        {
            int row = tid >> 2, q = tid & 3;
            *(uint4*)&sBh[row*LD + q*8] = pbh;
            *(uint4*)&sBl[row*LD + q*8] = pbl;
        }
        __syncthreads();
        if (t + 1 < nt) {
            int kc = (t+1)*32;
            if (ABF16) {
                #pragma unroll
                for (int i = 0; i < 2; i++) {
                    int idx = tid + i*512, row = idx >> 2, q = idx & 3;
                    pah[i] = *(const uint4*)&Agh[(size_t)(m0+row)*K + kc + q*8];
                    pal[i] = *(const uint4*)&Agl[(size_t)(m0+row)*K + kc + q*8];
                }
            } else {
                #pragma unroll
                for (int i = 0; i < 4; i++) {
                    int idx = tid + i*512, row = idx >> 3, c4 = idx & 7;
                    pa[i] = *(const float4*)&A[(size_t)(m0+row)*K + kc + c4*4];
                }
            }
            {
                int row = tid >> 2, q = tid & 3;
                pbh = *(const uint4*)&Bh[(size_t)(n0+row)*K + kc + q*8];
                pbl = *(const uint4*)&Bl[(size_t)(n0+row)*K + kc + q*8];
            }
        }
        mma_chunk(acc, sAh, sAl, sBh, sBl, lane, warpM, warpN);
    }

    #pragma unroll
    for (int mi = 0; mi < 2; mi++) {
        #pragma unroll
        for (int nj = 0; nj < 8; nj++) {
            int r0  = m0 + warpM + mi*16 + (lane >> 2);
            int col = n0 + warpN + nj*8 + (lane & 3)*2;
            float v0 = acc[mi][nj][0], v1 = acc[mi][nj][1];
            float v2 = acc[mi][nj][2], v3 = acc[mi][nj][3];
            if (EPI == 2 || EPI == 3) {
                v0 = fmaxf(v0, 0.f); v1 = fmaxf(v1, 0.f);
                v2 = fmaxf(v2, 0.f); v3 = fmaxf(v3, 0.f);
            }
            if (EPI == 0 || EPI == 3) {
                float2 o0; o0.x = v0; o0.y = v1;
                float2 o1; o1.x = v2; o1.y = v3;
                *(float2*)&C[(size_t)r0*N + col]     = o0;
                *(float2*)&C[(size_t)(r0+8)*N + col] = o1;
            }
            if (EPI == 2) {
                __nv_bfloat162 hh0, hh1, ll0, ll1;
                hh0.x = __float2bfloat16(v0); hh0.y = __float2bfloat16(v1);
                hh1.x = __float2bfloat16(v2); hh1.y = __float2bfloat16(v3);
                ll0.x = __float2bfloat16(v0 - __bfloat162float(hh0.x));
                ll0.y = __float2bfloat16(v1 - __bfloat162float(hh0.y));
                ll1.x = __float2bfloat16(v2 - __bfloat162float(hh1.x));
                ll1.y = __float2bfloat16(v3 - __bfloat162float(hh1.y));
                *(__nv_bfloat162*)&Hh[(size_t)r0*N + col]     = hh0;
                *(__nv_bfloat162*)&Hh[(size_t)(r0+8)*N + col] = hh1;
                *(__nv_bfloat162*)&Hl[(size_t)r0*N + col]     = ll0;
                *(__nv_bfloat162*)&Hl[(size_t)(r0+8)*N + col] = ll1;
            }
        }
    }
}

// ---------------- fused FF (+ optional next-layer QKV projection) -----------
// x += relu(h@W1)@W2; if !LAST: LN -> h' (kept in smem) -> qkv = h' @ Wqkv.
template<bool LAST>
__global__ void __launch_bounds__(256)
ff_fused(const __nv_bfloat16* __restrict__ Agh, const __nv_bfloat16* __restrict__ Agl,
         const __nv_bfloat16* __restrict__ B1h, const __nv_bfloat16* __restrict__ B1l,
         const __nv_bfloat16* __restrict__ B2h, const __nv_bfloat16* __restrict__ B2l,
         const __nv_bfloat16* __restrict__ Qwh, const __nv_bfloat16* __restrict__ Qwl,
         const float* __restrict__ Cin, float* __restrict__ C,
         float* __restrict__ qkvout)
{
    constexpr int LD = 40;
    constexpr int CH = 128*LD;
    extern __shared__ __nv_bfloat16 dyns[];
    __nv_bfloat16* sAh = dyns;
    __nv_bfloat16* sAl = sAh + 4*CH;
    __nv_bfloat16* sFh = sAl + 4*CH;
    __nv_bfloat16* sFl = sFh + 4*CH;
    __nv_bfloat16* sBh = sFl + 4*CH;
    __nv_bfloat16* sBl = sBh + CH;
    __shared__ float2 ssum[128][2];

    int tid = threadIdx.x, lane = tid & 31, warp = tid >> 5;
    int m0 = blockIdx.x*128;
    int warpM = (warp >> 1)*32, warpN = (warp & 1)*64;
    int brow = tid >> 2, bq = tid & 3;    // brow in [0,64)

    #pragma unroll
    for (int i = 0; i < 8; i++) {
        int idx = tid + i*256;
        int row = idx >> 4, q = idx & 15;
        int off = (q >> 2)*CH + row*LD + (q & 3)*8;
        *(uint4*)&sAh[off] = *(const uint4*)&Agh[(size_t)(m0+row)*128 + q*8];
        *(uint4*)&sAl[off] = *(const uint4*)&Agl[(size_t)(m0+row)*128 + q*8];
    }

    auto bptr = [&](int i, int row, const __nv_bfloat16* b1, const __nv_bfloat16* b2)
        -> const __nv_bfloat16* {
        int c = i >> 3, t = i & 3;
        if (((i >> 2) & 1) == 0)
            return &b1[(size_t)(c*128 + row)*128 + t*32 + bq*8];
        else
            return &b2[(size_t)row*512 + c*128 + t*32 + bq*8];
    };

    uint4 pbh[2], pbl[2];
    pbh[0] = *(const uint4*)bptr(0, brow,    B1h, B2h);
    pbh[1] = *(const uint4*)bptr(0, brow+64, B1h, B2h);
    pbl[0] = *(const uint4*)bptr(0, brow,    B1l, B2l);
    pbl[1] = *(const uint4*)bptr(0, brow+64, B1l, B2l);
    float acc2[2][8][4] = {};

    #pragma unroll 1
    for (int c = 0; c < 4; c++) {
        float acc1[2][8][4] = {};
        #pragma unroll
        for (int t = 0; t < 4; t++) {
            __syncthreads();
            *(uint4*)&sBh[brow*LD + bq*8]      = pbh[0];
            *(uint4*)&sBh[(brow+64)*LD + bq*8] = pbh[1];
            *(uint4*)&sBl[brow*LD + bq*8]      = pbl[0];
            *(uint4*)&sBl[(brow+64)*LD + bq*8] = pbl[1];
            __syncthreads();
            int ni = c*8 + t + 1;
            pbh[0] = *(const uint4*)bptr(ni, brow,    B1h, B2h);
            pbh[1] = *(const uint4*)bptr(ni, brow+64, B1h, B2h);
            pbl[0] = *(const uint4*)bptr(ni, brow,    B1l, B2l);
            pbl[1] = *(const uint4*)bptr(ni, brow+64, B1l, B2l);
            mma_chunk(acc1, sAh + t*CH, sAl + t*CH, sBh, sBl, lane, warpM, warpN);
        }
        #pragma unroll
        for (int mi = 0; mi < 2; mi++) {
            #pragma unroll
            for (int nj = 0; nj < 8; nj++) {
                int r   = warpM + mi*16 + (lane >> 2);
                int col = warpN + nj*8 + (lane & 3)*2;
                int off = (col >> 5)*CH + (col & 31);
                float v0 = fmaxf(acc1[mi][nj][0], 0.f), v1 = fmaxf(acc1[mi][nj][1], 0.f);
                float v2 = fmaxf(acc1[mi][nj][2], 0.f), v3 = fmaxf(acc1[mi][nj][3], 0.f);
                __nv_bfloat162 h0, h1, l0, l1;
                h0.x = __float2bfloat16(v0); h0.y = __float2bfloat16(v1);
                h1.x = __float2bfloat16(v2); h1.y = __float2bfloat16(v3);
                l0.x = __float2bfloat16(v0 - __bfloat162float(h0.x));
                l0.y = __float2bfloat16(v1 - __bfloat162float(h0.y));
                l1.x = __float2bfloat16(v2 - __bfloat162float(h1.x));
                l1.y = __float2bfloat16(v3 - __bfloat162float(h1.y));
                *(__nv_bfloat162*)&sFh[off + r*LD]     = h0;
                *(__nv_bfloat162*)&sFh[off + (r+8)*LD] = h1;
                *(__nv_bfloat162*)&sFl[off + r*LD]     = l0;
                *(__nv_bfloat162*)&sFl[off + (r+8)*LD] = l1;
            }
        }
        #pragma unroll
        for (int t = 0; t < 4; t++) {
            __syncthreads();
            *(uint4*)&sBh[brow*LD + bq*8]      = pbh[0];
            *(uint4*)&sBh[(brow+64)*LD + bq*8] = pbh[1];
            *(uint4*)&sBl[brow*LD + bq*8]      = pbl[0];
            *(uint4*)&sBl[(brow+64)*LD + bq*8] = pbl[1];
            __syncthreads();
            int ni = c*8 + t + 5;
            if (ni < 32) {
                pbh[0] = *(const uint4*)bptr(ni, brow,    B1h, B2h);
                pbh[1] = *(const uint4*)bptr(ni, brow+64, B1h, B2h);
                pbl[0] = *(const uint4*)bptr(ni, brow,    B1l, B2l);
                pbl[1] = *(const uint4*)bptr(ni, brow+64, B1l, B2l);
            }
            mma_chunk(acc2, sFh + t*CH, sFl + t*CH, sBh, sBl, lane, warpM, warpN);
        }
    }

    // residual
    #pragma unroll
    for (int mi = 0; mi < 2; mi++) {
        #pragma unroll
        for (int nj = 0; nj < 8; nj++) {
            int r0  = m0 + warpM + mi*16 + (lane >> 2);
            int col = warpN + nj*8 + (lane & 3)*2;
            float2 c0 = *(const float2*)&Cin[(size_t)r0*128 + col];
            float2 c1 = *(const float2*)&Cin[(size_t)(r0+8)*128 + col];
            acc2[mi][nj][0] += c0.x; acc2[mi][nj][1] += c0.y;
            acc2[mi][nj][2] += c1.x; acc2[mi][nj][3] += c1.y;
        }
    }

    float mean[4], rsig[4];
    if (!LAST) {
        float s[4] = {}, s2[4] = {};
        #pragma unroll
        for (int mi = 0; mi < 2; mi++)
            #pragma unroll
            for (int nj = 0; nj < 8; nj++) {
                float v0 = acc2[mi][nj][0], v1 = acc2[mi][nj][1];
                float v2 = acc2[mi][nj][2], v3 = acc2[mi][nj][3];
                s[mi*2]    += v0 + v1;      s2[mi*2]   += v0*v0 + v1*v1;
                s[mi*2+1]  += v2 + v3;      s2[mi*2+1] += v2*v2 + v3*v3;
            }
        #pragma unroll
        for (int off = 1; off <= 2; off <<= 1)
            #pragma unroll
            for (int r = 0; r < 4; r++) {
                s[r]  += __shfl_xor_sync(~0u, s[r],  off);
                s2[r] += __shfl_xor_sync(~0u, s2[r], off);
            }
        __syncthreads();
        if ((lane & 3) == 0) {
            #pragma unroll
            for (int slot = 0; slot < 4; slot++) {
                int row = warpM + (slot >> 1)*16 + (lane >> 2) + 8*(slot & 1);
                ssum[row][warp & 1] = make_float2(s[slot], s2[slot]);
            }
        }
        __syncthreads();
        #pragma unroll
        for (int slot = 0; slot < 4; slot++) {
            int row = warpM + (slot >> 1)*16 + (lane >> 2) + 8*(slot & 1);
            float2 a = ssum[row][0], b = ssum[row][1];
            float m  = (a.x + b.x) * (1.f/128.f);
            float vv = (a.y + b.y) * (1.f/128.f) - m*m;
            mean[slot] = m;
            rsig[slot] = rsqrtf(vv + 1e-5f);
        }
    }

    // prefetch first Wqkv tile (independent)
    uint4 qbh[2], qbl[2];
    if (!LAST) {
        qbh[0] = *(const uint4*)&Qwh[(size_t)brow*128 + bq*8];
        qbh[1] = *(const uint4*)&Qwh[(size_t)(brow+64)*128 + bq*8];
        qbl[0] = *(const uint4*)&Qwl[(size_t)brow*128 + bq*8];
        qbl[1] = *(const uint4*)&Qwl[(size_t)(brow+64)*128 + bq*8];
    }

    // write x; if !LAST also write LN'd h split into sA (smem) for QKV
    #pragma unroll
    for (int mi = 0; mi < 2; mi++) {
        #pragma unroll
        for (int nj = 0; nj < 8; nj++) {
            int r   = warpM + mi*16 + (lane >> 2);
            int col = warpN + nj*8 + (lane & 3)*2;
            int r0  = m0 + r;
            float v0 = acc2[mi][nj][0], v1 = acc2[mi][nj][1];
            float v2 = acc2[mi][nj][2], v3 = acc2[mi][nj][3];
            float2 o0; o0.x = v0; o0.y = v1;
            float2 o1; o1.x = v2; o1.y = v3;
            *(float2*)&C[(size_t)r0*128 + col]     = o0;
            *(float2*)&C[(size_t)(r0+8)*128 + col] = o1;
            if (!LAST) {
                v0 = (v0 - mean[mi*2])*rsig[mi*2];
                v1 = (v1 - mean[mi*2])*rsig[mi*2];
                v2 = (v2 - mean[mi*2+1])*rsig[mi*2+1];
                v3 = (v3 - mean[mi*2+1])*rsig[mi*2+1];
                int off = (col >> 5)*CH + (col & 31);
                __nv_bfloat162 h0, h1, l0, l1;
                h0.x = __float2bfloat16(v0); h0.y = __float2bfloat16(v1);
                h1.x = __float2bfloat16(v2); h1.y = __float2bfloat16(v3);
                l0.x = __float2bfloat16(v0 - __bfloat162float(h0.x));
                l0.y = __float2bfloat16(v1 - __bfloat162float(h0.y));
                l1.x = __float2bfloat16(v2 - __bfloat162float(h1.x));
                l1.y = __float2bfloat16(v3 - __bfloat162float(h1.y));
                *(__nv_bfloat162*)&sAh[off + r*LD]     = h0;
                *(__nv_bfloat162*)&sAh[off + (r+8)*LD] = h1;
                *(__nv_bfloat162*)&sAl[off + r*LD]     = l0;
                *(__nv_bfloat162*)&sAl[off + (r+8)*LD] = l1;
            }
        }
    }

    if (!LAST) {
        // qkv[128 x 384] = h' @ Wqkv  (3 N-blocks x 4 k-chunks, streamed B)
        #pragma unroll 1
        for (int nb = 0; nb < 3; nb++) {
            float acc[2][8][4] = {};
            #pragma unroll
            for (int t = 0; t < 4; t++) {
                __syncthreads();
                *(uint4*)&sBh[brow*LD + bq*8]      = qbh[0];
                *(uint4*)&sBh[(brow+64)*LD + bq*8] = qbh[1];
                *(uint4*)&sBl[brow*LD + bq*8]      = qbl[0];
                *(uint4*)&sBl[(brow+64)*LD + bq*8] = qbl[1];
                __syncthreads();
                int ni = nb*4 + t + 1;
                if (ni < 12) {
                    int nrow = (ni >> 2)*128, kc = (ni & 3)*32;
                    qbh[0] = *(const uint4*)&Qwh[(size_t)(nrow + brow)*128 + kc + bq*8];
                    qbh[1] = *(const uint4*)&Qwh[(size_t)(nrow + brow+64)*128 + kc + bq*8];
                    qbl[0] = *(const uint4*)&Qwl[(size_t)(nrow + brow)*128 + kc + bq*8];
                    qbl[1] = *(const uint4*)&Qwl[(size_t)(nrow + brow+64)*128 + kc + bq*8];
                }
                mma_chunk(acc, sAh + t*CH, sAl + t*CH, sBh, sBl, lane, warpM, warpN);
            }
            #pragma unroll
            for (int mi = 0; mi < 2; mi++) {
                #pragma unroll
                for (int nj = 0; nj < 8; nj++) {
                    int r0  = m0 + warpM + mi*16 + (lane >> 2);
                    int col = nb*128 + warpN + nj*8 + (lane & 3)*2;
                    float2 o0; o0.x = acc[mi][nj][0]; o0.y = acc[mi][nj][1];
                    float2 o1; o1.x = acc[mi][nj][2]; o1.y = acc[mi][nj][3];
                    *(float2*)&qkvout[(size_t)r0*384 + col]     = o0;
                    *(float2*)&qkvout[(size_t)(r0+8)*384 + col] = o1;
                }
            }
        }
    }
}

// ---------------- small SIMT GEMM (only for N=32 outer projection) ----------
template<int BN, bool RELU_A, bool RELU_C, bool ACC>
__global__ void __launch_bounds__(256)
sgemm_kernel(const float* __restrict__ A, const float* __restrict__ Bm,
             const float* __restrict__ Cin, float* __restrict__ C,
             int M, int N, int K)
{
    constexpr int BM = 128, BK = 16;
    constexpr int TN = BN/16;
    constexpr int BSLOT = (BK*BN)/(4*256);
    __shared__ float As[BK][BM];
    __shared__ float Bs[BK][BN];
    int tid = threadIdx.x;
    int m0 = blockIdx.y*BM, n0 = blockIdx.x*BN;
    int ty = tid >> 4, tx = tid & 15;

    float4 areg[2], breg[BSLOT];
    #pragma unroll
    for (int i = 0; i < 2; i++) {
        int s = tid + i*256, m = s >> 2, kv = s & 3;
        float4 v = *(const float4*)&A[(size_t)(m0+m)*K + kv*4];
        if (RELU_A) { v.x=fmaxf(v.x,0.f); v.y=fmaxf(v.y,0.f); v.z=fmaxf(v.z,0.f); v.w=fmaxf(v.w,0.f); }
        areg[i] = v;
    }
    #pragma unroll
    for (int i = 0; i < BSLOT; i++) {
        int s = tid + i*256, r = s/(BN/4), nv = s%(BN/4);
        int gn = n0 + nv*4;
        breg[i] = (gn < N) ? *(const float4*)&Bm[(size_t)r*N + gn] : make_float4(0,0,0,0);
    }
    float acc[8][TN];
    #pragma unroll
    for (int i = 0; i < 8; i++)
        #pragma unroll
        for (int j = 0; j < TN; j++) acc[i][j] = 0.f;

    int ntiles = K / BK;
    for (int t = 0; t < ntiles; t++) {
        __syncthreads();
        #pragma unroll
        for (int i = 0; i < 2; i++) {
            int s = tid + i*256, m = s >> 2, kv = s & 3;
            As[kv*4+0][m] = areg[i].x; As[kv*4+1][m] = areg[i].y;
            As[kv*4+2][m] = areg[i].z; As[kv*4+3][m] = areg[i].w;
        }
        #pragma unroll
        for (int i = 0; i < BSLOT; i++) {
            int s = tid + i*256, r = s/(BN/4), nv = s%(BN/4);
            *(float4*)&Bs[r][nv*4] = breg[i];
        }
        __syncthreads();
        if (t+1 < ntiles) {
            int kt = (t+1)*BK;
            #pragma unroll
            for (int i = 0; i < 2; i++) {
                int s = tid + i*256, m = s >> 2, kv = s & 3;
                float4 v = *(const float4*)&A[(size_t)(m0+m)*K + kt + kv*4];
                if (RELU_A) { v.x=fmaxf(v.x,0.f); v.y=fmaxf(v.y,0.f); v.z=fmaxf(v.z,0.f); v.w=fmaxf(v.w,0.f); }
                areg[i] = v;
            }
            #pragma unroll
            for (int i = 0; i < BSLOT; i++) {
                int s = tid + i*256, r = s/(BN/4), nv = s%(BN/4);
                int gn = n0 + nv*4;
                breg[i] = (gn < N) ? *(const float4*)&Bm[(size_t)(kt+r)*N + gn] : make_float4(0,0,0,0);
            }
        }
        #pragma unroll
        for (int k = 0; k < BK; k++) {
            float a[8], bb[TN];
            *(float4*)&a[0] = *(const float4*)&As[k][ty*8];
            *(float4*)&a[4] = *(const float4*)&As[k][ty*8+4];
            #pragma unroll
            for (int j = 0; j < TN/4; j++)
                *(float4*)&bb[j*4] = *(const float4*)&Bs[k][tx*TN + j*4];
            #pragma unroll
            for (int i = 0; i < 8; i++)
                #pragma unroll
                for (int j = 0; j < TN; j++) acc[i][j] += a[i]*bb[j];
        }
    }
    #pragma unroll
    for (int i = 0; i < 8; i++) {
        int gm = m0 + ty*8 + i;
        #pragma unroll
        for (int j = 0; j < TN; j++) {
            int gn = n0 + tx*TN + j;
            if (gn < N) {
                float v = acc[i][j];
                if (ACC) v += Cin[(size_t)gm*N + gn];
                if (RELU_C) v = fmaxf(v, 0.f);
                C[(size_t)gm*N + gn] = v;
            }
        }
    }
}

// ---------------- fused pair-feature -> LN -> FF -> head bias ---------------
__global__ void __launch_bounds__(256)
bias_kernel(const float* __restrict__ pos, const int* __restrict__ uid,
            const float* __restrict__ Wp, const float* __restrict__ W1,
            const float* __restrict__ W2, const float* __restrict__ Wb)
{
    __shared__ float sposi[32][3], sposj[KWIN][3];
    __shared__ int   suidi[32],    suidj[KWIN];
    __shared__ float4 spi4[32][4], spj4[KWIN][4];
    __shared__ float sWp[80], sWb[64];
    __shared__ float4 sW1T[64][4];
    __shared__ float4 sW2b[64];
    __shared__ unsigned char svalid[KWIN];

    int bb = blockIdx.x;
    int half = bb & 1;
    int bw = bb >> 1;
    int b = bw / NW, w = bw % NW;
    int q0 = half*32;
    int tid = threadIdx.x;

    for (int i = tid; i < 80; i += 256) sWp[i] = Wp[i];
    for (int i = tid; i < 64; i += 256) sWb[i] = Wb[i];
    for (int i = tid; i < 1024; i += 256) {
        int j = i >> 4, c = i & 15;
        ((float*)sW1T)[j*16 + c] = W1[c*64 + j];
    }
    if (tid < 64) {
        float4 r = make_float4(0,0,0,0);
        #pragma unroll
        for (int c = 0; c < 16; c++) {
            float w2v = W2[tid*16 + c];
            r.x += w2v*Wb[c*4+0]; r.y += w2v*Wb[c*4+1];
            r.z += w2v*Wb[c*4+2]; r.w += w2v*Wb[c*4+3];
        }
        sW2b[tid] = r;
    }
    for (int q = tid; q < 32; q += 256) {
        int gi = b*N_ + w*QWIN + q0 + q;
        sposi[q][0] = pos[gi*3]; sposi[q][1] = pos[gi*3+1]; sposi[q][2] = pos[gi*3+2];
        suidi[q] = uid[gi];
        const float4* pp = (const float4*)&g_p[(size_t)gi*32];
        spi4[q][0] = pp[0]; spi4[q][1] = pp[1]; spi4[q][2] = pp[2]; spi4[q][3] = pp[3];
    }
    for (int k = tid; k < KWIN; k += 256) {
        int j = w*QWIN + k - PADW;
        bool valid = (j >= 0 && j < N_);
        svalid[k] = valid;
        if (valid) {
            int gj = b*N_ + j;
            sposj[k][0] = pos[gj*3]; sposj[k][1] = pos[gj*3+1]; sposj[k][2] = pos[gj*3+2];
            suidj[k] = uid[gj];
            const float4* pp = (const float4*)&g_p[(size_t)gj*32 + 16];
            spj4[k][0] = pp[0]; spj4[k][1] = pp[1]; spj4[k][2] = pp[2]; spj4[k][3] = pp[3];
        } else {
            sposj[k][0] = sposj[k][1] = sposj[k][2] = 0.f; suidj[k] = -1;
            float4 z = make_float4(0,0,0,0);
            spj4[k][0] = z; spj4[k][1] = z; spj4[k][2] = z; spj4[k][3] = z;
        }
    }
    __syncthreads();

    float* brow = g_bias + (size_t)bw*HEADS*QWIN*KWIN;

    auto prep = [&](int q, int k, float4* u, float& bh0, float& bh1, float& bh2, float& bh3) {
        float dx = sposi[q][0]-sposj[k][0];
        float dy = sposi[q][1]-sposj[k][1];
        float dz = sposi[q][2]-sposj[k][2];
        float inv = 1.f / (1.f + dx*dx + dy*dy + dz*dz);
        float bij = (suidi[q] == suidj[k]) ? 1.f : 0.f;
        float4 pr[4];
        #pragma unroll
        for (int c4 = 0; c4 < 4; c4++) {
            float4 r;
            #pragma unroll
            for (int e = 0; e < 4; e++) {
                int c = c4*4 + e;
                float base = dx*sWp[c] + dy*sWp[16+c] + dz*sWp[32+c] + inv*sWp[48+c] + sWp[64+c];
                (&r.x)[e] = base*bij + (&spi4[q][c4].x)[e] + (&spj4[k][c4].x)[e];
            }
            pr[c4] = r;
        }
        float s = 0.f, s2 = 0.f;
        #pragma unroll
        for (int c4 = 0; c4 < 4; c4++) {
            s  += pr[c4].x + pr[c4].y + pr[c4].z + pr[c4].w;
            s2 += pr[c4].x*pr[c4].x + pr[c4].y*pr[c4].y + pr[c4].z*pr[c4].z + pr[c4].w*pr[c4].w;
        }
        float mean = s * (1.f/DP);
        float var  = s2 * (1.f/DP) - mean*mean;
        float rinv = rsqrtf(var + 1e-5f);
        bh0 = bh1 = bh2 = bh3 = 0.f;
        #pragma unroll
        for (int c4 = 0; c4 < 4; c4++) {
            #pragma unroll
            for (int e = 0; e < 4; e++) {
                int c = c4*4 + e;
                float pv = (&pr[c4].x)[e];
                bh0 += pv*sWb[c*4+0]; bh1 += pv*sWb[c*4+1];
                bh2 += pv*sWb[c*4+2]; bh3 += pv*sWb[c*4+3];
                (&u[c4].x)[e] = (pv - mean)*rinv;
            }
        }
    };

    for (int t = tid; t < 32*64; t += 256) {
        int q = t >> 6, k0 = t & 63, k1 = k0 + 64;
        int gq = q0 + q;
        float4 u0[4], u1[4];
        float a0,a1,a2,a3, c0,c1,c2,c3;
        prep(q, k0, u0, a0, a1, a2, a3);
        prep(q, k1, u1, c0, c1, c2, c3);
        #pragma unroll 2
        for (int j = 0; j < 64; j++) {
            float4 w0 = sW1T[j][0], w1 = sW1T[j][1], w2 = sW1T[j][2], w3 = sW1T[j][3];
            float t0 = u0[0].x*w0.x + u0[0].y*w0.y + u0[0].z*w0.z + u0[0].w*w0.w
                     + u0[1].x*w1.x + u0[1].y*w1.y + u0[1].z*w1.z + u0[1].w*w1.w
                     + u0[2].x*w2.x + u0[2].y*w2.y + u0[2].z*w2.z + u0[2].w*w2.w
                     + u0[3].x*w3.x + u0[3].y*w3.y + u0[3].z*w3.z + u0[3].w*w3.w;
            float t1 = u1[0].x*w0.x + u1[0].y*w0.y + u1[0].z*w0.z + u1[0].w*w0.w
                     + u1[1].x*w1.x + u1[1].y*w1.y + u1[1].z*w1.z + u1[1].w*w1.w
                     + u1[2].x*w2.x + u1[2].y*w2.y + u1[2].z*w2.z + u1[2].w*w2.w
                     + u1[3].x*w3.x + u1[3].y*w3.y + u1[3].z*w3.z + u1[3].w*w3.w;
            t0 = fmaxf(t0, 0.f); t1 = fmaxf(t1, 0.f);
            float4 wb2 = sW2b[j];
            a0 += t0*wb2.x; a1 += t0*wb2.y; a2 += t0*wb2.z; a3 += t0*wb2.w;
            c0 += t1*wb2.x; c1 += t1*wb2.y; c2 += t1*wb2.z; c3 += t1*wb2.w;
        }
        bool v0 = svalid[k0], v1 = svalid[k1];
        brow[((0*QWIN + gq) << 7) + k0] = v0 ? a0 : 0.f;
        brow[((1*QWIN + gq) << 7) + k0] = v0 ? a1 : 0.f;
        brow[((2*QWIN + gq) << 7) + k0] = v0 ? a2 : 0.f;
        brow[((3*QWIN + gq) << 7) + k0] = v0 ? a3 : 0.f;
        brow[((0*QWIN + gq) << 7) + k1] = v1 ? c0 : 0.f;
        brow[((1*QWIN + gq) << 7) + k1] = v1 ? c1 : 0.f;
        brow[((2*QWIN + gq) << 7) + k1] = v1 ? c2 : 0.f;
        brow[((3*QWIN + gq) << 7) + k1] = v1 ? c3 : 0.f;
    }
}

// ---------------- attention per (b, window, head): lane-parallel -------------
__global__ void attn_kernel(const float* __restrict__ qkv, float* __restrict__ o)
{
    __shared__ float4 ks4[KWIN][8];
    __shared__ float4 vs4[KWIN][8];
    __shared__ float  ps[8][2][KWIN];

    int h  = blockIdx.x & 3;
    int bw = blockIdx.x >> 2;
    int w  = bw & (NW-1);
    int b  = bw >> 7;
    int tid = threadIdx.x, lane = tid & 31, warp = tid >> 5;
    int rowbase = b*N_ + w*QWIN;

    for (int s = tid; s < KWIN*8; s += 256) {
        int kk = s >> 3, i = s & 7;
        int j = w*QWIN + kk - PADW;
        float4 kv = make_float4(0,0,0,0), vv = make_float4(0,0,0,0);
        if (j >= 0 && j < N_) {
            const float* base = &qkv[(size_t)(b*N_ + j)*384 + h*32 + i*4];
            kv = *(const float4*)(base + 128);
            vv = *(const float4*)(base + 256);
        }
        int sw = i ^ (kk & 7);
        ks4[kk][sw] = kv;
        vs4[kk][sw] = vv;
    }
    __syncthreads();

    const float scale = 0.17677669529663687f;
    const float* brow = g_bias + ((size_t)bw*HEADS + h)*QWIN*KWIN;
    int lhi = lane >> 2, llo = lane & 3;

    for (int pass = 0; pass < 4; pass++) {
        int rA = warp*8 + pass*2, rB = rA + 1;
        float4 qa[8], qb[8];
        #pragma unroll
        for (int i = 0; i < 8; i++) {
            qa[i] = *(const float4*)&qkv[(size_t)(rowbase+rA)*384 + h*32 + i*4];
            qb[i] = *(const float4*)&qkv[(size_t)(rowbase+rB)*384 + h*32 + i*4];
        }
        float4 aA[4], aB[4];
        #pragma unroll
        for (int g = 0; g < 4; g++) { aA[g] = make_float4(0,0,0,0); aB[g] = make_float4(0,0,0,0); }
        #pragma unroll
        for (int i = 0; i < 8; i++) {
            #pragma unroll
            for (int g = 0; g < 4; g++) {
                int kk = g*32 + lane;
                float4 kv = ks4[kk][i ^ (kk & 7)];
                aA[g].x += qa[i].x*kv.x; aA[g].y += qa[i].y*kv.y;
                aA[g].z += qa[i].z*kv.z; aA[g].w += qa[i].w*kv.w;
                aB[g].x += qb[i].x*kv.x; aB[g].y += qb[i].y*kv.y;
                aB[g].z += qb[i].z*kv.z; aB[g].w += qb[i].w*kv.w;
            }
        }
        float lA[4], lB[4];
        float mA = -1e30f, mB = -1e30f;
        #pragma unroll
        for (int g = 0; g < 4; g++) {
            int kk = g*32 + lane;
            int j = w*QWIN + kk - PADW;
            float msk = (j >= 0 && j < N_) ? 0.f : -1e9f;
            lA[g] = ((aA[g].x+aA[g].y)+(aA[g].z+aA[g].w))*scale + brow[(rA<<7)+kk] + msk;
            lB[g] = ((aB[g].x+aB[g].y)+(aB[g].z+aB[g].w))*scale + brow[(rB<<7)+kk] + msk;
            mA = fmaxf(mA, lA[g]); mB = fmaxf(mB, lB[g]);
        }
        #pragma unroll
        for (int off = 16; off > 0; off >>= 1) {
            mA = fmaxf(mA, __shfl_xor_sync(~0u, mA, off));
            mB = fmaxf(mB, __shfl_xor_sync(~0u, mB, off));
        }
        float sA = 0.f, sB = 0.f, eA[4], eB[4];
        #pragma unroll
        for (int g = 0; g < 4; g++) {
            eA[g] = __expf(lA[g]-mA); sA += eA[g];
            eB[g] = __expf(lB[g]-mB); sB += eB[g];
        }
        #pragma unroll
        for (int off = 16; off > 0; off >>= 1) {
            sA += __shfl_xor_sync(~0u, sA, off);
            sB += __shfl_xor_sync(~0u, sB, off);
        }
        float rsA = 1.f/sA, rsB = 1.f/sB;
        #pragma unroll
        for (int g = 0; g < 4; g++) {
            ps[warp][0][g*32+lane] = eA[g]*rsA;
            ps[warp][1][g*32+lane] = eB[g]*rsB;
        }
        __syncwarp();
        float oA = 0.f, oB = 0.f;
        #pragma unroll 4
        for (int k4 = 0; k4 < 32; k4++) {
            float4 pA = *(const float4*)&ps[warp][0][k4*4];
            float4 pB = *(const float4*)&ps[warp][1][k4*4];
            #pragma unroll
            for (int t = 0; t < 4; t++) {
                int kk = k4*4 + t;
                float v = ((const float*)&vs4[kk][0])[(((lhi ^ (kk&7))<<2) | llo)];
                oA += (&pA.x)[t]*v;
                oB += (&pB.x)[t]*v;
            }
        }
        o[(size_t)(rowbase+rA)*DS + h*32 + lane] = oA;
        o[(size_t)(rowbase+rB)*DS + h*32 + lane] = oB;
        __syncwarp();
    }
}

// ---------------- deterministic segment mean (indices sorted) ---------------
__global__ void segmean_kernel(const int* __restrict__ a2t, float* __restrict__ out)
{
    int bt = blockIdx.x;
    int b = bt / NTOK, t = bt % NTOK;
    const int* idx = a2t + b*N_;
    __shared__ int slo, shi;
    if (threadIdx.x == 0) {
        int lo = 0, hi = N_;
        while (lo < hi) { int mid = (lo+hi) >> 1; if (idx[mid] < t) lo = mid+1; else hi = mid; }
        slo = lo;
        int lo2 = lo, hi2 = N_;
        while (lo2 < hi2) { int mid = (lo2+hi2) >> 1; if (idx[mid] < t+1) lo2 = mid+1; else hi2 = mid; }
        shi = lo2;
    }
    __syncthreads();
    int lo = slo, hi = shi;
    float rcnt = 1.f / fmaxf((float)(hi - lo), 1.f);
    for (int d = threadIdx.x; d < DT; d += blockDim.x) {
        float ssum = 0.f;
        for (int i = lo; i < hi; i++) ssum += g_tok[((size_t)(b*N_ + i))*DT + d];
        out[(size_t)bt*DT + d] = ssum * rcnt;
    }
}

// ---------------- launch ----------------------------------------------------
extern "C" void kernel_launch(void* const* d_in, const int* in_sizes, int n_in,
                              void* d_out, int out_size)
{
    const float* ref_pos    = (const float*)d_in[0];
    const float* ref_charge = (const float*)d_in[1];
    const float* ref_mask   = (const float*)d_in[2];
    const float* ref_elem   = (const float*)d_in[3];
    const float* ref_chars  = (const float*)d_in[4];
    const float* W_single   = (const float*)d_in[5];
    const float* W_pair     = (const float*)d_in[6];
    const float* W_outer    = (const float*)d_in[7];
    const float* Wp_ff1     = (const float*)d_in[8];
    const float* Wp_ff2     = (const float*)d_in[9];
    const float* Wq         = (const float*)d_in[10];
    const float* Wk         = (const float*)d_in[11];
    const float* Wv         = (const float*)d_in[12];
    const float* Wo         = (const float*)d_in[13];
    const float* Wb         = (const float*)d_in[14];
    const float* Wff1       = (const float*)d_in[15];
    const float* Wff2       = (const float*)d_in[16];
    const float* W_out      = (const float*)d_in[17];
    const int*   uid        = (const int*)d_in[18];
    const int*   a2t        = (const int*)d_in[19];
    float* out = (float*)d_out;

    float *feats, *x, *qkv, *o, *p, *tok;
    __nv_bfloat16 *bh, *bl, *hh, *hl;
    cudaGetSymbolAddress((void**)&feats, g_feats);
    cudaGetSymbolAddress((void**)&x,     g_x);
    cudaGetSymbolAddress((void**)&qkv,   g_qkv);
    cudaGetSymbolAddress((void**)&o,     g_o);
    cudaGetSymbolAddress((void**)&p,     g_p);
    cudaGetSymbolAddress((void**)&tok,   g_tok);
    cudaGetSymbolAddress((void**)&bh,    g_bh);
    cudaGetSymbolAddress((void**)&bl,    g_bl);
    cudaGetSymbolAddress((void**)&hh,    g_hh);
    cudaGetSymbolAddress((void**)&hl,    g_hl);

    const int WIDE_SMEM = (2*256*40 + 2*128*40) * 2;         // 61440 bytes
    const int FF_SMEM   = (4*128*40*4 + 2*128*40) * 2;       // 184320 bytes
    cudaFuncSetAttribute(mma_gemm_wide<true,0>,  cudaFuncAttributeMaxDynamicSharedMemorySize, WIDE_SMEM);
    cudaFuncSetAttribute(mma_gemm_wide<false,3>, cudaFuncAttributeMaxDynamicSharedMemorySize, WIDE_SMEM);
    cudaFuncSetAttribute(ff_fused<false>, cudaFuncAttributeMaxDynamicSharedMemorySize, FF_SMEM);
    cudaFuncSetAttribute(ff_fused<true>,  cudaFuncAttributeMaxDynamicSharedMemorySize, FF_SMEM);

    // 0) pack all weights (one launch)
    pack_all_kernel<<<(PACK_TOT+255)/256, 256>>>(W_single, Wq, Wk, Wv, Wo, Wff1, Wff2, W_out);

    // 1) feats + embed: x = feats @ W_single, fused LN -> h split
    build_feats_kernel<<<R_, 128>>>(ref_pos, ref_charge, ref_mask, ref_elem, ref_chars);
    mma_gemm<false,1,false><<<dim3(1, R_/128), 256>>>(feats, nullptr, nullptr,
        bh+OFF_EMB, bl+OFF_EMB, nullptr, x, hh, hl, R_, DS, KFP);

    // 2) p = relu(s) @ W_outer  (N=32, SIMT)
    sgemm_kernel<64,true,false,false><<<dim3(1, R_/128), 256>>>(x, W_outer, nullptr, p, R_, 2*DP, DS);

    // 3) pair bias
    bias_kernel<<<B_*NW*2, 256>>>(ref_pos, uid, W_pair, Wp_ff1, Wp_ff2, Wb);

    // 4) layer-0 QKV from embed's h, then per layer: attn -> WO+LN -> FF(+next QKV)
    mma_gemm_wide<true,0><<<dim3(3, R_/256), 512, WIDE_SMEM>>>(nullptr, hh, hl,
        bh+OFF_QKV, bl+OFF_QKV, qkv, nullptr, nullptr, R_, 3*DS, DS);
    for (int l = 0; l < DEPTH; l++) {
        attn_kernel<<<B_*NW*HEADS, 256>>>(qkv, o);
        mma_gemm<false,1,true><<<dim3(1, R_/128), 256>>>(o, nullptr, nullptr,
            bh+OFF_WO+(size_t)l*16384, bl+OFF_WO+(size_t)l*16384,
            x, x, hh, hl, R_, DS, DS);
        if (l < DEPTH-1) {
            ff_fused<false><<<R_/128, 256, FF_SMEM>>>(hh, hl,
                bh+OFF_FF1+(size_t)l*65536, bl+OFF_FF1+(size_t)l*65536,
                bh+OFF_FF2+(size_t)l*65536, bl+OFF_FF2+(size_t)l*65536,
                bh+OFF_QKV+(size_t)(l+1)*49152, bl+OFF_QKV+(size_t)(l+1)*49152,
                x, x, qkv);
        } else {
            ff_fused<true><<<R_/128, 256, FF_SMEM>>>(hh, hl,
                bh+OFF_FF1+(size_t)l*65536, bl+OFF_FF1+(size_t)l*65536,
                bh+OFF_FF2+(size_t)l*65536, bl+OFF_FF2+(size_t)l*65536,
                nullptr, nullptr, x, x, nullptr);
        }
    }

    // 5) tok = relu(x @ W_out); segment mean -> out
    mma_gemm_wide<false,3><<<dim3(3, R_/256), 512, WIDE_SMEM>>>(x, nullptr, nullptr,
        bh+OFF_WOUT, bl+OFF_WOUT, tok, nullptr, nullptr, R_, DT, DS);
    segmean_kernel<<<B_*NTOK, 384>>>(a2t, out);
}

// round 10
// speedup vs baseline: 1.1883x; 1.0342x over previous
#include <cuda_runtime.h>
#include <cuda_bf16.h>
#include <math.h>

#define B_    2
#define N_    8192
#define R_    (B_*N_)          // 16384 rows
#define DS    128
#define DP    16
#define DT    384
#define NTOK  1024
#define QWIN  64
#define KWIN  128
#define PADW  32
#define NW    (N_/QWIN)        // 128 windows
#define HEADS 4
#define DH    32
#define DEPTH 3
#define KFEAT 389
#define KFP   416              // padded to multiple of 32

// packed bf16 weight offsets (hi/lo arrays, layout [N][Kp] row-major)
#define OFF_EMB   0            // 128 x 416
#define OFF_QKV   53248        // 3 layers x [Wq|Wk|Wv] 384 x 128
#define OFF_WO    200704       // 3 x 128 x 128
#define OFF_FF1   249856       // 3 x 512 x 128
#define OFF_FF2   446464       // 3 x 128 x 512
#define OFF_WOUT  643072       // 384 x 128
#define PACK_TOT  692224

// ---------------- scratch (device globals: allocation-free) ----------------
__device__ float g_feats[(size_t)R_*KFP];
__device__ float g_x    [(size_t)R_*DS];
__device__ float g_qkv  [(size_t)R_*3*DS];
__device__ float g_o    [(size_t)R_*DS];
__device__ float g_p    [(size_t)R_*2*DP];
__device__ float g_bias [(size_t)B_*NW*HEADS*QWIN*KWIN];
__device__ float g_tok  [(size_t)R_*DT];
__device__ __nv_bfloat16 g_hh[(size_t)R_*DS],  g_hl[(size_t)R_*DS];   // LN(x) split (embed only)
__device__ __nv_bfloat16 g_bh[PACK_TOT];
__device__ __nv_bfloat16 g_bl[PACK_TOT];

// ---------------- feats = concat(pos, charge, mask, element, chars), pad 0 --
__global__ void build_feats_kernel(const float* __restrict__ pos,
                                   const float* __restrict__ charge,
                                   const float* __restrict__ mask,
                                   const float* __restrict__ elem,
                                   const float* __restrict__ chars)
{
    int row = blockIdx.x;
    float* fr = g_feats + (size_t)row*KFP;
    for (int f = threadIdx.x; f < KFP; f += blockDim.x) {
        float v;
        if      (f < 3)    v = pos[row*3 + f];
        else if (f == 3)   v = charge[row];
        else if (f == 4)   v = mask[row];
        else if (f < 133)  v = elem[(size_t)row*128 + (f-5)];
        else if (f < KFEAT)v = chars[(size_t)row*256 + (f-133)];
        else               v = 0.f;
        fr[f] = v;
    }
}

// ---------------- one fused weight-pack kernel (transpose + hi/lo split) ----
__global__ void pack_all_kernel(const float* __restrict__ Ws, const float* __restrict__ Wq,
                                const float* __restrict__ Wk, const float* __restrict__ Wv,
                                const float* __restrict__ Wo, const float* __restrict__ W1,
                                const float* __restrict__ W2, const float* __restrict__ Wout)
{
    long idx = (long)blockIdx.x*256 + threadIdx.x;
    if (idx >= PACK_TOT) return;
    const float* src; int K, N, Kp; long rem;
    if (idx < OFF_QKV)      { src = Ws;  K = KFEAT; N = 128; Kp = KFP; rem = idx; }
    else if (idx < OFF_WO)  { long r = idx - OFF_QKV; int l = (int)(r/49152); r %= 49152;
                              int ws = (int)(r/16384); rem = r % 16384;
                              src = (ws==0 ? Wq : ws==1 ? Wk : Wv) + (size_t)l*16384;
                              K = 128; N = 128; Kp = 128; }
    else if (idx < OFF_FF1) { long r = idx - OFF_WO; int l = (int)(r/16384); rem = r % 16384;
                              src = Wo + (size_t)l*16384; K = 128; N = 128; Kp = 128; }
    else if (idx < OFF_FF2) { long r = idx - OFF_FF1; int l = (int)(r/65536); rem = r % 65536;
                              src = W1 + (size_t)l*65536; K = 128; N = 512; Kp = 128; }
    else if (idx < OFF_WOUT){ long r = idx - OFF_FF2; int l = (int)(r/65536); rem = r % 65536;
                              src = W2 + (size_t)l*65536; K = 512; N = 128; Kp = 512; }
    else                    { rem = idx - OFF_WOUT; src = Wout; K = 128; N = 384; Kp = 128; }
    int n = (int)(rem / Kp), k = (int)(rem % Kp);
    float v = (k < K) ? src[(size_t)k*N + n] : 0.f;
    __nv_bfloat16 h = __float2bfloat16(v);
    g_bh[idx] = h;
    g_bl[idx] = __float2bfloat16(v - __bfloat162float(h));
}

// ---------------- mma helpers ------------------------------------------------
__device__ __forceinline__ void ldsm4(unsigned &r0, unsigned &r1, unsigned &r2, unsigned &r3,
                                      const __nv_bfloat16* p)
{
    unsigned a = (unsigned)__cvta_generic_to_shared(p);
    asm volatile("ldmatrix.sync.aligned.m8n8.x4.shared.b16 {%0,%1,%2,%3},[%4];"
                 : "=r"(r0), "=r"(r1), "=r"(r2), "=r"(r3) : "r"(a));
}
__device__ __forceinline__ void mma16816(float* d, const unsigned* a, unsigned b0, unsigned b1)
{
    asm volatile("mma.sync.aligned.m16n8k16.row.col.f32.bf16.bf16.f32 "
                 "{%0,%1,%2,%3},{%4,%5,%6,%7},{%8,%9},{%0,%1,%2,%3};"
                 : "+f"(d[0]), "+f"(d[1]), "+f"(d[2]), "+f"(d[3])
                 : "r"(a[0]), "r"(a[1]), "r"(a[2]), "r"(a[3]), "r"(b0), "r"(b1));
}

// shared 32-k-step mma over one A chunk + one B tile (both bf16-split, LD=40)
__device__ __forceinline__ void mma_chunk(float acc[2][8][4],
    const __nv_bfloat16* sXh, const __nv_bfloat16* sXl,
    const __nv_bfloat16* sBh, const __nv_bfloat16* sBl,
    int lane, int warpM, int warpN)
{
    constexpr int LD = 40;
    #pragma unroll
    for (int ks = 0; ks < 2; ks++) {
        int rowin = lane & 7, tile = lane >> 3;
        unsigned ah[2][4], al[2][4];
        #pragma unroll
        for (int mi = 0; mi < 2; mi++) {
            int r = warpM + mi*16 + (tile & 1)*8 + rowin;
            int c = ks*16 + (tile >> 1)*8;
            ldsm4(ah[mi][0], ah[mi][1], ah[mi][2], ah[mi][3], &sXh[r*LD + c]);
            ldsm4(al[mi][0], al[mi][1], al[mi][2], al[mi][3], &sXl[r*LD + c]);
        }
        #pragma unroll
        for (int np = 0; np < 4; np++) {
            int nrow = warpN + np*16 + (tile >> 1)*8 + rowin;
            int c = ks*16 + (tile & 1)*8;
            unsigned bh0, bh1, bh2, bh3, bl0, bl1, bl2, bl3;
            ldsm4(bh0, bh1, bh2, bh3, &sBh[nrow*LD + c]);
            ldsm4(bl0, bl1, bl2, bl3, &sBl[nrow*LD + c]);
            #pragma unroll
            for (int mi = 0; mi < 2; mi++) {
                mma16816(acc[mi][np*2],   ah[mi], bh0, bh1);
                mma16816(acc[mi][np*2],   al[mi], bh0, bh1);
                mma16816(acc[mi][np*2],   ah[mi], bl0, bl1);
                mma16816(acc[mi][np*2+1], ah[mi], bh2, bh3);
                mma16816(acc[mi][np*2+1], al[mi], bh2, bh3);
                mma16816(acc[mi][np*2+1], ah[mi], bl2, bl3);
            }
        }
    }
}

// ---------------- tensor-core GEMM with fused epilogues (BM=128) -------------
template<bool ABF16, int EPI, bool ACC>
__global__ void __launch_bounds__(256)
mma_gemm(const float* __restrict__ A,
         const __nv_bfloat16* __restrict__ Agh, const __nv_bfloat16* __restrict__ Agl,
         const __nv_bfloat16* __restrict__ Bh,  const __nv_bfloat16* __restrict__ Bl,
         const float* __restrict__ Cin, float* __restrict__ C,
         __nv_bfloat16* __restrict__ Hh, __nv_bfloat16* __restrict__ Hl,
         int M, int N, int K)
{
    constexpr int LD = 40;
    __shared__ __nv_bfloat16 sAh[128*LD], sAl[128*LD], sBh[128*LD], sBl[128*LD];
    __shared__ float2 ssum[128][2];
    int tid = threadIdx.x, lane = tid & 31, warp = tid >> 5;
    int m0 = blockIdx.y*128, n0 = blockIdx.x*128;
    int warpM = (warp >> 1)*32, warpN = (warp & 1)*64;

    float acc[2][8][4] = {};
    float4 pa[4]; uint4 pah[2], pal[2], pbh[2], pbl[2];

    if (ABF16) {
        #pragma unroll
        for (int i = 0; i < 2; i++) {
            int idx = tid + i*256, row = idx >> 2, q = idx & 3;
            pah[i] = *(const uint4*)&Agh[(size_t)(m0+row)*K + q*8];
            pal[i] = *(const uint4*)&Agl[(size_t)(m0+row)*K + q*8];
        }
    } else {
        #pragma unroll
        for (int i = 0; i < 4; i++) {
            int idx = tid + i*256, row = idx >> 3, c4 = idx & 7;
            pa[i] = *(const float4*)&A[(size_t)(m0+row)*K + c4*4];
        }
    }
    #pragma unroll
    for (int i = 0; i < 2; i++) {
        int idx = tid + i*256, row = idx >> 2, q = idx & 3;
        pbh[i] = *(const uint4*)&Bh[(size_t)(n0+row)*K + q*8];
        pbl[i] = *(const uint4*)&Bl[(size_t)(n0+row)*K + q*8];
    }

    int nt = K / 32;
    for (int t = 0; t < nt; t++) {
        __syncthreads();
        if (ABF16) {
            #pragma unroll
            for (int i = 0; i < 2; i++) {
                int idx = tid + i*256, row = idx >> 2, q = idx & 3;
                *(uint4*)&sAh[row*LD + q*8] = pah[i];
                *(uint4*)&sAl[row*LD + q*8] = pal[i];
            }
        } else {
            #pragma unroll
            for (int i = 0; i < 4; i++) {
                int idx = tid + i*256, row = idx >> 3, c = (idx & 7)*4;
                float4 v = pa[i];
                __nv_bfloat16 h0 = __float2bfloat16(v.x), h1 = __float2bfloat16(v.y);
                __nv_bfloat16 h2 = __float2bfloat16(v.z), h3 = __float2bfloat16(v.w);
                __nv_bfloat162 hh0; hh0.x = h0; hh0.y = h1;
                __nv_bfloat162 hh1; hh1.x = h2; hh1.y = h3;
                *(__nv_bfloat162*)&sAh[row*LD + c]     = hh0;
                *(__nv_bfloat162*)&sAh[row*LD + c + 2] = hh1;
                __nv_bfloat162 ll0, ll1;
                ll0.x = __float2bfloat16(v.x - __bfloat162float(h0));
                ll0.y = __float2bfloat16(v.y - __bfloat162float(h1));
                ll1.x = __float2bfloat16(v.z - __bfloat162float(h2));
                ll1.y = __float2bfloat16(v.w - __bfloat162float(h3));
                *(__nv_bfloat162*)&sAl[row*LD + c]     = ll0;
                *(__nv_bfloat162*)&sAl[row*LD + c + 2] = ll1;
            }
        }
        #pragma unroll
        for (int i = 0; i < 2; i++) {
            int idx = tid + i*256, row = idx >> 2, q = idx & 3;
            *(uint4*)&sBh[row*LD + q*8] = pbh[i];
            *(uint4*)&sBl[row*LD + q*8] = pbl[i];
        }
        __syncthreads();
        if (t + 1 < nt) {
            int kc = (t+1)*32;
            if (ABF16) {
                #pragma unroll
                for (int i = 0; i < 2; i++) {
                    int idx = tid + i*256, row = idx >> 2, q = idx & 3;
                    pah[i] = *(const uint4*)&Agh[(size_t)(m0+row)*K + kc + q*8];
                    pal[i] = *(const uint4*)&Agl[(size_t)(m0+row)*K + kc + q*8];
                }
            } else {
                #pragma unroll
                for (int i = 0; i < 4; i++) {
                    int idx = tid + i*256, row = idx >> 3, c4 = idx & 7;
                    pa[i] = *(const float4*)&A[(size_t)(m0+row)*K + kc + c4*4];
                }
            }
            #pragma unroll
            for (int i = 0; i < 2; i++) {
                int idx = tid + i*256, row = idx >> 2, q = idx & 3;
                pbh[i] = *(const uint4*)&Bh[(size_t)(n0+row)*K + kc + q*8];
                pbl[i] = *(const uint4*)&Bl[(size_t)(n0+row)*K + kc + q*8];
            }
        }
        mma_chunk(acc, sAh, sAl, sBh, sBl, lane, warpM, warpN);
    }

    if (ACC) {
        #pragma unroll
        for (int mi = 0; mi < 2; mi++) {
            #pragma unroll
            for (int nj = 0; nj < 8; nj++) {
                int r0  = m0 + warpM + mi*16 + (lane >> 2);
                int col = n0 + warpN + nj*8 + (lane & 3)*2;
                float2 c0 = *(const float2*)&Cin[(size_t)r0*N + col];
                float2 c1 = *(const float2*)&Cin[(size_t)(r0+8)*N + col];
                acc[mi][nj][0] += c0.x; acc[mi][nj][1] += c0.y;
                acc[mi][nj][2] += c1.x; acc[mi][nj][3] += c1.y;
            }
        }
    }

    float mean[4], rsig[4];
    if (EPI == 1) {
        float s[4] = {}, s2[4] = {};
        #pragma unroll
        for (int mi = 0; mi < 2; mi++)
            #pragma unroll
            for (int nj = 0; nj < 8; nj++) {
                float v0 = acc[mi][nj][0], v1 = acc[mi][nj][1];
                float v2 = acc[mi][nj][2], v3 = acc[mi][nj][3];
                s[mi*2]    += v0 + v1;      s2[mi*2]   += v0*v0 + v1*v1;
                s[mi*2+1]  += v2 + v3;      s2[mi*2+1] += v2*v2 + v3*v3;
            }
        #pragma unroll
        for (int off = 1; off <= 2; off <<= 1)
            #pragma unroll
            for (int r = 0; r < 4; r++) {
                s[r]  += __shfl_xor_sync(~0u, s[r],  off);
                s2[r] += __shfl_xor_sync(~0u, s2[r], off);
            }
        if ((lane & 3) == 0) {
            #pragma unroll
            for (int slot = 0; slot < 4; slot++) {
                int row = warpM + (slot >> 1)*16 + (lane >> 2) + 8*(slot & 1);
                ssum[row][warp & 1] = make_float2(s[slot], s2[slot]);
            }
        }
        __syncthreads();
        #pragma unroll
        for (int slot = 0; slot < 4; slot++) {
            int row = warpM + (slot >> 1)*16 + (lane >> 2) + 8*(slot & 1);
            float2 a = ssum[row][0], b = ssum[row][1];
            float m  = (a.x + b.x) * (1.f/128.f);
            float vv = (a.y + b.y) * (1.f/128.f) - m*m;
            mean[slot] = m;
            rsig[slot] = rsqrtf(vv + 1e-5f);
        }
    }

    #pragma unroll
    for (int mi = 0; mi < 2; mi++) {
        #pragma unroll
        for (int nj = 0; nj < 8; nj++) {
            int r0  = m0 + warpM + mi*16 + (lane >> 2);
            int col = n0 + warpN + nj*8 + (lane & 3)*2;
            float v0 = acc[mi][nj][0], v1 = acc[mi][nj][1];
            float v2 = acc[mi][nj][2], v3 = acc[mi][nj][3];
            if (EPI == 2 || EPI == 3) {
                v0 = fmaxf(v0, 0.f); v1 = fmaxf(v1, 0.f);
                v2 = fmaxf(v2, 0.f); v3 = fmaxf(v3, 0.f);
            }
            if (EPI == 0 || EPI == 1 || EPI == 3) {
                float2 o0; o0.x = v0; o0.y = v1;
                float2 o1; o1.x = v2; o1.y = v3;
                *(float2*)&C[(size_t)r0*N + col]     = o0;
                *(float2*)&C[(size_t)(r0+8)*N + col] = o1;
            }
            if (EPI == 1) {
                v0 = (v0 - mean[mi*2])*rsig[mi*2];
                v1 = (v1 - mean[mi*2])*rsig[mi*2];
                v2 = (v2 - mean[mi*2+1])*rsig[mi*2+1];
                v3 = (v3 - mean[mi*2+1])*rsig[mi*2+1];
            }
            if (EPI == 1 || EPI == 2) {
                __nv_bfloat162 hh0, hh1, ll0, ll1;
                hh0.x = __float2bfloat16(v0); hh0.y = __float2bfloat16(v1);
                hh1.x = __float2bfloat16(v2); hh1.y = __float2bfloat16(v3);
                ll0.x = __float2bfloat16(v0 - __bfloat162float(hh0.x));
                ll0.y = __float2bfloat16(v1 - __bfloat162float(hh0.y));
                ll1.x = __float2bfloat16(v2 - __bfloat162float(hh1.x));
                ll1.y = __float2bfloat16(v3 - __bfloat162float(hh1.y));
                *(__nv_bfloat162*)&Hh[(size_t)r0*N + col]     = hh0;
                *(__nv_bfloat162*)&Hh[(size_t)(r0+8)*N + col] = hh1;
                *(__nv_bfloat162*)&Hl[(size_t)r0*N + col]     = ll0;
                *(__nv_bfloat162*)&Hl[(size_t)(r0+8)*N + col] = ll1;
            }
        }
    }
}

// ---------------- wide GEMM: BM=256, 512 threads, dynamic smem ---------------
template<bool ABF16, int EPI>
__global__ void __launch_bounds__(512)
mma_gemm_wide(const float* __restrict__ A,
              const __nv_bfloat16* __restrict__ Agh, const __nv_bfloat16* __restrict__ Agl,
              const __nv_bfloat16* __restrict__ Bh,  const __nv_bfloat16* __restrict__ Bl,
              float* __restrict__ C,
              __nv_bfloat16* __restrict__ Hh, __nv_bfloat16* __restrict__ Hl,
              int M, int N, int K)
{
    constexpr int LD = 40;
    extern __shared__ __nv_bfloat16 dyns[];
    __nv_bfloat16* sAh = dyns;
    __nv_bfloat16* sAl = sAh + 256*LD;
    __nv_bfloat16* sBh = sAl + 256*LD;
    __nv_bfloat16* sBl = sBh + 128*LD;
    int tid = threadIdx.x, lane = tid & 31, warp = tid >> 5;
    int m0 = blockIdx.y*256, n0 = blockIdx.x*128;
    int warpM = (warp >> 1)*32, warpN = (warp & 1)*64;

    float acc[2][8][4] = {};
    float4 pa[4]; uint4 pah[2], pal[2], pbh, pbl;

    if (ABF16) {
        #pragma unroll
        for (int i = 0; i < 2; i++) {
            int idx = tid + i*512, row = idx >> 2, q = idx & 3;
            pah[i] = *(const uint4*)&Agh[(size_t)(m0+row)*K + q*8];
            pal[i] = *(const uint4*)&Agl[(size_t)(m0+row)*K + q*8];
        }
    } else {
        #pragma unroll
        for (int i = 0; i < 4; i++) {
            int idx = tid + i*512, row = idx >> 3, c4 = idx & 7;
            pa[i] = *(const float4*)&A[(size_t)(m0+row)*K + c4*4];
        }
    }
    {
        int row = tid >> 2, q = tid & 3;
        pbh = *(const uint4*)&Bh[(size_t)(n0+row)*K + q*8];
        pbl = *(const uint4*)&Bl[(size_t)(n0+row)*K + q*8];
    }

    int nt = K / 32;
    for (int t = 0; t < nt; t++) {
        __syncthreads();
        if (ABF16) {
            #pragma unroll
            for (int i = 0; i < 2; i++) {
                int idx = tid + i*512, row = idx >> 2, q = idx & 3;
                *(uint4*)&sAh[row*LD + q*8] = pah[i];
                *(uint4*)&sAl[row*LD + q*8] = pal[i];
            }
        } else {
            #pragma unroll
            for (int i = 0; i < 4; i++) {
                int idx = tid + i*512, row = idx >> 3, c = (idx & 7)*4;
                float4 v = pa[i];
                __nv_bfloat16 h0 = __float2bfloat16(v.x), h1 = __float2bfloat16(v.y);
                __nv_bfloat16 h2 = __float2bfloat16(v.z), h3 = __float2bfloat16(v.w);
                __nv_bfloat162 hh0; hh0.x = h0; hh0.y = h1;
                __nv_bfloat162 hh1; hh1.x = h2; hh1.y = h3;
                *(__nv_bfloat162*)&sAh[row*LD + c]     = hh0;
                *(__nv_bfloat162*)&sAh[row*LD + c + 2] = hh1;
                __nv_bfloat162 ll0, ll1;
                ll0.x = __float2bfloat16(v.x - __bfloat162float(h0));
                ll0.y = __float2bfloat16(v.y - __bfloat162float(h1));
                ll1.x = __float2bfloat16(v.z - __bfloat162float(h2));
                ll1.y = __float2bfloat16(v.w - __bfloat162float(h3));
                *(__nv_bfloat162*)&sAl[row*LD + c]     = ll0;
                *(__nv_bfloat162*)&sAl[row*LD + c + 2] = ll1;
            }
        }
        {
            int row = tid >> 2, q = tid & 3;
            *(uint4*)&sBh[row*LD + q*8] = pbh;
            *(uint4*)&sBl[row*LD + q*8] = pbl;
        }
        __syncthreads();
        if (t + 1 < nt) {
            int kc = (t+1)*32;
            if (ABF16) {
                #pragma unroll
                for (int i = 0; i < 2; i++) {
                    int idx = tid + i*512, row = idx >> 2, q = idx & 3;
                    pah[i] = *(const uint4*)&Agh[(size_t)(m0+row)*K + kc + q*8];
                    pal[i] = *(const uint4*)&Agl[(size_t)(m0+row)*K + kc + q*8];
                }
            } else {
                #pragma unroll
                for (int i = 0; i < 4; i++) {
                    int idx = tid + i*512, row = idx >> 3, c4 = idx & 7;
                    pa[i] = *(const float4*)&A[(size_t)(m0+row)*K + kc + c4*4];
                }
            }
            {
                int row = tid >> 2, q = tid & 3;
                pbh = *(const uint4*)&Bh[(size_t)(n0+row)*K + kc + q*8];
                pbl = *(const uint4*)&Bl[(size_t)(n0+row)*K + kc + q*8];
            }
        }
        mma_chunk(acc, sAh, sAl, sBh, sBl, lane, warpM, warpN);
    }

    #pragma unroll
    for (int mi = 0; mi < 2; mi++) {
        #pragma unroll
        for (int nj = 0; nj < 8; nj++) {
            int r0  = m0 + warpM + mi*16 + (lane >> 2);
            int col = n0 + warpN + nj*8 + (lane & 3)*2;
            float v0 = acc[mi][nj][0], v1 = acc[mi][nj][1];
            float v2 = acc[mi][nj][2], v3 = acc[mi][nj][3];
            if (EPI == 2 || EPI == 3) {
                v0 = fmaxf(v0, 0.f); v1 = fmaxf(v1, 0.f);
                v2 = fmaxf(v2, 0.f); v3 = fmaxf(v3, 0.f);
            }
            if (EPI == 0 || EPI == 3) {
                float2 o0; o0.x = v0; o0.y = v1;
                float2 o1; o1.x = v2; o1.y = v3;
                *(float2*)&C[(size_t)r0*N + col]     = o0;
                *(float2*)&C[(size_t)(r0+8)*N + col] = o1;
            }
            if (EPI == 2) {
                __nv_bfloat162 hh0, hh1, ll0, ll1;
                hh0.x = __float2bfloat16(v0); hh0.y = __float2bfloat16(v1);
                hh1.x = __float2bfloat16(v2); hh1.y = __float2bfloat16(v3);
                ll0.x = __float2bfloat16(v0 - __bfloat162float(hh0.x));
                ll0.y = __float2bfloat16(v1 - __bfloat162float(hh0.y));
                ll1.x = __float2bfloat16(v2 - __bfloat162float(hh1.x));
                ll1.y = __float2bfloat16(v3 - __bfloat162float(hh1.y));
                *(__nv_bfloat162*)&Hh[(size_t)r0*N + col]     = hh0;
                *(__nv_bfloat162*)&Hh[(size_t)(r0+8)*N + col] = hh1;
                *(__nv_bfloat162*)&Hl[(size_t)r0*N + col]     = ll0;
                *(__nv_bfloat162*)&Hl[(size_t)(r0+8)*N + col] = ll1;
            }
        }
    }
}

// ---------------- fused layer tail: WO + res + LN + FF + (next QKV) ---------
// x += o@Wo; LN -> h'; x += relu(h'@W1)@W2; if !LAST: LN -> h'' -> qkv.
template<bool LAST>
__global__ void __launch_bounds__(256)
layer_fused(const float* __restrict__ oin,
            const __nv_bfloat16* __restrict__ Woh, const __nv_bfloat16* __restrict__ Wol,
            const __nv_bfloat16* __restrict__ B1h, const __nv_bfloat16* __restrict__ B1l,
            const __nv_bfloat16* __restrict__ B2h, const __nv_bfloat16* __restrict__ B2l,
            const __nv_bfloat16* __restrict__ Qwh, const __nv_bfloat16* __restrict__ Qwl,
            float* __restrict__ X, float* __restrict__ qkvout)
{
    constexpr int LD = 40;
    constexpr int CH = 128*LD;
    extern __shared__ __nv_bfloat16 dyns[];
    __nv_bfloat16* sAh = dyns;
    __nv_bfloat16* sAl = sAh + 4*CH;
    __nv_bfloat16* sFh = sAl + 4*CH;
    __nv_bfloat16* sFl = sFh + 4*CH;
    __nv_bfloat16* sBh = sFl + 4*CH;
    __nv_bfloat16* sBl = sBh + CH;
    __shared__ float2 ssum[128][2];

    int tid = threadIdx.x, lane = tid & 31, warp = tid >> 5;
    int m0 = blockIdx.x*128;
    int warpM = (warp >> 1)*32, warpN = (warp & 1)*64;
    int brow = tid >> 2, bq = tid & 3;    // brow in [0,64)

    uint4 pbh[2], pbl[2];   // shared B prefetch regs across stages

    // LN helper (2-way N partials), writes mean/rsig
    auto ln_stats = [&](float acc[2][8][4], float* mean, float* rsig) {
        float s[4] = {}, s2[4] = {};
        #pragma unroll
        for (int mi = 0; mi < 2; mi++)
            #pragma unroll
            for (int nj = 0; nj < 8; nj++) {
                float v0 = acc[mi][nj][0], v1 = acc[mi][nj][1];
                float v2 = acc[mi][nj][2], v3 = acc[mi][nj][3];
                s[mi*2]    += v0 + v1;      s2[mi*2]   += v0*v0 + v1*v1;
                s[mi*2+1]  += v2 + v3;      s2[mi*2+1] += v2*v2 + v3*v3;
            }
        #pragma unroll
        for (int off = 1; off <= 2; off <<= 1)
            #pragma unroll
            for (int r = 0; r < 4; r++) {
                s[r]  += __shfl_xor_sync(~0u, s[r],  off);
                s2[r] += __shfl_xor_sync(~0u, s2[r], off);
            }
        __syncthreads();
        if ((lane & 3) == 0) {
            #pragma unroll
            for (int slot = 0; slot < 4; slot++) {
                int row = warpM + (slot >> 1)*16 + (lane >> 2) + 8*(slot & 1);
                ssum[row][warp & 1] = make_float2(s[slot], s2[slot]);
            }
        }
        __syncthreads();
        #pragma unroll
        for (int slot = 0; slot < 4; slot++) {
            int row = warpM + (slot >> 1)*16 + (lane >> 2) + 8*(slot & 1);
            float2 a = ssum[row][0], b = ssum[row][1];
            float m  = (a.x + b.x) * (1.f/128.f);
            float vv = (a.y + b.y) * (1.f/128.f) - m*m;
            mean[slot] = m;
            rsig[slot] = rsqrtf(vv + 1e-5f);
        }
    };

    // ---- stage W: load o -> split into sF; x_mid = x + o@Wo; LN -> h' in sA
    {
        #pragma unroll
        for (int i = 0; i < 16; i++) {
            int idx = tid + i*256;
            int row = idx >> 5, q = idx & 31;          // q = float4 index in row
            float4 v = *(const float4*)&oin[(size_t)(m0+row)*128 + q*4];
            int off = (q >> 3)*CH + row*LD + (q & 7)*4;
            __nv_bfloat162 h0, h1, l0, l1;
            h0.x = __float2bfloat16(v.x); h0.y = __float2bfloat16(v.y);
            h1.x = __float2bfloat16(v.z); h1.y = __float2bfloat16(v.w);
            l0.x = __float2bfloat16(v.x - __bfloat162float(h0.x));
            l0.y = __float2bfloat16(v.y - __bfloat162float(h0.y));
            l1.x = __float2bfloat16(v.z - __bfloat162float(h1.x));
            l1.y = __float2bfloat16(v.w - __bfloat162float(h1.y));
            *(__nv_bfloat162*)&sFh[off]     = h0;
            *(__nv_bfloat162*)&sFh[off + 2] = h1;
            *(__nv_bfloat162*)&sFl[off]     = l0;
            *(__nv_bfloat162*)&sFl[off + 2] = l1;
        }
        pbh[0] = *(const uint4*)&Woh[(size_t)brow*128 + bq*8];
        pbh[1] = *(const uint4*)&Woh[(size_t)(brow+64)*128 + bq*8];
        pbl[0] = *(const uint4*)&Wol[(size_t)brow*128 + bq*8];
        pbl[1] = *(const uint4*)&Wol[(size_t)(brow+64)*128 + bq*8];

        float accW[2][8][4] = {};
        #pragma unroll
        for (int t = 0; t < 4; t++) {
            __syncthreads();
            *(uint4*)&sBh[brow*LD + bq*8]      = pbh[0];
            *(uint4*)&sBh[(brow+64)*LD + bq*8] = pbh[1];
            *(uint4*)&sBl[brow*LD + bq*8]      = pbl[0];
            *(uint4*)&sBl[(brow+64)*LD + bq*8] = pbl[1];
            __syncthreads();
            if (t + 1 < 4) {
                int kc = (t+1)*32;
                pbh[0] = *(const uint4*)&Woh[(size_t)brow*128 + kc + bq*8];
                pbh[1] = *(const uint4*)&Woh[(size_t)(brow+64)*128 + kc + bq*8];
                pbl[0] = *(const uint4*)&Wol[(size_t)brow*128 + kc + bq*8];
                pbl[1] = *(const uint4*)&Wol[(size_t)(brow+64)*128 + kc + bq*8];
            } else {
                // prefetch first FF1 tile
                pbh[0] = *(const uint4*)&B1h[(size_t)brow*128 + bq*8];
                pbh[1] = *(const uint4*)&B1h[(size_t)(brow+64)*128 + bq*8];
                pbl[0] = *(const uint4*)&B1l[(size_t)brow*128 + bq*8];
                pbl[1] = *(const uint4*)&B1l[(size_t)(brow+64)*128 + bq*8];
            }
            mma_chunk(accW, sFh + t*CH, sFl + t*CH, sBh, sBl, lane, warpM, warpN);
        }
        // residual x_old
        #pragma unroll
        for (int mi = 0; mi < 2; mi++) {
            #pragma unroll
            for (int nj = 0; nj < 8; nj++) {
                int r0  = m0 + warpM + mi*16 + (lane >> 2);
                int col = warpN + nj*8 + (lane & 3)*2;
                float2 c0 = *(const float2*)&X[(size_t)r0*128 + col];
                float2 c1 = *(const float2*)&X[(size_t)(r0+8)*128 + col];
                accW[mi][nj][0] += c0.x; accW[mi][nj][1] += c0.y;
                accW[mi][nj][2] += c1.x; accW[mi][nj][3] += c1.y;
            }
        }
        float mean[4], rsig[4];
        ln_stats(accW, mean, rsig);
        // write x_mid to X and h' split into sA
        #pragma unroll
        for (int mi = 0; mi < 2; mi++) {
            #pragma unroll
            for (int nj = 0; nj < 8; nj++) {
                int r   = warpM + mi*16 + (lane >> 2);
                int col = warpN + nj*8 + (lane & 3)*2;
                int r0  = m0 + r;
                float v0 = accW[mi][nj][0], v1 = accW[mi][nj][1];
                float v2 = accW[mi][nj][2], v3 = accW[mi][nj][3];
                float2 o0; o0.x = v0; o0.y = v1;
                float2 o1; o1.x = v2; o1.y = v3;
                *(float2*)&X[(size_t)r0*128 + col]     = o0;
                *(float2*)&X[(size_t)(r0+8)*128 + col] = o1;
                v0 = (v0 - mean[mi*2])*rsig[mi*2];
                v1 = (v1 - mean[mi*2])*rsig[mi*2];
                v2 = (v2 - mean[mi*2+1])*rsig[mi*2+1];
                v3 = (v3 - mean[mi*2+1])*rsig[mi*2+1];
                int off = (col >> 5)*CH + (col & 31);
                __nv_bfloat162 h0, h1, l0, l1;
                h0.x = __float2bfloat16(v0); h0.y = __float2bfloat16(v1);
                h1.x = __float2bfloat16(v2); h1.y = __float2bfloat16(v3);
                l0.x = __float2bfloat16(v0 - __bfloat162float(h0.x));
                l0.y = __float2bfloat16(v1 - __bfloat162float(h0.y));
                l1.x = __float2bfloat16(v2 - __bfloat162float(h1.x));
                l1.y = __float2bfloat16(v3 - __bfloat162float(h1.y));
                *(__nv_bfloat162*)&sAh[off + r*LD]     = h0;
                *(__nv_bfloat162*)&sAh[off + (r+8)*LD] = h1;
                *(__nv_bfloat162*)&sAl[off + r*LD]     = l0;
                *(__nv_bfloat162*)&sAl[off + (r+8)*LD] = l1;
            }
        }
    }

    // ---- FF stages (B stream index i over 32 tiles; pbh holds tile 0) ----
    auto bptr = [&](int i, int row, const __nv_bfloat16* b1, const __nv_bfloat16* b2)
        -> const __nv_bfloat16* {
        int c = i >> 3, t = i & 3;
        if (((i >> 2) & 1) == 0)
            return &b1[(size_t)(c*128 + row)*128 + t*32 + bq*8];
        else
            return &b2[(size_t)row*512 + c*128 + t*32 + bq*8];
    };

    float acc2[2][8][4] = {};
    #pragma unroll 1
    for (int c = 0; c < 4; c++) {
        float acc1[2][8][4] = {};
        #pragma unroll
        for (int t = 0; t < 4; t++) {
            __syncthreads();
            *(uint4*)&sBh[brow*LD + bq*8]      = pbh[0];
            *(uint4*)&sBh[(brow+64)*LD + bq*8] = pbh[1];
            *(uint4*)&sBl[brow*LD + bq*8]      = pbl[0];
            *(uint4*)&sBl[(brow+64)*LD + bq*8] = pbl[1];
            __syncthreads();
            int ni = c*8 + t + 1;
            pbh[0] = *(const uint4*)bptr(ni, brow,    B1h, B2h);
            pbh[1] = *(const uint4*)bptr(ni, brow+64, B1h, B2h);
            pbl[0] = *(const uint4*)bptr(ni, brow,    B1l, B2l);
            pbl[1] = *(const uint4*)bptr(ni, brow+64, B1l, B2l);
            mma_chunk(acc1, sAh + t*CH, sAl + t*CH, sBh, sBl, lane, warpM, warpN);
        }
        #pragma unroll
        for (int mi = 0; mi < 2; mi++) {
            #pragma unroll
            for (int nj = 0; nj < 8; nj++) {
                int r   = warpM + mi*16 + (lane >> 2);
                int col = warpN + nj*8 + (lane & 3)*2;
                int off = (col >> 5)*CH + (col & 31);
                float v0 = fmaxf(acc1[mi][nj][0], 0.f), v1 = fmaxf(acc1[mi][nj][1], 0.f);
                float v2 = fmaxf(acc1[mi][nj][2], 0.f), v3 = fmaxf(acc1[mi][nj][3], 0.f);
                __nv_bfloat162 h0, h1, l0, l1;
                h0.x = __float2bfloat16(v0); h0.y = __float2bfloat16(v1);
                h1.x = __float2bfloat16(v2); h1.y = __float2bfloat16(v3);
                l0.x = __float2bfloat16(v0 - __bfloat162float(h0.x));
                l0.y = __float2bfloat16(v1 - __bfloat162float(h0.y));
                l1.x = __float2bfloat16(v2 - __bfloat162float(h1.x));
                l1.y = __float2bfloat16(v3 - __bfloat162float(h1.y));
                *(__nv_bfloat162*)&sFh[off + r*LD]     = h0;
                *(__nv_bfloat162*)&sFh[off + (r+8)*LD] = h1;
                *(__nv_bfloat162*)&sFl[off + r*LD]     = l0;
                *(__nv_bfloat162*)&sFl[off + (r+8)*LD] = l1;
            }
        }
        #pragma unroll
        for (int t = 0; t < 4; t++) {
            __syncthreads();
            *(uint4*)&sBh[brow*LD + bq*8]      = pbh[0];
            *(uint4*)&sBh[(brow+64)*LD + bq*8] = pbh[1];
            *(uint4*)&sBl[brow*LD + bq*8]      = pbl[0];
            *(uint4*)&sBl[(brow+64)*LD + bq*8] = pbl[1];
            __syncthreads();
            int ni = c*8 + t + 5;
            if (ni < 32) {
                pbh[0] = *(const uint4*)bptr(ni, brow,    B1h, B2h);
                pbh[1] = *(const uint4*)bptr(ni, brow+64, B1h, B2h);
                pbl[0] = *(const uint4*)bptr(ni, brow,    B1l, B2l);
                pbl[1] = *(const uint4*)bptr(ni, brow+64, B1l, B2l);
            } else if (!LAST) {
                pbh[0] = *(const uint4*)&Qwh[(size_t)brow*128 + bq*8];
                pbh[1] = *(const uint4*)&Qwh[(size_t)(brow+64)*128 + bq*8];
                pbl[0] = *(const uint4*)&Qwl[(size_t)brow*128 + bq*8];
                pbl[1] = *(const uint4*)&Qwl[(size_t)(brow+64)*128 + bq*8];
            }
            mma_chunk(acc2, sFh + t*CH, sFl + t*CH, sBh, sBl, lane, warpM, warpN);
        }
    }

    // residual (x_mid from X, same thread wrote it)
    #pragma unroll
    for (int mi = 0; mi < 2; mi++) {
        #pragma unroll
        for (int nj = 0; nj < 8; nj++) {
            int r0  = m0 + warpM + mi*16 + (lane >> 2);
            int col = warpN + nj*8 + (lane & 3)*2;
            float2 c0 = *(const float2*)&X[(size_t)r0*128 + col];
            float2 c1 = *(const float2*)&X[(size_t)(r0+8)*128 + col];
            acc2[mi][nj][0] += c0.x; acc2[mi][nj][1] += c0.y;
            acc2[mi][nj][2] += c1.x; acc2[mi][nj][3] += c1.y;
        }
    }

    float mean[4], rsig[4];
    if (!LAST) ln_stats(acc2, mean, rsig);

    #pragma unroll
    for (int mi = 0; mi < 2; mi++) {
        #pragma unroll
        for (int nj = 0; nj < 8; nj++) {
            int r   = warpM + mi*16 + (lane >> 2);
            int col = warpN + nj*8 + (lane & 3)*2;
            int r0  = m0 + r;
            float v0 = acc2[mi][nj][0], v1 = acc2[mi][nj][1];
            float v2 = acc2[mi][nj][2], v3 = acc2[mi][nj][3];
            float2 o0; o0.x = v0; o0.y = v1;
            float2 o1; o1.x = v2; o1.y = v3;
            *(float2*)&X[(size_t)r0*128 + col]     = o0;
            *(float2*)&X[(size_t)(r0+8)*128 + col] = o1;
            if (!LAST) {
                v0 = (v0 - mean[mi*2])*rsig[mi*2];
                v1 = (v1 - mean[mi*2])*rsig[mi*2];
                v2 = (v2 - mean[mi*2+1])*rsig[mi*2+1];
                v3 = (v3 - mean[mi*2+1])*rsig[mi*2+1];
                int off = (col >> 5)*CH + (col & 31);
                __nv_bfloat162 h0, h1, l0, l1;
                h0.x = __float2bfloat16(v0); h0.y = __float2bfloat16(v1);
                h1.x = __float2bfloat16(v2); h1.y = __float2bfloat16(v3);
                l0.x = __float2bfloat16(v0 - __bfloat162float(h0.x));
                l0.y = __float2bfloat16(v1 - __bfloat162float(h0.y));
                l1.x = __float2bfloat16(v2 - __bfloat162float(h1.x));
                l1.y = __float2bfloat16(v3 - __bfloat162float(h1.y));
                *(__nv_bfloat162*)&sAh[off + r*LD]     = h0;
                *(__nv_bfloat162*)&sAh[off + (r+8)*LD] = h1;
                *(__nv_bfloat162*)&sAl[off + r*LD]     = l0;
                *(__nv_bfloat162*)&sAl[off + (r+8)*LD] = l1;
            }
        }
    }

    if (!LAST) {
        // qkv[128 x 384] = h'' @ Wqkv  (3 N-blocks x 4 k-chunks, streamed B)
        #pragma unroll 1
        for (int nb = 0; nb < 3; nb++) {
            float acc[2][8][4] = {};
            #pragma unroll
            for (int t = 0; t < 4; t++) {
                __syncthreads();
                *(uint4*)&sBh[brow*LD + bq*8]      = pbh[0];
                *(uint4*)&sBh[(brow+64)*LD + bq*8] = pbh[1];
                *(uint4*)&sBl[brow*LD + bq*8]      = pbl[0];
                *(uint4*)&sBl[(brow+64)*LD + bq*8] = pbl[1];
                __syncthreads();
                int ni = nb*4 + t + 1;
                if (ni < 12) {
                    int nrow = (ni >> 2)*128, kc = (ni & 3)*32;
                    pbh[0] = *(const uint4*)&Qwh[(size_t)(nrow + brow)*128 + kc + bq*8];
                    pbh[1] = *(const uint4*)&Qwh[(size_t)(nrow + brow+64)*128 + kc + bq*8];
                    pbl[0] = *(const uint4*)&Qwl[(size_t)(nrow + brow)*128 + kc + bq*8];
                    pbl[1] = *(const uint4*)&Qwl[(size_t)(nrow + brow+64)*128 + kc + bq*8];
                }
                mma_chunk(acc, sAh + t*CH, sAl + t*CH, sBh, sBl, lane, warpM, warpN);
            }
            #pragma unroll
            for (int mi = 0; mi < 2; mi++) {
                #pragma unroll
                for (int nj = 0; nj < 8; nj++) {
                    int r0  = m0 + warpM + mi*16 + (lane >> 2);
                    int col = nb*128 + warpN + nj*8 + (lane & 3)*2;
                    float2 o0; o0.x = acc[mi][nj][0]; o0.y = acc[mi][nj][1];
                    float2 o1; o1.x = acc[mi][nj][2]; o1.y = acc[mi][nj][3];
                    *(float2*)&qkvout[(size_t)r0*384 + col]     = o0;
                    *(float2*)&qkvout[(size_t)(r0+8)*384 + col] = o1;
                }
            }
        }
    }
}

// ---------------- small SIMT GEMM (only for N=32 outer projection) ----------
template<int BN, bool RELU_A, bool RELU_C, bool ACC>
__global__ void __launch_bounds__(256)
sgemm_kernel(const float* __restrict__ A, const float* __restrict__ Bm,
             const float* __restrict__ Cin, float* __restrict__ C,
             int M, int N, int K)
{
    constexpr int BM = 128, BK = 16;
    constexpr int TN = BN/16;
    constexpr int BSLOT = (BK*BN)/(4*256);
    __shared__ float As[BK][BM];
    __shared__ float Bs[BK][BN];
    int tid = threadIdx.x;
    int m0 = blockIdx.y*BM, n0 = blockIdx.x*BN;
    int ty = tid >> 4, tx = tid & 15;

    float4 areg[2], breg[BSLOT];
    #pragma unroll
    for (int i = 0; i < 2; i++) {
        int s = tid + i*256, m = s >> 2, kv = s & 3;
        float4 v = *(const float4*)&A[(size_t)(m0+m)*K + kv*4];
        if (RELU_A) { v.x=fmaxf(v.x,0.f); v.y=fmaxf(v.y,0.f); v.z=fmaxf(v.z,0.f); v.w=fmaxf(v.w,0.f); }
        areg[i] = v;
    }
    #pragma unroll
    for (int i = 0; i < BSLOT; i++) {
        int s = tid + i*256, r = s/(BN/4), nv = s%(BN/4);
        int gn = n0 + nv*4;
        breg[i] = (gn < N) ? *(const float4*)&Bm[(size_t)r*N + gn] : make_float4(0,0,0,0);
    }
    float acc[8][TN];
    #pragma unroll
    for (int i = 0; i < 8; i++)
        #pragma unroll
        for (int j = 0; j < TN; j++) acc[i][j] = 0.f;

    int ntiles = K / BK;
    for (int t = 0; t < ntiles; t++) {
        __syncthreads();
        #pragma unroll
        for (int i = 0; i < 2; i++) {
            int s = tid + i*256, m = s >> 2, kv = s & 3;
            As[kv*4+0][m] = areg[i].x; As[kv*4+1][m] = areg[i].y;
            As[kv*4+2][m] = areg[i].z; As[kv*4+3][m] = areg[i].w;
        }
        #pragma unroll
        for (int i = 0; i < BSLOT; i++) {
            int s = tid + i*256, r = s/(BN/4), nv = s%(BN/4);
            *(float4*)&Bs[r][nv*4] = breg[i];
        }
        __syncthreads();
        if (t+1 < ntiles) {
            int kt = (t+1)*BK;
            #pragma unroll
            for (int i = 0; i < 2; i++) {
                int s = tid + i*256, m = s >> 2, kv = s & 3;
                float4 v = *(const float4*)&A[(size_t)(m0+m)*K + kt + kv*4];
                if (RELU_A) { v.x=fmaxf(v.x,0.f); v.y=fmaxf(v.y,0.f); v.z=fmaxf(v.z,0.f); v.w=fmaxf(v.w,0.f); }
                areg[i] = v;
            }
            #pragma unroll
            for (int i = 0; i < BSLOT; i++) {
                int s = tid + i*256, r = s/(BN/4), nv = s%(BN/4);
                int gn = n0 + nv*4;
                breg[i] = (gn < N) ? *(const float4*)&Bm[(size_t)(kt+r)*N + gn] : make_float4(0,0,0,0);
            }
        }
        #pragma unroll
        for (int k = 0; k < BK; k++) {
            float a[8], bb[TN];
            *(float4*)&a[0] = *(const float4*)&As[k][ty*8];
            *(float4*)&a[4] = *(const float4*)&As[k][ty*8+4];
            #pragma unroll
            for (int j = 0; j < TN/4; j++)
                *(float4*)&bb[j*4] = *(const float4*)&Bs[k][tx*TN + j*4];
            #pragma unroll
            for (int i = 0; i < 8; i++)
                #pragma unroll
                for (int j = 0; j < TN; j++) acc[i][j] += a[i]*bb[j];
        }
    }
    #pragma unroll
    for (int i = 0; i < 8; i++) {
        int gm = m0 + ty*8 + i;
        #pragma unroll
        for (int j = 0; j < TN; j++) {
            int gn = n0 + tx*TN + j;
            if (gn < N) {
                float v = acc[i][j];
                if (ACC) v += Cin[(size_t)gm*N + gn];
                if (RELU_C) v = fmaxf(v, 0.f);
                C[(size_t)gm*N + gn] = v;
            }
        }
    }
}

// ---------------- fused pair-feature -> LN -> FF -> head bias ---------------
__global__ void __launch_bounds__(256)
bias_kernel(const float* __restrict__ pos, const int* __restrict__ uid,
            const float* __restrict__ Wp, const float* __restrict__ W1,
            const float* __restrict__ W2, const float* __restrict__ Wb)
{
    __shared__ float sposi[32][3], sposj[KWIN][3];
    __shared__ int   suidi[32],    suidj[KWIN];
    __shared__ float4 spi4[32][4], spj4[KWIN][4];
    __shared__ float sWp[80], sWb[64];
    __shared__ float4 sW1T[64][4];
    __shared__ float4 sW2b[64];
    __shared__ unsigned char svalid[KWIN];

    int bb = blockIdx.x;
    int half = bb & 1;
    int bw = bb >> 1;
    int b = bw / NW, w = bw % NW;
    int q0 = half*32;
    int tid = threadIdx.x;

    for (int i = tid; i < 80; i += 256) sWp[i] = Wp[i];
    for (int i = tid; i < 64; i += 256) sWb[i] = Wb[i];
    for (int i = tid; i < 1024; i += 256) {
        int j = i >> 4, c = i & 15;
        ((float*)sW1T)[j*16 + c] = W1[c*64 + j];
    }
    if (tid < 64) {
        float4 r = make_float4(0,0,0,0);
        #pragma unroll
        for (int c = 0; c < 16; c++) {
            float w2v = W2[tid*16 + c];
            r.x += w2v*Wb[c*4+0]; r.y += w2v*Wb[c*4+1];
            r.z += w2v*Wb[c*4+2]; r.w += w2v*Wb[c*4+3];
        }
        sW2b[tid] = r;
    }
    for (int q = tid; q < 32; q += 256) {
        int gi = b*N_ + w*QWIN + q0 + q;
        sposi[q][0] = pos[gi*3]; sposi[q][1] = pos[gi*3+1]; sposi[q][2] = pos[gi*3+2];
        suidi[q] = uid[gi];
        const float4* pp = (const float4*)&g_p[(size_t)gi*32];
        spi4[q][0] = pp[0]; spi4[q][1] = pp[1]; spi4[q][2] = pp[2]; spi4[q][3] = pp[3];
    }
    for (int k = tid; k < KWIN; k += 256) {
        int j = w*QWIN + k - PADW;
        bool valid = (j >= 0 && j < N_);
        svalid[k] = valid;
        if (valid) {
            int gj = b*N_ + j;
            sposj[k][0] = pos[gj*3]; sposj[k][1] = pos[gj*3+1]; sposj[k][2] = pos[gj*3+2];
            suidj[k] = uid[gj];
            const float4* pp = (const float4*)&g_p[(size_t)gj*32 + 16];
            spj4[k][0] = pp[0]; spj4[k][1] = pp[1]; spj4[k][2] = pp[2]; spj4[k][3] = pp[3];
        } else {
            sposj[k][0] = sposj[k][1] = sposj[k][2] = 0.f; suidj[k] = -1;
            float4 z = make_float4(0,0,0,0);
            spj4[k][0] = z; spj4[k][1] = z; spj4[k][2] = z; spj4[k][3] = z;
        }
    }
    __syncthreads();

    float* brow = g_bias + (size_t)bw*HEADS*QWIN*KWIN;

    auto prep = [&](int q, int k, float4* u, float& bh0, float& bh1, float& bh2, float& bh3) {
        float dx = sposi[q][0]-sposj[k][0];
        float dy = sposi[q][1]-sposj[k][1];
        float dz = sposi[q][2]-sposj[k][2];
        float inv = 1.f / (1.f + dx*dx + dy*dy + dz*dz);
        float bij = (suidi[q] == suidj[k]) ? 1.f : 0.f;
        float4 pr[4];
        #pragma unroll
        for (int c4 = 0; c4 < 4; c4++) {
            float4 r;
            #pragma unroll
            for (int e = 0; e < 4; e++) {
                int c = c4*4 + e;
                float base = dx*sWp[c] + dy*sWp[16+c] + dz*sWp[32+c] + inv*sWp[48+c] + sWp[64+c];
                (&r.x)[e] = base*bij + (&spi4[q][c4].x)[e] + (&spj4[k][c4].x)[e];
            }
            pr[c4] = r;
        }
        float s = 0.f, s2 = 0.f;
        #pragma unroll
        for (int c4 = 0; c4 < 4; c4++) {
            s  += pr[c4].x + pr[c4].y + pr[c4].z + pr[c4].w;
            s2 += pr[c4].x*pr[c4].x + pr[c4].y*pr[c4].y + pr[c4].z*pr[c4].z + pr[c4].w*pr[c4].w;
        }
        float mean = s * (1.f/DP);
        float var  = s2 * (1.f/DP) - mean*mean;
        float rinv = rsqrtf(var + 1e-5f);
        bh0 = bh1 = bh2 = bh3 = 0.f;
        #pragma unroll
        for (int c4 = 0; c4 < 4; c4++) {
            #pragma unroll
            for (int e = 0; e < 4; e++) {
                int c = c4*4 + e;
                float pv = (&pr[c4].x)[e];
                bh0 += pv*sWb[c*4+0]; bh1 += pv*sWb[c*4+1];
                bh2 += pv*sWb[c*4+2]; bh3 += pv*sWb[c*4+3];
                (&u[c4].x)[e] = (pv - mean)*rinv;
            }
        }
    };

    for (int t = tid; t < 32*64; t += 256) {
        int q = t >> 6, k0 = t & 63, k1 = k0 + 64;
        int gq = q0 + q;
        float4 u0[4], u1[4];
        float a0,a1,a2,a3, c0,c1,c2,c3;
        prep(q, k0, u0, a0, a1, a2, a3);
        prep(q, k1, u1, c0, c1, c2, c3);
        #pragma unroll 2
        for (int j = 0; j < 64; j++) {
            float4 w0 = sW1T[j][0], w1 = sW1T[j][1], w2 = sW1T[j][2], w3 = sW1T[j][3];
            float t0 = u0[0].x*w0.x + u0[0].y*w0.y + u0[0].z*w0.z + u0[0].w*w0.w
                     + u0[1].x*w1.x + u0[1].y*w1.y + u0[1].z*w1.z + u0[1].w*w1.w
                     + u0[2].x*w2.x + u0[2].y*w2.y + u0[2].z*w2.z + u0[2].w*w2.w
                     + u0[3].x*w3.x + u0[3].y*w3.y + u0[3].z*w3.z + u0[3].w*w3.w;
            float t1 = u1[0].x*w0.x + u1[0].y*w0.y + u1[0].z*w0.z + u1[0].w*w0.w
                     + u1[1].x*w1.x + u1[1].y*w1.y + u1[1].z*w1.z + u1[1].w*w1.w
                     + u1[2].x*w2.x + u1[2].y*w2.y + u1[2].z*w2.z + u1[2].w*w2.w
                     + u1[3].x*w3.x + u1[3].y*w3.y + u1[3].z*w3.z + u1[3].w*w3.w;
            t0 = fmaxf(t0, 0.f); t1 = fmaxf(t1, 0.f);
            float4 wb2 = sW2b[j];
            a0 += t0*wb2.x; a1 += t0*wb2.y; a2 += t0*wb2.z; a3 += t0*wb2.w;
            c0 += t1*wb2.x; c1 += t1*wb2.y; c2 += t1*wb2.z; c3 += t1*wb2.w;
        }
        bool v0 = svalid[k0], v1 = svalid[k1];
        brow[((0*QWIN + gq) << 7) + k0] = v0 ? a0 : 0.f;
        brow[((1*QWIN + gq) << 7) + k0] = v0 ? a1 : 0.f;
        brow[((2*QWIN + gq) << 7) + k0] = v0 ? a2 : 0.f;
        brow[((3*QWIN + gq) << 7) + k0] = v0 ? a3 : 0.f;
        brow[((0*QWIN + gq) << 7) + k1] = v1 ? c0 : 0.f;
        brow[((1*QWIN + gq) << 7) + k1] = v1 ? c1 : 0.f;
        brow[((2*QWIN + gq) << 7) + k1] = v1 ? c2 : 0.f;
        brow[((3*QWIN + gq) << 7) + k1] = v1 ? c3 : 0.f;
    }
}

// ---------------- attention per (b, window, head): lane-parallel -------------
__global__ void attn_kernel(const float* __restrict__ qkv, float* __restrict__ o)
{
    __shared__ float4 ks4[KWIN][8];
    __shared__ float4 vs4[KWIN][8];
    __shared__ float  ps[8][2][KWIN];

    int h  = blockIdx.x & 3;
    int bw = blockIdx.x >> 2;
    int w  = bw & (NW-1);
    int b  = bw >> 7;
    int tid = threadIdx.x, lane = tid & 31, warp = tid >> 5;
    int rowbase = b*N_ + w*QWIN;

    for (int s = tid; s < KWIN*8; s += 256) {
        int kk = s >> 3, i = s & 7;
        int j = w*QWIN + kk - PADW;
        float4 kv = make_float4(0,0,0,0), vv = make_float4(0,0,0,0);
        if (j >= 0 && j < N_) {
            const float* base = &qkv[(size_t)(b*N_ + j)*384 + h*32 + i*4];
            kv = *(const float4*)(base + 128);
            vv = *(const float4*)(base + 256);
        }
        int sw = i ^ (kk & 7);
        ks4[kk][sw] = kv;
        vs4[kk][sw] = vv;
    }
    __syncthreads();

    const float scale = 0.17677669529663687f;
    const float* brow = g_bias + ((size_t)bw*HEADS + h)*QWIN*KWIN;
    int lhi = lane >> 2, llo = lane & 3;

    for (int pass = 0; pass < 4; pass++) {
        int rA = warp*8 + pass*2, rB = rA + 1;
        float4 qa[8], qb[8];
        #pragma unroll
        for (int i = 0; i < 8; i++) {
            qa[i] = *(const float4*)&qkv[(size_t)(rowbase+rA)*384 + h*32 + i*4];
            qb[i] = *(const float4*)&qkv[(size_t)(rowbase+rB)*384 + h*32 + i*4];
        }
        float4 aA[4], aB[4];
        #pragma unroll
        for (int g = 0; g < 4; g++) { aA[g] = make_float4(0,0,0,0); aB[g] = make_float4(0,0,0,0); }
        #pragma unroll
        for (int i = 0; i < 8; i++) {
            #pragma unroll
            for (int g = 0; g < 4; g++) {
                int kk = g*32 + lane;
                float4 kv = ks4[kk][i ^ (kk & 7)];
                aA[g].x += qa[i].x*kv.x; aA[g].y += qa[i].y*kv.y;
                aA[g].z += qa[i].z*kv.z; aA[g].w += qa[i].w*kv.w;
                aB[g].x += qb[i].x*kv.x; aB[g].y += qb[i].y*kv.y;
                aB[g].z += qb[i].z*kv.z; aB[g].w += qb[i].w*kv.w;
            }
        }
        float lA[4], lB[4];
        float mA = -1e30f, mB = -1e30f;
        #pragma unroll
        for (int g = 0; g < 4; g++) {
            int kk = g*32 + lane;
            int j = w*QWIN + kk - PADW;
            float msk = (j >= 0 && j < N_) ? 0.f : -1e9f;
            lA[g] = ((aA[g].x+aA[g].y)+(aA[g].z+aA[g].w))*scale + brow[(rA<<7)+kk] + msk;
            lB[g] = ((aB[g].x+aB[g].y)+(aB[g].z+aB[g].w))*scale + brow[(rB<<7)+kk] + msk;
            mA = fmaxf(mA, lA[g]); mB = fmaxf(mB, lB[g]);
        }
        #pragma unroll
        for (int off = 16; off > 0; off >>= 1) {
            mA = fmaxf(mA, __shfl_xor_sync(~0u, mA, off));
            mB = fmaxf(mB, __shfl_xor_sync(~0u, mB, off));
        }
        float sA = 0.f, sB = 0.f, eA[4], eB[4];
        #pragma unroll
        for (int g = 0; g < 4; g++) {
            eA[g] = __expf(lA[g]-mA); sA += eA[g];
            eB[g] = __expf(lB[g]-mB); sB += eB[g];
        }
        #pragma unroll
        for (int off = 16; off > 0; off >>= 1) {
            sA += __shfl_xor_sync(~0u, sA, off);
            sB += __shfl_xor_sync(~0u, sB, off);
        }
        float rsA = 1.f/sA, rsB = 1.f/sB;
        #pragma unroll
        for (int g = 0; g < 4; g++) {
            ps[warp][0][g*32+lane] = eA[g]*rsA;
            ps[warp][1][g*32+lane] = eB[g]*rsB;
        }
        __syncwarp();
        float oA = 0.f, oB = 0.f;
        #pragma unroll 4
        for (int k4 = 0; k4 < 32; k4++) {
            float4 pA = *(const float4*)&ps[warp][0][k4*4];
            float4 pB = *(const float4*)&ps[warp][1][k4*4];
            #pragma unroll
            for (int t = 0; t < 4; t++) {
                int kk = k4*4 + t;
                float v = ((const float*)&vs4[kk][0])[(((lhi ^ (kk&7))<<2) | llo)];
                oA += (&pA.x)[t]*v;
                oB += (&pB.x)[t]*v;
            }
        }
        o[(size_t)(rowbase+rA)*DS + h*32 + lane] = oA;
        o[(size_t)(rowbase+rB)*DS + h*32 + lane] = oB;
        __syncwarp();
    }
}

// ---------------- deterministic segment mean (indices sorted) ---------------
__global__ void segmean_kernel(const int* __restrict__ a2t, float* __restrict__ out)
{
    int bt = blockIdx.x;
    int b = bt / NTOK, t = bt % NTOK;
    const int* idx = a2t + b*N_;
    __shared__ int slo, shi;
    if (threadIdx.x == 0) {
        int lo = 0, hi = N_;
        while (lo < hi) { int mid = (lo+hi) >> 1; if (idx[mid] < t) lo = mid+1; else hi = mid; }
        slo = lo;
        int lo2 = lo, hi2 = N_;
        while (lo2 < hi2) { int mid = (lo2+hi2) >> 1; if (idx[mid] < t+1) lo2 = mid+1; else hi2 = mid; }
        shi = lo2;
    }
    __syncthreads();
    int lo = slo, hi = shi;
    float rcnt = 1.f / fmaxf((float)(hi - lo), 1.f);
    for (int d = threadIdx.x; d < DT; d += blockDim.x) {
        float ssum = 0.f;
        for (int i = lo; i < hi; i++) ssum += g_tok[((size_t)(b*N_ + i))*DT + d];
        out[(size_t)bt*DT + d] = ssum * rcnt;
    }
}

// ---------------- launch ----------------------------------------------------
extern "C" void kernel_launch(void* const* d_in, const int* in_sizes, int n_in,
                              void* d_out, int out_size)
{
    const float* ref_pos    = (const float*)d_in[0];
    const float* ref_charge = (const float*)d_in[1];
    const float* ref_mask   = (const float*)d_in[2];
    const float* ref_elem   = (const float*)d_in[3];
    const float* ref_chars  = (const float*)d_in[4];
    const float* W_single   = (const float*)d_in[5];
    const float* W_pair     = (const float*)d_in[6];
    const float* W_outer    = (const float*)d_in[7];
    const float* Wp_ff1     = (const float*)d_in[8];
    const float* Wp_ff2     = (const float*)d_in[9];
    const float* Wq         = (const float*)d_in[10];
    const float* Wk         = (const float*)d_in[11];
    const float* Wv         = (const float*)d_in[12];
    const float* Wo         = (const float*)d_in[13];
    const float* Wb         = (const float*)d_in[14];
    const float* Wff1       = (const float*)d_in[15];
    const float* Wff2       = (const float*)d_in[16];
    const float* W_out      = (const float*)d_in[17];
    const int*   uid        = (const int*)d_in[18];
    const int*   a2t        = (const int*)d_in[19];
    float* out = (float*)d_out;

    float *feats, *x, *qkv, *o, *p, *tok;
    __nv_bfloat16 *bh, *bl, *hh, *hl;
    cudaGetSymbolAddress((void**)&feats, g_feats);
    cudaGetSymbolAddress((void**)&x,     g_x);
    cudaGetSymbolAddress((void**)&qkv,   g_qkv);
    cudaGetSymbolAddress((void**)&o,     g_o);
    cudaGetSymbolAddress((void**)&p,     g_p);
    cudaGetSymbolAddress((void**)&tok,   g_tok);
    cudaGetSymbolAddress((void**)&bh,    g_bh);
    cudaGetSymbolAddress((void**)&bl,    g_bl);
    cudaGetSymbolAddress((void**)&hh,    g_hh);
    cudaGetSymbolAddress((void**)&hl,    g_hl);

    const int WIDE_SMEM = (2*256*40 + 2*128*40) * 2;         // 61440 bytes
    const int FF_SMEM   = (4*128*40*4 + 2*128*40) * 2;       // 184320 bytes
    cudaFuncSetAttribute(mma_gemm_wide<true,0>,  cudaFuncAttributeMaxDynamicSharedMemorySize, WIDE_SMEM);
    cudaFuncSetAttribute(mma_gemm_wide<false,3>, cudaFuncAttributeMaxDynamicSharedMemorySize, WIDE_SMEM);
    cudaFuncSetAttribute(layer_fused<false>, cudaFuncAttributeMaxDynamicSharedMemorySize, FF_SMEM);
    cudaFuncSetAttribute(layer_fused<true>,  cudaFuncAttributeMaxDynamicSharedMemorySize, FF_SMEM);

    // 0) pack all weights (one launch)
    pack_all_kernel<<<(PACK_TOT+255)/256, 256>>>(W_single, Wq, Wk, Wv, Wo, Wff1, Wff2, W_out);

    // 1) feats + embed: x = feats @ W_single, fused LN -> h split
    build_feats_kernel<<<R_, 128>>>(ref_pos, ref_charge, ref_mask, ref_elem, ref_chars);
    mma_gemm<false,1,false><<<dim3(1, R_/128), 256>>>(feats, nullptr, nullptr,
        bh+OFF_EMB, bl+OFF_EMB, nullptr, x, hh, hl, R_, DS, KFP);

    // 2) p = relu(s) @ W_outer  (N=32, SIMT)
    sgemm_kernel<64,true,false,false><<<dim3(1, R_/128), 256>>>(x, W_outer, nullptr, p, R_, 2*DP, DS);

    // 3) pair bias
    bias_kernel<<<B_*NW*2, 256>>>(ref_pos, uid, W_pair, Wp_ff1, Wp_ff2, Wb);

    // 4) layer-0 QKV from embed's h, then per layer: attn -> layer_fused
    mma_gemm_wide<true,0><<<dim3(3, R_/256), 512, WIDE_SMEM>>>(nullptr, hh, hl,
        bh+OFF_QKV, bl+OFF_QKV, qkv, nullptr, nullptr, R_, 3*DS, DS);
    for (int l = 0; l < DEPTH; l++) {
        attn_kernel<<<B_*NW*HEADS, 256>>>(qkv, o);
        if (l < DEPTH-1) {
            layer_fused<false><<<R_/128, 256, FF_SMEM>>>(o,
                bh+OFF_WO+(size_t)l*16384, bl+OFF_WO+(size_t)l*16384,
                bh+OFF_FF1+(size_t)l*65536, bl+OFF_FF1+(size_t)l*65536,
                bh+OFF_FF2+(size_t)l*65536, bl+OFF_FF2+(size_t)l*65536,
                bh+OFF_QKV+(size_t)(l+1)*49152, bl+OFF_QKV+(size_t)(l+1)*49152,
                x, qkv);
        } else {
            layer_fused<true><<<R_/128, 256, FF_SMEM>>>(o,
                bh+OFF_WO+(size_t)l*16384, bl+OFF_WO+(size_t)l*16384,
                bh+OFF_FF1+(size_t)l*65536, bl+OFF_FF1+(size_t)l*65536,
                bh+OFF_FF2+(size_t)l*65536, bl+OFF_FF2+(size_t)l*65536,
                nullptr, nullptr, x, nullptr);
        }
    }

    // 5) tok = relu(x @ W_out); segment mean -> out
    mma_gemm_wide<false,3><<<dim3(3, R_/256), 512, WIDE_SMEM>>>(x, nullptr, nullptr,
        bh+OFF_WOUT, bl+OFF_WOUT, tok, nullptr, nullptr, R_, DT, DS);
    segmean_kernel<<<B_*NTOK, 384>>>(a2t, out);
}

// round 11
// speedup vs baseline: 1.2269x; 1.0325x over previous
#include <cuda_runtime.h>
#include <cuda_bf16.h>
#include <math.h>

#define B_    2
#define N_    8192
#define R_    (B_*N_)          // 16384 rows
#define DS    128
#define DP    16
#define DT    384
#define NTOK  1024
#define QWIN  64
#define KWIN  128
#define PADW  32
#define NW    (N_/QWIN)        // 128 windows
#define HEADS 4
#define DH    32
#define DEPTH 3
#define KFEAT 389
#define KFP   416              // padded to multiple of 32

// packed bf16 weight offsets (hi/lo arrays, layout [N][Kp] row-major)
#define OFF_EMB    0           // 128 x 416
#define OFF_QKV    53248       // 3 layers x [Wq|Wk|Wv] 384 x 128
#define OFF_WO     200704      // 3 x 128 x 128
#define OFF_FF1    249856      // 3 x 512 x 128
#define OFF_FF2    446464      // 3 x 128 x 512
#define OFF_WOUT   643072      // 384 x 128
#define OFF_WOUTER 692224      // 128(pad from 32) x 128
#define PACK_TOT   708608

// ---------------- scratch (device globals: allocation-free) ----------------
__device__ float g_feats[(size_t)R_*KFP];
__device__ float g_x    [(size_t)R_*DS];
__device__ float g_qkv  [(size_t)R_*3*DS];
__device__ float g_o    [(size_t)R_*DS];
__device__ float g_p    [(size_t)R_*2*DP];
__device__ float g_bias [(size_t)B_*NW*HEADS*QWIN*KWIN];
__device__ float g_tok  [(size_t)R_*DT];
__device__ __nv_bfloat16 g_bh[PACK_TOT];
__device__ __nv_bfloat16 g_bl[PACK_TOT];

// ---------------- prep: weight pack (transpose + hi/lo split) + feats build -
__global__ void prep_kernel(const float* __restrict__ Ws, const float* __restrict__ Wq,
                            const float* __restrict__ Wk, const float* __restrict__ Wv,
                            const float* __restrict__ Wo, const float* __restrict__ W1,
                            const float* __restrict__ W2, const float* __restrict__ Wout,
                            const float* __restrict__ Wouter,
                            const float* __restrict__ pos, const float* __restrict__ charge,
                            const float* __restrict__ mask, const float* __restrict__ elem,
                            const float* __restrict__ chars)
{
    const int PB = (PACK_TOT + 255)/256;
    if ((int)blockIdx.x >= PB) {
        int row = blockIdx.x - PB;
        float* fr = g_feats + (size_t)row*KFP;
        for (int f = threadIdx.x; f < KFP; f += 256) {
            float v;
            if      (f < 3)    v = pos[row*3 + f];
            else if (f == 3)   v = charge[row];
            else if (f == 4)   v = mask[row];
            else if (f < 133)  v = elem[(size_t)row*128 + (f-5)];
            else if (f < KFEAT)v = chars[(size_t)row*256 + (f-133)];
            else               v = 0.f;
            fr[f] = v;
        }
        return;
    }
    long idx = (long)blockIdx.x*256 + threadIdx.x;
    if (idx >= PACK_TOT) return;
    float v;
    if (idx >= OFF_WOUTER) {
        long rem = idx - OFF_WOUTER;
        int n = (int)(rem / 128), k = (int)(rem % 128);
        v = (n < 32) ? Wouter[(size_t)k*32 + n] : 0.f;
    } else {
        const float* src; int K, N, Kp; long rem;
        if (idx < OFF_QKV)      { src = Ws;  K = KFEAT; N = 128; Kp = KFP; rem = idx; }
        else if (idx < OFF_WO)  { long r = idx - OFF_QKV; int l = (int)(r/49152); r %= 49152;
                                  int ws = (int)(r/16384); rem = r % 16384;
                                  src = (ws==0 ? Wq : ws==1 ? Wk : Wv) + (size_t)l*16384;
                                  K = 128; N = 128; Kp = 128; }
        else if (idx < OFF_FF1) { long r = idx - OFF_WO; int l = (int)(r/16384); rem = r % 16384;
                                  src = Wo + (size_t)l*16384; K = 128; N = 128; Kp = 128; }
        else if (idx < OFF_FF2) { long r = idx - OFF_FF1; int l = (int)(r/65536); rem = r % 65536;
                                  src = W1 + (size_t)l*65536; K = 128; N = 512; Kp = 128; }
        else if (idx < OFF_WOUT){ long r = idx - OFF_FF2; int l = (int)(r/65536); rem = r % 65536;
                                  src = W2 + (size_t)l*65536; K = 512; N = 128; Kp = 512; }
        else                    { rem = idx - OFF_WOUT; src = Wout; K = 128; N = 384; Kp = 128; }
        int n = (int)(rem / Kp), k = (int)(rem % Kp);
        v = (k < K) ? src[(size_t)k*N + n] : 0.f;
    }
    __nv_bfloat16 h = __float2bfloat16(v);
    g_bh[idx] = h;
    g_bl[idx] = __float2bfloat16(v - __bfloat162float(h));
}

// ---------------- mma helpers ------------------------------------------------
__device__ __forceinline__ void ldsm4(unsigned &r0, unsigned &r1, unsigned &r2, unsigned &r3,
                                      const __nv_bfloat16* p)
{
    unsigned a = (unsigned)__cvta_generic_to_shared(p);
    asm volatile("ldmatrix.sync.aligned.m8n8.x4.shared.b16 {%0,%1,%2,%3},[%4];"
                 : "=r"(r0), "=r"(r1), "=r"(r2), "=r"(r3) : "r"(a));
}
__device__ __forceinline__ void mma16816(float* d, const unsigned* a, unsigned b0, unsigned b1)
{
    asm volatile("mma.sync.aligned.m16n8k16.row.col.f32.bf16.bf16.f32 "
                 "{%0,%1,%2,%3},{%4,%5,%6,%7},{%8,%9},{%0,%1,%2,%3};"
                 : "+f"(d[0]), "+f"(d[1]), "+f"(d[2]), "+f"(d[3])
                 : "r"(a[0]), "r"(a[1]), "r"(a[2]), "r"(a[3]), "r"(b0), "r"(b1));
}

// shared 32-k-step mma over one A chunk + one B tile (both bf16-split, LD=40)
__device__ __forceinline__ void mma_chunk(float acc[2][8][4],
    const __nv_bfloat16* sXh, const __nv_bfloat16* sXl,
    const __nv_bfloat16* sBh, const __nv_bfloat16* sBl,
    int lane, int warpM, int warpN)
{
    constexpr int LD = 40;
    #pragma unroll
    for (int ks = 0; ks < 2; ks++) {
        int rowin = lane & 7, tile = lane >> 3;
        unsigned ah[2][4], al[2][4];
        #pragma unroll
        for (int mi = 0; mi < 2; mi++) {
            int r = warpM + mi*16 + (tile & 1)*8 + rowin;
            int c = ks*16 + (tile >> 1)*8;
            ldsm4(ah[mi][0], ah[mi][1], ah[mi][2], ah[mi][3], &sXh[r*LD + c]);
            ldsm4(al[mi][0], al[mi][1], al[mi][2], al[mi][3], &sXl[r*LD + c]);
        }
        #pragma unroll
        for (int np = 0; np < 4; np++) {
            int nrow = warpN + np*16 + (tile >> 1)*8 + rowin;
            int c = ks*16 + (tile & 1)*8;
            unsigned bh0, bh1, bh2, bh3, bl0, bl1, bl2, bl3;
            ldsm4(bh0, bh1, bh2, bh3, &sBh[nrow*LD + c]);
            ldsm4(bl0, bl1, bl2, bl3, &sBl[nrow*LD + c]);
            #pragma unroll
            for (int mi = 0; mi < 2; mi++) {
                mma16816(acc[mi][np*2],   ah[mi], bh0, bh1);
                mma16816(acc[mi][np*2],   al[mi], bh0, bh1);
                mma16816(acc[mi][np*2],   ah[mi], bl0, bl1);
                mma16816(acc[mi][np*2+1], ah[mi], bh2, bh3);
                mma16816(acc[mi][np*2+1], al[mi], bh2, bh3);
                mma16816(acc[mi][np*2+1], ah[mi], bl2, bl3);
            }
        }
    }
}

// ---------------- wide GEMM: BM=256, 512 threads, dynamic smem (W_out only) --
template<bool ABF16, int EPI>
__global__ void __launch_bounds__(512)
mma_gemm_wide(const float* __restrict__ A,
              const __nv_bfloat16* __restrict__ Agh, const __nv_bfloat16* __restrict__ Agl,
              const __nv_bfloat16* __restrict__ Bh,  const __nv_bfloat16* __restrict__ Bl,
              float* __restrict__ C,
              __nv_bfloat16* __restrict__ Hh, __nv_bfloat16* __restrict__ Hl,
              int M, int N, int K)
{
    constexpr int LD = 40;
    extern __shared__ __nv_bfloat16 dyns[];
    __nv_bfloat16* sAh = dyns;
    __nv_bfloat16* sAl = sAh + 256*LD;
    __nv_bfloat16* sBh = sAl + 256*LD;
    __nv_bfloat16* sBl = sBh + 128*LD;
    int tid = threadIdx.x, lane = tid & 31, warp = tid >> 5;
    int m0 = blockIdx.y*256, n0 = blockIdx.x*128;
    int warpM = (warp >> 1)*32, warpN = (warp & 1)*64;

    float acc[2][8][4] = {};
    float4 pa[4]; uint4 pah[2], pal[2], pbh, pbl;

    if (ABF16) {
        #pragma unroll
        for (int i = 0; i < 2; i++) {
            int idx = tid + i*512, row = idx >> 2, q = idx & 3;
            pah[i] = *(const uint4*)&Agh[(size_t)(m0+row)*K + q*8];
            pal[i] = *(const uint4*)&Agl[(size_t)(m0+row)*K + q*8];
        }
    } else {
        #pragma unroll
        for (int i = 0; i < 4; i++) {
            int idx = tid + i*512, row = idx >> 3, c4 = idx & 7;
            pa[i] = *(const float4*)&A[(size_t)(m0+row)*K + c4*4];
        }
    }
    {
        int row = tid >> 2, q = tid & 3;
        pbh = *(const uint4*)&Bh[(size_t)(n0+row)*K + q*8];
        pbl = *(const uint4*)&Bl[(size_t)(n0+row)*K + q*8];
    }

    int nt = K / 32;
    for (int t = 0; t < nt; t++) {
        __syncthreads();
        if (ABF16) {
            #pragma unroll
            for (int i = 0; i < 2; i++) {
                int idx = tid + i*512, row = idx >> 2, q = idx & 3;
                *(uint4*)&sAh[row*LD + q*8] = pah[i];
                *(uint4*)&sAl[row*LD + q*8] = pal[i];
            }
        } else {
            #pragma unroll
            for (int i = 0; i < 4; i++) {
                int idx = tid + i*512, row = idx >> 3, c = (idx & 7)*4;
                float4 v = pa[i];
                __nv_bfloat16 h0 = __float2bfloat16(v.x), h1 = __float2bfloat16(v.y);
                __nv_bfloat16 h2 = __float2bfloat16(v.z), h3 = __float2bfloat16(v.w);
                __nv_bfloat162 hh0; hh0.x = h0; hh0.y = h1;
                __nv_bfloat162 hh1; hh1.x = h2; hh1.y = h3;
                *(__nv_bfloat162*)&sAh[row*LD + c]     = hh0;
                *(__nv_bfloat162*)&sAh[row*LD + c + 2] = hh1;
                __nv_bfloat162 ll0, ll1;
                ll0.x = __float2bfloat16(v.x - __bfloat162float(h0));
                ll0.y = __float2bfloat16(v.y - __bfloat162float(h1));
                ll1.x = __float2bfloat16(v.z - __bfloat162float(h2));
                ll1.y = __float2bfloat16(v.w - __bfloat162float(h3));
                *(__nv_bfloat162*)&sAl[row*LD + c]     = ll0;
                *(__nv_bfloat162*)&sAl[row*LD + c + 2] = ll1;
            }
        }
        {
            int row = tid >> 2, q = tid & 3;
            *(uint4*)&sBh[row*LD + q*8] = pbh;
            *(uint4*)&sBl[row*LD + q*8] = pbl;
        }
        __syncthreads();
        if (t + 1 < nt) {
            int kc = (t+1)*32;
            if (ABF16) {
                #pragma unroll
                for (int i = 0; i < 2; i++) {
                    int idx = tid + i*512, row = idx >> 2, q = idx & 3;
                    pah[i] = *(const uint4*)&Agh[(size_t)(m0+row)*K + kc + q*8];
                    pal[i] = *(const uint4*)&Agl[(size_t)(m0+row)*K + kc + q*8];
                }
            } else {
                #pragma unroll
                for (int i = 0; i < 4; i++) {
                    int idx = tid + i*512, row = idx >> 3, c4 = idx & 7;
                    pa[i] = *(const float4*)&A[(size_t)(m0+row)*K + kc + c4*4];
                }
            }
            {
                int row = tid >> 2, q = tid & 3;
                pbh = *(const uint4*)&Bh[(size_t)(n0+row)*K + kc + q*8];
                pbl = *(const uint4*)&Bl[(size_t)(n0+row)*K + kc + q*8];
            }
        }
        mma_chunk(acc, sAh, sAl, sBh, sBl, lane, warpM, warpN);
    }

    #pragma unroll
    for (int mi = 0; mi < 2; mi++) {
        #pragma unroll
        for (int nj = 0; nj < 8; nj++) {
            int r0  = m0 + warpM + mi*16 + (lane >> 2);
            int col = n0 + warpN + nj*8 + (lane & 3)*2;
            float v0 = acc[mi][nj][0], v1 = acc[mi][nj][1];
            float v2 = acc[mi][nj][2], v3 = acc[mi][nj][3];
            if (EPI == 3) {
                v0 = fmaxf(v0, 0.f); v1 = fmaxf(v1, 0.f);
                v2 = fmaxf(v2, 0.f); v3 = fmaxf(v3, 0.f);
            }
            float2 o0; o0.x = v0; o0.y = v1;
            float2 o1; o1.x = v2; o1.y = v3;
            *(float2*)&C[(size_t)r0*N + col]     = o0;
            *(float2*)&C[(size_t)(r0+8)*N + col] = o1;
        }
    }
}

// ---------------- fused embed: x = feats@Wemb; LN; p = relu(x)@Wouter; qkv ---
__global__ void __launch_bounds__(256)
embed_fused(const float* __restrict__ feats,
            const __nv_bfloat16* __restrict__ Weh, const __nv_bfloat16* __restrict__ Wel,
            const __nv_bfloat16* __restrict__ Wph, const __nv_bfloat16* __restrict__ Wpl,
            const __nv_bfloat16* __restrict__ Qwh, const __nv_bfloat16* __restrict__ Qwl,
            float* __restrict__ X, float* __restrict__ Pout, float* __restrict__ qkvout)
{
    constexpr int LD = 40;
    constexpr int CH = 128*LD;
    extern __shared__ __nv_bfloat16 dyns[];
    __nv_bfloat16* sAh = dyns;            // h' split (4 chunks)
    __nv_bfloat16* sAl = sAh + 4*CH;
    __nv_bfloat16* sFh = sAl + 4*CH;      // staging then relu(x) split
    __nv_bfloat16* sFl = sFh + 4*CH;
    __nv_bfloat16* sBh = sFl + 4*CH;
    __nv_bfloat16* sBl = sBh + CH;
    __shared__ float2 ssum[128][2];

    int tid = threadIdx.x, lane = tid & 31, warp = tid >> 5;
    int m0 = blockIdx.x*128;
    int warpM = (warp >> 1)*32, warpN = (warp & 1)*64;
    int brow = tid >> 2, bq = tid & 3;

    uint4 pbh[2], pbl[2];
    float4 pa[4];

    auto ln_stats = [&](float acc[2][8][4], float* mean, float* rsig) {
        float s[4] = {}, s2[4] = {};
        #pragma unroll
        for (int mi = 0; mi < 2; mi++)
            #pragma unroll
            for (int nj = 0; nj < 8; nj++) {
                float v0 = acc[mi][nj][0], v1 = acc[mi][nj][1];
                float v2 = acc[mi][nj][2], v3 = acc[mi][nj][3];
                s[mi*2]    += v0 + v1;      s2[mi*2]   += v0*v0 + v1*v1;
                s[mi*2+1]  += v2 + v3;      s2[mi*2+1] += v2*v2 + v3*v3;
            }
        #pragma unroll
        for (int off = 1; off <= 2; off <<= 1)
            #pragma unroll
            for (int r = 0; r < 4; r++) {
                s[r]  += __shfl_xor_sync(~0u, s[r],  off);
                s2[r] += __shfl_xor_sync(~0u, s2[r], off);
            }
        __syncthreads();
        if ((lane & 3) == 0) {
            #pragma unroll
            for (int slot = 0; slot < 4; slot++) {
                int row = warpM + (slot >> 1)*16 + (lane >> 2) + 8*(slot & 1);
                ssum[row][warp & 1] = make_float2(s[slot], s2[slot]);
            }
        }
        __syncthreads();
        #pragma unroll
        for (int slot = 0; slot < 4; slot++) {
            int row = warpM + (slot >> 1)*16 + (lane >> 2) + 8*(slot & 1);
            float2 a = ssum[row][0], b = ssum[row][1];
            float m  = (a.x + b.x) * (1.f/128.f);
            float vv = (a.y + b.y) * (1.f/128.f) - m*m;
            mean[slot] = m;
            rsig[slot] = rsqrtf(vv + 1e-5f);
        }
    };

    // ---- stage E: x = feats @ Wemb (K = 416 = 13 chunks), A fp32 on the fly
    float accE[2][8][4] = {};
    #pragma unroll
    for (int i = 0; i < 4; i++) {
        int idx = tid + i*256, row = idx >> 3, c4 = idx & 7;
        pa[i] = *(const float4*)&feats[(size_t)(m0+row)*KFP + c4*4];
    }
    pbh[0] = *(const uint4*)&Weh[(size_t)brow*KFP + bq*8];
    pbh[1] = *(const uint4*)&Weh[(size_t)(brow+64)*KFP + bq*8];
    pbl[0] = *(const uint4*)&Wel[(size_t)brow*KFP + bq*8];
    pbl[1] = *(const uint4*)&Wel[(size_t)(brow+64)*KFP + bq*8];

    #pragma unroll 1
    for (int t = 0; t < 13; t++) {
        __syncthreads();
        #pragma unroll
        for (int i = 0; i < 4; i++) {
            int idx = tid + i*256, row = idx >> 3, c = (idx & 7)*4;
            float4 v = pa[i];
            __nv_bfloat16 h0 = __float2bfloat16(v.x), h1 = __float2bfloat16(v.y);
            __nv_bfloat16 h2 = __float2bfloat16(v.z), h3 = __float2bfloat16(v.w);
            __nv_bfloat162 hh0; hh0.x = h0; hh0.y = h1;
            __nv_bfloat162 hh1; hh1.x = h2; hh1.y = h3;
            *(__nv_bfloat162*)&sFh[row*LD + c]     = hh0;
            *(__nv_bfloat162*)&sFh[row*LD + c + 2] = hh1;
            __nv_bfloat162 ll0, ll1;
            ll0.x = __float2bfloat16(v.x - __bfloat162float(h0));
            ll0.y = __float2bfloat16(v.y - __bfloat162float(h1));
            ll1.x = __float2bfloat16(v.z - __bfloat162float(h2));
            ll1.y = __float2bfloat16(v.w - __bfloat162float(h3));
            *(__nv_bfloat162*)&sFl[row*LD + c]     = ll0;
            *(__nv_bfloat162*)&sFl[row*LD + c + 2] = ll1;
        }
        *(uint4*)&sBh[brow*LD + bq*8]      = pbh[0];
        *(uint4*)&sBh[(brow+64)*LD + bq*8] = pbh[1];
        *(uint4*)&sBl[brow*LD + bq*8]      = pbl[0];
        *(uint4*)&sBl[(brow+64)*LD + bq*8] = pbl[1];
        __syncthreads();
        if (t + 1 < 13) {
            int kc = (t+1)*32;
            #pragma unroll
            for (int i = 0; i < 4; i++) {
                int idx = tid + i*256, row = idx >> 3, c4 = idx & 7;
                pa[i] = *(const float4*)&feats[(size_t)(m0+row)*KFP + kc + c4*4];
            }
            pbh[0] = *(const uint4*)&Weh[(size_t)brow*KFP + kc + bq*8];
            pbh[1] = *(const uint4*)&Weh[(size_t)(brow+64)*KFP + kc + bq*8];
            pbl[0] = *(const uint4*)&Wel[(size_t)brow*KFP + kc + bq*8];
            pbl[1] = *(const uint4*)&Wel[(size_t)(brow+64)*KFP + kc + bq*8];
        } else {
            pbh[0] = *(const uint4*)&Wph[(size_t)brow*128 + bq*8];
            pbh[1] = *(const uint4*)&Wph[(size_t)(brow+64)*128 + bq*8];
            pbl[0] = *(const uint4*)&Wpl[(size_t)brow*128 + bq*8];
            pbl[1] = *(const uint4*)&Wpl[(size_t)(brow+64)*128 + bq*8];
        }
        mma_chunk(accE, sFh, sFl, sBh, sBl, lane, warpM, warpN);
    }

    // LN stats (first __syncthreads inside covers the staging-read hazard)
    float mean[4], rsig[4];
    ln_stats(accE, mean, rsig);

    // write x; h' split -> sA; relu(x) split -> sF
    #pragma unroll
    for (int mi = 0; mi < 2; mi++) {
        #pragma unroll
        for (int nj = 0; nj < 8; nj++) {
            int r   = warpM + mi*16 + (lane >> 2);
            int col = warpN + nj*8 + (lane & 3)*2;
            int r0  = m0 + r;
            float v0 = accE[mi][nj][0], v1 = accE[mi][nj][1];
            float v2 = accE[mi][nj][2], v3 = accE[mi][nj][3];
            float2 o0; o0.x = v0; o0.y = v1;
            float2 o1; o1.x = v2; o1.y = v3;
            *(float2*)&X[(size_t)r0*128 + col]     = o0;
            *(float2*)&X[(size_t)(r0+8)*128 + col] = o1;
            int off = (col >> 5)*CH + (col & 31);
            // relu(x)
            {
                float a0 = fmaxf(v0,0.f), a1 = fmaxf(v1,0.f);
                float a2 = fmaxf(v2,0.f), a3 = fmaxf(v3,0.f);
                __nv_bfloat162 h0, h1, l0, l1;
                h0.x = __float2bfloat16(a0); h0.y = __float2bfloat16(a1);
                h1.x = __float2bfloat16(a2); h1.y = __float2bfloat16(a3);
                l0.x = __float2bfloat16(a0 - __bfloat162float(h0.x));
                l0.y = __float2bfloat16(a1 - __bfloat162float(h0.y));
                l1.x = __float2bfloat16(a2 - __bfloat162float(h1.x));
                l1.y = __float2bfloat16(a3 - __bfloat162float(h1.y));
                *(__nv_bfloat162*)&sFh[off + r*LD]     = h0;
                *(__nv_bfloat162*)&sFh[off + (r+8)*LD] = h1;
                *(__nv_bfloat162*)&sFl[off + r*LD]     = l0;
                *(__nv_bfloat162*)&sFl[off + (r+8)*LD] = l1;
            }
            // LN(x)
            {
                float a0 = (v0 - mean[mi*2])*rsig[mi*2];
                float a1 = (v1 - mean[mi*2])*rsig[mi*2];
                float a2 = (v2 - mean[mi*2+1])*rsig[mi*2+1];
                float a3 = (v3 - mean[mi*2+1])*rsig[mi*2+1];
                __nv_bfloat162 h0, h1, l0, l1;
                h0.x = __float2bfloat16(a0); h0.y = __float2bfloat16(a1);
                h1.x = __float2bfloat16(a2); h1.y = __float2bfloat16(a3);
                l0.x = __float2bfloat16(a0 - __bfloat162float(h0.x));
                l0.y = __float2bfloat16(a1 - __bfloat162float(h0.y));
                l1.x = __float2bfloat16(a2 - __bfloat162float(h1.x));
                l1.y = __float2bfloat16(a3 - __bfloat162float(h1.y));
                *(__nv_bfloat162*)&sAh[off + r*LD]     = h0;
                *(__nv_bfloat162*)&sAh[off + (r+8)*LD] = h1;
                *(__nv_bfloat162*)&sAl[off + r*LD]     = l0;
                *(__nv_bfloat162*)&sAl[off + (r+8)*LD] = l1;
            }
        }
    }

    // ---- stage P: p = relu(x) @ Wouter_pad (valid cols 0..31) ----
    {
        float accP[2][8][4] = {};
        #pragma unroll
        for (int t = 0; t < 4; t++) {
            __syncthreads();
            *(uint4*)&sBh[brow*LD + bq*8]      = pbh[0];
            *(uint4*)&sBh[(brow+64)*LD + bq*8] = pbh[1];
            *(uint4*)&sBl[brow*LD + bq*8]      = pbl[0];
            *(uint4*)&sBl[(brow+64)*LD + bq*8] = pbl[1];
            __syncthreads();
            if (t + 1 < 4) {
                int kc = (t+1)*32;
                pbh[0] = *(const uint4*)&Wph[(size_t)brow*128 + kc + bq*8];
                pbh[1] = *(const uint4*)&Wph[(size_t)(brow+64)*128 + kc + bq*8];
                pbl[0] = *(const uint4*)&Wpl[(size_t)brow*128 + kc + bq*8];
                pbl[1] = *(const uint4*)&Wpl[(size_t)(brow+64)*128 + kc + bq*8];
            } else {
                pbh[0] = *(const uint4*)&Qwh[(size_t)brow*128 + bq*8];
                pbh[1] = *(const uint4*)&Qwh[(size_t)(brow+64)*128 + bq*8];
                pbl[0] = *(const uint4*)&Qwl[(size_t)brow*128 + bq*8];
                pbl[1] = *(const uint4*)&Qwl[(size_t)(brow+64)*128 + bq*8];
            }
            mma_chunk(accP, sFh + t*CH, sFl + t*CH, sBh, sBl, lane, warpM, warpN);
        }
        if (warpN == 0) {
            #pragma unroll
            for (int mi = 0; mi < 2; mi++) {
                #pragma unroll
                for (int nj = 0; nj < 4; nj++) {
                    int r0  = m0 + warpM + mi*16 + (lane >> 2);
                    int col = nj*8 + (lane & 3)*2;
                    float2 o0; o0.x = accP[mi][nj][0]; o0.y = accP[mi][nj][1];
                    float2 o1; o1.x = accP[mi][nj][2]; o1.y = accP[mi][nj][3];
                    *(float2*)&Pout[(size_t)r0*32 + col]     = o0;
                    *(float2*)&Pout[(size_t)(r0+8)*32 + col] = o1;
                }
            }
        }
    }

    // ---- stage Q: qkv = h' @ Wqkv (3 N-blocks x 4 k-chunks) ----
    #pragma unroll 1
    for (int nb = 0; nb < 3; nb++) {
        float acc[2][8][4] = {};
        #pragma unroll
        for (int t = 0; t < 4; t++) {
            __syncthreads();
            *(uint4*)&sBh[brow*LD + bq*8]      = pbh[0];
            *(uint4*)&sBh[(brow+64)*LD + bq*8] = pbh[1];
            *(uint4*)&sBl[brow*LD + bq*8]      = pbl[0];
            *(uint4*)&sBl[(brow+64)*LD + bq*8] = pbl[1];
            __syncthreads();
            int ni = nb*4 + t + 1;
            if (ni < 12) {
                int nrow = (ni >> 2)*128, kc = (ni & 3)*32;
                pbh[0] = *(const uint4*)&Qwh[(size_t)(nrow + brow)*128 + kc + bq*8];
                pbh[1] = *(const uint4*)&Qwh[(size_t)(nrow + brow+64)*128 + kc + bq*8];
                pbl[0] = *(const uint4*)&Qwl[(size_t)(nrow + brow)*128 + kc + bq*8];
                pbl[1] = *(const uint4*)&Qwl[(size_t)(nrow + brow+64)*128 + kc + bq*8];
            }
            mma_chunk(acc, sAh + t*CH, sAl + t*CH, sBh, sBl, lane, warpM, warpN);
        }
        #pragma unroll
        for (int mi = 0; mi < 2; mi++) {
            #pragma unroll
            for (int nj = 0; nj < 8; nj++) {
                int r0  = m0 + warpM + mi*16 + (lane >> 2);
                int col = nb*128 + warpN + nj*8 + (lane & 3)*2;
                float2 o0; o0.x = acc[mi][nj][0]; o0.y = acc[mi][nj][1];
                float2 o1; o1.x = acc[mi][nj][2]; o1.y = acc[mi][nj][3];
                *(float2*)&qkvout[(size_t)r0*384 + col]     = o0;
                *(float2*)&qkvout[(size_t)(r0+8)*384 + col] = o1;
            }
        }
    }
}

// ---------------- fused layer tail: WO + res + LN + FF + (next QKV) ---------
template<bool LAST>
__global__ void __launch_bounds__(256)
layer_fused(const float* __restrict__ oin,
            const __nv_bfloat16* __restrict__ Woh, const __nv_bfloat16* __restrict__ Wol,
            const __nv_bfloat16* __restrict__ B1h, const __nv_bfloat16* __restrict__ B1l,
            const __nv_bfloat16* __restrict__ B2h, const __nv_bfloat16* __restrict__ B2l,
            const __nv_bfloat16* __restrict__ Qwh, const __nv_bfloat16* __restrict__ Qwl,
            float* __restrict__ X, float* __restrict__ qkvout)
{
    constexpr int LD = 40;
    constexpr int CH = 128*LD;
    extern __shared__ __nv_bfloat16 dyns[];
    __nv_bfloat16* sAh = dyns;
    __nv_bfloat16* sAl = sAh + 4*CH;
    __nv_bfloat16* sFh = sAl + 4*CH;
    __nv_bfloat16* sFl = sFh + 4*CH;
    __nv_bfloat16* sBh = sFl + 4*CH;
    __nv_bfloat16* sBl = sBh + CH;
    __shared__ float2 ssum[128][2];

    int tid = threadIdx.x, lane = tid & 31, warp = tid >> 5;
    int m0 = blockIdx.x*128;
    int warpM = (warp >> 1)*32, warpN = (warp & 1)*64;
    int brow = tid >> 2, bq = tid & 3;

    uint4 pbh[2], pbl[2];

    auto ln_stats = [&](float acc[2][8][4], float* mean, float* rsig) {
        float s[4] = {}, s2[4] = {};
        #pragma unroll
        for (int mi = 0; mi < 2; mi++)
            #pragma unroll
            for (int nj = 0; nj < 8; nj++) {
                float v0 = acc[mi][nj][0], v1 = acc[mi][nj][1];
                float v2 = acc[mi][nj][2], v3 = acc[mi][nj][3];
                s[mi*2]    += v0 + v1;      s2[mi*2]   += v0*v0 + v1*v1;
                s[mi*2+1]  += v2 + v3;      s2[mi*2+1] += v2*v2 + v3*v3;
            }
        #pragma unroll
        for (int off = 1; off <= 2; off <<= 1)
            #pragma unroll
            for (int r = 0; r < 4; r++) {
                s[r]  += __shfl_xor_sync(~0u, s[r],  off);
                s2[r] += __shfl_xor_sync(~0u, s2[r], off);
            }
        __syncthreads();
        if ((lane & 3) == 0) {
            #pragma unroll
            for (int slot = 0; slot < 4; slot++) {
                int row = warpM + (slot >> 1)*16 + (lane >> 2) + 8*(slot & 1);
                ssum[row][warp & 1] = make_float2(s[slot], s2[slot]);
            }
        }
        __syncthreads();
        #pragma unroll
        for (int slot = 0; slot < 4; slot++) {
            int row = warpM + (slot >> 1)*16 + (lane >> 2) + 8*(slot & 1);
            float2 a = ssum[row][0], b = ssum[row][1];
            float m  = (a.x + b.x) * (1.f/128.f);
            float vv = (a.y + b.y) * (1.f/128.f) - m*m;
            mean[slot] = m;
            rsig[slot] = rsqrtf(vv + 1e-5f);
        }
    };

    // ---- stage W: x_mid = x + o@Wo; LN -> h' in sA
    {
        #pragma unroll
        for (int i = 0; i < 16; i++) {
            int idx = tid + i*256;
            int row = idx >> 5, q = idx & 31;
            float4 v = *(const float4*)&oin[(size_t)(m0+row)*128 + q*4];
            int off = (q >> 3)*CH + row*LD + (q & 7)*4;
            __nv_bfloat162 h0, h1, l0, l1;
            h0.x = __float2bfloat16(v.x); h0.y = __float2bfloat16(v.y);
            h1.x = __float2bfloat16(v.z); h1.y = __float2bfloat16(v.w);
            l0.x = __float2bfloat16(v.x - __bfloat162float(h0.x));
            l0.y = __float2bfloat16(v.y - __bfloat162float(h0.y));
            l1.x = __float2bfloat16(v.z - __bfloat162float(h1.x));
            l1.y = __float2bfloat16(v.w - __bfloat162float(h1.y));
            *(__nv_bfloat162*)&sFh[off]     = h0;
            *(__nv_bfloat162*)&sFh[off + 2] = h1;
            *(__nv_bfloat162*)&sFl[off]     = l0;
            *(__nv_bfloat162*)&sFl[off + 2] = l1;
        }
        pbh[0] = *(const uint4*)&Woh[(size_t)brow*128 + bq*8];
        pbh[1] = *(const uint4*)&Woh[(size_t)(brow+64)*128 + bq*8];
        pbl[0] = *(const uint4*)&Wol[(size_t)brow*128 + bq*8];
        pbl[1] = *(const uint4*)&Wol[(size_t)(brow+64)*128 + bq*8];

        float accW[2][8][4] = {};
        #pragma unroll
        for (int t = 0; t < 4; t++) {
            __syncthreads();
            *(uint4*)&sBh[brow*LD + bq*8]      = pbh[0];
            *(uint4*)&sBh[(brow+64)*LD + bq*8] = pbh[1];
            *(uint4*)&sBl[brow*LD + bq*8]      = pbl[0];
            *(uint4*)&sBl[(brow+64)*LD + bq*8] = pbl[1];
            __syncthreads();
            if (t + 1 < 4) {
                int kc = (t+1)*32;
                pbh[0] = *(const uint4*)&Woh[(size_t)brow*128 + kc + bq*8];
                pbh[1] = *(const uint4*)&Woh[(size_t)(brow+64)*128 + kc + bq*8];
                pbl[0] = *(const uint4*)&Wol[(size_t)brow*128 + kc + bq*8];
                pbl[1] = *(const uint4*)&Wol[(size_t)(brow+64)*128 + kc + bq*8];
            } else {
                pbh[0] = *(const uint4*)&B1h[(size_t)brow*128 + bq*8];
                pbh[1] = *(const uint4*)&B1h[(size_t)(brow+64)*128 + bq*8];
                pbl[0] = *(const uint4*)&B1l[(size_t)brow*128 + bq*8];
                pbl[1] = *(const uint4*)&B1l[(size_t)(brow+64)*128 + bq*8];
            }
            mma_chunk(accW, sFh + t*CH, sFl + t*CH, sBh, sBl, lane, warpM, warpN);
        }
        #pragma unroll
        for (int mi = 0; mi < 2; mi++) {
            #pragma unroll
            for (int nj = 0; nj < 8; nj++) {
                int r0  = m0 + warpM + mi*16 + (lane >> 2);
                int col = warpN + nj*8 + (lane & 3)*2;
                float2 c0 = *(const float2*)&X[(size_t)r0*128 + col];
                float2 c1 = *(const float2*)&X[(size_t)(r0+8)*128 + col];
                accW[mi][nj][0] += c0.x; accW[mi][nj][1] += c0.y;
                accW[mi][nj][2] += c1.x; accW[mi][nj][3] += c1.y;
            }
        }
        float mean[4], rsig[4];
        ln_stats(accW, mean, rsig);
        #pragma unroll
        for (int mi = 0; mi < 2; mi++) {
            #pragma unroll
            for (int nj = 0; nj < 8; nj++) {
                int r   = warpM + mi*16 + (lane >> 2);
                int col = warpN + nj*8 + (lane & 3)*2;
                int r0  = m0 + r;
                float v0 = accW[mi][nj][0], v1 = accW[mi][nj][1];
                float v2 = accW[mi][nj][2], v3 = accW[mi][nj][3];
                float2 o0; o0.x = v0; o0.y = v1;
                float2 o1; o1.x = v2; o1.y = v3;
                *(float2*)&X[(size_t)r0*128 + col]     = o0;
                *(float2*)&X[(size_t)(r0+8)*128 + col] = o1;
                v0 = (v0 - mean[mi*2])*rsig[mi*2];
                v1 = (v1 - mean[mi*2])*rsig[mi*2];
                v2 = (v2 - mean[mi*2+1])*rsig[mi*2+1];
                v3 = (v3 - mean[mi*2+1])*rsig[mi*2+1];
                int off = (col >> 5)*CH + (col & 31);
                __nv_bfloat162 h0, h1, l0, l1;
                h0.x = __float2bfloat16(v0); h0.y = __float2bfloat16(v1);
                h1.x = __float2bfloat16(v2); h1.y = __float2bfloat16(v3);
                l0.x = __float2bfloat16(v0 - __bfloat162float(h0.x));
                l0.y = __float2bfloat16(v1 - __bfloat162float(h0.y));
                l1.x = __float2bfloat16(v2 - __bfloat162float(h1.x));
                l1.y = __float2bfloat16(v3 - __bfloat162float(h1.y));
                *(__nv_bfloat162*)&sAh[off + r*LD]     = h0;
                *(__nv_bfloat162*)&sAh[off + (r+8)*LD] = h1;
                *(__nv_bfloat162*)&sAl[off + r*LD]     = l0;
                *(__nv_bfloat162*)&sAl[off + (r+8)*LD] = l1;
            }
        }
    }

    // ---- FF stages ----
    auto bptr = [&](int i, int row, const __nv_bfloat16* b1, const __nv_bfloat16* b2)
        -> const __nv_bfloat16* {
        int c = i >> 3, t = i & 3;
        if (((i >> 2) & 1) == 0)
            return &b1[(size_t)(c*128 + row)*128 + t*32 + bq*8];
        else
            return &b2[(size_t)row*512 + c*128 + t*32 + bq*8];
    };

    float acc2[2][8][4] = {};
    #pragma unroll 1
    for (int c = 0; c < 4; c++) {
        float acc1[2][8][4] = {};
        #pragma unroll
        for (int t = 0; t < 4; t++) {
            __syncthreads();
            *(uint4*)&sBh[brow*LD + bq*8]      = pbh[0];
            *(uint4*)&sBh[(brow+64)*LD + bq*8] = pbh[1];
            *(uint4*)&sBl[brow*LD + bq*8]      = pbl[0];
            *(uint4*)&sBl[(brow+64)*LD + bq*8] = pbl[1];
            __syncthreads();
            int ni = c*8 + t + 1;
            pbh[0] = *(const uint4*)bptr(ni, brow,    B1h, B2h);
            pbh[1] = *(const uint4*)bptr(ni, brow+64, B1h, B2h);
            pbl[0] = *(const uint4*)bptr(ni, brow,    B1l, B2l);
            pbl[1] = *(const uint4*)bptr(ni, brow+64, B1l, B2l);
            mma_chunk(acc1, sAh + t*CH, sAl + t*CH, sBh, sBl, lane, warpM, warpN);
        }
        #pragma unroll
        for (int mi = 0; mi < 2; mi++) {
            #pragma unroll
            for (int nj = 0; nj < 8; nj++) {
                int r   = warpM + mi*16 + (lane >> 2);
                int col = warpN + nj*8 + (lane & 3)*2;
                int off = (col >> 5)*CH + (col & 31);
                float v0 = fmaxf(acc1[mi][nj][0], 0.f), v1 = fmaxf(acc1[mi][nj][1], 0.f);
                float v2 = fmaxf(acc1[mi][nj][2], 0.f), v3 = fmaxf(acc1[mi][nj][3], 0.f);
                __nv_bfloat162 h0, h1, l0, l1;
                h0.x = __float2bfloat16(v0); h0.y = __float2bfloat16(v1);
                h1.x = __float2bfloat16(v2); h1.y = __float2bfloat16(v3);
                l0.x = __float2bfloat16(v0 - __bfloat162float(h0.x));
                l0.y = __float2bfloat16(v1 - __bfloat162float(h0.y));
                l1.x = __float2bfloat16(v2 - __bfloat162float(h1.x));
                l1.y = __float2bfloat16(v3 - __bfloat162float(h1.y));
                *(__nv_bfloat162*)&sFh[off + r*LD]     = h0;
                *(__nv_bfloat162*)&sFh[off + (r+8)*LD] = h1;
                *(__nv_bfloat162*)&sFl[off + r*LD]     = l0;
                *(__nv_bfloat162*)&sFl[off + (r+8)*LD] = l1;
            }
        }
        #pragma unroll
        for (int t = 0; t < 4; t++) {
            __syncthreads();
            *(uint4*)&sBh[brow*LD + bq*8]      = pbh[0];
            *(uint4*)&sBh[(brow+64)*LD + bq*8] = pbh[1];
            *(uint4*)&sBl[brow*LD + bq*8]      = pbl[0];
            *(uint4*)&sBl[(brow+64)*LD + bq*8] = pbl[1];
            __syncthreads();
            int ni = c*8 + t + 5;
            if (ni < 32) {
                pbh[0] = *(const uint4*)bptr(ni, brow,    B1h, B2h);
                pbh[1] = *(const uint4*)bptr(ni, brow+64, B1h, B2h);
                pbl[0] = *(const uint4*)bptr(ni, brow,    B1l, B2l);
                pbl[1] = *(const uint4*)bptr(ni, brow+64, B1l, B2l);
            } else if (!LAST) {
                pbh[0] = *(const uint4*)&Qwh[(size_t)brow*128 + bq*8];
                pbh[1] = *(const uint4*)&Qwh[(size_t)(brow+64)*128 + bq*8];
                pbl[0] = *(const uint4*)&Qwl[(size_t)brow*128 + bq*8];
                pbl[1] = *(const uint4*)&Qwl[(size_t)(brow+64)*128 + bq*8];
            }
            mma_chunk(acc2, sFh + t*CH, sFl + t*CH, sBh, sBl, lane, warpM, warpN);
        }
    }

    #pragma unroll
    for (int mi = 0; mi < 2; mi++) {
        #pragma unroll
        for (int nj = 0; nj < 8; nj++) {
            int r0  = m0 + warpM + mi*16 + (lane >> 2);
            int col = warpN + nj*8 + (lane & 3)*2;
            float2 c0 = *(const float2*)&X[(size_t)r0*128 + col];
            float2 c1 = *(const float2*)&X[(size_t)(r0+8)*128 + col];
            acc2[mi][nj][0] += c0.x; acc2[mi][nj][1] += c0.y;
            acc2[mi][nj][2] += c1.x; acc2[mi][nj][3] += c1.y;
        }
    }

    float mean[4], rsig[4];
    if (!LAST) ln_stats(acc2, mean, rsig);

    #pragma unroll
    for (int mi = 0; mi < 2; mi++) {
        #pragma unroll
        for (int nj = 0; nj < 8; nj++) {
            int r   = warpM + mi*16 + (lane >> 2);
            int col = warpN + nj*8 + (lane & 3)*2;
            int r0  = m0 + r;
            float v0 = acc2[mi][nj][0], v1 = acc2[mi][nj][1];
            float v2 = acc2[mi][nj][2], v3 = acc2[mi][nj][3];
            float2 o0; o0.x = v0; o0.y = v1;
            float2 o1; o1.x = v2; o1.y = v3;
            *(float2*)&X[(size_t)r0*128 + col]     = o0;
            *(float2*)&X[(size_t)(r0+8)*128 + col] = o1;
            if (!LAST) {
                v0 = (v0 - mean[mi*2])*rsig[mi*2];
                v1 = (v1 - mean[mi*2])*rsig[mi*2];
                v2 = (v2 - mean[mi*2+1])*rsig[mi*2+1];
                v3 = (v3 - mean[mi*2+1])*rsig[mi*2+1];
                int off = (col >> 5)*CH + (col & 31);
                __nv_bfloat162 h0, h1, l0, l1;
                h0.x = __float2bfloat16(v0); h0.y = __float2bfloat16(v1);
                h1.x = __float2bfloat16(v2); h1.y = __float2bfloat16(v3);
                l0.x = __float2bfloat16(v0 - __bfloat162float(h0.x));
                l0.y = __float2bfloat16(v1 - __bfloat162float(h0.y));
                l1.x = __float2bfloat16(v2 - __bfloat162float(h1.x));
                l1.y = __float2bfloat16(v3 - __bfloat162float(h1.y));
                *(__nv_bfloat162*)&sAh[off + r*LD]     = h0;
                *(__nv_bfloat162*)&sAh[off + (r+8)*LD] = h1;
                *(__nv_bfloat162*)&sAl[off + r*LD]     = l0;
                *(__nv_bfloat162*)&sAl[off + (r+8)*LD] = l1;
            }
        }
    }

    if (!LAST) {
        #pragma unroll 1
        for (int nb = 0; nb < 3; nb++) {
            float acc[2][8][4] = {};
            #pragma unroll
            for (int t = 0; t < 4; t++) {
                __syncthreads();
                *(uint4*)&sBh[brow*LD + bq*8]      = pbh[0];
                *(uint4*)&sBh[(brow+64)*LD + bq*8] = pbh[1];
                *(uint4*)&sBl[brow*LD + bq*8]      = pbl[0];
                *(uint4*)&sBl[(brow+64)*LD + bq*8] = pbl[1];
                __syncthreads();
                int ni = nb*4 + t + 1;
                if (ni < 12) {
                    int nrow = (ni >> 2)*128, kc = (ni & 3)*32;
                    pbh[0] = *(const uint4*)&Qwh[(size_t)(nrow + brow)*128 + kc + bq*8];
                    pbh[1] = *(const uint4*)&Qwh[(size_t)(nrow + brow+64)*128 + kc + bq*8];
                    pbl[0] = *(const uint4*)&Qwl[(size_t)(nrow + brow)*128 + kc + bq*8];
                    pbl[1] = *(const uint4*)&Qwl[(size_t)(nrow + brow+64)*128 + kc + bq*8];
                }
                mma_chunk(acc, sAh + t*CH, sAl + t*CH, sBh, sBl, lane, warpM, warpN);
            }
            #pragma unroll
            for (int mi = 0; mi < 2; mi++) {
                #pragma unroll
                for (int nj = 0; nj < 8; nj++) {
                    int r0  = m0 + warpM + mi*16 + (lane >> 2);
                    int col = nb*128 + warpN + nj*8 + (lane & 3)*2;
                    float2 o0; o0.x = acc[mi][nj][0]; o0.y = acc[mi][nj][1];
                    float2 o1; o1.x = acc[mi][nj][2]; o1.y = acc[mi][nj][3];
                    *(float2*)&qkvout[(size_t)r0*384 + col]     = o0;
                    *(float2*)&qkvout[(size_t)(r0+8)*384 + col] = o1;
                }
            }
        }
    }
}

// ---------------- fused pair-feature -> LN -> FF -> head bias ---------------
__global__ void __launch_bounds__(256)
bias_kernel(const float* __restrict__ pos, const int* __restrict__ uid,
            const float* __restrict__ Wp, const float* __restrict__ W1,
            const float* __restrict__ W2, const float* __restrict__ Wb)
{
    __shared__ float sposi[32][3], sposj[KWIN][3];
    __shared__ int   suidi[32],    suidj[KWIN];
    __shared__ float4 spi4[32][4], spj4[KWIN][4];
    __shared__ float sWp[80], sWb[64];
    __shared__ float4 sW1T[64][4];
    __shared__ float4 sW2b[64];
    __shared__ unsigned char svalid[KWIN];

    int bb = blockIdx.x;
    int half = bb & 1;
    int bw = bb >> 1;
    int b = bw / NW, w = bw % NW;
    int q0 = half*32;
    int tid = threadIdx.x;

    for (int i = tid; i < 80; i += 256) sWp[i] = Wp[i];
    for (int i = tid; i < 64; i += 256) sWb[i] = Wb[i];
    for (int i = tid; i < 1024; i += 256) {
        int j = i >> 4, c = i & 15;
        ((float*)sW1T)[j*16 + c] = W1[c*64 + j];
    }
    if (tid < 64) {
        float4 r = make_float4(0,0,0,0);
        #pragma unroll
        for (int c = 0; c < 16; c++) {
            float w2v = W2[tid*16 + c];
            r.x += w2v*Wb[c*4+0]; r.y += w2v*Wb[c*4+1];
            r.z += w2v*Wb[c*4+2]; r.w += w2v*Wb[c*4+3];
        }
        sW2b[tid] = r;
    }
    for (int q = tid; q < 32; q += 256) {
        int gi = b*N_ + w*QWIN + q0 + q;
        sposi[q][0] = pos[gi*3]; sposi[q][1] = pos[gi*3+1]; sposi[q][2] = pos[gi*3+2];
        suidi[q] = uid[gi];
        const float4* pp = (const float4*)&g_p[(size_t)gi*32];
        spi4[q][0] = pp[0]; spi4[q][1] = pp[1]; spi4[q][2] = pp[2]; spi4[q][3] = pp[3];
    }
    for (int k = tid; k < KWIN; k += 256) {
        int j = w*QWIN + k - PADW;
        bool valid = (j >= 0 && j < N_);
        svalid[k] = valid;
        if (valid) {
            int gj = b*N_ + j;
            sposj[k][0] = pos[gj*3]; sposj[k][1] = pos[gj*3+1]; sposj[k][2] = pos[gj*3+2];
            suidj[k] = uid[gj];
            const float4* pp = (const float4*)&g_p[(size_t)gj*32 + 16];
            spj4[k][0] = pp[0]; spj4[k][1] = pp[1]; spj4[k][2] = pp[2]; spj4[k][3] = pp[3];
        } else {
            sposj[k][0] = sposj[k][1] = sposj[k][2] = 0.f; suidj[k] = -1;
            float4 z = make_float4(0,0,0,0);
            spj4[k][0] = z; spj4[k][1] = z; spj4[k][2] = z; spj4[k][3] = z;
        }
    }
    __syncthreads();

    float* brow = g_bias + (size_t)bw*HEADS*QWIN*KWIN;

    auto prep = [&](int q, int k, float4* u, float& bh0, float& bh1, float& bh2, float& bh3) {
        float dx = sposi[q][0]-sposj[k][0];
        float dy = sposi[q][1]-sposj[k][1];
        float dz = sposi[q][2]-sposj[k][2];
        float inv = 1.f / (1.f + dx*dx + dy*dy + dz*dz);
        float bij = (suidi[q] == suidj[k]) ? 1.f : 0.f;
        float4 pr[4];
        #pragma unroll
        for (int c4 = 0; c4 < 4; c4++) {
            float4 r;
            #pragma unroll
            for (int e = 0; e < 4; e++) {
                int c = c4*4 + e;
                float base = dx*sWp[c] + dy*sWp[16+c] + dz*sWp[32+c] + inv*sWp[48+c] + sWp[64+c];
                (&r.x)[e] = base*bij + (&spi4[q][c4].x)[e] + (&spj4[k][c4].x)[e];
            }
            pr[c4] = r;
        }
        float s = 0.f, s2 = 0.f;
        #pragma unroll
        for (int c4 = 0; c4 < 4; c4++) {
            s  += pr[c4].x + pr[c4].y + pr[c4].z + pr[c4].w;
            s2 += pr[c4].x*pr[c4].x + pr[c4].y*pr[c4].y + pr[c4].z*pr[c4].z + pr[c4].w*pr[c4].w;
        }
        float mean = s * (1.f/DP);
        float var  = s2 * (1.f/DP) - mean*mean;
        float rinv = rsqrtf(var + 1e-5f);
        bh0 = bh1 = bh2 = bh3 = 0.f;
        #pragma unroll
        for (int c4 = 0; c4 < 4; c4++) {
            #pragma unroll
            for (int e = 0; e < 4; e++) {
                int c = c4*4 + e;
                float pv = (&pr[c4].x)[e];
                bh0 += pv*sWb[c*4+0]; bh1 += pv*sWb[c*4+1];
                bh2 += pv*sWb[c*4+2]; bh3 += pv*sWb[c*4+3];
                (&u[c4].x)[e] = (pv - mean)*rinv;
            }
        }
    };

    for (int t = tid; t < 32*64; t += 256) {
        int q = t >> 6, k0 = t & 63, k1 = k0 + 64;
        int gq = q0 + q;
        float4 u0[4], u1[4];
        float a0,a1,a2,a3, c0,c1,c2,c3;
        prep(q, k0, u0, a0, a1, a2, a3);
        prep(q, k1, u1, c0, c1, c2, c3);
        #pragma unroll 2
        for (int j = 0; j < 64; j++) {
            float4 w0 = sW1T[j][0], w1 = sW1T[j][1], w2 = sW1T[j][2], w3 = sW1T[j][3];
            float t0 = u0[0].x*w0.x + u0[0].y*w0.y + u0[0].z*w0.z + u0[0].w*w0.w
                     + u0[1].x*w1.x + u0[1].y*w1.y + u0[1].z*w1.z + u0[1].w*w1.w
                     + u0[2].x*w2.x + u0[2].y*w2.y + u0[2].z*w2.z + u0[2].w*w2.w
                     + u0[3].x*w3.x + u0[3].y*w3.y + u0[3].z*w3.z + u0[3].w*w3.w;
            float t1 = u1[0].x*w0.x + u1[0].y*w0.y + u1[0].z*w0.z + u1[0].w*w0.w
                     + u1[1].x*w1.x + u1[1].y*w1.y + u1[1].z*w1.z + u1[1].w*w1.w
                     + u1[2].x*w2.x + u1[2].y*w2.y + u1[2].z*w2.z + u1[2].w*w2.w
                     + u1[3].x*w3.x + u1[3].y*w3.y + u1[3].z*w3.z + u1[3].w*w3.w;
            t0 = fmaxf(t0, 0.f); t1 = fmaxf(t1, 0.f);
            float4 wb2 = sW2b[j];
            a0 += t0*wb2.x; a1 += t0*wb2.y; a2 += t0*wb2.z; a3 += t0*wb2.w;
            c0 += t1*wb2.x; c1 += t1*wb2.y; c2 += t1*wb2.z; c3 += t1*wb2.w;
        }
        bool v0 = svalid[k0], v1 = svalid[k1];
        brow[((0*QWIN + gq) << 7) + k0] = v0 ? a0 : 0.f;
        brow[((1*QWIN + gq) << 7) + k0] = v0 ? a1 : 0.f;
        brow[((2*QWIN + gq) << 7) + k0] = v0 ? a2 : 0.f;
        brow[((3*QWIN + gq) << 7) + k0] = v0 ? a3 : 0.f;
        brow[((0*QWIN + gq) << 7) + k1] = v1 ? c0 : 0.f;
        brow[((1*QWIN + gq) << 7) + k1] = v1 ? c1 : 0.f;
        brow[((2*QWIN + gq) << 7) + k1] = v1 ? c2 : 0.f;
        brow[((3*QWIN + gq) << 7) + k1] = v1 ? c3 : 0.f;
    }
}

// ---------------- attention per (b, window, head): lane-parallel -------------
__global__ void attn_kernel(const float* __restrict__ qkv, float* __restrict__ o)
{
    __shared__ float4 ks4[KWIN][8];
    __shared__ float4 vs4[KWIN][8];
    __shared__ float  ps[8][2][KWIN];

    int h  = blockIdx.x & 3;
    int bw = blockIdx.x >> 2;
    int w  = bw & (NW-1);
    int b  = bw >> 7;
    int tid = threadIdx.x, lane = tid & 31, warp = tid >> 5;
    int rowbase = b*N_ + w*QWIN;

    for (int s = tid; s < KWIN*8; s += 256) {
        int kk = s >> 3, i = s & 7;
        int j = w*QWIN + kk - PADW;
        float4 kv = make_float4(0,0,0,0), vv = make_float4(0,0,0,0);
        if (j >= 0 && j < N_) {
            const float* base = &qkv[(size_t)(b*N_ + j)*384 + h*32 + i*4];
            kv = *(const float4*)(base + 128);
            vv = *(const float4*)(base + 256);
        }
        int sw = i ^ (kk & 7);
        ks4[kk][sw] = kv;
        vs4[kk][sw] = vv;
    }
    __syncthreads();

    const float scale = 0.17677669529663687f;
    const float* brow = g_bias + ((size_t)bw*HEADS + h)*QWIN*KWIN;
    int lhi = lane >> 2, llo = lane & 3;

    for (int pass = 0; pass < 4; pass++) {
        int rA = warp*8 + pass*2, rB = rA + 1;
        float4 qa[8], qb[8];
        #pragma unroll
        for (int i = 0; i < 8; i++) {
            qa[i] = *(const float4*)&qkv[(size_t)(rowbase+rA)*384 + h*32 + i*4];
            qb[i] = *(const float4*)&qkv[(size_t)(rowbase+rB)*384 + h*32 + i*4];
        }
        float4 aA[4], aB[4];
        #pragma unroll
        for (int g = 0; g < 4; g++) { aA[g] = make_float4(0,0,0,0); aB[g] = make_float4(0,0,0,0); }
        #pragma unroll
        for (int i = 0; i < 8; i++) {
            #pragma unroll
            for (int g = 0; g < 4; g++) {
                int kk = g*32 + lane;
                float4 kv = ks4[kk][i ^ (kk & 7)];
                aA[g].x += qa[i].x*kv.x; aA[g].y += qa[i].y*kv.y;
                aA[g].z += qa[i].z*kv.z; aA[g].w += qa[i].w*kv.w;
                aB[g].x += qb[i].x*kv.x; aB[g].y += qb[i].y*kv.y;
                aB[g].z += qb[i].z*kv.z; aB[g].w += qb[i].w*kv.w;
            }
        }
        float lA[4], lB[4];
        float mA = -1e30f, mB = -1e30f;
        #pragma unroll
        for (int g = 0; g < 4; g++) {
            int kk = g*32 + lane;
            int j = w*QWIN + kk - PADW;
            float msk = (j >= 0 && j < N_) ? 0.f : -1e9f;
            lA[g] = ((aA[g].x+aA[g].y)+(aA[g].z+aA[g].w))*scale + brow[(rA<<7)+kk] + msk;
            lB[g] = ((aB[g].x+aB[g].y)+(aB[g].z+aB[g].w))*scale + brow[(rB<<7)+kk] + msk;
            mA = fmaxf(mA, lA[g]); mB = fmaxf(mB, lB[g]);
        }
        #pragma unroll
        for (int off = 16; off > 0; off >>= 1) {
            mA = fmaxf(mA, __shfl_xor_sync(~0u, mA, off));
            mB = fmaxf(mB, __shfl_xor_sync(~0u, mB, off));
        }
        float sA = 0.f, sB = 0.f, eA[4], eB[4];
        #pragma unroll
        for (int g = 0; g < 4; g++) {
            eA[g] = __expf(lA[g]-mA); sA += eA[g];
            eB[g] = __expf(lB[g]-mB); sB += eB[g];
        }
        #pragma unroll
        for (int off = 16; off > 0; off >>= 1) {
            sA += __shfl_xor_sync(~0u, sA, off);
            sB += __shfl_xor_sync(~0u, sB, off);
        }
        float rsA = 1.f/sA, rsB = 1.f/sB;
        #pragma unroll
        for (int g = 0; g < 4; g++) {
            ps[warp][0][g*32+lane] = eA[g]*rsA;
            ps[warp][1][g*32+lane] = eB[g]*rsB;
        }
        __syncwarp();
        float oA = 0.f, oB = 0.f;
        #pragma unroll 4
        for (int k4 = 0; k4 < 32; k4++) {
            float4 pA = *(const float4*)&ps[warp][0][k4*4];
            float4 pB = *(const float4*)&ps[warp][1][k4*4];
            #pragma unroll
            for (int t = 0; t < 4; t++) {
                int kk = k4*4 + t;
                float v = ((const float*)&vs4[kk][0])[(((lhi ^ (kk&7))<<2) | llo)];
                oA += (&pA.x)[t]*v;
                oB += (&pB.x)[t]*v;
            }
        }
        o[(size_t)(rowbase+rA)*DS + h*32 + lane] = oA;
        o[(size_t)(rowbase+rB)*DS + h*32 + lane] = oB;
        __syncwarp();
    }
}

// ---------------- deterministic segment mean (indices sorted) ---------------
__global__ void segmean_kernel(const int* __restrict__ a2t, float* __restrict__ out)
{
    int bt = blockIdx.x;
    int b = bt / NTOK, t = bt % NTOK;
    const int* idx = a2t + b*N_;
    __shared__ int slo, shi;
    if (threadIdx.x == 0) {
        int lo = 0, hi = N_;
        while (lo < hi) { int mid = (lo+hi) >> 1; if (idx[mid] < t) lo = mid+1; else hi = mid; }
        slo = lo;
        int lo2 = lo, hi2 = N_;
        while (lo2 < hi2) { int mid = (lo2+hi2) >> 1; if (idx[mid] < t+1) lo2 = mid+1; else hi2 = mid; }
        shi = lo2;
    }
    __syncthreads();
    int lo = slo, hi = shi;
    float rcnt = 1.f / fmaxf((float)(hi - lo), 1.f);
    for (int d = threadIdx.x; d < DT; d += blockDim.x) {
        float ssum = 0.f;
        for (int i = lo; i < hi; i++) ssum += g_tok[((size_t)(b*N_ + i))*DT + d];
        out[(size_t)bt*DT + d] = ssum * rcnt;
    }
}

// ---------------- launch ----------------------------------------------------
extern "C" void kernel_launch(void* const* d_in, const int* in_sizes, int n_in,
                              void* d_out, int out_size)
{
    const float* ref_pos    = (const float*)d_in[0];
    const float* ref_charge = (const float*)d_in[1];
    const float* ref_mask   = (const float*)d_in[2];
    const float* ref_elem   = (const float*)d_in[3];
    const float* ref_chars  = (const float*)d_in[4];
    const float* W_single   = (const float*)d_in[5];
    const float* W_pair     = (const float*)d_in[6];
    const float* W_outer    = (const float*)d_in[7];
    const float* Wp_ff1     = (const float*)d_in[8];
    const float* Wp_ff2     = (const float*)d_in[9];
    const float* Wq         = (const float*)d_in[10];
    const float* Wk         = (const float*)d_in[11];
    const float* Wv         = (const float*)d_in[12];
    const float* Wo         = (const float*)d_in[13];
    const float* Wb         = (const float*)d_in[14];
    const float* Wff1       = (const float*)d_in[15];
    const float* Wff2       = (const float*)d_in[16];
    const float* W_out      = (const float*)d_in[17];
    const int*   uid        = (const int*)d_in[18];
    const int*   a2t        = (const int*)d_in[19];
    float* out = (float*)d_out;

    float *feats, *x, *qkv, *o, *p, *tok;
    __nv_bfloat16 *bh, *bl;
    cudaGetSymbolAddress((void**)&feats, g_feats);
    cudaGetSymbolAddress((void**)&x,     g_x);
    cudaGetSymbolAddress((void**)&qkv,   g_qkv);
    cudaGetSymbolAddress((void**)&o,     g_o);
    cudaGetSymbolAddress((void**)&p,     g_p);
    cudaGetSymbolAddress((void**)&tok,   g_tok);
    cudaGetSymbolAddress((void**)&bh,    g_bh);
    cudaGetSymbolAddress((void**)&bl,    g_bl);

    const int WIDE_SMEM = (2*256*40 + 2*128*40) * 2;         // 61440 bytes
    const int FF_SMEM   = (4*128*40*4 + 2*128*40) * 2;       // 184320 bytes
    cudaFuncSetAttribute(mma_gemm_wide<false,3>, cudaFuncAttributeMaxDynamicSharedMemorySize, WIDE_SMEM);
    cudaFuncSetAttribute(embed_fused, cudaFuncAttributeMaxDynamicSharedMemorySize, FF_SMEM);
    cudaFuncSetAttribute(layer_fused<false>, cudaFuncAttributeMaxDynamicSharedMemorySize, FF_SMEM);
    cudaFuncSetAttribute(layer_fused<true>,  cudaFuncAttributeMaxDynamicSharedMemorySize, FF_SMEM);

    // 0) prep: weight pack + feats build (one launch)
    const int PB = (PACK_TOT + 255)/256;
    prep_kernel<<<PB + R_, 256>>>(W_single, Wq, Wk, Wv, Wo, Wff1, Wff2, W_out, W_outer,
                                  ref_pos, ref_charge, ref_mask, ref_elem, ref_chars);

    // 1) fused embed: x, p, qkv(layer 0)
    embed_fused<<<R_/128, 256, FF_SMEM>>>(feats,
        bh+OFF_EMB, bl+OFF_EMB, bh+OFF_WOUTER, bl+OFF_WOUTER,
        bh+OFF_QKV, bl+OFF_QKV, x, p, qkv);

    // 2) pair bias
    bias_kernel<<<B_*NW*2, 256>>>(ref_pos, uid, W_pair, Wp_ff1, Wp_ff2, Wb);

    // 3) transformer layers: attn -> layer_fused (WO+LN+FF+next QKV)
    for (int l = 0; l < DEPTH; l++) {
        attn_kernel<<<B_*NW*HEADS, 256>>>(qkv, o);
        if (l < DEPTH-1) {
            layer_fused<false><<<R_/128, 256, FF_SMEM>>>(o,
                bh+OFF_WO+(size_t)l*16384, bl+OFF_WO+(size_t)l*16384,
                bh+OFF_FF1+(size_t)l*65536, bl+OFF_FF1+(size_t)l*65536,
                bh+OFF_FF2+(size_t)l*65536, bl+OFF_FF2+(size_t)l*65536,
                bh+OFF_QKV+(size_t)(l+1)*49152, bl+OFF_QKV+(size_t)(l+1)*49152,
                x, qkv);
        } else {
            layer_fused<true><<<R_/128, 256, FF_SMEM>>>(o,
                bh+OFF_WO+(size_t)l*16384, bl+OFF_WO+(size_t)l*16384,
                bh+OFF_FF1+(size_t)l*65536, bl+OFF_FF1+(size_t)l*65536,
                bh+OFF_FF2+(size_t)l*65536, bl+OFF_FF2+(size_t)l*65536,
                nullptr, nullptr, x, nullptr);
        }
    }

    // 4) tok = relu(x @ W_out); segment mean -> out
    mma_gemm_wide<false,3><<<dim3(3, R_/256), 512, WIDE_SMEM>>>(x, nullptr, nullptr,
        bh+OFF_WOUT, bl+OFF_WOUT, tok, nullptr, nullptr, R_, DT, DS);
    segmean_kernel<<<B_*NTOK, 384>>>(a2t, out);
}

// round 12
// speedup vs baseline: 1.2277x; 1.0006x over previous
#include <cuda_runtime.h>
#include <cuda_bf16.h>
#include <math.h>

#define B_    2
#define N_    8192
#define R_    (B_*N_)          // 16384 rows
#define DS    128
#define DP    16
#define DT    384
#define NTOK  1024
#define QWIN  64
#define KWIN  128
#define PADW  32
#define NW    (N_/QWIN)        // 128 windows
#define HEADS 4
#define DH    32
#define DEPTH 3
#define KFEAT 389
#define KFP   416              // padded to multiple of 32

// packed bf16 weight offsets (hi/lo arrays, layout [N][Kp] row-major)
#define OFF_EMB    0           // 128 x 416
#define OFF_QKV    53248       // 3 layers x [Wq|Wk|Wv] 384 x 128
#define OFF_WO     200704      // 3 x 128 x 128
#define OFF_FF1    249856      // 3 x 512 x 128
#define OFF_FF2    446464      // 3 x 128 x 512
#define OFF_WOUT   643072      // 384 x 128
#define OFF_WOUTER 692224      // 128(pad from 32) x 128
#define PACK_TOT   708608

// ---------------- scratch (device globals: allocation-free) ----------------
__device__ float g_feats[(size_t)R_*KFP];
__device__ float g_x    [(size_t)R_*DS];
__device__ float g_qkv  [(size_t)R_*3*DS];
__device__ float g_o    [(size_t)R_*DS];
__device__ float g_p    [(size_t)R_*2*DP];
__device__ float g_bias [(size_t)B_*NW*HEADS*QWIN*KWIN];
__device__ float g_tok  [(size_t)R_*DT];
__device__ __nv_bfloat16 g_bh[PACK_TOT];
__device__ __nv_bfloat16 g_bl[PACK_TOT];

// ---------------- prep: weight pack (transpose + hi/lo split) + feats build -
__global__ void prep_kernel(const float* __restrict__ Ws, const float* __restrict__ Wq,
                            const float* __restrict__ Wk, const float* __restrict__ Wv,
                            const float* __restrict__ Wo, const float* __restrict__ W1,
                            const float* __restrict__ W2, const float* __restrict__ Wout,
                            const float* __restrict__ Wouter,
                            const float* __restrict__ pos, const float* __restrict__ charge,
                            const float* __restrict__ mask, const float* __restrict__ elem,
                            const float* __restrict__ chars)
{
    const int PB = (PACK_TOT + 255)/256;
    if ((int)blockIdx.x >= PB) {
        int row = blockIdx.x - PB;
        float* fr = g_feats + (size_t)row*KFP;
        for (int f = threadIdx.x; f < KFP; f += 256) {
            float v;
            if      (f < 3)    v = pos[row*3 + f];
            else if (f == 3)   v = charge[row];
            else if (f == 4)   v = mask[row];
            else if (f < 133)  v = elem[(size_t)row*128 + (f-5)];
            else if (f < KFEAT)v = chars[(size_t)row*256 + (f-133)];
            else               v = 0.f;
            fr[f] = v;
        }
        return;
    }
    long idx = (long)blockIdx.x*256 + threadIdx.x;
    if (idx >= PACK_TOT) return;
    float v;
    if (idx >= OFF_WOUTER) {
        long rem = idx - OFF_WOUTER;
        int n = (int)(rem / 128), k = (int)(rem % 128);
        v = (n < 32) ? Wouter[(size_t)k*32 + n] : 0.f;
    } else {
        const float* src; int K, N, Kp; long rem;
        if (idx < OFF_QKV)      { src = Ws;  K = KFEAT; N = 128; Kp = KFP; rem = idx; }
        else if (idx < OFF_WO)  { long r = idx - OFF_QKV; int l = (int)(r/49152); r %= 49152;
                                  int ws = (int)(r/16384); rem = r % 16384;
                                  src = (ws==0 ? Wq : ws==1 ? Wk : Wv) + (size_t)l*16384;
                                  K = 128; N = 128; Kp = 128; }
        else if (idx < OFF_FF1) { long r = idx - OFF_WO; int l = (int)(r/16384); rem = r % 16384;
                                  src = Wo + (size_t)l*16384; K = 128; N = 128; Kp = 128; }
        else if (idx < OFF_FF2) { long r = idx - OFF_FF1; int l = (int)(r/65536); rem = r % 65536;
                                  src = W1 + (size_t)l*65536; K = 128; N = 512; Kp = 128; }
        else if (idx < OFF_WOUT){ long r = idx - OFF_FF2; int l = (int)(r/65536); rem = r % 65536;
                                  src = W2 + (size_t)l*65536; K = 512; N = 128; Kp = 512; }
        else                    { rem = idx - OFF_WOUT; src = Wout; K = 128; N = 384; Kp = 128; }
        int n = (int)(rem / Kp), k = (int)(rem % Kp);
        v = (k < K) ? src[(size_t)k*N + n] : 0.f;
    }
    __nv_bfloat16 h = __float2bfloat16(v);
    g_bh[idx] = h;
    g_bl[idx] = __float2bfloat16(v - __bfloat162float(h));
}

// ---------------- mma helpers ------------------------------------------------
__device__ __forceinline__ void ldsm4(unsigned &r0, unsigned &r1, unsigned &r2, unsigned &r3,
                                      const __nv_bfloat16* p)
{
    unsigned a = (unsigned)__cvta_generic_to_shared(p);
    asm volatile("ldmatrix.sync.aligned.m8n8.x4.shared.b16 {%0,%1,%2,%3},[%4];"
                 : "=r"(r0), "=r"(r1), "=r"(r2), "=r"(r3) : "r"(a));
}
__device__ __forceinline__ void mma16816(float* d, const unsigned* a, unsigned b0, unsigned b1)
{
    asm volatile("mma.sync.aligned.m16n8k16.row.col.f32.bf16.bf16.f32 "
                 "{%0,%1,%2,%3},{%4,%5,%6,%7},{%8,%9},{%0,%1,%2,%3};"
                 : "+f"(d[0]), "+f"(d[1]), "+f"(d[2]), "+f"(d[3])
                 : "r"(a[0]), "r"(a[1]), "r"(a[2]), "r"(a[3]), "r"(b0), "r"(b1));
}

// shared 32-k-step mma over one A chunk + one B tile (both bf16-split, LD=40)
__device__ __forceinline__ void mma_chunk(float acc[2][8][4],
    const __nv_bfloat16* sXh, const __nv_bfloat16* sXl,
    const __nv_bfloat16* sBh, const __nv_bfloat16* sBl,
    int lane, int warpM, int warpN)
{
    constexpr int LD = 40;
    #pragma unroll
    for (int ks = 0; ks < 2; ks++) {
        int rowin = lane & 7, tile = lane >> 3;
        unsigned ah[2][4], al[2][4];
        #pragma unroll
        for (int mi = 0; mi < 2; mi++) {
            int r = warpM + mi*16 + (tile & 1)*8 + rowin;
            int c = ks*16 + (tile >> 1)*8;
            ldsm4(ah[mi][0], ah[mi][1], ah[mi][2], ah[mi][3], &sXh[r*LD + c]);
            ldsm4(al[mi][0], al[mi][1], al[mi][2], al[mi][3], &sXl[r*LD + c]);
        }
        #pragma unroll
        for (int np = 0; np < 4; np++) {
            int nrow = warpN + np*16 + (tile >> 1)*8 + rowin;
            int c = ks*16 + (tile & 1)*8;
            unsigned bh0, bh1, bh2, bh3, bl0, bl1, bl2, bl3;
            ldsm4(bh0, bh1, bh2, bh3, &sBh[nrow*LD + c]);
            ldsm4(bl0, bl1, bl2, bl3, &sBl[nrow*LD + c]);
            #pragma unroll
            for (int mi = 0; mi < 2; mi++) {
                mma16816(acc[mi][np*2],   ah[mi], bh0, bh1);
                mma16816(acc[mi][np*2],   al[mi], bh0, bh1);
                mma16816(acc[mi][np*2],   ah[mi], bl0, bl1);
                mma16816(acc[mi][np*2+1], ah[mi], bh2, bh3);
                mma16816(acc[mi][np*2+1], al[mi], bh2, bh3);
                mma16816(acc[mi][np*2+1], ah[mi], bl2, bl3);
            }
        }
    }
}

// ---------------- wide GEMM: BM=256, 512 threads, dynamic smem (W_out only) --
template<bool ABF16, int EPI>
__global__ void __launch_bounds__(512)
mma_gemm_wide(const float* __restrict__ A,
              const __nv_bfloat16* __restrict__ Agh, const __nv_bfloat16* __restrict__ Agl,
              const __nv_bfloat16* __restrict__ Bh,  const __nv_bfloat16* __restrict__ Bl,
              float* __restrict__ C,
              __nv_bfloat16* __restrict__ Hh, __nv_bfloat16* __restrict__ Hl,
              int M, int N, int K)
{
    constexpr int LD = 40;
    extern __shared__ __nv_bfloat16 dyns[];
    __nv_bfloat16* sAh = dyns;
    __nv_bfloat16* sAl = sAh + 256*LD;
    __nv_bfloat16* sBh = sAl + 256*LD;
    __nv_bfloat16* sBl = sBh + 128*LD;
    int tid = threadIdx.x, lane = tid & 31, warp = tid >> 5;
    int m0 = blockIdx.y*256, n0 = blockIdx.x*128;
    int warpM = (warp >> 1)*32, warpN = (warp & 1)*64;

    float acc[2][8][4] = {};
    float4 pa[4]; uint4 pah[2], pal[2], pbh, pbl;

    if (ABF16) {
        #pragma unroll
        for (int i = 0; i < 2; i++) {
            int idx = tid + i*512, row = idx >> 2, q = idx & 3;
            pah[i] = *(const uint4*)&Agh[(size_t)(m0+row)*K + q*8];
            pal[i] = *(const uint4*)&Agl[(size_t)(m0+row)*K + q*8];
        }
    } else {
        #pragma unroll
        for (int i = 0; i < 4; i++) {
            int idx = tid + i*512, row = idx >> 3, c4 = idx & 7;
            pa[i] = *(const float4*)&A[(size_t)(m0+row)*K + c4*4];
        }
    }
    {
        int row = tid >> 2, q = tid & 3;
        pbh = *(const uint4*)&Bh[(size_t)(n0+row)*K + q*8];
        pbl = *(const uint4*)&Bl[(size_t)(n0+row)*K + q*8];
    }

    int nt = K / 32;
    for (int t = 0; t < nt; t++) {
        __syncthreads();
        if (ABF16) {
            #pragma unroll
            for (int i = 0; i < 2; i++) {
                int idx = tid + i*512, row = idx >> 2, q = idx & 3;
                *(uint4*)&sAh[row*LD + q*8] = pah[i];
                *(uint4*)&sAl[row*LD + q*8] = pal[i];
            }
        } else {
            #pragma unroll
            for (int i = 0; i < 4; i++) {
                int idx = tid + i*512, row = idx >> 3, c = (idx & 7)*4;
                float4 v = pa[i];
                __nv_bfloat16 h0 = __float2bfloat16(v.x), h1 = __float2bfloat16(v.y);
                __nv_bfloat16 h2 = __float2bfloat16(v.z), h3 = __float2bfloat16(v.w);
                __nv_bfloat162 hh0; hh0.x = h0; hh0.y = h1;
                __nv_bfloat162 hh1; hh1.x = h2; hh1.y = h3;
                *(__nv_bfloat162*)&sAh[row*LD + c]     = hh0;
                *(__nv_bfloat162*)&sAh[row*LD + c + 2] = hh1;
                __nv_bfloat162 ll0, ll1;
                ll0.x = __float2bfloat16(v.x - __bfloat162float(h0));
                ll0.y = __float2bfloat16(v.y - __bfloat162float(h1));
                ll1.x = __float2bfloat16(v.z - __bfloat162float(h2));
                ll1.y = __float2bfloat16(v.w - __bfloat162float(h3));
                *(__nv_bfloat162*)&sAl[row*LD + c]     = ll0;
                *(__nv_bfloat162*)&sAl[row*LD + c + 2] = ll1;
            }
        }
        {
            int row = tid >> 2, q = tid & 3;
            *(uint4*)&sBh[row*LD + q*8] = pbh;
            *(uint4*)&sBl[row*LD + q*8] = pbl;
        }
        __syncthreads();
        if (t + 1 < nt) {
            int kc = (t+1)*32;
            if (ABF16) {
                #pragma unroll
                for (int i = 0; i < 2; i++) {
                    int idx = tid + i*512, row = idx >> 2, q = idx & 3;
                    pah[i] = *(const uint4*)&Agh[(size_t)(m0+row)*K + kc + q*8];
                    pal[i] = *(const uint4*)&Agl[(size_t)(m0+row)*K + kc + q*8];
                }
            } else {
                #pragma unroll
                for (int i = 0; i < 4; i++) {
                    int idx = tid + i*512, row = idx >> 3, c4 = idx & 7;
                    pa[i] = *(const float4*)&A[(size_t)(m0+row)*K + kc + c4*4];
                }
            }
            {
                int row = tid >> 2, q = tid & 3;
                pbh = *(const uint4*)&Bh[(size_t)(n0+row)*K + kc + q*8];
                pbl = *(const uint4*)&Bl[(size_t)(n0+row)*K + kc + q*8];
            }
        }
        mma_chunk(acc, sAh, sAl, sBh, sBl, lane, warpM, warpN);
    }

    #pragma unroll
    for (int mi = 0; mi < 2; mi++) {
        #pragma unroll
        for (int nj = 0; nj < 8; nj++) {
            int r0  = m0 + warpM + mi*16 + (lane >> 2);
            int col = n0 + warpN + nj*8 + (lane & 3)*2;
            float v0 = acc[mi][nj][0], v1 = acc[mi][nj][1];
            float v2 = acc[mi][nj][2], v3 = acc[mi][nj][3];
            if (EPI == 3) {
                v0 = fmaxf(v0, 0.f); v1 = fmaxf(v1, 0.f);
                v2 = fmaxf(v2, 0.f); v3 = fmaxf(v3, 0.f);
            }
            float2 o0; o0.x = v0; o0.y = v1;
            float2 o1; o1.x = v2; o1.y = v3;
            *(float2*)&C[(size_t)r0*N + col]     = o0;
            *(float2*)&C[(size_t)(r0+8)*N + col] = o1;
        }
    }
}

// ---------------- fused embed: x = feats@Wemb; LN; p = relu(x)@Wouter; qkv ---
__global__ void __launch_bounds__(256)
embed_fused(const float* __restrict__ feats,
            const __nv_bfloat16* __restrict__ Weh, const __nv_bfloat16* __restrict__ Wel,
            const __nv_bfloat16* __restrict__ Wph, const __nv_bfloat16* __restrict__ Wpl,
            const __nv_bfloat16* __restrict__ Qwh, const __nv_bfloat16* __restrict__ Qwl,
            float* __restrict__ X, float* __restrict__ Pout, float* __restrict__ qkvout)
{
    constexpr int LD = 40;
    constexpr int CH = 128*LD;
    extern __shared__ __nv_bfloat16 dyns[];
    __nv_bfloat16* sAh = dyns;
    __nv_bfloat16* sAl = sAh + 4*CH;
    __nv_bfloat16* sFh = sAl + 4*CH;
    __nv_bfloat16* sFl = sFh + 4*CH;
    __nv_bfloat16* sBh = sFl + 4*CH;
    __nv_bfloat16* sBl = sBh + CH;
    __shared__ float2 ssum[128][2];

    int tid = threadIdx.x, lane = tid & 31, warp = tid >> 5;
    int m0 = blockIdx.x*128;
    int warpM = (warp >> 1)*32, warpN = (warp & 1)*64;
    int brow = tid >> 2, bq = tid & 3;

    uint4 pbh[2], pbl[2];
    float4 pa[4];

    auto ln_stats = [&](float acc[2][8][4], float* mean, float* rsig) {
        float s[4] = {}, s2[4] = {};
        #pragma unroll
        for (int mi = 0; mi < 2; mi++)
            #pragma unroll
            for (int nj = 0; nj < 8; nj++) {
                float v0 = acc[mi][nj][0], v1 = acc[mi][nj][1];
                float v2 = acc[mi][nj][2], v3 = acc[mi][nj][3];
                s[mi*2]    += v0 + v1;      s2[mi*2]   += v0*v0 + v1*v1;
                s[mi*2+1]  += v2 + v3;      s2[mi*2+1] += v2*v2 + v3*v3;
            }
        #pragma unroll
        for (int off = 1; off <= 2; off <<= 1)
            #pragma unroll
            for (int r = 0; r < 4; r++) {
                s[r]  += __shfl_xor_sync(~0u, s[r],  off);
                s2[r] += __shfl_xor_sync(~0u, s2[r], off);
            }
        __syncthreads();
        if ((lane & 3) == 0) {
            #pragma unroll
            for (int slot = 0; slot < 4; slot++) {
                int row = warpM + (slot >> 1)*16 + (lane >> 2) + 8*(slot & 1);
                ssum[row][warp & 1] = make_float2(s[slot], s2[slot]);
            }
        }
        __syncthreads();
        #pragma unroll
        for (int slot = 0; slot < 4; slot++) {
            int row = warpM + (slot >> 1)*16 + (lane >> 2) + 8*(slot & 1);
            float2 a = ssum[row][0], b = ssum[row][1];
            float m  = (a.x + b.x) * (1.f/128.f);
            float vv = (a.y + b.y) * (1.f/128.f) - m*m;
            mean[slot] = m;
            rsig[slot] = rsqrtf(vv + 1e-5f);
        }
    };

    // ---- stage E: x = feats @ Wemb (K = 416 = 13 chunks), A fp32 on the fly
    float accE[2][8][4] = {};
    #pragma unroll
    for (int i = 0; i < 4; i++) {
        int idx = tid + i*256, row = idx >> 3, c4 = idx & 7;
        pa[i] = *(const float4*)&feats[(size_t)(m0+row)*KFP + c4*4];
    }
    pbh[0] = *(const uint4*)&Weh[(size_t)brow*KFP + bq*8];
    pbh[1] = *(const uint4*)&Weh[(size_t)(brow+64)*KFP + bq*8];
    pbl[0] = *(const uint4*)&Wel[(size_t)brow*KFP + bq*8];
    pbl[1] = *(const uint4*)&Wel[(size_t)(brow+64)*KFP + bq*8];

    #pragma unroll 1
    for (int t = 0; t < 13; t++) {
        __syncthreads();
        #pragma unroll
        for (int i = 0; i < 4; i++) {
            int idx = tid + i*256, row = idx >> 3, c = (idx & 7)*4;
            float4 v = pa[i];
            __nv_bfloat16 h0 = __float2bfloat16(v.x), h1 = __float2bfloat16(v.y);
            __nv_bfloat16 h2 = __float2bfloat16(v.z), h3 = __float2bfloat16(v.w);
            __nv_bfloat162 hh0; hh0.x = h0; hh0.y = h1;
            __nv_bfloat162 hh1; hh1.x = h2; hh1.y = h3;
            *(__nv_bfloat162*)&sFh[row*LD + c]     = hh0;
            *(__nv_bfloat162*)&sFh[row*LD + c + 2] = hh1;
            __nv_bfloat162 ll0, ll1;
            ll0.x = __float2bfloat16(v.x - __bfloat162float(h0));
            ll0.y = __float2bfloat16(v.y - __bfloat162float(h1));
            ll1.x = __float2bfloat16(v.z - __bfloat162float(h2));
            ll1.y = __float2bfloat16(v.w - __bfloat162float(h3));
            *(__nv_bfloat162*)&sFl[row*LD + c]     = ll0;
            *(__nv_bfloat162*)&sFl[row*LD + c + 2] = ll1;
        }
        *(uint4*)&sBh[brow*LD + bq*8]      = pbh[0];
        *(uint4*)&sBh[(brow+64)*LD + bq*8] = pbh[1];
        *(uint4*)&sBl[brow*LD + bq*8]      = pbl[0];
        *(uint4*)&sBl[(brow+64)*LD + bq*8] = pbl[1];
        __syncthreads();
        if (t + 1 < 13) {
            int kc = (t+1)*32;
            #pragma unroll
            for (int i = 0; i < 4; i++) {
                int idx = tid + i*256, row = idx >> 3, c4 = idx & 7;
                pa[i] = *(const float4*)&feats[(size_t)(m0+row)*KFP + kc + c4*4];
            }
            pbh[0] = *(const uint4*)&Weh[(size_t)brow*KFP + kc + bq*8];
            pbh[1] = *(const uint4*)&Weh[(size_t)(brow+64)*KFP + kc + bq*8];
            pbl[0] = *(const uint4*)&Wel[(size_t)brow*KFP + kc + bq*8];
            pbl[1] = *(const uint4*)&Wel[(size_t)(brow+64)*KFP + kc + bq*8];
        } else {
            pbh[0] = *(const uint4*)&Wph[(size_t)brow*128 + bq*8];
            pbh[1] = *(const uint4*)&Wph[(size_t)(brow+64)*128 + bq*8];
            pbl[0] = *(const uint4*)&Wpl[(size_t)brow*128 + bq*8];
            pbl[1] = *(const uint4*)&Wpl[(size_t)(brow+64)*128 + bq*8];
        }
        mma_chunk(accE, sFh, sFl, sBh, sBl, lane, warpM, warpN);
    }

    float mean[4], rsig[4];
    ln_stats(accE, mean, rsig);

    #pragma unroll
    for (int mi = 0; mi < 2; mi++) {
        #pragma unroll
        for (int nj = 0; nj < 8; nj++) {
            int r   = warpM + mi*16 + (lane >> 2);
            int col = warpN + nj*8 + (lane & 3)*2;
            int r0  = m0 + r;
            float v0 = accE[mi][nj][0], v1 = accE[mi][nj][1];
            float v2 = accE[mi][nj][2], v3 = accE[mi][nj][3];
            float2 o0; o0.x = v0; o0.y = v1;
            float2 o1; o1.x = v2; o1.y = v3;
            *(float2*)&X[(size_t)r0*128 + col]     = o0;
            *(float2*)&X[(size_t)(r0+8)*128 + col] = o1;
            int off = (col >> 5)*CH + (col & 31);
            {
                float a0 = fmaxf(v0,0.f), a1 = fmaxf(v1,0.f);
                float a2 = fmaxf(v2,0.f), a3 = fmaxf(v3,0.f);
                __nv_bfloat162 h0, h1, l0, l1;
                h0.x = __float2bfloat16(a0); h0.y = __float2bfloat16(a1);
                h1.x = __float2bfloat16(a2); h1.y = __float2bfloat16(a3);
                l0.x = __float2bfloat16(a0 - __bfloat162float(h0.x));
                l0.y = __float2bfloat16(a1 - __bfloat162float(h0.y));
                l1.x = __float2bfloat16(a2 - __bfloat162float(h1.x));
                l1.y = __float2bfloat16(a3 - __bfloat162float(h1.y));
                *(__nv_bfloat162*)&sFh[off + r*LD]     = h0;
                *(__nv_bfloat162*)&sFh[off + (r+8)*LD] = h1;
                *(__nv_bfloat162*)&sFl[off + r*LD]     = l0;
                *(__nv_bfloat162*)&sFl[off + (r+8)*LD] = l1;
            }
            {
                float a0 = (v0 - mean[mi*2])*rsig[mi*2];
                float a1 = (v1 - mean[mi*2])*rsig[mi*2];
                float a2 = (v2 - mean[mi*2+1])*rsig[mi*2+1];
                float a3 = (v3 - mean[mi*2+1])*rsig[mi*2+1];
                __nv_bfloat162 h0, h1, l0, l1;
                h0.x = __float2bfloat16(a0); h0.y = __float2bfloat16(a1);
                h1.x = __float2bfloat16(a2); h1.y = __float2bfloat16(a3);
                l0.x = __float2bfloat16(a0 - __bfloat162float(h0.x));
                l0.y = __float2bfloat16(a1 - __bfloat162float(h0.y));
                l1.x = __float2bfloat16(a2 - __bfloat162float(h1.x));
                l1.y = __float2bfloat16(a3 - __bfloat162float(h1.y));
                *(__nv_bfloat162*)&sAh[off + r*LD]     = h0;
                *(__nv_bfloat162*)&sAh[off + (r+8)*LD] = h1;
                *(__nv_bfloat162*)&sAl[off + r*LD]     = l0;
                *(__nv_bfloat162*)&sAl[off + (r+8)*LD] = l1;
            }
        }
    }

    // ---- stage P: p = relu(x) @ Wouter_pad (valid cols 0..31) ----
    {
        float accP[2][8][4] = {};
        #pragma unroll
        for (int t = 0; t < 4; t++) {
            __syncthreads();
            *(uint4*)&sBh[brow*LD + bq*8]      = pbh[0];
            *(uint4*)&sBh[(brow+64)*LD + bq*8] = pbh[1];
            *(uint4*)&sBl[brow*LD + bq*8]      = pbl[0];
            *(uint4*)&sBl[(brow+64)*LD + bq*8] = pbl[1];
            __syncthreads();
            if (t + 1 < 4) {
                int kc = (t+1)*32;
                pbh[0] = *(const uint4*)&Wph[(size_t)brow*128 + kc + bq*8];
                pbh[1] = *(const uint4*)&Wph[(size_t)(brow+64)*128 + kc + bq*8];
                pbl[0] = *(const uint4*)&Wpl[(size_t)brow*128 + kc + bq*8];
                pbl[1] = *(const uint4*)&Wpl[(size_t)(brow+64)*128 + kc + bq*8];
            } else {
                pbh[0] = *(const uint4*)&Qwh[(size_t)brow*128 + bq*8];
                pbh[1] = *(const uint4*)&Qwh[(size_t)(brow+64)*128 + bq*8];
                pbl[0] = *(const uint4*)&Qwl[(size_t)brow*128 + bq*8];
                pbl[1] = *(const uint4*)&Qwl[(size_t)(brow+64)*128 + bq*8];
            }
            mma_chunk(accP, sFh + t*CH, sFl + t*CH, sBh, sBl, lane, warpM, warpN);
        }
        if (warpN == 0) {
            #pragma unroll
            for (int mi = 0; mi < 2; mi++) {
                #pragma unroll
                for (int nj = 0; nj < 4; nj++) {
                    int r0  = m0 + warpM + mi*16 + (lane >> 2);
                    int col = nj*8 + (lane & 3)*2;
                    float2 o0; o0.x = accP[mi][nj][0]; o0.y = accP[mi][nj][1];
                    float2 o1; o1.x = accP[mi][nj][2]; o1.y = accP[mi][nj][3];
                    *(float2*)&Pout[(size_t)r0*32 + col]     = o0;
                    *(float2*)&Pout[(size_t)(r0+8)*32 + col] = o1;
                }
            }
        }
    }

    // ---- stage Q: qkv = h' @ Wqkv (3 N-blocks x 4 k-chunks) ----
    #pragma unroll 1
    for (int nb = 0; nb < 3; nb++) {
        float acc[2][8][4] = {};
        #pragma unroll
        for (int t = 0; t < 4; t++) {
            __syncthreads();
            *(uint4*)&sBh[brow*LD + bq*8]      = pbh[0];
            *(uint4*)&sBh[(brow+64)*LD + bq*8] = pbh[1];
            *(uint4*)&sBl[brow*LD + bq*8]      = pbl[0];
            *(uint4*)&sBl[(brow+64)*LD + bq*8] = pbl[1];
            __syncthreads();
            int ni = nb*4 + t + 1;
            if (ni < 12) {
                int nrow = (ni >> 2)*128, kc = (ni & 3)*32;
                pbh[0] = *(const uint4*)&Qwh[(size_t)(nrow + brow)*128 + kc + bq*8];
                pbh[1] = *(const uint4*)&Qwh[(size_t)(nrow + brow+64)*128 + kc + bq*8];
                pbl[0] = *(const uint4*)&Qwl[(size_t)(nrow + brow)*128 + kc + bq*8];
                pbl[1] = *(const uint4*)&Qwl[(size_t)(nrow + brow+64)*128 + kc + bq*8];
            }
            mma_chunk(acc, sAh + t*CH, sAl + t*CH, sBh, sBl, lane, warpM, warpN);
        }
        #pragma unroll
        for (int mi = 0; mi < 2; mi++) {
            #pragma unroll
            for (int nj = 0; nj < 8; nj++) {
                int r0  = m0 + warpM + mi*16 + (lane >> 2);
                int col = nb*128 + warpN + nj*8 + (lane & 3)*2;
                float2 o0; o0.x = acc[mi][nj][0]; o0.y = acc[mi][nj][1];
                float2 o1; o1.x = acc[mi][nj][2]; o1.y = acc[mi][nj][3];
                *(float2*)&qkvout[(size_t)r0*384 + col]     = o0;
                *(float2*)&qkvout[(size_t)(r0+8)*384 + col] = o1;
            }
        }
    }
}

// ---------------- fused layer tail: WO + res + LN + FF + (next QKV) ---------
template<bool LAST>
__global__ void __launch_bounds__(256)
layer_fused(const float* __restrict__ oin,
            const __nv_bfloat16* __restrict__ Woh, const __nv_bfloat16* __restrict__ Wol,
            const __nv_bfloat16* __restrict__ B1h, const __nv_bfloat16* __restrict__ B1l,
            const __nv_bfloat16* __restrict__ B2h, const __nv_bfloat16* __restrict__ B2l,
            const __nv_bfloat16* __restrict__ Qwh, const __nv_bfloat16* __restrict__ Qwl,
            float* __restrict__ X, float* __restrict__ qkvout)
{
    constexpr int LD = 40;
    constexpr int CH = 128*LD;
    extern __shared__ __nv_bfloat16 dyns[];
    __nv_bfloat16* sAh = dyns;
    __nv_bfloat16* sAl = sAh + 4*CH;
    __nv_bfloat16* sFh = sAl + 4*CH;
    __nv_bfloat16* sFl = sFh + 4*CH;
    __nv_bfloat16* sBh = sFl + 4*CH;
    __nv_bfloat16* sBl = sBh + CH;
    __shared__ float2 ssum[128][2];

    int tid = threadIdx.x, lane = tid & 31, warp = tid >> 5;
    int m0 = blockIdx.x*128;
    int warpM = (warp >> 1)*32, warpN = (warp & 1)*64;
    int brow = tid >> 2, bq = tid & 3;

    uint4 pbh[2], pbl[2];

    auto ln_stats = [&](float acc[2][8][4], float* mean, float* rsig) {
        float s[4] = {}, s2[4] = {};
        #pragma unroll
        for (int mi = 0; mi < 2; mi++)
            #pragma unroll
            for (int nj = 0; nj < 8; nj++) {
                float v0 = acc[mi][nj][0], v1 = acc[mi][nj][1];
                float v2 = acc[mi][nj][2], v3 = acc[mi][nj][3];
                s[mi*2]    += v0 + v1;      s2[mi*2]   += v0*v0 + v1*v1;
                s[mi*2+1]  += v2 + v3;      s2[mi*2+1] += v2*v2 + v3*v3;
            }
        #pragma unroll
        for (int off = 1; off <= 2; off <<= 1)
            #pragma unroll
            for (int r = 0; r < 4; r++) {
                s[r]  += __shfl_xor_sync(~0u, s[r],  off);
                s2[r] += __shfl_xor_sync(~0u, s2[r], off);
            }
        __syncthreads();
        if ((lane & 3) == 0) {
            #pragma unroll
            for (int slot = 0; slot < 4; slot++) {
                int row = warpM + (slot >> 1)*16 + (lane >> 2) + 8*(slot & 1);
                ssum[row][warp & 1] = make_float2(s[slot], s2[slot]);
            }
        }
        __syncthreads();
        #pragma unroll
        for (int slot = 0; slot < 4; slot++) {
            int row = warpM + (slot >> 1)*16 + (lane >> 2) + 8*(slot & 1);
            float2 a = ssum[row][0], b = ssum[row][1];
            float m  = (a.x + b.x) * (1.f/128.f);
            float vv = (a.y + b.y) * (1.f/128.f) - m*m;
            mean[slot] = m;
            rsig[slot] = rsqrtf(vv + 1e-5f);
        }
    };

    // ---- stage W: x_mid = x + o@Wo; LN -> h' in sA
    {
        #pragma unroll
        for (int i = 0; i < 16; i++) {
            int idx = tid + i*256;
            int row = idx >> 5, q = idx & 31;
            float4 v = *(const float4*)&oin[(size_t)(m0+row)*128 + q*4];
            int off = (q >> 3)*CH + row*LD + (q & 7)*4;
            __nv_bfloat162 h0, h1, l0, l1;
            h0.x = __float2bfloat16(v.x); h0.y = __float2bfloat16(v.y);
            h1.x = __float2bfloat16(v.z); h1.y = __float2bfloat16(v.w);
            l0.x = __float2bfloat16(v.x - __bfloat162float(h0.x));
            l0.y = __float2bfloat16(v.y - __bfloat162float(h0.y));
            l1.x = __float2bfloat16(v.z - __bfloat162float(h1.x));
            l1.y = __float2bfloat16(v.w - __bfloat162float(h1.y));
            *(__nv_bfloat162*)&sFh[off]     = h0;
            *(__nv_bfloat162*)&sFh[off + 2] = h1;
            *(__nv_bfloat162*)&sFl[off]     = l0;
            *(__nv_bfloat162*)&sFl[off + 2] = l1;
        }
        pbh[0] = *(const uint4*)&Woh[(size_t)brow*128 + bq*8];
        pbh[1] = *(const uint4*)&Woh[(size_t)(brow+64)*128 + bq*8];
        pbl[0] = *(const uint4*)&Wol[(size_t)brow*128 + bq*8];
        pbl[1] = *(const uint4*)&Wol[(size_t)(brow+64)*128 + bq*8];

        float accW[2][8][4] = {};
        #pragma unroll
        for (int t = 0; t < 4; t++) {
            __syncthreads();
            *(uint4*)&sBh[brow*LD + bq*8]      = pbh[0];
            *(uint4*)&sBh[(brow+64)*LD + bq*8] = pbh[1];
            *(uint4*)&sBl[brow*LD + bq*8]      = pbl[0];
            *(uint4*)&sBl[(brow+64)*LD + bq*8] = pbl[1];
            __syncthreads();
            if (t + 1 < 4) {
                int kc = (t+1)*32;
                pbh[0] = *(const uint4*)&Woh[(size_t)brow*128 + kc + bq*8];
                pbh[1] = *(const uint4*)&Woh[(size_t)(brow+64)*128 + kc + bq*8];
                pbl[0] = *(const uint4*)&Wol[(size_t)brow*128 + kc + bq*8];
                pbl[1] = *(const uint4*)&Wol[(size_t)(brow+64)*128 + kc + bq*8];
            } else {
                pbh[0] = *(const uint4*)&B1h[(size_t)brow*128 + bq*8];
                pbh[1] = *(const uint4*)&B1h[(size_t)(brow+64)*128 + bq*8];
                pbl[0] = *(const uint4*)&B1l[(size_t)brow*128 + bq*8];
                pbl[1] = *(const uint4*)&B1l[(size_t)(brow+64)*128 + bq*8];
            }
            mma_chunk(accW, sFh + t*CH, sFl + t*CH, sBh, sBl, lane, warpM, warpN);
        }
        #pragma unroll
        for (int mi = 0; mi < 2; mi++) {
            #pragma unroll
            for (int nj = 0; nj < 8; nj++) {
                int r0  = m0 + warpM + mi*16 + (lane >> 2);
                int col = warpN + nj*8 + (lane & 3)*2;
                float2 c0 = *(const float2*)&X[(size_t)r0*128 + col];
                float2 c1 = *(const float2*)&X[(size_t)(r0+8)*128 + col];
                accW[mi][nj][0] += c0.x; accW[mi][nj][1] += c0.y;
                accW[mi][nj][2] += c1.x; accW[mi][nj][3] += c1.y;
            }
        }
        float mean[4], rsig[4];
        ln_stats(accW, mean, rsig);
        #pragma unroll
        for (int mi = 0; mi < 2; mi++) {
            #pragma unroll
            for (int nj = 0; nj < 8; nj++) {
                int r   = warpM + mi*16 + (lane >> 2);
                int col = warpN + nj*8 + (lane & 3)*2;
                int r0  = m0 + r;
                float v0 = accW[mi][nj][0], v1 = accW[mi][nj][1];
                float v2 = accW[mi][nj][2], v3 = accW[mi][nj][3];
                float2 o0; o0.x = v0; o0.y = v1;
                float2 o1; o1.x = v2; o1.y = v3;
                *(float2*)&X[(size_t)r0*128 + col]     = o0;
                *(float2*)&X[(size_t)(r0+8)*128 + col] = o1;
                v0 = (v0 - mean[mi*2])*rsig[mi*2];
                v1 = (v1 - mean[mi*2])*rsig[mi*2];
                v2 = (v2 - mean[mi*2+1])*rsig[mi*2+1];
                v3 = (v3 - mean[mi*2+1])*rsig[mi*2+1];
                int off = (col >> 5)*CH + (col & 31);
                __nv_bfloat162 h0, h1, l0, l1;
                h0.x = __float2bfloat16(v0); h0.y = __float2bfloat16(v1);
                h1.x = __float2bfloat16(v2); h1.y = __float2bfloat16(v3);
                l0.x = __float2bfloat16(v0 - __bfloat162float(h0.x));
                l0.y = __float2bfloat16(v1 - __bfloat162float(h0.y));
                l1.x = __float2bfloat16(v2 - __bfloat162float(h1.x));
                l1.y = __float2bfloat16(v3 - __bfloat162float(h1.y));
                *(__nv_bfloat162*)&sAh[off + r*LD]     = h0;
                *(__nv_bfloat162*)&sAh[off + (r+8)*LD] = h1;
                *(__nv_bfloat162*)&sAl[off + r*LD]     = l0;
                *(__nv_bfloat162*)&sAl[off + (r+8)*LD] = l1;
            }
        }
    }

    // ---- FF stages ----
    auto bptr = [&](int i, int row, const __nv_bfloat16* b1, const __nv_bfloat16* b2)
        -> const __nv_bfloat16* {
        int c = i >> 3, t = i & 3;
        if (((i >> 2) & 1) == 0)
            return &b1[(size_t)(c*128 + row)*128 + t*32 + bq*8];
        else
            return &b2[(size_t)row*512 + c*128 + t*32 + bq*8];
    };

    float acc2[2][8][4] = {};
    #pragma unroll 1
    for (int c = 0; c < 4; c++) {
        float acc1[2][8][4] = {};
        #pragma unroll
        for (int t = 0; t < 4; t++) {
            __syncthreads();
            *(uint4*)&sBh[brow*LD + bq*8]      = pbh[0];
            *(uint4*)&sBh[(brow+64)*LD + bq*8] = pbh[1];
            *(uint4*)&sBl[brow*LD + bq*8]      = pbl[0];
            *(uint4*)&sBl[(brow+64)*LD + bq*8] = pbl[1];
            __syncthreads();
            int ni = c*8 + t + 1;
            pbh[0] = *(const uint4*)bptr(ni, brow,    B1h, B2h);
            pbh[1] = *(const uint4*)bptr(ni, brow+64, B1h, B2h);
            pbl[0] = *(const uint4*)bptr(ni, brow,    B1l, B2l);
            pbl[1] = *(const uint4*)bptr(ni, brow+64, B1l, B2l);
            mma_chunk(acc1, sAh + t*CH, sAl + t*CH, sBh, sBl, lane, warpM, warpN);
        }
        #pragma unroll
        for (int mi = 0; mi < 2; mi++) {
            #pragma unroll
            for (int nj = 0; nj < 8; nj++) {
                int r   = warpM + mi*16 + (lane >> 2);
                int col = warpN + nj*8 + (lane & 3)*2;
                int off = (col >> 5)*CH + (col & 31);
                float v0 = fmaxf(acc1[mi][nj][0], 0.f), v1 = fmaxf(acc1[mi][nj][1], 0.f);
                float v2 = fmaxf(acc1[mi][nj][2], 0.f), v3 = fmaxf(acc1[mi][nj][3], 0.f);
                __nv_bfloat162 h0, h1, l0, l1;
                h0.x = __float2bfloat16(v0); h0.y = __float2bfloat16(v1);
                h1.x = __float2bfloat16(v2); h1.y = __float2bfloat16(v3);
                l0.x = __float2bfloat16(v0 - __bfloat162float(h0.x));
                l0.y = __float2bfloat16(v1 - __bfloat162float(h0.y));
                l1.x = __float2bfloat16(v2 - __bfloat162float(h1.x));
                l1.y = __float2bfloat16(v3 - __bfloat162float(h1.y));
                *(__nv_bfloat162*)&sFh[off + r*LD]     = h0;
                *(__nv_bfloat162*)&sFh[off + (r+8)*LD] = h1;
                *(__nv_bfloat162*)&sFl[off + r*LD]     = l0;
                *(__nv_bfloat162*)&sFl[off + (r+8)*LD] = l1;
            }
        }
        #pragma unroll
        for (int t = 0; t < 4; t++) {
            __syncthreads();
            *(uint4*)&sBh[brow*LD + bq*8]      = pbh[0];
            *(uint4*)&sBh[(brow+64)*LD + bq*8] = pbh[1];
            *(uint4*)&sBl[brow*LD + bq*8]      = pbl[0];
            *(uint4*)&sBl[(brow+64)*LD + bq*8] = pbl[1];
            __syncthreads();
            int ni = c*8 + t + 5;
            if (ni < 32) {
                pbh[0] = *(const uint4*)bptr(ni, brow,    B1h, B2h);
                pbh[1] = *(const uint4*)bptr(ni, brow+64, B1h, B2h);
                pbl[0] = *(const uint4*)bptr(ni, brow,    B1l, B2l);
                pbl[1] = *(const uint4*)bptr(ni, brow+64, B1l, B2l);
            } else if (!LAST) {
                pbh[0] = *(const uint4*)&Qwh[(size_t)brow*128 + bq*8];
                pbh[1] = *(const uint4*)&Qwh[(size_t)(brow+64)*128 + bq*8];
                pbl[0] = *(const uint4*)&Qwl[(size_t)brow*128 + bq*8];
                pbl[1] = *(const uint4*)&Qwl[(size_t)(brow+64)*128 + bq*8];
            }
            mma_chunk(acc2, sFh + t*CH, sFl + t*CH, sBh, sBl, lane, warpM, warpN);
        }
    }

    #pragma unroll
    for (int mi = 0; mi < 2; mi++) {
        #pragma unroll
        for (int nj = 0; nj < 8; nj++) {
            int r0  = m0 + warpM + mi*16 + (lane >> 2);
            int col = warpN + nj*8 + (lane & 3)*2;
            float2 c0 = *(const float2*)&X[(size_t)r0*128 + col];
            float2 c1 = *(const float2*)&X[(size_t)(r0+8)*128 + col];
            acc2[mi][nj][0] += c0.x; acc2[mi][nj][1] += c0.y;
            acc2[mi][nj][2] += c1.x; acc2[mi][nj][3] += c1.y;
        }
    }

    float mean[4], rsig[4];
    if (!LAST) ln_stats(acc2, mean, rsig);

    #pragma unroll
    for (int mi = 0; mi < 2; mi++) {
        #pragma unroll
        for (int nj = 0; nj < 8; nj++) {
            int r   = warpM + mi*16 + (lane >> 2);
            int col = warpN + nj*8 + (lane & 3)*2;
            int r0  = m0 + r;
            float v0 = acc2[mi][nj][0], v1 = acc2[mi][nj][1];
            float v2 = acc2[mi][nj][2], v3 = acc2[mi][nj][3];
            float2 o0; o0.x = v0; o0.y = v1;
            float2 o1; o1.x = v2; o1.y = v3;
            *(float2*)&X[(size_t)r0*128 + col]     = o0;
            *(float2*)&X[(size_t)(r0+8)*128 + col] = o1;
            if (!LAST) {
                v0 = (v0 - mean[mi*2])*rsig[mi*2];
                v1 = (v1 - mean[mi*2])*rsig[mi*2];
                v2 = (v2 - mean[mi*2+1])*rsig[mi*2+1];
                v3 = (v3 - mean[mi*2+1])*rsig[mi*2+1];
                int off = (col >> 5)*CH + (col & 31);
                __nv_bfloat162 h0, h1, l0, l1;
                h0.x = __float2bfloat16(v0); h0.y = __float2bfloat16(v1);
                h1.x = __float2bfloat16(v2); h1.y = __float2bfloat16(v3);
                l0.x = __float2bfloat16(v0 - __bfloat162float(h0.x));
                l0.y = __float2bfloat16(v1 - __bfloat162float(h0.y));
                l1.x = __float2bfloat16(v2 - __bfloat162float(h1.x));
                l1.y = __float2bfloat16(v3 - __bfloat162float(h1.y));
                *(__nv_bfloat162*)&sAh[off + r*LD]     = h0;
                *(__nv_bfloat162*)&sAh[off + (r+8)*LD] = h1;
                *(__nv_bfloat162*)&sAl[off + r*LD]     = l0;
                *(__nv_bfloat162*)&sAl[off + (r+8)*LD] = l1;
            }
        }
    }

    if (!LAST) {
        #pragma unroll 1
        for (int nb = 0; nb < 3; nb++) {
            float acc[2][8][4] = {};
            #pragma unroll
            for (int t = 0; t < 4; t++) {
                __syncthreads();
                *(uint4*)&sBh[brow*LD + bq*8]      = pbh[0];
                *(uint4*)&sBh[(brow+64)*LD + bq*8] = pbh[1];
                *(uint4*)&sBl[brow*LD + bq*8]      = pbl[0];
                *(uint4*)&sBl[(brow+64)*LD + bq*8] = pbl[1];
                __syncthreads();
                int ni = nb*4 + t + 1;
                if (ni < 12) {
                    int nrow = (ni >> 2)*128, kc = (ni & 3)*32;
                    pbh[0] = *(const uint4*)&Qwh[(size_t)(nrow + brow)*128 + kc + bq*8];
                    pbh[1] = *(const uint4*)&Qwh[(size_t)(nrow + brow+64)*128 + kc + bq*8];
                    pbl[0] = *(const uint4*)&Qwl[(size_t)(nrow + brow)*128 + kc + bq*8];
                    pbl[1] = *(const uint4*)&Qwl[(size_t)(nrow + brow+64)*128 + kc + bq*8];
                }
                mma_chunk(acc, sAh + t*CH, sAl + t*CH, sBh, sBl, lane, warpM, warpN);
            }
            #pragma unroll
            for (int mi = 0; mi < 2; mi++) {
                #pragma unroll
                for (int nj = 0; nj < 8; nj++) {
                    int r0  = m0 + warpM + mi*16 + (lane >> 2);
                    int col = nb*128 + warpN + nj*8 + (lane & 3)*2;
                    float2 o0; o0.x = acc[mi][nj][0]; o0.y = acc[mi][nj][1];
                    float2 o1; o1.x = acc[mi][nj][2]; o1.y = acc[mi][nj][3];
                    *(float2*)&qkvout[(size_t)r0*384 + col]     = o0;
                    *(float2*)&qkvout[(size_t)(r0+8)*384 + col] = o1;
                }
            }
        }
    }
}

// ---------------- fused pair-feature -> LN -> FF -> head bias ---------------
__global__ void __launch_bounds__(256)
bias_kernel(const float* __restrict__ pos, const int* __restrict__ uid,
            const float* __restrict__ Wp, const float* __restrict__ W1,
            const float* __restrict__ W2, const float* __restrict__ Wb)
{
    __shared__ float sposi[32][3], sposj[KWIN][3];
    __shared__ int   suidi[32],    suidj[KWIN];
    __shared__ float4 spi4[32][4], spj4[KWIN][4];
    __shared__ float sWp[80], sWb[64];
    __shared__ float4 sW1T[64][4];
    __shared__ float4 sW2b[64];
    __shared__ unsigned char svalid[KWIN];

    int bb = blockIdx.x;
    int half = bb & 1;
    int bw = bb >> 1;
    int b = bw / NW, w = bw % NW;
    int q0 = half*32;
    int tid = threadIdx.x;

    for (int i = tid; i < 80; i += 256) sWp[i] = Wp[i];
    for (int i = tid; i < 64; i += 256) sWb[i] = Wb[i];
    for (int i = tid; i < 1024; i += 256) {
        int j = i >> 4, c = i & 15;
        ((float*)sW1T)[j*16 + c] = W1[c*64 + j];
    }
    if (tid < 64) {
        float4 r = make_float4(0,0,0,0);
        #pragma unroll
        for (int c = 0; c < 16; c++) {
            float w2v = W2[tid*16 + c];
            r.x += w2v*Wb[c*4+0]; r.y += w2v*Wb[c*4+1];
            r.z += w2v*Wb[c*4+2]; r.w += w2v*Wb[c*4+3];
        }
        sW2b[tid] = r;
    }
    for (int q = tid; q < 32; q += 256) {
        int gi = b*N_ + w*QWIN + q0 + q;
        sposi[q][0] = pos[gi*3]; sposi[q][1] = pos[gi*3+1]; sposi[q][2] = pos[gi*3+2];
        suidi[q] = uid[gi];
        const float4* pp = (const float4*)&g_p[(size_t)gi*32];
        spi4[q][0] = pp[0]; spi4[q][1] = pp[1]; spi4[q][2] = pp[2]; spi4[q][3] = pp[3];
    }
    for (int k = tid; k < KWIN; k += 256) {
        int j = w*QWIN + k - PADW;
        bool valid = (j >= 0 && j < N_);
        svalid[k] = valid;
        if (valid) {
            int gj = b*N_ + j;
            sposj[k][0] = pos[gj*3]; sposj[k][1] = pos[gj*3+1]; sposj[k][2] = pos[gj*3+2];
            suidj[k] = uid[gj];
            const float4* pp = (const float4*)&g_p[(size_t)gj*32 + 16];
            spj4[k][0] = pp[0]; spj4[k][1] = pp[1]; spj4[k][2] = pp[2]; spj4[k][3] = pp[3];
        } else {
            sposj[k][0] = sposj[k][1] = sposj[k][2] = 0.f; suidj[k] = -1;
            float4 z = make_float4(0,0,0,0);
            spj4[k][0] = z; spj4[k][1] = z; spj4[k][2] = z; spj4[k][3] = z;
        }
    }
    __syncthreads();

    float* brow = g_bias + (size_t)bw*HEADS*QWIN*KWIN;

    auto prep = [&](int q, int k, float4* u, float& bh0, float& bh1, float& bh2, float& bh3) {
        float dx = sposi[q][0]-sposj[k][0];
        float dy = sposi[q][1]-sposj[k][1];
        float dz = sposi[q][2]-sposj[k][2];
        float inv = 1.f / (1.f + dx*dx + dy*dy + dz*dz);
        float bij = (suidi[q] == suidj[k]) ? 1.f : 0.f;
        float4 pr[4];
        #pragma unroll
        for (int c4 = 0; c4 < 4; c4++) {
            float4 r;
            #pragma unroll
            for (int e = 0; e < 4; e++) {
                int c = c4*4 + e;
                float base = dx*sWp[c] + dy*sWp[16+c] + dz*sWp[32+c] + inv*sWp[48+c] + sWp[64+c];
                (&r.x)[e] = base*bij + (&spi4[q][c4].x)[e] + (&spj4[k][c4].x)[e];
            }
            pr[c4] = r;
        }
        float s = 0.f, s2 = 0.f;
        #pragma unroll
        for (int c4 = 0; c4 < 4; c4++) {
            s  += pr[c4].x + pr[c4].y + pr[c4].z + pr[c4].w;
            s2 += pr[c4].x*pr[c4].x + pr[c4].y*pr[c4].y + pr[c4].z*pr[c4].z + pr[c4].w*pr[c4].w;
        }
        float mean = s * (1.f/DP);
        float var  = s2 * (1.f/DP) - mean*mean;
        float rinv = rsqrtf(var + 1e-5f);
        bh0 = bh1 = bh2 = bh3 = 0.f;
        #pragma unroll
        for (int c4 = 0; c4 < 4; c4++) {
            #pragma unroll
            for (int e = 0; e < 4; e++) {
                int c = c4*4 + e;
                float pv = (&pr[c4].x)[e];
                bh0 += pv*sWb[c*4+0]; bh1 += pv*sWb[c*4+1];
                bh2 += pv*sWb[c*4+2]; bh3 += pv*sWb[c*4+3];
                (&u[c4].x)[e] = (pv - mean)*rinv;
            }
        }
    };

    for (int t = tid; t < 32*64; t += 256) {
        int q = t >> 6, k0 = t & 63, k1 = k0 + 64;
        int gq = q0 + q;
        float4 u0[4], u1[4];
        float a0,a1,a2,a3, c0,c1,c2,c3;
        prep(q, k0, u0, a0, a1, a2, a3);
        prep(q, k1, u1, c0, c1, c2, c3);
        #pragma unroll 2
        for (int j = 0; j < 64; j++) {
            float4 w0 = sW1T[j][0], w1 = sW1T[j][1], w2 = sW1T[j][2], w3 = sW1T[j][3];
            float t0 = u0[0].x*w0.x + u0[0].y*w0.y + u0[0].z*w0.z + u0[0].w*w0.w
                     + u0[1].x*w1.x + u0[1].y*w1.y + u0[1].z*w1.z + u0[1].w*w1.w
                     + u0[2].x*w2.x + u0[2].y*w2.y + u0[2].z*w2.z + u0[2].w*w2.w
                     + u0[3].x*w3.x + u0[3].y*w3.y + u0[3].z*w3.z + u0[3].w*w3.w;
            float t1 = u1[0].x*w0.x + u1[0].y*w0.y + u1[0].z*w0.z + u1[0].w*w0.w
                     + u1[1].x*w1.x + u1[1].y*w1.y + u1[1].z*w1.z + u1[1].w*w1.w
                     + u1[2].x*w2.x + u1[2].y*w2.y + u1[2].z*w2.z + u1[2].w*w2.w
                     + u1[3].x*w3.x + u1[3].y*w3.y + u1[3].z*w3.z + u1[3].w*w3.w;
            t0 = fmaxf(t0, 0.f); t1 = fmaxf(t1, 0.f);
            float4 wb2 = sW2b[j];
            a0 += t0*wb2.x; a1 += t0*wb2.y; a2 += t0*wb2.z; a3 += t0*wb2.w;
            c0 += t1*wb2.x; c1 += t1*wb2.y; c2 += t1*wb2.z; c3 += t1*wb2.w;
        }
        bool v0 = svalid[k0], v1 = svalid[k1];
        brow[((0*QWIN + gq) << 7) + k0] = v0 ? a0 : 0.f;
        brow[((1*QWIN + gq) << 7) + k0] = v0 ? a1 : 0.f;
        brow[((2*QWIN + gq) << 7) + k0] = v0 ? a2 : 0.f;
        brow[((3*QWIN + gq) << 7) + k0] = v0 ? a3 : 0.f;
        brow[((0*QWIN + gq) << 7) + k1] = v1 ? c0 : 0.f;
        brow[((1*QWIN + gq) << 7) + k1] = v1 ? c1 : 0.f;
        brow[((2*QWIN + gq) << 7) + k1] = v1 ? c2 : 0.f;
        brow[((3*QWIN + gq) << 7) + k1] = v1 ? c3 : 0.f;
    }
}

// ---------------- attention per (b, window, head): lane-parallel -------------
// q staged in smem (kills 64-reg q arrays); swizzle/mask math hoisted.
__global__ void __launch_bounds__(256, 4)
attn_kernel(const float* __restrict__ qkv, float* __restrict__ o)
{
    __shared__ float4 ks4[KWIN][8];
    __shared__ float4 vs4[KWIN][8];
    __shared__ float4 sq[QWIN][8];
    __shared__ float  ps[8][2][KWIN];

    int h  = blockIdx.x & 3;
    int bw = blockIdx.x >> 2;
    int w  = bw & (NW-1);
    int b  = bw >> 7;
    int tid = threadIdx.x, lane = tid & 31, warp = tid >> 5;
    int rowbase = b*N_ + w*QWIN;

    for (int s = tid; s < KWIN*8; s += 256) {
        int kk = s >> 3, i = s & 7;
        int j = w*QWIN + kk - PADW;
        float4 kv = make_float4(0,0,0,0), vv = make_float4(0,0,0,0);
        if (j >= 0 && j < N_) {
            const float* base = &qkv[(size_t)(b*N_ + j)*384 + h*32 + i*4];
            kv = *(const float4*)(base + 128);
            vv = *(const float4*)(base + 256);
        }
        int sw = i ^ (kk & 7);
        ks4[kk][sw] = kv;
        vs4[kk][sw] = vv;
    }
    for (int s = tid; s < QWIN*8; s += 256) {
        int r = s >> 3, i = s & 7;
        sq[r][i] = *(const float4*)&qkv[(size_t)(rowbase + r)*384 + h*32 + i*4];
    }
    __syncthreads();

    const float scale = 0.17677669529663687f;
    const float* brow = g_bias + ((size_t)bw*HEADS + h)*QWIN*KWIN;
    int lane7 = lane & 7;
    int lhi = lane >> 2, llo = lane & 3;
    const float4* kbase = &ks4[lane][0];          // + g*256 + sw
    const float*  vbase = (const float*)vs4;

    // hoisted mask (per-thread constant across passes)
    float msk[4];
    #pragma unroll
    for (int g = 0; g < 4; g++) {
        int j = w*QWIN + g*32 + lane - PADW;
        msk[g] = (j >= 0 && j < N_) ? 0.f : -1e9f;
    }
    // hoisted PV swizzle offsets
    int voff[8];
    #pragma unroll
    for (int t = 0; t < 8; t++) voff[t] = ((lhi ^ t) << 2) | llo;

    for (int pass = 0; pass < 4; pass++) {
        int rA = warp*8 + pass*2, rB = rA + 1;
        float4 aA[4], aB[4];
        #pragma unroll
        for (int g = 0; g < 4; g++) { aA[g] = make_float4(0,0,0,0); aB[g] = make_float4(0,0,0,0); }
        #pragma unroll
        for (int i = 0; i < 8; i++) {
            float4 qa = sq[rA][i];
            float4 qb = sq[rB][i];
            int sw = i ^ lane7;
            #pragma unroll
            for (int g = 0; g < 4; g++) {
                float4 kv = kbase[g*256 + sw];
                aA[g].x += qa.x*kv.x; aA[g].y += qa.y*kv.y;
                aA[g].z += qa.z*kv.z; aA[g].w += qa.w*kv.w;
                aB[g].x += qb.x*kv.x; aB[g].y += qb.y*kv.y;
                aB[g].z += qb.z*kv.z; aB[g].w += qb.w*kv.w;
            }
        }
        float lA[4], lB[4];
        float mA = -1e30f, mB = -1e30f;
        #pragma unroll
        for (int g = 0; g < 4; g++) {
            int kk = g*32 + lane;
            lA[g] = ((aA[g].x+aA[g].y)+(aA[g].z+aA[g].w))*scale + brow[(rA<<7)+kk] + msk[g];
            lB[g] = ((aB[g].x+aB[g].y)+(aB[g].z+aB[g].w))*scale + brow[(rB<<7)+kk] + msk[g];
            mA = fmaxf(mA, lA[g]); mB = fmaxf(mB, lB[g]);
        }
        #pragma unroll
        for (int off = 16; off > 0; off >>= 1) {
            mA = fmaxf(mA, __shfl_xor_sync(~0u, mA, off));
            mB = fmaxf(mB, __shfl_xor_sync(~0u, mB, off));
        }
        float sA = 0.f, sB = 0.f, eA[4], eB[4];
        #pragma unroll
        for (int g = 0; g < 4; g++) {
            eA[g] = __expf(lA[g]-mA); sA += eA[g];
            eB[g] = __expf(lB[g]-mB); sB += eB[g];
        }
        #pragma unroll
        for (int off = 16; off > 0; off >>= 1) {
            sA += __shfl_xor_sync(~0u, sA, off);
            sB += __shfl_xor_sync(~0u, sB, off);
        }
        float rsA = 1.f/sA, rsB = 1.f/sB;
        #pragma unroll
        for (int g = 0; g < 4; g++) {
            ps[warp][0][g*32+lane] = eA[g]*rsA;
            ps[warp][1][g*32+lane] = eB[g]*rsB;
        }
        __syncwarp();
        float oA = 0.f, oB = 0.f;
        #pragma unroll 2
        for (int k8 = 0; k8 < 16; k8++) {
            const float* vb = vbase + k8*256;
            float4 pA0 = *(const float4*)&ps[warp][0][k8*8];
            float4 pA1 = *(const float4*)&ps[warp][0][k8*8+4];
            float4 pB0 = *(const float4*)&ps[warp][1][k8*8];
            float4 pB1 = *(const float4*)&ps[warp][1][k8*8+4];
            float v0 = vb[voff[0]],        v1 = vb[32  + voff[1]];
            float v2 = vb[64  + voff[2]],  v3 = vb[96  + voff[3]];
            float v4 = vb[128 + voff[4]],  v5 = vb[160 + voff[5]];
            float v6 = vb[192 + voff[6]],  v7 = vb[224 + voff[7]];
            oA += pA0.x*v0 + pA0.y*v1 + pA0.z*v2 + pA0.w*v3
                + pA1.x*v4 + pA1.y*v5 + pA1.z*v6 + pA1.w*v7;
            oB += pB0.x*v0 + pB0.y*v1 + pB0.z*v2 + pB0.w*v3
                + pB1.x*v4 + pB1.y*v5 + pB1.z*v6 + pB1.w*v7;
        }
        o[(size_t)(rowbase+rA)*DS + h*32 + lane] = oA;
        o[(size_t)(rowbase+rB)*DS + h*32 + lane] = oB;
        __syncwarp();
    }
}

// ---------------- deterministic segment mean (indices sorted) ---------------
__global__ void segmean_kernel(const int* __restrict__ a2t, float* __restrict__ out)
{
    int bt = blockIdx.x;
    int b = bt / NTOK, t = bt % NTOK;
    const int* idx = a2t + b*N_;
    __shared__ int slo, shi;
    if (threadIdx.x == 0) {
        int lo = 0, hi = N_;
        while (lo < hi) { int mid = (lo+hi) >> 1; if (idx[mid] < t) lo = mid+1; else hi = mid; }
        slo = lo;
        int lo2 = lo, hi2 = N_;
        while (lo2 < hi2) { int mid = (lo2+hi2) >> 1; if (idx[mid] < t+1) lo2 = mid+1; else hi2 = mid; }
        shi = lo2;
    }
    __syncthreads();
    int lo = slo, hi = shi;
    float rcnt = 1.f / fmaxf((float)(hi - lo), 1.f);
    for (int d = threadIdx.x; d < DT; d += blockDim.x) {
        float ssum = 0.f;
        for (int i = lo; i < hi; i++) ssum += g_tok[((size_t)(b*N_ + i))*DT + d];
        out[(size_t)bt*DT + d] = ssum * rcnt;
    }
}

// ---------------- launch ----------------------------------------------------
extern "C" void kernel_launch(void* const* d_in, const int* in_sizes, int n_in,
                              void* d_out, int out_size)
{
    const float* ref_pos    = (const float*)d_in[0];
    const float* ref_charge = (const float*)d_in[1];
    const float* ref_mask   = (const float*)d_in[2];
    const float* ref_elem   = (const float*)d_in[3];
    const float* ref_chars  = (const float*)d_in[4];
    const float* W_single   = (const float*)d_in[5];
    const float* W_pair     = (const float*)d_in[6];
    const float* W_outer    = (const float*)d_in[7];
    const float* Wp_ff1     = (const float*)d_in[8];
    const float* Wp_ff2     = (const float*)d_in[9];
    const float* Wq         = (const float*)d_in[10];
    const float* Wk         = (const float*)d_in[11];
    const float* Wv         = (const float*)d_in[12];
    const float* Wo         = (const float*)d_in[13];
    const float* Wb         = (const float*)d_in[14];
    const float* Wff1       = (const float*)d_in[15];
    const float* Wff2       = (const float*)d_in[16];
    const float* W_out      = (const float*)d_in[17];
    const int*   uid        = (const int*)d_in[18];
    const int*   a2t        = (const int*)d_in[19];
    float* out = (float*)d_out;

    float *feats, *x, *qkv, *o, *p, *tok;
    __nv_bfloat16 *bh, *bl;
    cudaGetSymbolAddress((void**)&feats, g_feats);
    cudaGetSymbolAddress((void**)&x,     g_x);
    cudaGetSymbolAddress((void**)&qkv,   g_qkv);
    cudaGetSymbolAddress((void**)&o,     g_o);
    cudaGetSymbolAddress((void**)&p,     g_p);
    cudaGetSymbolAddress((void**)&tok,   g_tok);
    cudaGetSymbolAddress((void**)&bh,    g_bh);
    cudaGetSymbolAddress((void**)&bl,    g_bl);

    const int WIDE_SMEM = (2*256*40 + 2*128*40) * 2;         // 61440 bytes
    const int FF_SMEM   = (4*128*40*4 + 2*128*40) * 2;       // 184320 bytes
    cudaFuncSetAttribute(mma_gemm_wide<false,3>, cudaFuncAttributeMaxDynamicSharedMemorySize, WIDE_SMEM);
    cudaFuncSetAttribute(embed_fused, cudaFuncAttributeMaxDynamicSharedMemorySize, FF_SMEM);
    cudaFuncSetAttribute(layer_fused<false>, cudaFuncAttributeMaxDynamicSharedMemorySize, FF_SMEM);
    cudaFuncSetAttribute(layer_fused<true>,  cudaFuncAttributeMaxDynamicSharedMemorySize, FF_SMEM);

    // 0) prep: weight pack + feats build (one launch)
    const int PB = (PACK_TOT + 255)/256;
    prep_kernel<<<PB + R_, 256>>>(W_single, Wq, Wk, Wv, Wo, Wff1, Wff2, W_out, W_outer,
                                  ref_pos, ref_charge, ref_mask, ref_elem, ref_chars);

    // 1) fused embed: x, p, qkv(layer 0)
    embed_fused<<<R_/128, 256, FF_SMEM>>>(feats,
        bh+OFF_EMB, bl+OFF_EMB, bh+OFF_WOUTER, bl+OFF_WOUTER,
        bh+OFF_QKV, bl+OFF_QKV, x, p, qkv);

    // 2) pair bias
    bias_kernel<<<B_*NW*2, 256>>>(ref_pos, uid, W_pair, Wp_ff1, Wp_ff2, Wb);

    // 3) transformer layers: attn -> layer_fused (WO+LN+FF+next QKV)
    for (int l = 0; l < DEPTH; l++) {
        attn_kernel<<<B_*NW*HEADS, 256>>>(qkv, o);
        if (l < DEPTH-1) {
            layer_fused<false><<<R_/128, 256, FF_SMEM>>>(o,
                bh+OFF_WO+(size_t)l*16384, bl+OFF_WO+(size_t)l*16384,
                bh+OFF_FF1+(size_t)l*65536, bl+OFF_FF1+(size_t)l*65536,
                bh+OFF_FF2+(size_t)l*65536, bl+OFF_FF2+(size_t)l*65536,
                bh+OFF_QKV+(size_t)(l+1)*49152, bl+OFF_QKV+(size_t)(l+1)*49152,
                x, qkv);
        } else {
            layer_fused<true><<<R_/128, 256, FF_SMEM>>>(o,
                bh+OFF_WO+(size_t)l*16384, bl+OFF_WO+(size_t)l*16384,
                bh+OFF_FF1+(size_t)l*65536, bl+OFF_FF1+(size_t)l*65536,
                bh+OFF_FF2+(size_t)l*65536, bl+OFF_FF2+(size_t)l*65536,
                nullptr, nullptr, x, nullptr);
        }
    }

    // 4) tok = relu(x @ W_out); segment mean -> out
    mma_gemm_wide<false,3><<<dim3(3, R_/256), 512, WIDE_SMEM>>>(x, nullptr, nullptr,
        bh+OFF_WOUT, bl+OFF_WOUT, tok, nullptr, nullptr, R_, DT, DS);
    segmean_kernel<<<B_*NTOK, 384>>>(a2t, out);
}

// round 13
// speedup vs baseline: 1.3015x; 1.0601x over previous
#include <cuda_runtime.h>
#include <cuda_bf16.h>
#include <math.h>

#define B_    2
#define N_    8192
#define R_    (B_*N_)          // 16384 rows
#define DS    128
#define DP    16
#define DT    384
#define NTOK  1024
#define QWIN  64
#define KWIN  128
#define PADW  32
#define NW    (N_/QWIN)        // 128 windows
#define HEADS 4
#define DH    32
#define DEPTH 3
#define KFEAT 389
#define KFP   416              // padded to multiple of 32

// packed bf16 weight offsets (hi/lo arrays, layout [N][Kp] row-major)
#define OFF_EMB    0           // 128 x 416
#define OFF_QKV    53248       // 3 layers x [Wq|Wk|Wv] 384 x 128
#define OFF_WO     200704      // 3 x 128 x 128
#define OFF_FF1    249856      // 3 x 512 x 128
#define OFF_FF2    446464      // 3 x 128 x 512
#define OFF_WOUT   643072      // 384 x 128
#define OFF_WOUTER 692224      // 128(pad from 32) x 128
#define PACK_TOT   708608

// ---------------- scratch (device globals: allocation-free) ----------------
__device__ float g_feats[(size_t)R_*KFP];
__device__ float g_x    [(size_t)R_*DS];
__device__ float g_qkv  [(size_t)R_*3*DS];
__device__ float g_o    [(size_t)R_*DS];
__device__ float g_p    [(size_t)R_*2*DP];
__device__ float g_bias [(size_t)B_*NW*HEADS*QWIN*KWIN];
__device__ float g_tok  [(size_t)R_*DT];
__device__ __nv_bfloat16 g_bh[PACK_TOT];
__device__ __nv_bfloat16 g_bl[PACK_TOT];

// ---------------- prep: weight pack (transpose + hi/lo split) + feats build -
__global__ void prep_kernel(const float* __restrict__ Ws, const float* __restrict__ Wq,
                            const float* __restrict__ Wk, const float* __restrict__ Wv,
                            const float* __restrict__ Wo, const float* __restrict__ W1,
                            const float* __restrict__ W2, const float* __restrict__ Wout,
                            const float* __restrict__ Wouter,
                            const float* __restrict__ pos, const float* __restrict__ charge,
                            const float* __restrict__ mask, const float* __restrict__ elem,
                            const float* __restrict__ chars)
{
    const int PB = (PACK_TOT + 255)/256;
    if ((int)blockIdx.x >= PB) {
        int row = blockIdx.x - PB;
        float* fr = g_feats + (size_t)row*KFP;
        for (int f = threadIdx.x; f < KFP; f += 256) {
            float v;
            if      (f < 3)    v = pos[row*3 + f];
            else if (f == 3)   v = charge[row];
            else if (f == 4)   v = mask[row];
            else if (f < 133)  v = elem[(size_t)row*128 + (f-5)];
            else if (f < KFEAT)v = chars[(size_t)row*256 + (f-133)];
            else               v = 0.f;
            fr[f] = v;
        }
        return;
    }
    long idx = (long)blockIdx.x*256 + threadIdx.x;
    if (idx >= PACK_TOT) return;
    float v;
    if (idx >= OFF_WOUTER) {
        long rem = idx - OFF_WOUTER;
        int n = (int)(rem / 128), k = (int)(rem % 128);
        v = (n < 32) ? Wouter[(size_t)k*32 + n] : 0.f;
    } else {
        const float* src; int K, N, Kp; long rem;
        if (idx < OFF_QKV)      { src = Ws;  K = KFEAT; N = 128; Kp = KFP; rem = idx; }
        else if (idx < OFF_WO)  { long r = idx - OFF_QKV; int l = (int)(r/49152); r %= 49152;
                                  int ws = (int)(r/16384); rem = r % 16384;
                                  src = (ws==0 ? Wq : ws==1 ? Wk : Wv) + (size_t)l*16384;
                                  K = 128; N = 128; Kp = 128; }
        else if (idx < OFF_FF1) { long r = idx - OFF_WO; int l = (int)(r/16384); rem = r % 16384;
                                  src = Wo + (size_t)l*16384; K = 128; N = 128; Kp = 128; }
        else if (idx < OFF_FF2) { long r = idx - OFF_FF1; int l = (int)(r/65536); rem = r % 65536;
                                  src = W1 + (size_t)l*65536; K = 128; N = 512; Kp = 128; }
        else if (idx < OFF_WOUT){ long r = idx - OFF_FF2; int l = (int)(r/65536); rem = r % 65536;
                                  src = W2 + (size_t)l*65536; K = 512; N = 128; Kp = 512; }
        else                    { rem = idx - OFF_WOUT; src = Wout; K = 128; N = 384; Kp = 128; }
        int n = (int)(rem / Kp), k = (int)(rem % Kp);
        v = (k < K) ? src[(size_t)k*N + n] : 0.f;
    }
    __nv_bfloat16 h = __float2bfloat16(v);
    g_bh[idx] = h;
    g_bl[idx] = __float2bfloat16(v - __bfloat162float(h));
}

// ---------------- mma helpers ------------------------------------------------
__device__ __forceinline__ void ldsm4(unsigned &r0, unsigned &r1, unsigned &r2, unsigned &r3,
                                      const __nv_bfloat16* p)
{
    unsigned a = (unsigned)__cvta_generic_to_shared(p);
    asm volatile("ldmatrix.sync.aligned.m8n8.x4.shared.b16 {%0,%1,%2,%3},[%4];"
                 : "=r"(r0), "=r"(r1), "=r"(r2), "=r"(r3) : "r"(a));
}
__device__ __forceinline__ void mma16816(float* d, const unsigned* a, unsigned b0, unsigned b1)
{
    asm volatile("mma.sync.aligned.m16n8k16.row.col.f32.bf16.bf16.f32 "
                 "{%0,%1,%2,%3},{%4,%5,%6,%7},{%8,%9},{%0,%1,%2,%3};"
                 : "+f"(d[0]), "+f"(d[1]), "+f"(d[2]), "+f"(d[3])
                 : "r"(a[0]), "r"(a[1]), "r"(a[2]), "r"(a[3]), "r"(b0), "r"(b1));
}

// shared 32-k-step mma over one A chunk + one B tile (both bf16-split, LD=40)
__device__ __forceinline__ void mma_chunk(float acc[2][8][4],
    const __nv_bfloat16* sXh, const __nv_bfloat16* sXl,
    const __nv_bfloat16* sBh, const __nv_bfloat16* sBl,
    int lane, int warpM, int warpN)
{
    constexpr int LD = 40;
    #pragma unroll
    for (int ks = 0; ks < 2; ks++) {
        int rowin = lane & 7, tile = lane >> 3;
        unsigned ah[2][4], al[2][4];
        #pragma unroll
        for (int mi = 0; mi < 2; mi++) {
            int r = warpM + mi*16 + (tile & 1)*8 + rowin;
            int c = ks*16 + (tile >> 1)*8;
            ldsm4(ah[mi][0], ah[mi][1], ah[mi][2], ah[mi][3], &sXh[r*LD + c]);
            ldsm4(al[mi][0], al[mi][1], al[mi][2], al[mi][3], &sXl[r*LD + c]);
        }
        #pragma unroll
        for (int np = 0; np < 4; np++) {
            int nrow = warpN + np*16 + (tile >> 1)*8 + rowin;
            int c = ks*16 + (tile & 1)*8;
            unsigned bh0, bh1, bh2, bh3, bl0, bl1, bl2, bl3;
            ldsm4(bh0, bh1, bh2, bh3, &sBh[nrow*LD + c]);
            ldsm4(bl0, bl1, bl2, bl3, &sBl[nrow*LD + c]);
            #pragma unroll
            for (int mi = 0; mi < 2; mi++) {
                mma16816(acc[mi][np*2],   ah[mi], bh0, bh1);
                mma16816(acc[mi][np*2],   al[mi], bh0, bh1);
                mma16816(acc[mi][np*2],   ah[mi], bl0, bl1);
                mma16816(acc[mi][np*2+1], ah[mi], bh2, bh3);
                mma16816(acc[mi][np*2+1], al[mi], bh2, bh3);
                mma16816(acc[mi][np*2+1], ah[mi], bl2, bl3);
            }
        }
    }
}

// ---------------- wide GEMM: BM=256, 512 threads, dynamic smem (W_out only) --
template<bool ABF16, int EPI>
__global__ void __launch_bounds__(512)
mma_gemm_wide(const float* __restrict__ A,
              const __nv_bfloat16* __restrict__ Agh, const __nv_bfloat16* __restrict__ Agl,
              const __nv_bfloat16* __restrict__ Bh,  const __nv_bfloat16* __restrict__ Bl,
              float* __restrict__ C,
              __nv_bfloat16* __restrict__ Hh, __nv_bfloat16* __restrict__ Hl,
              int M, int N, int K)
{
    constexpr int LD = 40;
    extern __shared__ __nv_bfloat16 dyns[];
    __nv_bfloat16* sAh = dyns;
    __nv_bfloat16* sAl = sAh + 256*LD;
    __nv_bfloat16* sBh = sAl + 256*LD;
    __nv_bfloat16* sBl = sBh + 128*LD;
    int tid = threadIdx.x, lane = tid & 31, warp = tid >> 5;
    int m0 = blockIdx.y*256, n0 = blockIdx.x*128;
    int warpM = (warp >> 1)*32, warpN = (warp & 1)*64;

    float acc[2][8][4] = {};
    float4 pa[4]; uint4 pah[2], pal[2], pbh, pbl;

    if (ABF16) {
        #pragma unroll
        for (int i = 0; i < 2; i++) {
            int idx = tid + i*512, row = idx >> 2, q = idx & 3;
            pah[i] = *(const uint4*)&Agh[(size_t)(m0+row)*K + q*8];
            pal[i] = *(const uint4*)&Agl[(size_t)(m0+row)*K + q*8];
        }
    } else {
        #pragma unroll
        for (int i = 0; i < 4; i++) {
            int idx = tid + i*512, row = idx >> 3, c4 = idx & 7;
            pa[i] = *(const float4*)&A[(size_t)(m0+row)*K + c4*4];
        }
    }
    {
        int row = tid >> 2, q = tid & 3;
        pbh = *(const uint4*)&Bh[(size_t)(n0+row)*K + q*8];
        pbl = *(const uint4*)&Bl[(size_t)(n0+row)*K + q*8];
    }

    int nt = K / 32;
    for (int t = 0; t < nt; t++) {
        __syncthreads();
        if (ABF16) {
            #pragma unroll
            for (int i = 0; i < 2; i++) {
                int idx = tid + i*512, row = idx >> 2, q = idx & 3;
                *(uint4*)&sAh[row*LD + q*8] = pah[i];
                *(uint4*)&sAl[row*LD + q*8] = pal[i];
            }
        } else {
            #pragma unroll
            for (int i = 0; i < 4; i++) {
                int idx = tid + i*512, row = idx >> 3, c = (idx & 7)*4;
                float4 v = pa[i];
                __nv_bfloat16 h0 = __float2bfloat16(v.x), h1 = __float2bfloat16(v.y);
                __nv_bfloat16 h2 = __float2bfloat16(v.z), h3 = __float2bfloat16(v.w);
                __nv_bfloat162 hh0; hh0.x = h0; hh0.y = h1;
                __nv_bfloat162 hh1; hh1.x = h2; hh1.y = h3;
                *(__nv_bfloat162*)&sAh[row*LD + c]     = hh0;
                *(__nv_bfloat162*)&sAh[row*LD + c + 2] = hh1;
                __nv_bfloat162 ll0, ll1;
                ll0.x = __float2bfloat16(v.x - __bfloat162float(h0));
                ll0.y = __float2bfloat16(v.y - __bfloat162float(h1));
                ll1.x = __float2bfloat16(v.z - __bfloat162float(h2));
                ll1.y = __float2bfloat16(v.w - __bfloat162float(h3));
                *(__nv_bfloat162*)&sAl[row*LD + c]     = ll0;
                *(__nv_bfloat162*)&sAl[row*LD + c + 2] = ll1;
            }
        }
        {
            int row = tid >> 2, q = tid & 3;
            *(uint4*)&sBh[row*LD + q*8] = pbh;
            *(uint4*)&sBl[row*LD + q*8] = pbl;
        }
        __syncthreads();
        if (t + 1 < nt) {
            int kc = (t+1)*32;
            if (ABF16) {
                #pragma unroll
                for (int i = 0; i < 2; i++) {
                    int idx = tid + i*512, row = idx >> 2, q = idx & 3;
                    pah[i] = *(const uint4*)&Agh[(size_t)(m0+row)*K + kc + q*8];
                    pal[i] = *(const uint4*)&Agl[(size_t)(m0+row)*K + kc + q*8];
                }
            } else {
                #pragma unroll
                for (int i = 0; i < 4; i++) {
                    int idx = tid + i*512, row = idx >> 3, c4 = idx & 7;
                    pa[i] = *(const float4*)&A[(size_t)(m0+row)*K + kc + c4*4];
                }
            }
            {
                int row = tid >> 2, q = tid & 3;
                pbh = *(const uint4*)&Bh[(size_t)(n0+row)*K + kc + q*8];
                pbl = *(const uint4*)&Bl[(size_t)(n0+row)*K + kc + q*8];
            }
        }
        mma_chunk(acc, sAh, sAl, sBh, sBl, lane, warpM, warpN);
    }

    #pragma unroll
    for (int mi = 0; mi < 2; mi++) {
        #pragma unroll
        for (int nj = 0; nj < 8; nj++) {
            int r0  = m0 + warpM + mi*16 + (lane >> 2);
            int col = n0 + warpN + nj*8 + (lane & 3)*2;
            float v0 = acc[mi][nj][0], v1 = acc[mi][nj][1];
            float v2 = acc[mi][nj][2], v3 = acc[mi][nj][3];
            if (EPI == 3) {
                v0 = fmaxf(v0, 0.f); v1 = fmaxf(v1, 0.f);
                v2 = fmaxf(v2, 0.f); v3 = fmaxf(v3, 0.f);
            }
            float2 o0; o0.x = v0; o0.y = v1;
            float2 o1; o1.x = v2; o1.y = v3;
            *(float2*)&C[(size_t)r0*N + col]     = o0;
            *(float2*)&C[(size_t)(r0+8)*N + col] = o1;
        }
    }
}

// ---------------- fused embed: x = feats@Wemb; LN; p = relu(x)@Wouter; qkv ---
__global__ void __launch_bounds__(256)
embed_fused(const float* __restrict__ feats,
            const __nv_bfloat16* __restrict__ Weh, const __nv_bfloat16* __restrict__ Wel,
            const __nv_bfloat16* __restrict__ Wph, const __nv_bfloat16* __restrict__ Wpl,
            const __nv_bfloat16* __restrict__ Qwh, const __nv_bfloat16* __restrict__ Qwl,
            float* __restrict__ X, float* __restrict__ Pout, float* __restrict__ qkvout)
{
    constexpr int LD = 40;
    constexpr int CH = 128*LD;
    extern __shared__ __nv_bfloat16 dyns[];
    __nv_bfloat16* sAh = dyns;
    __nv_bfloat16* sAl = sAh + 4*CH;
    __nv_bfloat16* sFh = sAl + 4*CH;
    __nv_bfloat16* sFl = sFh + 4*CH;
    __nv_bfloat16* sBh = sFl + 4*CH;
    __nv_bfloat16* sBl = sBh + CH;
    __shared__ float2 ssum[128][2];

    int tid = threadIdx.x, lane = tid & 31, warp = tid >> 5;
    int m0 = blockIdx.x*128;
    int warpM = (warp >> 1)*32, warpN = (warp & 1)*64;
    int brow = tid >> 2, bq = tid & 3;

    uint4 pbh[2], pbl[2];
    float4 pa[4];

    auto ln_stats = [&](float acc[2][8][4], float* mean, float* rsig) {
        float s[4] = {}, s2[4] = {};
        #pragma unroll
        for (int mi = 0; mi < 2; mi++)
            #pragma unroll
            for (int nj = 0; nj < 8; nj++) {
                float v0 = acc[mi][nj][0], v1 = acc[mi][nj][1];
                float v2 = acc[mi][nj][2], v3 = acc[mi][nj][3];
                s[mi*2]    += v0 + v1;      s2[mi*2]   += v0*v0 + v1*v1;
                s[mi*2+1]  += v2 + v3;      s2[mi*2+1] += v2*v2 + v3*v3;
            }
        #pragma unroll
        for (int off = 1; off <= 2; off <<= 1)
            #pragma unroll
            for (int r = 0; r < 4; r++) {
                s[r]  += __shfl_xor_sync(~0u, s[r],  off);
                s2[r] += __shfl_xor_sync(~0u, s2[r], off);
            }
        __syncthreads();
        if ((lane & 3) == 0) {
            #pragma unroll
            for (int slot = 0; slot < 4; slot++) {
                int row = warpM + (slot >> 1)*16 + (lane >> 2) + 8*(slot & 1);
                ssum[row][warp & 1] = make_float2(s[slot], s2[slot]);
            }
        }
        __syncthreads();
        #pragma unroll
        for (int slot = 0; slot < 4; slot++) {
            int row = warpM + (slot >> 1)*16 + (lane >> 2) + 8*(slot & 1);
            float2 a = ssum[row][0], b = ssum[row][1];
            float m  = (a.x + b.x) * (1.f/128.f);
            float vv = (a.y + b.y) * (1.f/128.f) - m*m;
            mean[slot] = m;
            rsig[slot] = rsqrtf(vv + 1e-5f);
        }
    };

    // ---- stage E: x = feats @ Wemb (K = 416 = 13 chunks), A fp32 on the fly
    float accE[2][8][4] = {};
    #pragma unroll
    for (int i = 0; i < 4; i++) {
        int idx = tid + i*256, row = idx >> 3, c4 = idx & 7;
        pa[i] = *(const float4*)&feats[(size_t)(m0+row)*KFP + c4*4];
    }
    pbh[0] = *(const uint4*)&Weh[(size_t)brow*KFP + bq*8];
    pbh[1] = *(const uint4*)&Weh[(size_t)(brow+64)*KFP + bq*8];
    pbl[0] = *(const uint4*)&Wel[(size_t)brow*KFP + bq*8];
    pbl[1] = *(const uint4*)&Wel[(size_t)(brow+64)*KFP + bq*8];

    #pragma unroll 1
    for (int t = 0; t < 13; t++) {
        __syncthreads();
        #pragma unroll
        for (int i = 0; i < 4; i++) {
            int idx = tid + i*256, row = idx >> 3, c = (idx & 7)*4;
            float4 v = pa[i];
            __nv_bfloat16 h0 = __float2bfloat16(v.x), h1 = __float2bfloat16(v.y);
            __nv_bfloat16 h2 = __float2bfloat16(v.z), h3 = __float2bfloat16(v.w);
            __nv_bfloat162 hh0; hh0.x = h0; hh0.y = h1;
            __nv_bfloat162 hh1; hh1.x = h2; hh1.y = h3;
            *(__nv_bfloat162*)&sFh[row*LD + c]     = hh0;
            *(__nv_bfloat162*)&sFh[row*LD + c + 2] = hh1;
            __nv_bfloat162 ll0, ll1;
            ll0.x = __float2bfloat16(v.x - __bfloat162float(h0));
            ll0.y = __float2bfloat16(v.y - __bfloat162float(h1));
            ll1.x = __float2bfloat16(v.z - __bfloat162float(h2));
            ll1.y = __float2bfloat16(v.w - __bfloat162float(h3));
            *(__nv_bfloat162*)&sFl[row*LD + c]     = ll0;
            *(__nv_bfloat162*)&sFl[row*LD + c + 2] = ll1;
        }
        *(uint4*)&sBh[brow*LD + bq*8]      = pbh[0];
        *(uint4*)&sBh[(brow+64)*LD + bq*8] = pbh[1];
        *(uint4*)&sBl[brow*LD + bq*8]      = pbl[0];
        *(uint4*)&sBl[(brow+64)*LD + bq*8] = pbl[1];
        __syncthreads();
        if (t + 1 < 13) {
            int kc = (t+1)*32;
            #pragma unroll
            for (int i = 0; i < 4; i++) {
                int idx = tid + i*256, row = idx >> 3, c4 = idx & 7;
                pa[i] = *(const float4*)&feats[(size_t)(m0+row)*KFP + kc + c4*4];
            }
            pbh[0] = *(const uint4*)&Weh[(size_t)brow*KFP + kc + bq*8];
            pbh[1] = *(const uint4*)&Weh[(size_t)(brow+64)*KFP + kc + bq*8];
            pbl[0] = *(const uint4*)&Wel[(size_t)brow*KFP + kc + bq*8];
            pbl[1] = *(const uint4*)&Wel[(size_t)(brow+64)*KFP + kc + bq*8];
        } else {
            pbh[0] = *(const uint4*)&Wph[(size_t)brow*128 + bq*8];
            pbh[1] = *(const uint4*)&Wph[(size_t)(brow+64)*128 + bq*8];
            pbl[0] = *(const uint4*)&Wpl[(size_t)brow*128 + bq*8];
            pbl[1] = *(const uint4*)&Wpl[(size_t)(brow+64)*128 + bq*8];
        }
        mma_chunk(accE, sFh, sFl, sBh, sBl, lane, warpM, warpN);
    }

    float mean[4], rsig[4];
    ln_stats(accE, mean, rsig);

    #pragma unroll
    for (int mi = 0; mi < 2; mi++) {
        #pragma unroll
        for (int nj = 0; nj < 8; nj++) {
            int r   = warpM + mi*16 + (lane >> 2);
            int col = warpN + nj*8 + (lane & 3)*2;
            int r0  = m0 + r;
            float v0 = accE[mi][nj][0], v1 = accE[mi][nj][1];
            float v2 = accE[mi][nj][2], v3 = accE[mi][nj][3];
            float2 o0; o0.x = v0; o0.y = v1;
            float2 o1; o1.x = v2; o1.y = v3;
            *(float2*)&X[(size_t)r0*128 + col]     = o0;
            *(float2*)&X[(size_t)(r0+8)*128 + col] = o1;
            int off = (col >> 5)*CH + (col & 31);
            {
                float a0 = fmaxf(v0,0.f), a1 = fmaxf(v1,0.f);
                float a2 = fmaxf(v2,0.f), a3 = fmaxf(v3,0.f);
                __nv_bfloat162 h0, h1, l0, l1;
                h0.x = __float2bfloat16(a0); h0.y = __float2bfloat16(a1);
                h1.x = __float2bfloat16(a2); h1.y = __float2bfloat16(a3);
                l0.x = __float2bfloat16(a0 - __bfloat162float(h0.x));
                l0.y = __float2bfloat16(a1 - __bfloat162float(h0.y));
                l1.x = __float2bfloat16(a2 - __bfloat162float(h1.x));
                l1.y = __float2bfloat16(a3 - __bfloat162float(h1.y));
                *(__nv_bfloat162*)&sFh[off + r*LD]     = h0;
                *(__nv_bfloat162*)&sFh[off + (r+8)*LD] = h1;
                *(__nv_bfloat162*)&sFl[off + r*LD]     = l0;
                *(__nv_bfloat162*)&sFl[off + (r+8)*LD] = l1;
            }
            {
                float a0 = (v0 - mean[mi*2])*rsig[mi*2];
                float a1 = (v1 - mean[mi*2])*rsig[mi*2];
                float a2 = (v2 - mean[mi*2+1])*rsig[mi*2+1];
                float a3 = (v3 - mean[mi*2+1])*rsig[mi*2+1];
                __nv_bfloat162 h0, h1, l0, l1;
                h0.x = __float2bfloat16(a0); h0.y = __float2bfloat16(a1);
                h1.x = __float2bfloat16(a2); h1.y = __float2bfloat16(a3);
                l0.x = __float2bfloat16(a0 - __bfloat162float(h0.x));
                l0.y = __float2bfloat16(a1 - __bfloat162float(h0.y));
                l1.x = __float2bfloat16(a2 - __bfloat162float(h1.x));
                l1.y = __float2bfloat16(a3 - __bfloat162float(h1.y));
                *(__nv_bfloat162*)&sAh[off + r*LD]     = h0;
                *(__nv_bfloat162*)&sAh[off + (r+8)*LD] = h1;
                *(__nv_bfloat162*)&sAl[off + r*LD]     = l0;
                *(__nv_bfloat162*)&sAl[off + (r+8)*LD] = l1;
            }
        }
    }

    // ---- stage P: p = relu(x) @ Wouter_pad (valid cols 0..31) ----
    {
        float accP[2][8][4] = {};
        #pragma unroll
        for (int t = 0; t < 4; t++) {
            __syncthreads();
            *(uint4*)&sBh[brow*LD + bq*8]      = pbh[0];
            *(uint4*)&sBh[(brow+64)*LD + bq*8] = pbh[1];
            *(uint4*)&sBl[brow*LD + bq*8]      = pbl[0];
            *(uint4*)&sBl[(brow+64)*LD + bq*8] = pbl[1];
            __syncthreads();
            if (t + 1 < 4) {
                int kc = (t+1)*32;
                pbh[0] = *(const uint4*)&Wph[(size_t)brow*128 + kc + bq*8];
                pbh[1] = *(const uint4*)&Wph[(size_t)(brow+64)*128 + kc + bq*8];
                pbl[0] = *(const uint4*)&Wpl[(size_t)brow*128 + kc + bq*8];
                pbl[1] = *(const uint4*)&Wpl[(size_t)(brow+64)*128 + kc + bq*8];
            } else {
                pbh[0] = *(const uint4*)&Qwh[(size_t)brow*128 + bq*8];
                pbh[1] = *(const uint4*)&Qwh[(size_t)(brow+64)*128 + bq*8];
                pbl[0] = *(const uint4*)&Qwl[(size_t)brow*128 + bq*8];
                pbl[1] = *(const uint4*)&Qwl[(size_t)(brow+64)*128 + bq*8];
            }
            mma_chunk(accP, sFh + t*CH, sFl + t*CH, sBh, sBl, lane, warpM, warpN);
        }
        if (warpN == 0) {
            #pragma unroll
            for (int mi = 0; mi < 2; mi++) {
                #pragma unroll
                for (int nj = 0; nj < 4; nj++) {
                    int r0  = m0 + warpM + mi*16 + (lane >> 2);
                    int col = nj*8 + (lane & 3)*2;
                    float2 o0; o0.x = accP[mi][nj][0]; o0.y = accP[mi][nj][1];
                    float2 o1; o1.x = accP[mi][nj][2]; o1.y = accP[mi][nj][3];
                    *(float2*)&Pout[(size_t)r0*32 + col]     = o0;
                    *(float2*)&Pout[(size_t)(r0+8)*32 + col] = o1;
                }
            }
        }
    }

    // ---- stage Q: qkv = h' @ Wqkv (3 N-blocks x 4 k-chunks) ----
    #pragma unroll 1
    for (int nb = 0; nb < 3; nb++) {
        float acc[2][8][4] = {};
        #pragma unroll
        for (int t = 0; t < 4; t++) {
            __syncthreads();
            *(uint4*)&sBh[brow*LD + bq*8]      = pbh[0];
            *(uint4*)&sBh[(brow+64)*LD + bq*8] = pbh[1];
            *(uint4*)&sBl[brow*LD + bq*8]      = pbl[0];
            *(uint4*)&sBl[(brow+64)*LD + bq*8] = pbl[1];
            __syncthreads();
            int ni = nb*4 + t + 1;
            if (ni < 12) {
                int nrow = (ni >> 2)*128, kc = (ni & 3)*32;
                pbh[0] = *(const uint4*)&Qwh[(size_t)(nrow + brow)*128 + kc + bq*8];
                pbh[1] = *(const uint4*)&Qwh[(size_t)(nrow + brow+64)*128 + kc + bq*8];
                pbl[0] = *(const uint4*)&Qwl[(size_t)(nrow + brow)*128 + kc + bq*8];
                pbl[1] = *(const uint4*)&Qwl[(size_t)(nrow + brow+64)*128 + kc + bq*8];
            }
            mma_chunk(acc, sAh + t*CH, sAl + t*CH, sBh, sBl, lane, warpM, warpN);
        }
        #pragma unroll
        for (int mi = 0; mi < 2; mi++) {
            #pragma unroll
            for (int nj = 0; nj < 8; nj++) {
                int r0  = m0 + warpM + mi*16 + (lane >> 2);
                int col = nb*128 + warpN + nj*8 + (lane & 3)*2;
                float2 o0; o0.x = acc[mi][nj][0]; o0.y = acc[mi][nj][1];
                float2 o1; o1.x = acc[mi][nj][2]; o1.y = acc[mi][nj][3];
                *(float2*)&qkvout[(size_t)r0*384 + col]     = o0;
                *(float2*)&qkvout[(size_t)(r0+8)*384 + col] = o1;
            }
        }
    }
}

// ---------------- fused layer tail: WO + res + LN + FF + (next QKV) ---------
template<bool LAST>
__global__ void __launch_bounds__(256)
layer_fused(const float* __restrict__ oin,
            const __nv_bfloat16* __restrict__ Woh, const __nv_bfloat16* __restrict__ Wol,
            const __nv_bfloat16* __restrict__ B1h, const __nv_bfloat16* __restrict__ B1l,
            const __nv_bfloat16* __restrict__ B2h, const __nv_bfloat16* __restrict__ B2l,
            const __nv_bfloat16* __restrict__ Qwh, const __nv_bfloat16* __restrict__ Qwl,
            float* __restrict__ X, float* __restrict__ qkvout)
{
    constexpr int LD = 40;
    constexpr int CH = 128*LD;
    extern __shared__ __nv_bfloat16 dyns[];
    __nv_bfloat16* sAh = dyns;
    __nv_bfloat16* sAl = sAh + 4*CH;
    __nv_bfloat16* sFh = sAl + 4*CH;
    __nv_bfloat16* sFl = sFh + 4*CH;
    __nv_bfloat16* sBh = sFl + 4*CH;
    __nv_bfloat16* sBl = sBh + CH;
    __shared__ float2 ssum[128][2];

    int tid = threadIdx.x, lane = tid & 31, warp = tid >> 5;
    int m0 = blockIdx.x*128;
    int warpM = (warp >> 1)*32, warpN = (warp & 1)*64;
    int brow = tid >> 2, bq = tid & 3;

    uint4 pbh[2], pbl[2];

    auto ln_stats = [&](float acc[2][8][4], float* mean, float* rsig) {
        float s[4] = {}, s2[4] = {};
        #pragma unroll
        for (int mi = 0; mi < 2; mi++)
            #pragma unroll
            for (int nj = 0; nj < 8; nj++) {
                float v0 = acc[mi][nj][0], v1 = acc[mi][nj][1];
                float v2 = acc[mi][nj][2], v3 = acc[mi][nj][3];
                s[mi*2]    += v0 + v1;      s2[mi*2]   += v0*v0 + v1*v1;
                s[mi*2+1]  += v2 + v3;      s2[mi*2+1] += v2*v2 + v3*v3;
            }
        #pragma unroll
        for (int off = 1; off <= 2; off <<= 1)
            #pragma unroll
            for (int r = 0; r < 4; r++) {
                s[r]  += __shfl_xor_sync(~0u, s[r],  off);
                s2[r] += __shfl_xor_sync(~0u, s2[r], off);
            }
        __syncthreads();
        if ((lane & 3) == 0) {
            #pragma unroll
            for (int slot = 0; slot < 4; slot++) {
                int row = warpM + (slot >> 1)*16 + (lane >> 2) + 8*(slot & 1);
                ssum[row][warp & 1] = make_float2(s[slot], s2[slot]);
            }
        }
        __syncthreads();
        #pragma unroll
        for (int slot = 0; slot < 4; slot++) {
            int row = warpM + (slot >> 1)*16 + (lane >> 2) + 8*(slot & 1);
            float2 a = ssum[row][0], b = ssum[row][1];
            float m  = (a.x + b.x) * (1.f/128.f);
            float vv = (a.y + b.y) * (1.f/128.f) - m*m;
            mean[slot] = m;
            rsig[slot] = rsqrtf(vv + 1e-5f);
        }
    };

    // ---- stage W: x_mid = x + o@Wo; LN -> h' in sA
    {
        #pragma unroll
        for (int i = 0; i < 16; i++) {
            int idx = tid + i*256;
            int row = idx >> 5, q = idx & 31;
            float4 v = *(const float4*)&oin[(size_t)(m0+row)*128 + q*4];
            int off = (q >> 3)*CH + row*LD + (q & 7)*4;
            __nv_bfloat162 h0, h1, l0, l1;
            h0.x = __float2bfloat16(v.x); h0.y = __float2bfloat16(v.y);
            h1.x = __float2bfloat16(v.z); h1.y = __float2bfloat16(v.w);
            l0.x = __float2bfloat16(v.x - __bfloat162float(h0.x));
            l0.y = __float2bfloat16(v.y - __bfloat162float(h0.y));
            l1.x = __float2bfloat16(v.z - __bfloat162float(h1.x));
            l1.y = __float2bfloat16(v.w - __bfloat162float(h1.y));
            *(__nv_bfloat162*)&sFh[off]     = h0;
            *(__nv_bfloat162*)&sFh[off + 2] = h1;
            *(__nv_bfloat162*)&sFl[off]     = l0;
            *(__nv_bfloat162*)&sFl[off + 2] = l1;
        }
        pbh[0] = *(const uint4*)&Woh[(size_t)brow*128 + bq*8];
        pbh[1] = *(const uint4*)&Woh[(size_t)(brow+64)*128 + bq*8];
        pbl[0] = *(const uint4*)&Wol[(size_t)brow*128 + bq*8];
        pbl[1] = *(const uint4*)&Wol[(size_t)(brow+64)*128 + bq*8];

        float accW[2][8][4] = {};
        #pragma unroll
        for (int t = 0; t < 4; t++) {
            __syncthreads();
            *(uint4*)&sBh[brow*LD + bq*8]      = pbh[0];
            *(uint4*)&sBh[(brow+64)*LD + bq*8] = pbh[1];
            *(uint4*)&sBl[brow*LD + bq*8]      = pbl[0];
            *(uint4*)&sBl[(brow+64)*LD + bq*8] = pbl[1];
            __syncthreads();
            if (t + 1 < 4) {
                int kc = (t+1)*32;
                pbh[0] = *(const uint4*)&Woh[(size_t)brow*128 + kc + bq*8];
                pbh[1] = *(const uint4*)&Woh[(size_t)(brow+64)*128 + kc + bq*8];
                pbl[0] = *(const uint4*)&Wol[(size_t)brow*128 + kc + bq*8];
                pbl[1] = *(const uint4*)&Wol[(size_t)(brow+64)*128 + kc + bq*8];
            } else {
                pbh[0] = *(const uint4*)&B1h[(size_t)brow*128 + bq*8];
                pbh[1] = *(const uint4*)&B1h[(size_t)(brow+64)*128 + bq*8];
                pbl[0] = *(const uint4*)&B1l[(size_t)brow*128 + bq*8];
                pbl[1] = *(const uint4*)&B1l[(size_t)(brow+64)*128 + bq*8];
            }
            mma_chunk(accW, sFh + t*CH, sFl + t*CH, sBh, sBl, lane, warpM, warpN);
        }
        #pragma unroll
        for (int mi = 0; mi < 2; mi++) {
            #pragma unroll
            for (int nj = 0; nj < 8; nj++) {
                int r0  = m0 + warpM + mi*16 + (lane >> 2);
                int col = warpN + nj*8 + (lane & 3)*2;
                float2 c0 = *(const float2*)&X[(size_t)r0*128 + col];
                float2 c1 = *(const float2*)&X[(size_t)(r0+8)*128 + col];
                accW[mi][nj][0] += c0.x; accW[mi][nj][1] += c0.y;
                accW[mi][nj][2] += c1.x; accW[mi][nj][3] += c1.y;
            }
        }
        float mean[4], rsig[4];
        ln_stats(accW, mean, rsig);
        #pragma unroll
        for (int mi = 0; mi < 2; mi++) {
            #pragma unroll
            for (int nj = 0; nj < 8; nj++) {
                int r   = warpM + mi*16 + (lane >> 2);
                int col = warpN + nj*8 + (lane & 3)*2;
                int r0  = m0 + r;
                float v0 = accW[mi][nj][0], v1 = accW[mi][nj][1];
                float v2 = accW[mi][nj][2], v3 = accW[mi][nj][3];
                float2 o0; o0.x = v0; o0.y = v1;
                float2 o1; o1.x = v2; o1.y = v3;
                *(float2*)&X[(size_t)r0*128 + col]     = o0;
                *(float2*)&X[(size_t)(r0+8)*128 + col] = o1;
                v0 = (v0 - mean[mi*2])*rsig[mi*2];
                v1 = (v1 - mean[mi*2])*rsig[mi*2];
                v2 = (v2 - mean[mi*2+1])*rsig[mi*2+1];
                v3 = (v3 - mean[mi*2+1])*rsig[mi*2+1];
                int off = (col >> 5)*CH + (col & 31);
                __nv_bfloat162 h0, h1, l0, l1;
                h0.x = __float2bfloat16(v0); h0.y = __float2bfloat16(v1);
                h1.x = __float2bfloat16(v2); h1.y = __float2bfloat16(v3);
                l0.x = __float2bfloat16(v0 - __bfloat162float(h0.x));
                l0.y = __float2bfloat16(v1 - __bfloat162float(h0.y));
                l1.x = __float2bfloat16(v2 - __bfloat162float(h1.x));
                l1.y = __float2bfloat16(v3 - __bfloat162float(h1.y));
                *(__nv_bfloat162*)&sAh[off + r*LD]     = h0;
                *(__nv_bfloat162*)&sAh[off + (r+8)*LD] = h1;
                *(__nv_bfloat162*)&sAl[off + r*LD]     = l0;
                *(__nv_bfloat162*)&sAl[off + (r+8)*LD] = l1;
            }
        }
    }

    // ---- FF stages ----
    auto bptr = [&](int i, int row, const __nv_bfloat16* b1, const __nv_bfloat16* b2)
        -> const __nv_bfloat16* {
        int c = i >> 3, t = i & 3;
        if (((i >> 2) & 1) == 0)
            return &b1[(size_t)(c*128 + row)*128 + t*32 + bq*8];
        else
            return &b2[(size_t)row*512 + c*128 + t*32 + bq*8];
    };

    float acc2[2][8][4] = {};
    #pragma unroll 1
    for (int c = 0; c < 4; c++) {
        float acc1[2][8][4] = {};
        #pragma unroll
        for (int t = 0; t < 4; t++) {
            __syncthreads();
            *(uint4*)&sBh[brow*LD + bq*8]      = pbh[0];
            *(uint4*)&sBh[(brow+64)*LD + bq*8] = pbh[1];
            *(uint4*)&sBl[brow*LD + bq*8]      = pbl[0];
            *(uint4*)&sBl[(brow+64)*LD + bq*8] = pbl[1];
            __syncthreads();
            int ni = c*8 + t + 1;
            pbh[0] = *(const uint4*)bptr(ni, brow,    B1h, B2h);
            pbh[1] = *(const uint4*)bptr(ni, brow+64, B1h, B2h);
            pbl[0] = *(const uint4*)bptr(ni, brow,    B1l, B2l);
            pbl[1] = *(const uint4*)bptr(ni, brow+64, B1l, B2l);
            mma_chunk(acc1, sAh + t*CH, sAl + t*CH, sBh, sBl, lane, warpM, warpN);
        }
        #pragma unroll
        for (int mi = 0; mi < 2; mi++) {
            #pragma unroll
            for (int nj = 0; nj < 8; nj++) {
                int r   = warpM + mi*16 + (lane >> 2);
                int col = warpN + nj*8 + (lane & 3)*2;
                int off = (col >> 5)*CH + (col & 31);
                float v0 = fmaxf(acc1[mi][nj][0], 0.f), v1 = fmaxf(acc1[mi][nj][1], 0.f);
                float v2 = fmaxf(acc1[mi][nj][2], 0.f), v3 = fmaxf(acc1[mi][nj][3], 0.f);
                __nv_bfloat162 h0, h1, l0, l1;
                h0.x = __float2bfloat16(v0); h0.y = __float2bfloat16(v1);
                h1.x = __float2bfloat16(v2); h1.y = __float2bfloat16(v3);
                l0.x = __float2bfloat16(v0 - __bfloat162float(h0.x));
                l0.y = __float2bfloat16(v1 - __bfloat162float(h0.y));
                l1.x = __float2bfloat16(v2 - __bfloat162float(h1.x));
                l1.y = __float2bfloat16(v3 - __bfloat162float(h1.y));
                *(__nv_bfloat162*)&sFh[off + r*LD]     = h0;
                *(__nv_bfloat162*)&sFh[off + (r+8)*LD] = h1;
                *(__nv_bfloat162*)&sFl[off + r*LD]     = l0;
                *(__nv_bfloat162*)&sFl[off + (r+8)*LD] = l1;
            }
        }
        #pragma unroll
        for (int t = 0; t < 4; t++) {
            __syncthreads();
            *(uint4*)&sBh[brow*LD + bq*8]      = pbh[0];
            *(uint4*)&sBh[(brow+64)*LD + bq*8] = pbh[1];
            *(uint4*)&sBl[brow*LD + bq*8]      = pbl[0];
            *(uint4*)&sBl[(brow+64)*LD + bq*8] = pbl[1];
            __syncthreads();
            int ni = c*8 + t + 5;
            if (ni < 32) {
                pbh[0] = *(const uint4*)bptr(ni, brow,    B1h, B2h);
                pbh[1] = *(const uint4*)bptr(ni, brow+64, B1h, B2h);
                pbl[0] = *(const uint4*)bptr(ni, brow,    B1l, B2l);
                pbl[1] = *(const uint4*)bptr(ni, brow+64, B1l, B2l);
            } else if (!LAST) {
                pbh[0] = *(const uint4*)&Qwh[(size_t)brow*128 + bq*8];
                pbh[1] = *(const uint4*)&Qwh[(size_t)(brow+64)*128 + bq*8];
                pbl[0] = *(const uint4*)&Qwl[(size_t)brow*128 + bq*8];
                pbl[1] = *(const uint4*)&Qwl[(size_t)(brow+64)*128 + bq*8];
            }
            mma_chunk(acc2, sFh + t*CH, sFl + t*CH, sBh, sBl, lane, warpM, warpN);
        }
    }

    #pragma unroll
    for (int mi = 0; mi < 2; mi++) {
        #pragma unroll
        for (int nj = 0; nj < 8; nj++) {
            int r0  = m0 + warpM + mi*16 + (lane >> 2);
            int col = warpN + nj*8 + (lane & 3)*2;
            float2 c0 = *(const float2*)&X[(size_t)r0*128 + col];
            float2 c1 = *(const float2*)&X[(size_t)(r0+8)*128 + col];
            acc2[mi][nj][0] += c0.x; acc2[mi][nj][1] += c0.y;
            acc2[mi][nj][2] += c1.x; acc2[mi][nj][3] += c1.y;
        }
    }

    float mean[4], rsig[4];
    if (!LAST) ln_stats(acc2, mean, rsig);

    #pragma unroll
    for (int mi = 0; mi < 2; mi++) {
        #pragma unroll
        for (int nj = 0; nj < 8; nj++) {
            int r   = warpM + mi*16 + (lane >> 2);
            int col = warpN + nj*8 + (lane & 3)*2;
            int r0  = m0 + r;
            float v0 = acc2[mi][nj][0], v1 = acc2[mi][nj][1];
            float v2 = acc2[mi][nj][2], v3 = acc2[mi][nj][3];
            float2 o0; o0.x = v0; o0.y = v1;
            float2 o1; o1.x = v2; o1.y = v3;
            *(float2*)&X[(size_t)r0*128 + col]     = o0;
            *(float2*)&X[(size_t)(r0+8)*128 + col] = o1;
            if (!LAST) {
                v0 = (v0 - mean[mi*2])*rsig[mi*2];
                v1 = (v1 - mean[mi*2])*rsig[mi*2];
                v2 = (v2 - mean[mi*2+1])*rsig[mi*2+1];
                v3 = (v3 - mean[mi*2+1])*rsig[mi*2+1];
                int off = (col >> 5)*CH + (col & 31);
                __nv_bfloat162 h0, h1, l0, l1;
                h0.x = __float2bfloat16(v0); h0.y = __float2bfloat16(v1);
                h1.x = __float2bfloat16(v2); h1.y = __float2bfloat16(v3);
                l0.x = __float2bfloat16(v0 - __bfloat162float(h0.x));
                l0.y = __float2bfloat16(v1 - __bfloat162float(h0.y));
                l1.x = __float2bfloat16(v2 - __bfloat162float(h1.x));
                l1.y = __float2bfloat16(v3 - __bfloat162float(h1.y));
                *(__nv_bfloat162*)&sAh[off + r*LD]     = h0;
                *(__nv_bfloat162*)&sAh[off + (r+8)*LD] = h1;
                *(__nv_bfloat162*)&sAl[off + r*LD]     = l0;
                *(__nv_bfloat162*)&sAl[off + (r+8)*LD] = l1;
            }
        }
    }

    if (!LAST) {
        #pragma unroll 1
        for (int nb = 0; nb < 3; nb++) {
            float acc[2][8][4] = {};
            #pragma unroll
            for (int t = 0; t < 4; t++) {
                __syncthreads();
                *(uint4*)&sBh[brow*LD + bq*8]      = pbh[0];
                *(uint4*)&sBh[(brow+64)*LD + bq*8] = pbh[1];
                *(uint4*)&sBl[brow*LD + bq*8]      = pbl[0];
                *(uint4*)&sBl[(brow+64)*LD + bq*8] = pbl[1];
                __syncthreads();
                int ni = nb*4 + t + 1;
                if (ni < 12) {
                    int nrow = (ni >> 2)*128, kc = (ni & 3)*32;
                    pbh[0] = *(const uint4*)&Qwh[(size_t)(nrow + brow)*128 + kc + bq*8];
                    pbh[1] = *(const uint4*)&Qwh[(size_t)(nrow + brow+64)*128 + kc + bq*8];
                    pbl[0] = *(const uint4*)&Qwl[(size_t)(nrow + brow)*128 + kc + bq*8];
                    pbl[1] = *(const uint4*)&Qwl[(size_t)(nrow + brow+64)*128 + kc + bq*8];
                }
                mma_chunk(acc, sAh + t*CH, sAl + t*CH, sBh, sBl, lane, warpM, warpN);
            }
            #pragma unroll
            for (int mi = 0; mi < 2; mi++) {
                #pragma unroll
                for (int nj = 0; nj < 8; nj++) {
                    int r0  = m0 + warpM + mi*16 + (lane >> 2);
                    int col = nb*128 + warpN + nj*8 + (lane & 3)*2;
                    float2 o0; o0.x = acc[mi][nj][0]; o0.y = acc[mi][nj][1];
                    float2 o1; o1.x = acc[mi][nj][2]; o1.y = acc[mi][nj][3];
                    *(float2*)&qkvout[(size_t)r0*384 + col]     = o0;
                    *(float2*)&qkvout[(size_t)(r0+8)*384 + col] = o1;
                }
            }
        }
    }
}

// ---------------- fused pair-feature -> LN -> FF -> head bias ---------------
__global__ void __launch_bounds__(256)
bias_kernel(const float* __restrict__ pos, const int* __restrict__ uid,
            const float* __restrict__ Wp, const float* __restrict__ W1,
            const float* __restrict__ W2, const float* __restrict__ Wb)
{
    __shared__ float sposi[32][3], sposj[KWIN][3];
    __shared__ int   suidi[32],    suidj[KWIN];
    __shared__ float4 spi4[32][4], spj4[KWIN][4];
    __shared__ float sWp[80], sWb[64];
    __shared__ float4 sW1T[64][4];
    __shared__ float4 sW2b[64];
    __shared__ unsigned char svalid[KWIN];

    int bb = blockIdx.x;
    int half = bb & 1;
    int bw = bb >> 1;
    int b = bw / NW, w = bw % NW;
    int q0 = half*32;
    int tid = threadIdx.x;

    for (int i = tid; i < 80; i += 256) sWp[i] = Wp[i];
    for (int i = tid; i < 64; i += 256) sWb[i] = Wb[i];
    for (int i = tid; i < 1024; i += 256) {
        int j = i >> 4, c = i & 15;
        ((float*)sW1T)[j*16 + c] = W1[c*64 + j];
    }
    if (tid < 64) {
        float4 r = make_float4(0,0,0,0);
        #pragma unroll
        for (int c = 0; c < 16; c++) {
            float w2v = W2[tid*16 + c];
            r.x += w2v*Wb[c*4+0]; r.y += w2v*Wb[c*4+1];
            r.z += w2v*Wb[c*4+2]; r.w += w2v*Wb[c*4+3];
        }
        sW2b[tid] = r;
    }
    for (int q = tid; q < 32; q += 256) {
        int gi = b*N_ + w*QWIN + q0 + q;
        sposi[q][0] = pos[gi*3]; sposi[q][1] = pos[gi*3+1]; sposi[q][2] = pos[gi*3+2];
        suidi[q] = uid[gi];
        const float4* pp = (const float4*)&g_p[(size_t)gi*32];
        spi4[q][0] = pp[0]; spi4[q][1] = pp[1]; spi4[q][2] = pp[2]; spi4[q][3] = pp[3];
    }
    for (int k = tid; k < KWIN; k += 256) {
        int j = w*QWIN + k - PADW;
        bool valid = (j >= 0 && j < N_);
        svalid[k] = valid;
        if (valid) {
            int gj = b*N_ + j;
            sposj[k][0] = pos[gj*3]; sposj[k][1] = pos[gj*3+1]; sposj[k][2] = pos[gj*3+2];
            suidj[k] = uid[gj];
            const float4* pp = (const float4*)&g_p[(size_t)gj*32 + 16];
            spj4[k][0] = pp[0]; spj4[k][1] = pp[1]; spj4[k][2] = pp[2]; spj4[k][3] = pp[3];
        } else {
            sposj[k][0] = sposj[k][1] = sposj[k][2] = 0.f; suidj[k] = -1;
            float4 z = make_float4(0,0,0,0);
            spj4[k][0] = z; spj4[k][1] = z; spj4[k][2] = z; spj4[k][3] = z;
        }
    }
    __syncthreads();

    float* brow = g_bias + (size_t)bw*HEADS*QWIN*KWIN;

    auto prep = [&](int q, int k, float4* u, float& bh0, float& bh1, float& bh2, float& bh3) {
        float dx = sposi[q][0]-sposj[k][0];
        float dy = sposi[q][1]-sposj[k][1];
        float dz = sposi[q][2]-sposj[k][2];
        float inv = 1.f / (1.f + dx*dx + dy*dy + dz*dz);
        float bij = (suidi[q] == suidj[k]) ? 1.f : 0.f;
        float4 pr[4];
        #pragma unroll
        for (int c4 = 0; c4 < 4; c4++) {
            float4 r;
            #pragma unroll
            for (int e = 0; e < 4; e++) {
                int c = c4*4 + e;
                float base = dx*sWp[c] + dy*sWp[16+c] + dz*sWp[32+c] + inv*sWp[48+c] + sWp[64+c];
                (&r.x)[e] = base*bij + (&spi4[q][c4].x)[e] + (&spj4[k][c4].x)[e];
            }
            pr[c4] = r;
        }
        float s = 0.f, s2 = 0.f;
        #pragma unroll
        for (int c4 = 0; c4 < 4; c4++) {
            s  += pr[c4].x + pr[c4].y + pr[c4].z + pr[c4].w;
            s2 += pr[c4].x*pr[c4].x + pr[c4].y*pr[c4].y + pr[c4].z*pr[c4].z + pr[c4].w*pr[c4].w;
        }
        float mean = s * (1.f/DP);
        float var  = s2 * (1.f/DP) - mean*mean;
        float rinv = rsqrtf(var + 1e-5f);
        bh0 = bh1 = bh2 = bh3 = 0.f;
        #pragma unroll
        for (int c4 = 0; c4 < 4; c4++) {
            #pragma unroll
            for (int e = 0; e < 4; e++) {
                int c = c4*4 + e;
                float pv = (&pr[c4].x)[e];
                bh0 += pv*sWb[c*4+0]; bh1 += pv*sWb[c*4+1];
                bh2 += pv*sWb[c*4+2]; bh3 += pv*sWb[c*4+3];
                (&u[c4].x)[e] = (pv - mean)*rinv;
            }
        }
    };

    for (int t = tid; t < 32*64; t += 256) {
        int q = t >> 6, k0 = t & 63, k1 = k0 + 64;
        int gq = q0 + q;
        float4 u0[4], u1[4];
        float a0,a1,a2,a3, c0,c1,c2,c3;
        prep(q, k0, u0, a0, a1, a2, a3);
        prep(q, k1, u1, c0, c1, c2, c3);
        #pragma unroll 2
        for (int j = 0; j < 64; j++) {
            float4 w0 = sW1T[j][0], w1 = sW1T[j][1], w2 = sW1T[j][2], w3 = sW1T[j][3];
            float t0 = u0[0].x*w0.x + u0[0].y*w0.y + u0[0].z*w0.z + u0[0].w*w0.w
                     + u0[1].x*w1.x + u0[1].y*w1.y + u0[1].z*w1.z + u0[1].w*w1.w
                     + u0[2].x*w2.x + u0[2].y*w2.y + u0[2].z*w2.z + u0[2].w*w2.w
                     + u0[3].x*w3.x + u0[3].y*w3.y + u0[3].z*w3.z + u0[3].w*w3.w;
            float t1 = u1[0].x*w0.x + u1[0].y*w0.y + u1[0].z*w0.z + u1[0].w*w0.w
                     + u1[1].x*w1.x + u1[1].y*w1.y + u1[1].z*w1.z + u1[1].w*w1.w
                     + u1[2].x*w2.x + u1[2].y*w2.y + u1[2].z*w2.z + u1[2].w*w2.w
                     + u1[3].x*w3.x + u1[3].y*w3.y + u1[3].z*w3.z + u1[3].w*w3.w;
            t0 = fmaxf(t0, 0.f); t1 = fmaxf(t1, 0.f);
            float4 wb2 = sW2b[j];
            a0 += t0*wb2.x; a1 += t0*wb2.y; a2 += t0*wb2.z; a3 += t0*wb2.w;
            c0 += t1*wb2.x; c1 += t1*wb2.y; c2 += t1*wb2.z; c3 += t1*wb2.w;
        }
        bool v0 = svalid[k0], v1 = svalid[k1];
        brow[((0*QWIN + gq) << 7) + k0] = v0 ? a0 : 0.f;
        brow[((1*QWIN + gq) << 7) + k0] = v0 ? a1 : 0.f;
        brow[((2*QWIN + gq) << 7) + k0] = v0 ? a2 : 0.f;
        brow[((3*QWIN + gq) << 7) + k0] = v0 ? a3 : 0.f;
        brow[((0*QWIN + gq) << 7) + k1] = v1 ? c0 : 0.f;
        brow[((1*QWIN + gq) << 7) + k1] = v1 ? c1 : 0.f;
        brow[((2*QWIN + gq) << 7) + k1] = v1 ? c2 : 0.f;
        brow[((3*QWIN + gq) << 7) + k1] = v1 ? c3 : 0.f;
    }
}

// ---------------- attention per (b, window, head): 4 q-rows per pass ---------
// K/V reads amortized over 4 rows (halved LDS traffic); scalar accumulators.
__global__ void __launch_bounds__(256, 4)
attn_kernel(const float* __restrict__ qkv, float* __restrict__ o)
{
    extern __shared__ char dynattn[];
    float4* ks4 = (float4*)dynattn;            // [128][8] = 16KB
    float4* vs4 = ks4 + 1024;                  // [128][8] = 16KB
    float4* sq  = vs4 + 1024;                  // [64][8]  =  8KB
    float*  ps  = (float*)(sq + 512);          // [8][4][128] = 16KB

    int h  = blockIdx.x & 3;
    int bw = blockIdx.x >> 2;
    int w  = bw & (NW-1);
    int b  = bw >> 7;
    int tid = threadIdx.x, lane = tid & 31, warp = tid >> 5;
    int rowbase = b*N_ + w*QWIN;

    for (int s = tid; s < KWIN*8; s += 256) {
        int kk = s >> 3, i = s & 7;
        int j = w*QWIN + kk - PADW;
        float4 kv = make_float4(0,0,0,0), vv = make_float4(0,0,0,0);
        if (j >= 0 && j < N_) {
            const float* base = &qkv[(size_t)(b*N_ + j)*384 + h*32 + i*4];
            kv = *(const float4*)(base + 128);
            vv = *(const float4*)(base + 256);
        }
        int sw = i ^ (kk & 7);
        ks4[kk*8 + sw] = kv;
        vs4[kk*8 + sw] = vv;
    }
    for (int s = tid; s < QWIN*8; s += 256) {
        int r = s >> 3, i = s & 7;
        sq[r*8 + i] = *(const float4*)&qkv[(size_t)(rowbase + r)*384 + h*32 + i*4];
    }
    __syncthreads();

    const float scale = 0.17677669529663687f;
    const float* brow = g_bias + ((size_t)bw*HEADS + h)*QWIN*KWIN;
    int lane7 = lane & 7;
    int lhi = lane >> 2, llo = lane & 3;
    const float4* kbase = &ks4[lane*8];
    const float*  vbase = (const float*)vs4;
    float* pw = ps + warp*4*128;

    float msk[4];
    #pragma unroll
    for (int g = 0; g < 4; g++) {
        int j = w*QWIN + g*32 + lane - PADW;
        msk[g] = (j >= 0 && j < N_) ? 0.f : -1e9f;
    }
    int voff[8];
    #pragma unroll
    for (int t = 0; t < 8; t++) voff[t] = ((lhi ^ t) << 2) | llo;

    for (int pass = 0; pass < 2; pass++) {
        int r0 = warp*8 + pass*4;
        float a[4][4] = {};
        #pragma unroll
        for (int i = 0; i < 8; i++) {
            float4 q0 = sq[(r0  )*8 + i];
            float4 q1 = sq[(r0+1)*8 + i];
            float4 q2 = sq[(r0+2)*8 + i];
            float4 q3 = sq[(r0+3)*8 + i];
            int sw = i ^ lane7;
            #pragma unroll
            for (int g = 0; g < 4; g++) {
                float4 kv = kbase[g*256 + sw];
                a[0][g] += q0.x*kv.x + q0.y*kv.y + q0.z*kv.z + q0.w*kv.w;
                a[1][g] += q1.x*kv.x + q1.y*kv.y + q1.z*kv.z + q1.w*kv.w;
                a[2][g] += q2.x*kv.x + q2.y*kv.y + q2.z*kv.z + q2.w*kv.w;
                a[3][g] += q3.x*kv.x + q3.y*kv.y + q3.z*kv.z + q3.w*kv.w;
            }
        }
        float m[4];
        #pragma unroll
        for (int r = 0; r < 4; r++) {
            m[r] = -1e30f;
            #pragma unroll
            for (int g = 0; g < 4; g++) {
                float l = a[r][g]*scale + brow[((r0+r)<<7) + g*32 + lane] + msk[g];
                a[r][g] = l;
                m[r] = fmaxf(m[r], l);
            }
        }
        #pragma unroll
        for (int off = 16; off > 0; off >>= 1)
            #pragma unroll
            for (int r = 0; r < 4; r++)
                m[r] = fmaxf(m[r], __shfl_xor_sync(~0u, m[r], off));
        float sums[4];
        #pragma unroll
        for (int r = 0; r < 4; r++) {
            sums[r] = 0.f;
            #pragma unroll
            for (int g = 0; g < 4; g++) {
                float e = __expf(a[r][g] - m[r]);
                a[r][g] = e;
                sums[r] += e;
            }
        }
        #pragma unroll
        for (int off = 16; off > 0; off >>= 1)
            #pragma unroll
            for (int r = 0; r < 4; r++)
                sums[r] += __shfl_xor_sync(~0u, sums[r], off);
        #pragma unroll
        for (int r = 0; r < 4; r++) {
            float rs = 1.f/sums[r];
            #pragma unroll
            for (int g = 0; g < 4; g++)
                pw[r*128 + g*32 + lane] = a[r][g]*rs;
        }
        __syncwarp();
        float o4[4] = {};
        #pragma unroll 2
        for (int k8 = 0; k8 < 16; k8++) {
            const float* vb = vbase + k8*256;
            float v0 = vb[voff[0]],        v1 = vb[32  + voff[1]];
            float v2 = vb[64  + voff[2]],  v3 = vb[96  + voff[3]];
            float v4 = vb[128 + voff[4]],  v5 = vb[160 + voff[5]];
            float v6 = vb[192 + voff[6]],  v7 = vb[224 + voff[7]];
            #pragma unroll
            for (int r = 0; r < 4; r++) {
                float4 p0 = *(const float4*)&pw[r*128 + k8*8];
                float4 p1 = *(const float4*)&pw[r*128 + k8*8 + 4];
                o4[r] += p0.x*v0 + p0.y*v1 + p0.z*v2 + p0.w*v3
                       + p1.x*v4 + p1.y*v5 + p1.z*v6 + p1.w*v7;
            }
        }
        #pragma unroll
        for (int r = 0; r < 4; r++)
            o[(size_t)(rowbase + r0 + r)*DS + h*32 + lane] = o4[r];
        __syncwarp();
    }
}

// ---------------- deterministic segment mean (indices sorted) ---------------
__global__ void segmean_kernel(const int* __restrict__ a2t, float* __restrict__ out)
{
    int bt = blockIdx.x;
    int b = bt / NTOK, t = bt % NTOK;
    const int* idx = a2t + b*N_;
    __shared__ int slo, shi;
    if (threadIdx.x == 0) {
        int lo = 0, hi = N_;
        while (lo < hi) { int mid = (lo+hi) >> 1; if (idx[mid] < t) lo = mid+1; else hi = mid; }
        slo = lo;
        int lo2 = lo, hi2 = N_;
        while (lo2 < hi2) { int mid = (lo2+hi2) >> 1; if (idx[mid] < t+1) lo2 = mid+1; else hi2 = mid; }
        shi = lo2;
    }
    __syncthreads();
    int lo = slo, hi = shi;
    float rcnt = 1.f / fmaxf((float)(hi - lo), 1.f);
    for (int d = threadIdx.x; d < DT; d += blockDim.x) {
        float ssum = 0.f;
        for (int i = lo; i < hi; i++) ssum += g_tok[((size_t)(b*N_ + i))*DT + d];
        out[(size_t)bt*DT + d] = ssum * rcnt;
    }
}

// ---------------- launch ----------------------------------------------------
extern "C" void kernel_launch(void* const* d_in, const int* in_sizes, int n_in,
                              void* d_out, int out_size)
{
    const float* ref_pos    = (const float*)d_in[0];
    const float* ref_charge = (const float*)d_in[1];
    const float* ref_mask   = (const float*)d_in[2];
    const float* ref_elem   = (const float*)d_in[3];
    const float* ref_chars  = (const float*)d_in[4];
    const float* W_single   = (const float*)d_in[5];
    const float* W_pair     = (const float*)d_in[6];
    const float* W_outer    = (const float*)d_in[7];
    const float* Wp_ff1     = (const float*)d_in[8];
    const float* Wp_ff2     = (const float*)d_in[9];
    const float* Wq         = (const float*)d_in[10];
    const float* Wk         = (const float*)d_in[11];
    const float* Wv         = (const float*)d_in[12];
    const float* Wo         = (const float*)d_in[13];
    const float* Wb         = (const float*)d_in[14];
    const float* Wff1       = (const float*)d_in[15];
    const float* Wff2       = (const float*)d_in[16];
    const float* W_out      = (const float*)d_in[17];
    const int*   uid        = (const int*)d_in[18];
    const int*   a2t        = (const int*)d_in[19];
    float* out = (float*)d_out;

    float *feats, *x, *qkv, *o, *p, *tok;
    __nv_bfloat16 *bh, *bl;
    cudaGetSymbolAddress((void**)&feats, g_feats);
    cudaGetSymbolAddress((void**)&x,     g_x);
    cudaGetSymbolAddress((void**)&qkv,   g_qkv);
    cudaGetSymbolAddress((void**)&o,     g_o);
    cudaGetSymbolAddress((void**)&p,     g_p);
    cudaGetSymbolAddress((void**)&tok,   g_tok);
    cudaGetSymbolAddress((void**)&bh,    g_bh);
    cudaGetSymbolAddress((void**)&bl,    g_bl);

    const int WIDE_SMEM = (2*256*40 + 2*128*40) * 2;         // 61440 bytes
    const int FF_SMEM   = (4*128*40*4 + 2*128*40) * 2;       // 184320 bytes
    const int ATTN_SMEM = 16384 + 16384 + 8192 + 16384;      // 57344 bytes
    cudaFuncSetAttribute(mma_gemm_wide<false,3>, cudaFuncAttributeMaxDynamicSharedMemorySize, WIDE_SMEM);
    cudaFuncSetAttribute(embed_fused, cudaFuncAttributeMaxDynamicSharedMemorySize, FF_SMEM);
    cudaFuncSetAttribute(layer_fused<false>, cudaFuncAttributeMaxDynamicSharedMemorySize, FF_SMEM);
    cudaFuncSetAttribute(layer_fused<true>,  cudaFuncAttributeMaxDynamicSharedMemorySize, FF_SMEM);
    cudaFuncSetAttribute(attn_kernel, cudaFuncAttributeMaxDynamicSharedMemorySize, ATTN_SMEM);

    // 0) prep: weight pack + feats build (one launch)
    const int PB = (PACK_TOT + 255)/256;
    prep_kernel<<<PB + R_, 256>>>(W_single, Wq, Wk, Wv, Wo, Wff1, Wff2, W_out, W_outer,
                                  ref_pos, ref_charge, ref_mask, ref_elem, ref_chars);

    // 1) fused embed: x, p, qkv(layer 0)
    embed_fused<<<R_/128, 256, FF_SMEM>>>(feats,
        bh+OFF_EMB, bl+OFF_EMB, bh+OFF_WOUTER, bl+OFF_WOUTER,
        bh+OFF_QKV, bl+OFF_QKV, x, p, qkv);

    // 2) pair bias
    bias_kernel<<<B_*NW*2, 256>>>(ref_pos, uid, W_pair, Wp_ff1, Wp_ff2, Wb);

    // 3) transformer layers: attn -> layer_fused (WO+LN+FF+next QKV)
    for (int l = 0; l < DEPTH; l++) {
        attn_kernel<<<B_*NW*HEADS, 256, ATTN_SMEM>>>(qkv, o);
        if (l < DEPTH-1) {
            layer_fused<false><<<R_/128, 256, FF_SMEM>>>(o,
                bh+OFF_WO+(size_t)l*16384, bl+OFF_WO+(size_t)l*16384,
                bh+OFF_FF1+(size_t)l*65536, bl+OFF_FF1+(size_t)l*65536,
                bh+OFF_FF2+(size_t)l*65536, bl+OFF_FF2+(size_t)l*65536,
                bh+OFF_QKV+(size_t)(l+1)*49152, bl+OFF_QKV+(size_t)(l+1)*49152,
                x, qkv);
        } else {
            layer_fused<true><<<R_/128, 256, FF_SMEM>>>(o,
                bh+OFF_WO+(size_t)l*16384, bl+OFF_WO+(size_t)l*16384,
                bh+OFF_FF1+(size_t)l*65536, bl+OFF_FF1+(size_t)l*65536,
                bh+OFF_FF2+(size_t)l*65536, bl+OFF_FF2+(size_t)l*65536,
                nullptr, nullptr, x, nullptr);
        }
    }

    // 4) tok = relu(x @ W_out); segment mean -> out
    mma_gemm_wide<false,3><<<dim3(3, R_/256), 512, WIDE_SMEM>>>(x, nullptr, nullptr,
        bh+OFF_WOUT, bl+OFF_WOUT, tok, nullptr, nullptr, R_, DT, DS);
    segmean_kernel<<<B_*NTOK, 384>>>(a2t, out);
}

// round 14
// speedup vs baseline: 1.3454x; 1.0338x over previous
#include <cuda_runtime.h>
#include <cuda_bf16.h>
#include <math.h>

#define B_    2
#define N_    8192
#define R_    (B_*N_)          // 16384 rows
#define DS    128
#define DP    16
#define DT    384
#define NTOK  1024
#define QWIN  64
#define KWIN  128
#define PADW  32
#define NW    (N_/QWIN)        // 128 windows
#define HEADS 4
#define DH    32
#define DEPTH 3
#define KFEAT 389
#define KFP   416              // padded to multiple of 32

// packed bf16 weight offsets (hi/lo arrays, layout [N][Kp] row-major)
#define OFF_EMB    0           // 128 x 416
#define OFF_QKV    53248       // 3 layers x [Wq|Wk|Wv] 384 x 128
#define OFF_WO     200704      // 3 x 128 x 128
#define OFF_FF1    249856      // 3 x 512 x 128
#define OFF_FF2    446464      // 3 x 128 x 512
#define OFF_WOUT   643072      // 384 x 128
#define OFF_WOUTER 692224      // 128(pad from 32) x 128
#define PACK_TOT   708608

// ---------------- scratch (device globals: allocation-free) ----------------
__device__ float g_feats[(size_t)R_*KFP];
__device__ float g_x    [(size_t)R_*DS];
__device__ float g_qkv  [(size_t)R_*3*DS];
__device__ float g_o    [(size_t)R_*DS];
__device__ float g_p    [(size_t)R_*2*DP];
__device__ float g_bias [(size_t)B_*NW*HEADS*QWIN*KWIN];
__device__ float g_tok  [(size_t)R_*DT];
__device__ __nv_bfloat16 g_bh[PACK_TOT];
__device__ __nv_bfloat16 g_bl[PACK_TOT];

// ---------------- prep: weight pack (transpose + hi/lo split) + feats build -
__global__ void prep_kernel(const float* __restrict__ Ws, const float* __restrict__ Wq,
                            const float* __restrict__ Wk, const float* __restrict__ Wv,
                            const float* __restrict__ Wo, const float* __restrict__ W1,
                            const float* __restrict__ W2, const float* __restrict__ Wout,
                            const float* __restrict__ Wouter,
                            const float* __restrict__ pos, const float* __restrict__ charge,
                            const float* __restrict__ mask, const float* __restrict__ elem,
                            const float* __restrict__ chars)
{
    const int PB = (PACK_TOT + 255)/256;
    if ((int)blockIdx.x >= PB) {
        int row = blockIdx.x - PB;
        float* fr = g_feats + (size_t)row*KFP;
        for (int f = threadIdx.x; f < KFP; f += 256) {
            float v;
            if      (f < 3)    v = pos[row*3 + f];
            else if (f == 3)   v = charge[row];
            else if (f == 4)   v = mask[row];
            else if (f < 133)  v = elem[(size_t)row*128 + (f-5)];
            else if (f < KFEAT)v = chars[(size_t)row*256 + (f-133)];
            else               v = 0.f;
            fr[f] = v;
        }
        return;
    }
    long idx = (long)blockIdx.x*256 + threadIdx.x;
    if (idx >= PACK_TOT) return;
    float v;
    if (idx >= OFF_WOUTER) {
        long rem = idx - OFF_WOUTER;
        int n = (int)(rem / 128), k = (int)(rem % 128);
        v = (n < 32) ? Wouter[(size_t)k*32 + n] : 0.f;
    } else {
        const float* src; int K, N, Kp; long rem;
        if (idx < OFF_QKV)      { src = Ws;  K = KFEAT; N = 128; Kp = KFP; rem = idx; }
        else if (idx < OFF_WO)  { long r = idx - OFF_QKV; int l = (int)(r/49152); r %= 49152;
                                  int ws = (int)(r/16384); rem = r % 16384;
                                  src = (ws==0 ? Wq : ws==1 ? Wk : Wv) + (size_t)l*16384;
                                  K = 128; N = 128; Kp = 128; }
        else if (idx < OFF_FF1) { long r = idx - OFF_WO; int l = (int)(r/16384); rem = r % 16384;
                                  src = Wo + (size_t)l*16384; K = 128; N = 128; Kp = 128; }
        else if (idx < OFF_FF2) { long r = idx - OFF_FF1; int l = (int)(r/65536); rem = r % 65536;
                                  src = W1 + (size_t)l*65536; K = 128; N = 512; Kp = 128; }
        else if (idx < OFF_WOUT){ long r = idx - OFF_FF2; int l = (int)(r/65536); rem = r % 65536;
                                  src = W2 + (size_t)l*65536; K = 512; N = 128; Kp = 512; }
        else                    { rem = idx - OFF_WOUT; src = Wout; K = 128; N = 384; Kp = 128; }
        int n = (int)(rem / Kp), k = (int)(rem % Kp);
        v = (k < K) ? src[(size_t)k*N + n] : 0.f;
    }
    __nv_bfloat16 h = __float2bfloat16(v);
    g_bh[idx] = h;
    g_bl[idx] = __float2bfloat16(v - __bfloat162float(h));
}

// ---------------- mma helpers ------------------------------------------------
__device__ __forceinline__ void ldsm4(unsigned &r0, unsigned &r1, unsigned &r2, unsigned &r3,
                                      const __nv_bfloat16* p)
{
    unsigned a = (unsigned)__cvta_generic_to_shared(p);
    asm volatile("ldmatrix.sync.aligned.m8n8.x4.shared.b16 {%0,%1,%2,%3},[%4];"
                 : "=r"(r0), "=r"(r1), "=r"(r2), "=r"(r3) : "r"(a));
}
__device__ __forceinline__ void mma16816(float* d, const unsigned* a, unsigned b0, unsigned b1)
{
    asm volatile("mma.sync.aligned.m16n8k16.row.col.f32.bf16.bf16.f32 "
                 "{%0,%1,%2,%3},{%4,%5,%6,%7},{%8,%9},{%0,%1,%2,%3};"
                 : "+f"(d[0]), "+f"(d[1]), "+f"(d[2]), "+f"(d[3])
                 : "r"(a[0]), "r"(a[1]), "r"(a[2]), "r"(a[3]), "r"(b0), "r"(b1));
}

// shared 32-k-step mma over one A chunk + one B tile (both bf16-split, LD=40)
__device__ __forceinline__ void mma_chunk(float acc[2][8][4],
    const __nv_bfloat16* sXh, const __nv_bfloat16* sXl,
    const __nv_bfloat16* sBh, const __nv_bfloat16* sBl,
    int lane, int warpM, int warpN)
{
    constexpr int LD = 40;
    #pragma unroll
    for (int ks = 0; ks < 2; ks++) {
        int rowin = lane & 7, tile = lane >> 3;
        unsigned ah[2][4], al[2][4];
        #pragma unroll
        for (int mi = 0; mi < 2; mi++) {
            int r = warpM + mi*16 + (tile & 1)*8 + rowin;
            int c = ks*16 + (tile >> 1)*8;
            ldsm4(ah[mi][0], ah[mi][1], ah[mi][2], ah[mi][3], &sXh[r*LD + c]);
            ldsm4(al[mi][0], al[mi][1], al[mi][2], al[mi][3], &sXl[r*LD + c]);
        }
        #pragma unroll
        for (int np = 0; np < 4; np++) {
            int nrow = warpN + np*16 + (tile >> 1)*8 + rowin;
            int c = ks*16 + (tile & 1)*8;
            unsigned bh0, bh1, bh2, bh3, bl0, bl1, bl2, bl3;
            ldsm4(bh0, bh1, bh2, bh3, &sBh[nrow*LD + c]);
            ldsm4(bl0, bl1, bl2, bl3, &sBl[nrow*LD + c]);
            #pragma unroll
            for (int mi = 0; mi < 2; mi++) {
                mma16816(acc[mi][np*2],   ah[mi], bh0, bh1);
                mma16816(acc[mi][np*2],   al[mi], bh0, bh1);
                mma16816(acc[mi][np*2],   ah[mi], bl0, bl1);
                mma16816(acc[mi][np*2+1], ah[mi], bh2, bh3);
                mma16816(acc[mi][np*2+1], al[mi], bh2, bh3);
                mma16816(acc[mi][np*2+1], ah[mi], bl2, bl3);
            }
        }
    }
}

// ---------------- wide GEMM: BM=256, 512 threads, dynamic smem (W_out only) --
template<bool ABF16, int EPI>
__global__ void __launch_bounds__(512)
mma_gemm_wide(const float* __restrict__ A,
              const __nv_bfloat16* __restrict__ Agh, const __nv_bfloat16* __restrict__ Agl,
              const __nv_bfloat16* __restrict__ Bh,  const __nv_bfloat16* __restrict__ Bl,
              float* __restrict__ C,
              __nv_bfloat16* __restrict__ Hh, __nv_bfloat16* __restrict__ Hl,
              int M, int N, int K)
{
    constexpr int LD = 40;
    extern __shared__ __nv_bfloat16 dyns[];
    __nv_bfloat16* sAh = dyns;
    __nv_bfloat16* sAl = sAh + 256*LD;
    __nv_bfloat16* sBh = sAl + 256*LD;
    __nv_bfloat16* sBl = sBh + 128*LD;
    int tid = threadIdx.x, lane = tid & 31, warp = tid >> 5;
    int m0 = blockIdx.y*256, n0 = blockIdx.x*128;
    int warpM = (warp >> 1)*32, warpN = (warp & 1)*64;

    float acc[2][8][4] = {};
    float4 pa[4]; uint4 pah[2], pal[2], pbh, pbl;

    if (ABF16) {
        #pragma unroll
        for (int i = 0; i < 2; i++) {
            int idx = tid + i*512, row = idx >> 2, q = idx & 3;
            pah[i] = *(const uint4*)&Agh[(size_t)(m0+row)*K + q*8];
            pal[i] = *(const uint4*)&Agl[(size_t)(m0+row)*K + q*8];
        }
    } else {
        #pragma unroll
        for (int i = 0; i < 4; i++) {
            int idx = tid + i*512, row = idx >> 3, c4 = idx & 7;
            pa[i] = *(const float4*)&A[(size_t)(m0+row)*K + c4*4];
        }
    }
    {
        int row = tid >> 2, q = tid & 3;
        pbh = *(const uint4*)&Bh[(size_t)(n0+row)*K + q*8];
        pbl = *(const uint4*)&Bl[(size_t)(n0+row)*K + q*8];
    }

    int nt = K / 32;
    for (int t = 0; t < nt; t++) {
        __syncthreads();
        if (ABF16) {
            #pragma unroll
            for (int i = 0; i < 2; i++) {
                int idx = tid + i*512, row = idx >> 2, q = idx & 3;
                *(uint4*)&sAh[row*LD + q*8] = pah[i];
                *(uint4*)&sAl[row*LD + q*8] = pal[i];
            }
        } else {
            #pragma unroll
            for (int i = 0; i < 4; i++) {
                int idx = tid + i*512, row = idx >> 3, c = (idx & 7)*4;
                float4 v = pa[i];
                __nv_bfloat16 h0 = __float2bfloat16(v.x), h1 = __float2bfloat16(v.y);
                __nv_bfloat16 h2 = __float2bfloat16(v.z), h3 = __float2bfloat16(v.w);
                __nv_bfloat162 hh0; hh0.x = h0; hh0.y = h1;
                __nv_bfloat162 hh1; hh1.x = h2; hh1.y = h3;
                *(__nv_bfloat162*)&sAh[row*LD + c]     = hh0;
                *(__nv_bfloat162*)&sAh[row*LD + c + 2] = hh1;
                __nv_bfloat162 ll0, ll1;
                ll0.x = __float2bfloat16(v.x - __bfloat162float(h0));
                ll0.y = __float2bfloat16(v.y - __bfloat162float(h1));
                ll1.x = __float2bfloat16(v.z - __bfloat162float(h2));
                ll1.y = __float2bfloat16(v.w - __bfloat162float(h3));
                *(__nv_bfloat162*)&sAl[row*LD + c]     = ll0;
                *(__nv_bfloat162*)&sAl[row*LD + c + 2] = ll1;
            }
        }
        {
            int row = tid >> 2, q = tid & 3;
            *(uint4*)&sBh[row*LD + q*8] = pbh;
            *(uint4*)&sBl[row*LD + q*8] = pbl;
        }
        __syncthreads();
        if (t + 1 < nt) {
            int kc = (t+1)*32;
            if (ABF16) {
                #pragma unroll
                for (int i = 0; i < 2; i++) {
                    int idx = tid + i*512, row = idx >> 2, q = idx & 3;
                    pah[i] = *(const uint4*)&Agh[(size_t)(m0+row)*K + kc + q*8];
                    pal[i] = *(const uint4*)&Agl[(size_t)(m0+row)*K + kc + q*8];
                }
            } else {
                #pragma unroll
                for (int i = 0; i < 4; i++) {
                    int idx = tid + i*512, row = idx >> 3, c4 = idx & 7;
                    pa[i] = *(const float4*)&A[(size_t)(m0+row)*K + kc + c4*4];
                }
            }
            {
                int row = tid >> 2, q = tid & 3;
                pbh = *(const uint4*)&Bh[(size_t)(n0+row)*K + kc + q*8];
                pbl = *(const uint4*)&Bl[(size_t)(n0+row)*K + kc + q*8];
            }
        }
        mma_chunk(acc, sAh, sAl, sBh, sBl, lane, warpM, warpN);
    }

    #pragma unroll
    for (int mi = 0; mi < 2; mi++) {
        #pragma unroll
        for (int nj = 0; nj < 8; nj++) {
            int r0  = m0 + warpM + mi*16 + (lane >> 2);
            int col = n0 + warpN + nj*8 + (lane & 3)*2;
            float v0 = acc[mi][nj][0], v1 = acc[mi][nj][1];
            float v2 = acc[mi][nj][2], v3 = acc[mi][nj][3];
            if (EPI == 3) {
                v0 = fmaxf(v0, 0.f); v1 = fmaxf(v1, 0.f);
                v2 = fmaxf(v2, 0.f); v3 = fmaxf(v3, 0.f);
            }
            float2 o0; o0.x = v0; o0.y = v1;
            float2 o1; o1.x = v2; o1.y = v3;
            *(float2*)&C[(size_t)r0*N + col]     = o0;
            *(float2*)&C[(size_t)(r0+8)*N + col] = o1;
        }
    }
}

// ---------------- fused embed: x = feats@Wemb; LN; p = relu(x)@Wouter; qkv ---
__global__ void __launch_bounds__(256)
embed_fused(const float* __restrict__ feats,
            const __nv_bfloat16* __restrict__ Weh, const __nv_bfloat16* __restrict__ Wel,
            const __nv_bfloat16* __restrict__ Wph, const __nv_bfloat16* __restrict__ Wpl,
            const __nv_bfloat16* __restrict__ Qwh, const __nv_bfloat16* __restrict__ Qwl,
            float* __restrict__ X, float* __restrict__ Pout, float* __restrict__ qkvout)
{
    constexpr int LD = 40;
    constexpr int CH = 128*LD;
    extern __shared__ __nv_bfloat16 dyns[];
    __nv_bfloat16* sAh = dyns;
    __nv_bfloat16* sAl = sAh + 4*CH;
    __nv_bfloat16* sFh = sAl + 4*CH;
    __nv_bfloat16* sFl = sFh + 4*CH;
    __nv_bfloat16* sBh = sFl + 4*CH;
    __nv_bfloat16* sBl = sBh + CH;
    __shared__ float2 ssum[128][2];

    int tid = threadIdx.x, lane = tid & 31, warp = tid >> 5;
    int m0 = blockIdx.x*128;
    int warpM = (warp >> 1)*32, warpN = (warp & 1)*64;
    int brow = tid >> 2, bq = tid & 3;

    uint4 pbh[2], pbl[2];
    float4 pa[4];

    auto ln_stats = [&](float acc[2][8][4], float* mean, float* rsig) {
        float s[4] = {}, s2[4] = {};
        #pragma unroll
        for (int mi = 0; mi < 2; mi++)
            #pragma unroll
            for (int nj = 0; nj < 8; nj++) {
                float v0 = acc[mi][nj][0], v1 = acc[mi][nj][1];
                float v2 = acc[mi][nj][2], v3 = acc[mi][nj][3];
                s[mi*2]    += v0 + v1;      s2[mi*2]   += v0*v0 + v1*v1;
                s[mi*2+1]  += v2 + v3;      s2[mi*2+1] += v2*v2 + v3*v3;
            }
        #pragma unroll
        for (int off = 1; off <= 2; off <<= 1)
            #pragma unroll
            for (int r = 0; r < 4; r++) {
                s[r]  += __shfl_xor_sync(~0u, s[r],  off);
                s2[r] += __shfl_xor_sync(~0u, s2[r], off);
            }
        __syncthreads();
        if ((lane & 3) == 0) {
            #pragma unroll
            for (int slot = 0; slot < 4; slot++) {
                int row = warpM + (slot >> 1)*16 + (lane >> 2) + 8*(slot & 1);
                ssum[row][warp & 1] = make_float2(s[slot], s2[slot]);
            }
        }
        __syncthreads();
        #pragma unroll
        for (int slot = 0; slot < 4; slot++) {
            int row = warpM + (slot >> 1)*16 + (lane >> 2) + 8*(slot & 1);
            float2 a = ssum[row][0], b = ssum[row][1];
            float m  = (a.x + b.x) * (1.f/128.f);
            float vv = (a.y + b.y) * (1.f/128.f) - m*m;
            mean[slot] = m;
            rsig[slot] = rsqrtf(vv + 1e-5f);
        }
    };

    // ---- stage E: x = feats @ Wemb (K = 416 = 13 chunks), A fp32 on the fly
    float accE[2][8][4] = {};
    #pragma unroll
    for (int i = 0; i < 4; i++) {
        int idx = tid + i*256, row = idx >> 3, c4 = idx & 7;
        pa[i] = *(const float4*)&feats[(size_t)(m0+row)*KFP + c4*4];
    }
    pbh[0] = *(const uint4*)&Weh[(size_t)brow*KFP + bq*8];
    pbh[1] = *(const uint4*)&Weh[(size_t)(brow+64)*KFP + bq*8];
    pbl[0] = *(const uint4*)&Wel[(size_t)brow*KFP + bq*8];
    pbl[1] = *(const uint4*)&Wel[(size_t)(brow+64)*KFP + bq*8];

    #pragma unroll 1
    for (int t = 0; t < 13; t++) {
        __syncthreads();
        #pragma unroll
        for (int i = 0; i < 4; i++) {
            int idx = tid + i*256, row = idx >> 3, c = (idx & 7)*4;
            float4 v = pa[i];
            __nv_bfloat16 h0 = __float2bfloat16(v.x), h1 = __float2bfloat16(v.y);
            __nv_bfloat16 h2 = __float2bfloat16(v.z), h3 = __float2bfloat16(v.w);
            __nv_bfloat162 hh0; hh0.x = h0; hh0.y = h1;
            __nv_bfloat162 hh1; hh1.x = h2; hh1.y = h3;
            *(__nv_bfloat162*)&sFh[row*LD + c]     = hh0;
            *(__nv_bfloat162*)&sFh[row*LD + c + 2] = hh1;
            __nv_bfloat162 ll0, ll1;
            ll0.x = __float2bfloat16(v.x - __bfloat162float(h0));
            ll0.y = __float2bfloat16(v.y - __bfloat162float(h1));
            ll1.x = __float2bfloat16(v.z - __bfloat162float(h2));
            ll1.y = __float2bfloat16(v.w - __bfloat162float(h3));
            *(__nv_bfloat162*)&sFl[row*LD + c]     = ll0;
            *(__nv_bfloat162*)&sFl[row*LD + c + 2] = ll1;
        }
        *(uint4*)&sBh[brow*LD + bq*8]      = pbh[0];
        *(uint4*)&sBh[(brow+64)*LD + bq*8] = pbh[1];
        *(uint4*)&sBl[brow*LD + bq*8]      = pbl[0];
        *(uint4*)&sBl[(brow+64)*LD + bq*8] = pbl[1];
        __syncthreads();
        if (t + 1 < 13) {
            int kc = (t+1)*32;
            #pragma unroll
            for (int i = 0; i < 4; i++) {
                int idx = tid + i*256, row = idx >> 3, c4 = idx & 7;
                pa[i] = *(const float4*)&feats[(size_t)(m0+row)*KFP + kc + c4*4];
            }
            pbh[0] = *(const uint4*)&Weh[(size_t)brow*KFP + kc + bq*8];
            pbh[1] = *(const uint4*)&Weh[(size_t)(brow+64)*KFP + kc + bq*8];
            pbl[0] = *(const uint4*)&Wel[(size_t)brow*KFP + kc + bq*8];
            pbl[1] = *(const uint4*)&Wel[(size_t)(brow+64)*KFP + kc + bq*8];
        } else {
            pbh[0] = *(const uint4*)&Wph[(size_t)brow*128 + bq*8];
            pbh[1] = *(const uint4*)&Wph[(size_t)(brow+64)*128 + bq*8];
            pbl[0] = *(const uint4*)&Wpl[(size_t)brow*128 + bq*8];
            pbl[1] = *(const uint4*)&Wpl[(size_t)(brow+64)*128 + bq*8];
        }
        mma_chunk(accE, sFh, sFl, sBh, sBl, lane, warpM, warpN);
    }

    float mean[4], rsig[4];
    ln_stats(accE, mean, rsig);

    #pragma unroll
    for (int mi = 0; mi < 2; mi++) {
        #pragma unroll
        for (int nj = 0; nj < 8; nj++) {
            int r   = warpM + mi*16 + (lane >> 2);
            int col = warpN + nj*8 + (lane & 3)*2;
            int r0  = m0 + r;
            float v0 = accE[mi][nj][0], v1 = accE[mi][nj][1];
            float v2 = accE[mi][nj][2], v3 = accE[mi][nj][3];
            float2 o0; o0.x = v0; o0.y = v1;
            float2 o1; o1.x = v2; o1.y = v3;
            *(float2*)&X[(size_t)r0*128 + col]     = o0;
            *(float2*)&X[(size_t)(r0+8)*128 + col] = o1;
            int off = (col >> 5)*CH + (col & 31);
            {
                float a0 = fmaxf(v0,0.f), a1 = fmaxf(v1,0.f);
                float a2 = fmaxf(v2,0.f), a3 = fmaxf(v3,0.f);
                __nv_bfloat162 h0, h1, l0, l1;
                h0.x = __float2bfloat16(a0); h0.y = __float2bfloat16(a1);
                h1.x = __float2bfloat16(a2); h1.y = __float2bfloat16(a3);
                l0.x = __float2bfloat16(a0 - __bfloat162float(h0.x));
                l0.y = __float2bfloat16(a1 - __bfloat162float(h0.y));
                l1.x = __float2bfloat16(a2 - __bfloat162float(h1.x));
                l1.y = __float2bfloat16(a3 - __bfloat162float(h1.y));
                *(__nv_bfloat162*)&sFh[off + r*LD]     = h0;
                *(__nv_bfloat162*)&sFh[off + (r+8)*LD] = h1;
                *(__nv_bfloat162*)&sFl[off + r*LD]     = l0;
                *(__nv_bfloat162*)&sFl[off + (r+8)*LD] = l1;
            }
            {
                float a0 = (v0 - mean[mi*2])*rsig[mi*2];
                float a1 = (v1 - mean[mi*2])*rsig[mi*2];
                float a2 = (v2 - mean[mi*2+1])*rsig[mi*2+1];
                float a3 = (v3 - mean[mi*2+1])*rsig[mi*2+1];
                __nv_bfloat162 h0, h1, l0, l1;
                h0.x = __float2bfloat16(a0); h0.y = __float2bfloat16(a1);
                h1.x = __float2bfloat16(a2); h1.y = __float2bfloat16(a3);
                l0.x = __float2bfloat16(a0 - __bfloat162float(h0.x));
                l0.y = __float2bfloat16(a1 - __bfloat162float(h0.y));
                l1.x = __float2bfloat16(a2 - __bfloat162float(h1.x));
                l1.y = __float2bfloat16(a3 - __bfloat162float(h1.y));
                *(__nv_bfloat162*)&sAh[off + r*LD]     = h0;
                *(__nv_bfloat162*)&sAh[off + (r+8)*LD] = h1;
                *(__nv_bfloat162*)&sAl[off + r*LD]     = l0;
                *(__nv_bfloat162*)&sAl[off + (r+8)*LD] = l1;
            }
        }
    }

    // ---- stage P: p = relu(x) @ Wouter_pad (valid cols 0..31) ----
    {
        float accP[2][8][4] = {};
        #pragma unroll
        for (int t = 0; t < 4; t++) {
            __syncthreads();
            *(uint4*)&sBh[brow*LD + bq*8]      = pbh[0];
            *(uint4*)&sBh[(brow+64)*LD + bq*8] = pbh[1];
            *(uint4*)&sBl[brow*LD + bq*8]      = pbl[0];
            *(uint4*)&sBl[(brow+64)*LD + bq*8] = pbl[1];
            __syncthreads();
            if (t + 1 < 4) {
                int kc = (t+1)*32;
                pbh[0] = *(const uint4*)&Wph[(size_t)brow*128 + kc + bq*8];
                pbh[1] = *(const uint4*)&Wph[(size_t)(brow+64)*128 + kc + bq*8];
                pbl[0] = *(const uint4*)&Wpl[(size_t)brow*128 + kc + bq*8];
                pbl[1] = *(const uint4*)&Wpl[(size_t)(brow+64)*128 + kc + bq*8];
            } else {
                pbh[0] = *(const uint4*)&Qwh[(size_t)brow*128 + bq*8];
                pbh[1] = *(const uint4*)&Qwh[(size_t)(brow+64)*128 + bq*8];
                pbl[0] = *(const uint4*)&Qwl[(size_t)brow*128 + bq*8];
                pbl[1] = *(const uint4*)&Qwl[(size_t)(brow+64)*128 + bq*8];
            }
            mma_chunk(accP, sFh + t*CH, sFl + t*CH, sBh, sBl, lane, warpM, warpN);
        }
        if (warpN == 0) {
            #pragma unroll
            for (int mi = 0; mi < 2; mi++) {
                #pragma unroll
                for (int nj = 0; nj < 4; nj++) {
                    int r0  = m0 + warpM + mi*16 + (lane >> 2);
                    int col = nj*8 + (lane & 3)*2;
                    float2 o0; o0.x = accP[mi][nj][0]; o0.y = accP[mi][nj][1];
                    float2 o1; o1.x = accP[mi][nj][2]; o1.y = accP[mi][nj][3];
                    *(float2*)&Pout[(size_t)r0*32 + col]     = o0;
                    *(float2*)&Pout[(size_t)(r0+8)*32 + col] = o1;
                }
            }
        }
    }

    // ---- stage Q: qkv = h' @ Wqkv (3 N-blocks x 4 k-chunks) ----
    #pragma unroll 1
    for (int nb = 0; nb < 3; nb++) {
        float acc[2][8][4] = {};
        #pragma unroll
        for (int t = 0; t < 4; t++) {
            __syncthreads();
            *(uint4*)&sBh[brow*LD + bq*8]      = pbh[0];
            *(uint4*)&sBh[(brow+64)*LD + bq*8] = pbh[1];
            *(uint4*)&sBl[brow*LD + bq*8]      = pbl[0];
            *(uint4*)&sBl[(brow+64)*LD + bq*8] = pbl[1];
            __syncthreads();
            int ni = nb*4 + t + 1;
            if (ni < 12) {
                int nrow = (ni >> 2)*128, kc = (ni & 3)*32;
                pbh[0] = *(const uint4*)&Qwh[(size_t)(nrow + brow)*128 + kc + bq*8];
                pbh[1] = *(const uint4*)&Qwh[(size_t)(nrow + brow+64)*128 + kc + bq*8];
                pbl[0] = *(const uint4*)&Qwl[(size_t)(nrow + brow)*128 + kc + bq*8];
                pbl[1] = *(const uint4*)&Qwl[(size_t)(nrow + brow+64)*128 + kc + bq*8];
            }
            mma_chunk(acc, sAh + t*CH, sAl + t*CH, sBh, sBl, lane, warpM, warpN);
        }
        #pragma unroll
        for (int mi = 0; mi < 2; mi++) {
            #pragma unroll
            for (int nj = 0; nj < 8; nj++) {
                int r0  = m0 + warpM + mi*16 + (lane >> 2);
                int col = nb*128 + warpN + nj*8 + (lane & 3)*2;
                float2 o0; o0.x = acc[mi][nj][0]; o0.y = acc[mi][nj][1];
                float2 o1; o1.x = acc[mi][nj][2]; o1.y = acc[mi][nj][3];
                *(float2*)&qkvout[(size_t)r0*384 + col]     = o0;
                *(float2*)&qkvout[(size_t)(r0+8)*384 + col] = o1;
            }
        }
    }
}

// ---------------- fused layer tail: WO + res + LN + FF + (next QKV) ---------
template<bool LAST>
__global__ void __launch_bounds__(256)
layer_fused(const float* __restrict__ oin,
            const __nv_bfloat16* __restrict__ Woh, const __nv_bfloat16* __restrict__ Wol,
            const __nv_bfloat16* __restrict__ B1h, const __nv_bfloat16* __restrict__ B1l,
            const __nv_bfloat16* __restrict__ B2h, const __nv_bfloat16* __restrict__ B2l,
            const __nv_bfloat16* __restrict__ Qwh, const __nv_bfloat16* __restrict__ Qwl,
            float* __restrict__ X, float* __restrict__ qkvout)
{
    constexpr int LD = 40;
    constexpr int CH = 128*LD;
    extern __shared__ __nv_bfloat16 dyns[];
    __nv_bfloat16* sAh = dyns;
    __nv_bfloat16* sAl = sAh + 4*CH;
    __nv_bfloat16* sFh = sAl + 4*CH;
    __nv_bfloat16* sFl = sFh + 4*CH;
    __nv_bfloat16* sBh = sFl + 4*CH;
    __nv_bfloat16* sBl = sBh + CH;
    __shared__ float2 ssum[128][2];

    int tid = threadIdx.x, lane = tid & 31, warp = tid >> 5;
    int m0 = blockIdx.x*128;
    int warpM = (warp >> 1)*32, warpN = (warp & 1)*64;
    int brow = tid >> 2, bq = tid & 3;

    uint4 pbh[2], pbl[2];

    auto ln_stats = [&](float acc[2][8][4], float* mean, float* rsig) {
        float s[4] = {}, s2[4] = {};
        #pragma unroll
        for (int mi = 0; mi < 2; mi++)
            #pragma unroll
            for (int nj = 0; nj < 8; nj++) {
                float v0 = acc[mi][nj][0], v1 = acc[mi][nj][1];
                float v2 = acc[mi][nj][2], v3 = acc[mi][nj][3];
                s[mi*2]    += v0 + v1;      s2[mi*2]   += v0*v0 + v1*v1;
                s[mi*2+1]  += v2 + v3;      s2[mi*2+1] += v2*v2 + v3*v3;
            }
        #pragma unroll
        for (int off = 1; off <= 2; off <<= 1)
            #pragma unroll
            for (int r = 0; r < 4; r++) {
                s[r]  += __shfl_xor_sync(~0u, s[r],  off);
                s2[r] += __shfl_xor_sync(~0u, s2[r], off);
            }
        __syncthreads();
        if ((lane & 3) == 0) {
            #pragma unroll
            for (int slot = 0; slot < 4; slot++) {
                int row = warpM + (slot >> 1)*16 + (lane >> 2) + 8*(slot & 1);
                ssum[row][warp & 1] = make_float2(s[slot], s2[slot]);
            }
        }
        __syncthreads();
        #pragma unroll
        for (int slot = 0; slot < 4; slot++) {
            int row = warpM + (slot >> 1)*16 + (lane >> 2) + 8*(slot & 1);
            float2 a = ssum[row][0], b = ssum[row][1];
            float m  = (a.x + b.x) * (1.f/128.f);
            float vv = (a.y + b.y) * (1.f/128.f) - m*m;
            mean[slot] = m;
            rsig[slot] = rsqrtf(vv + 1e-5f);
        }
    };

    // ---- stage W: x_mid = x + o@Wo; LN -> h' in sA
    {
        #pragma unroll
        for (int i = 0; i < 16; i++) {
            int idx = tid + i*256;
            int row = idx >> 5, q = idx & 31;
            float4 v = *(const float4*)&oin[(size_t)(m0+row)*128 + q*4];
            int off = (q >> 3)*CH + row*LD + (q & 7)*4;
            __nv_bfloat162 h0, h1, l0, l1;
            h0.x = __float2bfloat16(v.x); h0.y = __float2bfloat16(v.y);
            h1.x = __float2bfloat16(v.z); h1.y = __float2bfloat16(v.w);
            l0.x = __float2bfloat16(v.x - __bfloat162float(h0.x));
            l0.y = __float2bfloat16(v.y - __bfloat162float(h0.y));
            l1.x = __float2bfloat16(v.z - __bfloat162float(h1.x));
            l1.y = __float2bfloat16(v.w - __bfloat162float(h1.y));
            *(__nv_bfloat162*)&sFh[off]     = h0;
            *(__nv_bfloat162*)&sFh[off + 2] = h1;
            *(__nv_bfloat162*)&sFl[off]     = l0;
            *(__nv_bfloat162*)&sFl[off + 2] = l1;
        }
        pbh[0] = *(const uint4*)&Woh[(size_t)brow*128 + bq*8];
        pbh[1] = *(const uint4*)&Woh[(size_t)(brow+64)*128 + bq*8];
        pbl[0] = *(const uint4*)&Wol[(size_t)brow*128 + bq*8];
        pbl[1] = *(const uint4*)&Wol[(size_t)(brow+64)*128 + bq*8];

        float accW[2][8][4] = {};
        #pragma unroll
        for (int t = 0; t < 4; t++) {
            __syncthreads();
            *(uint4*)&sBh[brow*LD + bq*8]      = pbh[0];
            *(uint4*)&sBh[(brow+64)*LD + bq*8] = pbh[1];
            *(uint4*)&sBl[brow*LD + bq*8]      = pbl[0];
            *(uint4*)&sBl[(brow+64)*LD + bq*8] = pbl[1];
            __syncthreads();
            if (t + 1 < 4) {
                int kc = (t+1)*32;
                pbh[0] = *(const uint4*)&Woh[(size_t)brow*128 + kc + bq*8];
                pbh[1] = *(const uint4*)&Woh[(size_t)(brow+64)*128 + kc + bq*8];
                pbl[0] = *(const uint4*)&Wol[(size_t)brow*128 + kc + bq*8];
                pbl[1] = *(const uint4*)&Wol[(size_t)(brow+64)*128 + kc + bq*8];
            } else {
                pbh[0] = *(const uint4*)&B1h[(size_t)brow*128 + bq*8];
                pbh[1] = *(const uint4*)&B1h[(size_t)(brow+64)*128 + bq*8];
                pbl[0] = *(const uint4*)&B1l[(size_t)brow*128 + bq*8];
                pbl[1] = *(const uint4*)&B1l[(size_t)(brow+64)*128 + bq*8];
            }
            mma_chunk(accW, sFh + t*CH, sFl + t*CH, sBh, sBl, lane, warpM, warpN);
        }
        #pragma unroll
        for (int mi = 0; mi < 2; mi++) {
            #pragma unroll
            for (int nj = 0; nj < 8; nj++) {
                int r0  = m0 + warpM + mi*16 + (lane >> 2);
                int col = warpN + nj*8 + (lane & 3)*2;
                float2 c0 = *(const float2*)&X[(size_t)r0*128 + col];
                float2 c1 = *(const float2*)&X[(size_t)(r0+8)*128 + col];
                accW[mi][nj][0] += c0.x; accW[mi][nj][1] += c0.y;
                accW[mi][nj][2] += c1.x; accW[mi][nj][3] += c1.y;
            }
        }
        float mean[4], rsig[4];
        ln_stats(accW, mean, rsig);
        #pragma unroll
        for (int mi = 0; mi < 2; mi++) {
            #pragma unroll
            for (int nj = 0; nj < 8; nj++) {
                int r   = warpM + mi*16 + (lane >> 2);
                int col = warpN + nj*8 + (lane & 3)*2;
                int r0  = m0 + r;
                float v0 = accW[mi][nj][0], v1 = accW[mi][nj][1];
                float v2 = accW[mi][nj][2], v3 = accW[mi][nj][3];
                float2 o0; o0.x = v0; o0.y = v1;
                float2 o1; o1.x = v2; o1.y = v3;
                *(float2*)&X[(size_t)r0*128 + col]     = o0;
                *(float2*)&X[(size_t)(r0+8)*128 + col] = o1;
                v0 = (v0 - mean[mi*2])*rsig[mi*2];
                v1 = (v1 - mean[mi*2])*rsig[mi*2];
                v2 = (v2 - mean[mi*2+1])*rsig[mi*2+1];
                v3 = (v3 - mean[mi*2+1])*rsig[mi*2+1];
                int off = (col >> 5)*CH + (col & 31);
                __nv_bfloat162 h0, h1, l0, l1;
                h0.x = __float2bfloat16(v0); h0.y = __float2bfloat16(v1);
                h1.x = __float2bfloat16(v2); h1.y = __float2bfloat16(v3);
                l0.x = __float2bfloat16(v0 - __bfloat162float(h0.x));
                l0.y = __float2bfloat16(v1 - __bfloat162float(h0.y));
                l1.x = __float2bfloat16(v2 - __bfloat162float(h1.x));
                l1.y = __float2bfloat16(v3 - __bfloat162float(h1.y));
                *(__nv_bfloat162*)&sAh[off + r*LD]     = h0;
                *(__nv_bfloat162*)&sAh[off + (r+8)*LD] = h1;
                *(__nv_bfloat162*)&sAl[off + r*LD]     = l0;
                *(__nv_bfloat162*)&sAl[off + (r+8)*LD] = l1;
            }
        }
    }

    // ---- FF stages ----
    auto bptr = [&](int i, int row, const __nv_bfloat16* b1, const __nv_bfloat16* b2)
        -> const __nv_bfloat16* {
        int c = i >> 3, t = i & 3;
        if (((i >> 2) & 1) == 0)
            return &b1[(size_t)(c*128 + row)*128 + t*32 + bq*8];
        else
            return &b2[(size_t)row*512 + c*128 + t*32 + bq*8];
    };

    float acc2[2][8][4] = {};
    #pragma unroll 1
    for (int c = 0; c < 4; c++) {
        float acc1[2][8][4] = {};
        #pragma unroll
        for (int t = 0; t < 4; t++) {
            __syncthreads();
            *(uint4*)&sBh[brow*LD + bq*8]      = pbh[0];
            *(uint4*)&sBh[(brow+64)*LD + bq*8] = pbh[1];
            *(uint4*)&sBl[brow*LD + bq*8]      = pbl[0];
            *(uint4*)&sBl[(brow+64)*LD + bq*8] = pbl[1];
            __syncthreads();
            int ni = c*8 + t + 1;
            pbh[0] = *(const uint4*)bptr(ni, brow,    B1h, B2h);
            pbh[1] = *(const uint4*)bptr(ni, brow+64, B1h, B2h);
            pbl[0] = *(const uint4*)bptr(ni, brow,    B1l, B2l);
            pbl[1] = *(const uint4*)bptr(ni, brow+64, B1l, B2l);
            mma_chunk(acc1, sAh + t*CH, sAl + t*CH, sBh, sBl, lane, warpM, warpN);
        }
        #pragma unroll
        for (int mi = 0; mi < 2; mi++) {
            #pragma unroll
            for (int nj = 0; nj < 8; nj++) {
                int r   = warpM + mi*16 + (lane >> 2);
                int col = warpN + nj*8 + (lane & 3)*2;
                int off = (col >> 5)*CH + (col & 31);
                float v0 = fmaxf(acc1[mi][nj][0], 0.f), v1 = fmaxf(acc1[mi][nj][1], 0.f);
                float v2 = fmaxf(acc1[mi][nj][2], 0.f), v3 = fmaxf(acc1[mi][nj][3], 0.f);
                __nv_bfloat162 h0, h1, l0, l1;
                h0.x = __float2bfloat16(v0); h0.y = __float2bfloat16(v1);
                h1.x = __float2bfloat16(v2); h1.y = __float2bfloat16(v3);
                l0.x = __float2bfloat16(v0 - __bfloat162float(h0.x));
                l0.y = __float2bfloat16(v1 - __bfloat162float(h0.y));
                l1.x = __float2bfloat16(v2 - __bfloat162float(h1.x));
                l1.y = __float2bfloat16(v3 - __bfloat162float(h1.y));
                *(__nv_bfloat162*)&sFh[off + r*LD]     = h0;
                *(__nv_bfloat162*)&sFh[off + (r+8)*LD] = h1;
                *(__nv_bfloat162*)&sFl[off + r*LD]     = l0;
                *(__nv_bfloat162*)&sFl[off + (r+8)*LD] = l1;
            }
        }
        #pragma unroll
        for (int t = 0; t < 4; t++) {
            __syncthreads();
            *(uint4*)&sBh[brow*LD + bq*8]      = pbh[0];
            *(uint4*)&sBh[(brow+64)*LD + bq*8] = pbh[1];
            *(uint4*)&sBl[brow*LD + bq*8]      = pbl[0];
            *(uint4*)&sBl[(brow+64)*LD + bq*8] = pbl[1];
            __syncthreads();
            int ni = c*8 + t + 5;
            if (ni < 32) {
                pbh[0] = *(const uint4*)bptr(ni, brow,    B1h, B2h);
                pbh[1] = *(const uint4*)bptr(ni, brow+64, B1h, B2h);
                pbl[0] = *(const uint4*)bptr(ni, brow,    B1l, B2l);
                pbl[1] = *(const uint4*)bptr(ni, brow+64, B1l, B2l);
            } else if (!LAST) {
                pbh[0] = *(const uint4*)&Qwh[(size_t)brow*128 + bq*8];
                pbh[1] = *(const uint4*)&Qwh[(size_t)(brow+64)*128 + bq*8];
                pbl[0] = *(const uint4*)&Qwl[(size_t)brow*128 + bq*8];
                pbl[1] = *(const uint4*)&Qwl[(size_t)(brow+64)*128 + bq*8];
            }
            mma_chunk(acc2, sFh + t*CH, sFl + t*CH, sBh, sBl, lane, warpM, warpN);
        }
    }

    #pragma unroll
    for (int mi = 0; mi < 2; mi++) {
        #pragma unroll
        for (int nj = 0; nj < 8; nj++) {
            int r0  = m0 + warpM + mi*16 + (lane >> 2);
            int col = warpN + nj*8 + (lane & 3)*2;
            float2 c0 = *(const float2*)&X[(size_t)r0*128 + col];
            float2 c1 = *(const float2*)&X[(size_t)(r0+8)*128 + col];
            acc2[mi][nj][0] += c0.x; acc2[mi][nj][1] += c0.y;
            acc2[mi][nj][2] += c1.x; acc2[mi][nj][3] += c1.y;
        }
    }

    float mean[4], rsig[4];
    if (!LAST) ln_stats(acc2, mean, rsig);

    #pragma unroll
    for (int mi = 0; mi < 2; mi++) {
        #pragma unroll
        for (int nj = 0; nj < 8; nj++) {
            int r   = warpM + mi*16 + (lane >> 2);
            int col = warpN + nj*8 + (lane & 3)*2;
            int r0  = m0 + r;
            float v0 = acc2[mi][nj][0], v1 = acc2[mi][nj][1];
            float v2 = acc2[mi][nj][2], v3 = acc2[mi][nj][3];
            float2 o0; o0.x = v0; o0.y = v1;
            float2 o1; o1.x = v2; o1.y = v3;
            *(float2*)&X[(size_t)r0*128 + col]     = o0;
            *(float2*)&X[(size_t)(r0+8)*128 + col] = o1;
            if (!LAST) {
                v0 = (v0 - mean[mi*2])*rsig[mi*2];
                v1 = (v1 - mean[mi*2])*rsig[mi*2];
                v2 = (v2 - mean[mi*2+1])*rsig[mi*2+1];
                v3 = (v3 - mean[mi*2+1])*rsig[mi*2+1];
                int off = (col >> 5)*CH + (col & 31);
                __nv_bfloat162 h0, h1, l0, l1;
                h0.x = __float2bfloat16(v0); h0.y = __float2bfloat16(v1);
                h1.x = __float2bfloat16(v2); h1.y = __float2bfloat16(v3);
                l0.x = __float2bfloat16(v0 - __bfloat162float(h0.x));
                l0.y = __float2bfloat16(v1 - __bfloat162float(h0.y));
                l1.x = __float2bfloat16(v2 - __bfloat162float(h1.x));
                l1.y = __float2bfloat16(v3 - __bfloat162float(h1.y));
                *(__nv_bfloat162*)&sAh[off + r*LD]     = h0;
                *(__nv_bfloat162*)&sAh[off + (r+8)*LD] = h1;
                *(__nv_bfloat162*)&sAl[off + r*LD]     = l0;
                *(__nv_bfloat162*)&sAl[off + (r+8)*LD] = l1;
            }
        }
    }

    if (!LAST) {
        #pragma unroll 1
        for (int nb = 0; nb < 3; nb++) {
            float acc[2][8][4] = {};
            #pragma unroll
            for (int t = 0; t < 4; t++) {
                __syncthreads();
                *(uint4*)&sBh[brow*LD + bq*8]      = pbh[0];
                *(uint4*)&sBh[(brow+64)*LD + bq*8] = pbh[1];
                *(uint4*)&sBl[brow*LD + bq*8]      = pbl[0];
                *(uint4*)&sBl[(brow+64)*LD + bq*8] = pbl[1];
                __syncthreads();
                int ni = nb*4 + t + 1;
                if (ni < 12) {
                    int nrow = (ni >> 2)*128, kc = (ni & 3)*32;
                    pbh[0] = *(const uint4*)&Qwh[(size_t)(nrow + brow)*128 + kc + bq*8];
                    pbh[1] = *(const uint4*)&Qwh[(size_t)(nrow + brow+64)*128 + kc + bq*8];
                    pbl[0] = *(const uint4*)&Qwl[(size_t)(nrow + brow)*128 + kc + bq*8];
                    pbl[1] = *(const uint4*)&Qwl[(size_t)(nrow + brow+64)*128 + kc + bq*8];
                }
                mma_chunk(acc, sAh + t*CH, sAl + t*CH, sBh, sBl, lane, warpM, warpN);
            }
            #pragma unroll
            for (int mi = 0; mi < 2; mi++) {
                #pragma unroll
                for (int nj = 0; nj < 8; nj++) {
                    int r0  = m0 + warpM + mi*16 + (lane >> 2);
                    int col = nb*128 + warpN + nj*8 + (lane & 3)*2;
                    float2 o0; o0.x = acc[mi][nj][0]; o0.y = acc[mi][nj][1];
                    float2 o1; o1.x = acc[mi][nj][2]; o1.y = acc[mi][nj][3];
                    *(float2*)&qkvout[(size_t)r0*384 + col]     = o0;
                    *(float2*)&qkvout[(size_t)(r0+8)*384 + col] = o1;
                }
            }
        }
    }
}

// ---------------- fused pair-feature -> LN -> FF -> head bias ---------------
__global__ void __launch_bounds__(256)
bias_kernel(const float* __restrict__ pos, const int* __restrict__ uid,
            const float* __restrict__ Wp, const float* __restrict__ W1,
            const float* __restrict__ W2, const float* __restrict__ Wb)
{
    __shared__ float sposi[32][3], sposj[KWIN][3];
    __shared__ int   suidi[32],    suidj[KWIN];
    __shared__ float4 spi4[32][4], spj4[KWIN][4];
    __shared__ float sWp[80], sWb[64];
    __shared__ float4 sW1T[64][4];
    __shared__ float4 sW2b[64];
    __shared__ unsigned char svalid[KWIN];

    int bb = blockIdx.x;
    int half = bb & 1;
    int bw = bb >> 1;
    int b = bw / NW, w = bw % NW;
    int q0 = half*32;
    int tid = threadIdx.x;

    for (int i = tid; i < 80; i += 256) sWp[i] = Wp[i];
    for (int i = tid; i < 64; i += 256) sWb[i] = Wb[i];
    for (int i = tid; i < 1024; i += 256) {
        int j = i >> 4, c = i & 15;
        ((float*)sW1T)[j*16 + c] = W1[c*64 + j];
    }
    if (tid < 64) {
        float4 r = make_float4(0,0,0,0);
        #pragma unroll
        for (int c = 0; c < 16; c++) {
            float w2v = W2[tid*16 + c];
            r.x += w2v*Wb[c*4+0]; r.y += w2v*Wb[c*4+1];
            r.z += w2v*Wb[c*4+2]; r.w += w2v*Wb[c*4+3];
        }
        sW2b[tid] = r;
    }
    for (int q = tid; q < 32; q += 256) {
        int gi = b*N_ + w*QWIN + q0 + q;
        sposi[q][0] = pos[gi*3]; sposi[q][1] = pos[gi*3+1]; sposi[q][2] = pos[gi*3+2];
        suidi[q] = uid[gi];
        const float4* pp = (const float4*)&g_p[(size_t)gi*32];
        spi4[q][0] = pp[0]; spi4[q][1] = pp[1]; spi4[q][2] = pp[2]; spi4[q][3] = pp[3];
    }
    for (int k = tid; k < KWIN; k += 256) {
        int j = w*QWIN + k - PADW;
        bool valid = (j >= 0 && j < N_);
        svalid[k] = valid;
        if (valid) {
            int gj = b*N_ + j;
            sposj[k][0] = pos[gj*3]; sposj[k][1] = pos[gj*3+1]; sposj[k][2] = pos[gj*3+2];
            suidj[k] = uid[gj];
            const float4* pp = (const float4*)&g_p[(size_t)gj*32 + 16];
            spj4[k][0] = pp[0]; spj4[k][1] = pp[1]; spj4[k][2] = pp[2]; spj4[k][3] = pp[3];
        } else {
            sposj[k][0] = sposj[k][1] = sposj[k][2] = 0.f; suidj[k] = -1;
            float4 z = make_float4(0,0,0,0);
            spj4[k][0] = z; spj4[k][1] = z; spj4[k][2] = z; spj4[k][3] = z;
        }
    }
    __syncthreads();

    float* brow = g_bias + (size_t)bw*HEADS*QWIN*KWIN;

    auto prep = [&](int q, int k, float4* u, float& bh0, float& bh1, float& bh2, float& bh3) {
        float dx = sposi[q][0]-sposj[k][0];
        float dy = sposi[q][1]-sposj[k][1];
        float dz = sposi[q][2]-sposj[k][2];
        float inv = 1.f / (1.f + dx*dx + dy*dy + dz*dz);
        float bij = (suidi[q] == suidj[k]) ? 1.f : 0.f;
        float4 pr[4];
        #pragma unroll
        for (int c4 = 0; c4 < 4; c4++) {
            float4 r;
            #pragma unroll
            for (int e = 0; e < 4; e++) {
                int c = c4*4 + e;
                float base = dx*sWp[c] + dy*sWp[16+c] + dz*sWp[32+c] + inv*sWp[48+c] + sWp[64+c];
                (&r.x)[e] = base*bij + (&spi4[q][c4].x)[e] + (&spj4[k][c4].x)[e];
            }
            pr[c4] = r;
        }
        float s = 0.f, s2 = 0.f;
        #pragma unroll
        for (int c4 = 0; c4 < 4; c4++) {
            s  += pr[c4].x + pr[c4].y + pr[c4].z + pr[c4].w;
            s2 += pr[c4].x*pr[c4].x + pr[c4].y*pr[c4].y + pr[c4].z*pr[c4].z + pr[c4].w*pr[c4].w;
        }
        float mean = s * (1.f/DP);
        float var  = s2 * (1.f/DP) - mean*mean;
        float rinv = rsqrtf(var + 1e-5f);
        bh0 = bh1 = bh2 = bh3 = 0.f;
        #pragma unroll
        for (int c4 = 0; c4 < 4; c4++) {
            #pragma unroll
            for (int e = 0; e < 4; e++) {
                int c = c4*4 + e;
                float pv = (&pr[c4].x)[e];
                bh0 += pv*sWb[c*4+0]; bh1 += pv*sWb[c*4+1];
                bh2 += pv*sWb[c*4+2]; bh3 += pv*sWb[c*4+3];
                (&u[c4].x)[e] = (pv - mean)*rinv;
            }
        }
    };

    for (int t = tid; t < 32*64; t += 256) {
        int q = t >> 6, k0 = t & 63, k1 = k0 + 64;
        int gq = q0 + q;
        float4 u0[4], u1[4];
        float a0,a1,a2,a3, c0,c1,c2,c3;
        prep(q, k0, u0, a0, a1, a2, a3);
        prep(q, k1, u1, c0, c1, c2, c3);
        #pragma unroll 2
        for (int j = 0; j < 64; j++) {
            float4 w0 = sW1T[j][0], w1 = sW1T[j][1], w2 = sW1T[j][2], w3 = sW1T[j][3];
            float t0 = u0[0].x*w0.x + u0[0].y*w0.y + u0[0].z*w0.z + u0[0].w*w0.w
                     + u0[1].x*w1.x + u0[1].y*w1.y + u0[1].z*w1.z + u0[1].w*w1.w
                     + u0[2].x*w2.x + u0[2].y*w2.y + u0[2].z*w2.z + u0[2].w*w2.w
                     + u0[3].x*w3.x + u0[3].y*w3.y + u0[3].z*w3.z + u0[3].w*w3.w;
            float t1 = u1[0].x*w0.x + u1[0].y*w0.y + u1[0].z*w0.z + u1[0].w*w0.w
                     + u1[1].x*w1.x + u1[1].y*w1.y + u1[1].z*w1.z + u1[1].w*w1.w
                     + u1[2].x*w2.x + u1[2].y*w2.y + u1[2].z*w2.z + u1[2].w*w2.w
                     + u1[3].x*w3.x + u1[3].y*w3.y + u1[3].z*w3.z + u1[3].w*w3.w;
            t0 = fmaxf(t0, 0.f); t1 = fmaxf(t1, 0.f);
            float4 wb2 = sW2b[j];
            a0 += t0*wb2.x; a1 += t0*wb2.y; a2 += t0*wb2.z; a3 += t0*wb2.w;
            c0 += t1*wb2.x; c1 += t1*wb2.y; c2 += t1*wb2.z; c3 += t1*wb2.w;
        }
        bool v0 = svalid[k0], v1 = svalid[k1];
        brow[((0*QWIN + gq) << 7) + k0] = v0 ? a0 : 0.f;
        brow[((1*QWIN + gq) << 7) + k0] = v0 ? a1 : 0.f;
        brow[((2*QWIN + gq) << 7) + k0] = v0 ? a2 : 0.f;
        brow[((3*QWIN + gq) << 7) + k0] = v0 ? a3 : 0.f;
        brow[((0*QWIN + gq) << 7) + k1] = v1 ? c0 : 0.f;
        brow[((1*QWIN + gq) << 7) + k1] = v1 ? c1 : 0.f;
        brow[((2*QWIN + gq) << 7) + k1] = v1 ? c2 : 0.f;
        brow[((3*QWIN + gq) << 7) + k1] = v1 ? c3 : 0.f;
    }
}

// ---------------- attention per (b, window, head): 8 q-rows, single pass -----
// K/V reads amortized over all 8 rows a warp owns (halved LDS traffic again).
__global__ void __launch_bounds__(256)
attn_kernel(const float* __restrict__ qkv, float* __restrict__ o)
{
    extern __shared__ char dynattn[];
    float4* ks4 = (float4*)dynattn;            // [128][8] = 16KB
    float4* vs4 = ks4 + 1024;                  // [128][8] = 16KB
    float4* sq  = vs4 + 1024;                  // [64][8]  =  8KB
    float*  ps  = (float*)(sq + 512);          // [8][8][128] = 32KB

    int h  = blockIdx.x & 3;
    int bw = blockIdx.x >> 2;
    int w  = bw & (NW-1);
    int b  = bw >> 7;
    int tid = threadIdx.x, lane = tid & 31, warp = tid >> 5;
    int rowbase = b*N_ + w*QWIN;

    for (int s = tid; s < KWIN*8; s += 256) {
        int kk = s >> 3, i = s & 7;
        int j = w*QWIN + kk - PADW;
        float4 kv = make_float4(0,0,0,0), vv = make_float4(0,0,0,0);
        if (j >= 0 && j < N_) {
            const float* base = &qkv[(size_t)(b*N_ + j)*384 + h*32 + i*4];
            kv = *(const float4*)(base + 128);
            vv = *(const float4*)(base + 256);
        }
        int sw = i ^ (kk & 7);
        ks4[kk*8 + sw] = kv;
        vs4[kk*8 + sw] = vv;
    }
    for (int s = tid; s < QWIN*8; s += 256) {
        int r = s >> 3, i = s & 7;
        sq[r*8 + i] = *(const float4*)&qkv[(size_t)(rowbase + r)*384 + h*32 + i*4];
    }
    __syncthreads();

    const float scale = 0.17677669529663687f;
    const float* brow = g_bias + ((size_t)bw*HEADS + h)*QWIN*KWIN;
    int lane7 = lane & 7;
    int lhi = lane >> 2, llo = lane & 3;
    const float4* kbase = &ks4[lane*8];
    const float*  vbase = (const float*)vs4;
    float* pw = ps + warp*8*128;
    int r0 = warp*8;

    float msk[4];
    #pragma unroll
    for (int g = 0; g < 4; g++) {
        int j = w*QWIN + g*32 + lane - PADW;
        msk[g] = (j >= 0 && j < N_) ? 0.f : -1e9f;
    }
    int voff[8];
    #pragma unroll
    for (int t = 0; t < 8; t++) voff[t] = ((lhi ^ t) << 2) | llo;

    // ---- QK: 8 rows share every K read ----
    float a[8][4] = {};
    #pragma unroll
    for (int i = 0; i < 8; i++) {
        int sw = i ^ lane7;
        float4 kv0 = kbase[sw];
        float4 kv1 = kbase[256 + sw];
        float4 kv2 = kbase[512 + sw];
        float4 kv3 = kbase[768 + sw];
        #pragma unroll
        for (int r = 0; r < 8; r++) {
            float4 q = sq[(r0 + r)*8 + i];
            a[r][0] += q.x*kv0.x + q.y*kv0.y + q.z*kv0.z + q.w*kv0.w;
            a[r][1] += q.x*kv1.x + q.y*kv1.y + q.z*kv1.z + q.w*kv1.w;
            a[r][2] += q.x*kv2.x + q.y*kv2.y + q.z*kv2.z + q.w*kv2.w;
            a[r][3] += q.x*kv3.x + q.y*kv3.y + q.z*kv3.z + q.w*kv3.w;
        }
    }
    // ---- softmax per row ----
    float m[8];
    #pragma unroll
    for (int r = 0; r < 8; r++) {
        m[r] = -1e30f;
        #pragma unroll
        for (int g = 0; g < 4; g++) {
            float l = a[r][g]*scale + brow[((r0+r)<<7) + g*32 + lane] + msk[g];
            a[r][g] = l;
            m[r] = fmaxf(m[r], l);
        }
    }
    #pragma unroll
    for (int off = 16; off > 0; off >>= 1)
        #pragma unroll
        for (int r = 0; r < 8; r++)
            m[r] = fmaxf(m[r], __shfl_xor_sync(~0u, m[r], off));
    float sums[8];
    #pragma unroll
    for (int r = 0; r < 8; r++) {
        sums[r] = 0.f;
        #pragma unroll
        for (int g = 0; g < 4; g++) {
            float e = __expf(a[r][g] - m[r]);
            a[r][g] = e;
            sums[r] += e;
        }
    }
    #pragma unroll
    for (int off = 16; off > 0; off >>= 1)
        #pragma unroll
        for (int r = 0; r < 8; r++)
            sums[r] += __shfl_xor_sync(~0u, sums[r], off);
    #pragma unroll
    for (int r = 0; r < 8; r++) {
        float rs = 1.f/sums[r];
        #pragma unroll
        for (int g = 0; g < 4; g++)
            pw[r*128 + g*32 + lane] = a[r][g]*rs;
    }
    __syncwarp();

    // ---- PV: 8 rows share every V read ----
    float o8[8] = {};
    #pragma unroll 2
    for (int k8 = 0; k8 < 16; k8++) {
        const float* vb = vbase + k8*256;
        float v0 = vb[voff[0]],        v1 = vb[32  + voff[1]];
        float v2 = vb[64  + voff[2]],  v3 = vb[96  + voff[3]];
        float v4 = vb[128 + voff[4]],  v5 = vb[160 + voff[5]];
        float v6 = vb[192 + voff[6]],  v7 = vb[224 + voff[7]];
        #pragma unroll
        for (int r = 0; r < 8; r++) {
            float4 p0 = *(const float4*)&pw[r*128 + k8*8];
            float4 p1 = *(const float4*)&pw[r*128 + k8*8 + 4];
            o8[r] += p0.x*v0 + p0.y*v1 + p0.z*v2 + p0.w*v3
                   + p1.x*v4 + p1.y*v5 + p1.z*v6 + p1.w*v7;
        }
    }
    #pragma unroll
    for (int r = 0; r < 8; r++)
        o[(size_t)(rowbase + r0 + r)*DS + h*32 + lane] = o8[r];
}

// ---------------- deterministic segment mean (indices sorted) ---------------
__global__ void segmean_kernel(const int* __restrict__ a2t, float* __restrict__ out)
{
    int bt = blockIdx.x;
    int b = bt / NTOK, t = bt % NTOK;
    const int* idx = a2t + b*N_;
    __shared__ int slo, shi;
    if (threadIdx.x == 0) {
        int lo = 0, hi = N_;
        while (lo < hi) { int mid = (lo+hi) >> 1; if (idx[mid] < t) lo = mid+1; else hi = mid; }
        slo = lo;
        int lo2 = lo, hi2 = N_;
        while (lo2 < hi2) { int mid = (lo2+hi2) >> 1; if (idx[mid] < t+1) lo2 = mid+1; else hi2 = mid; }
        shi = lo2;
    }
    __syncthreads();
    int lo = slo, hi = shi;
    float rcnt = 1.f / fmaxf((float)(hi - lo), 1.f);
    for (int d = threadIdx.x; d < DT; d += blockDim.x) {
        float ssum = 0.f;
        for (int i = lo; i < hi; i++) ssum += g_tok[((size_t)(b*N_ + i))*DT + d];
        out[(size_t)bt*DT + d] = ssum * rcnt;
    }
}

// ---------------- launch ----------------------------------------------------
extern "C" void kernel_launch(void* const* d_in, const int* in_sizes, int n_in,
                              void* d_out, int out_size)
{
    const float* ref_pos    = (const float*)d_in[0];
    const float* ref_charge = (const float*)d_in[1];
    const float* ref_mask   = (const float*)d_in[2];
    const float* ref_elem   = (const float*)d_in[3];
    const float* ref_chars  = (const float*)d_in[4];
    const float* W_single   = (const float*)d_in[5];
    const float* W_pair     = (const float*)d_in[6];
    const float* W_outer    = (const float*)d_in[7];
    const float* Wp_ff1     = (const float*)d_in[8];
    const float* Wp_ff2     = (const float*)d_in[9];
    const float* Wq         = (const float*)d_in[10];
    const float* Wk         = (const float*)d_in[11];
    const float* Wv         = (const float*)d_in[12];
    const float* Wo         = (const float*)d_in[13];
    const float* Wb         = (const float*)d_in[14];
    const float* Wff1       = (const float*)d_in[15];
    const float* Wff2       = (const float*)d_in[16];
    const float* W_out      = (const float*)d_in[17];
    const int*   uid        = (const int*)d_in[18];
    const int*   a2t        = (const int*)d_in[19];
    float* out = (float*)d_out;

    float *feats, *x, *qkv, *o, *p, *tok;
    __nv_bfloat16 *bh, *bl;
    cudaGetSymbolAddress((void**)&feats, g_feats);
    cudaGetSymbolAddress((void**)&x,     g_x);
    cudaGetSymbolAddress((void**)&qkv,   g_qkv);
    cudaGetSymbolAddress((void**)&o,     g_o);
    cudaGetSymbolAddress((void**)&p,     g_p);
    cudaGetSymbolAddress((void**)&tok,   g_tok);
    cudaGetSymbolAddress((void**)&bh,    g_bh);
    cudaGetSymbolAddress((void**)&bl,    g_bl);

    const int WIDE_SMEM = (2*256*40 + 2*128*40) * 2;         // 61440 bytes
    const int FF_SMEM   = (4*128*40*4 + 2*128*40) * 2;       // 184320 bytes
    const int ATTN_SMEM = 16384 + 16384 + 8192 + 32768;      // 73728 bytes
    cudaFuncSetAttribute(mma_gemm_wide<false,3>, cudaFuncAttributeMaxDynamicSharedMemorySize, WIDE_SMEM);
    cudaFuncSetAttribute(embed_fused, cudaFuncAttributeMaxDynamicSharedMemorySize, FF_SMEM);
    cudaFuncSetAttribute(layer_fused<false>, cudaFuncAttributeMaxDynamicSharedMemorySize, FF_SMEM);
    cudaFuncSetAttribute(layer_fused<true>,  cudaFuncAttributeMaxDynamicSharedMemorySize, FF_SMEM);
    cudaFuncSetAttribute(attn_kernel, cudaFuncAttributeMaxDynamicSharedMemorySize, ATTN_SMEM);

    // 0) prep: weight pack + feats build (one launch)
    const int PB = (PACK_TOT + 255)/256;
    prep_kernel<<<PB + R_, 256>>>(W_single, Wq, Wk, Wv, Wo, Wff1, Wff2, W_out, W_outer,
                                  ref_pos, ref_charge, ref_mask, ref_elem, ref_chars);

    // 1) fused embed: x, p, qkv(layer 0)
    embed_fused<<<R_/128, 256, FF_SMEM>>>(feats,
        bh+OFF_EMB, bl+OFF_EMB, bh+OFF_WOUTER, bl+OFF_WOUTER,
        bh+OFF_QKV, bl+OFF_QKV, x, p, qkv);

    // 2) pair bias
    bias_kernel<<<B_*NW*2, 256>>>(ref_pos, uid, W_pair, Wp_ff1, Wp_ff2, Wb);

    // 3) transformer layers: attn -> layer_fused (WO+LN+FF+next QKV)
    for (int l = 0; l < DEPTH; l++) {
        attn_kernel<<<B_*NW*HEADS, 256, ATTN_SMEM>>>(qkv, o);
        if (l < DEPTH-1) {
            layer_fused<false><<<R_/128, 256, FF_SMEM>>>(o,
                bh+OFF_WO+(size_t)l*16384, bl+OFF_WO+(size_t)l*16384,
                bh+OFF_FF1+(size_t)l*65536, bl+OFF_FF1+(size_t)l*65536,
                bh+OFF_FF2+(size_t)l*65536, bl+OFF_FF2+(size_t)l*65536,
                bh+OFF_QKV+(size_t)(l+1)*49152, bl+OFF_QKV+(size_t)(l+1)*49152,
                x, qkv);
        } else {
            layer_fused<true><<<R_/128, 256, FF_SMEM>>>(o,
                bh+OFF_WO+(size_t)l*16384, bl+OFF_WO+(size_t)l*16384,
                bh+OFF_FF1+(size_t)l*65536, bl+OFF_FF1+(size_t)l*65536,
                bh+OFF_FF2+(size_t)l*65536, bl+OFF_FF2+(size_t)l*65536,
                nullptr, nullptr, x, nullptr);
        }
    }

    // 4) tok = relu(x @ W_out); segment mean -> out
    mma_gemm_wide<false,3><<<dim3(3, R_/256), 512, WIDE_SMEM>>>(x, nullptr, nullptr,
        bh+OFF_WOUT, bl+OFF_WOUT, tok, nullptr, nullptr, R_, DT, DS);
    segmean_kernel<<<B_*NTOK, 384>>>(a2t, out);
}